// round 2
// baseline (speedup 1.0000x reference)
#include <cuda_runtime.h>
#include <math.h>

#define FINAL 229376        // 16 * 14336 final flat length
#define XLD   262144        // fixed channel stride for x buffers
#define TOUT  14336

// Scratch (device globals; no allocation anywhere)
__device__ float g_xa[32 * XLD];
__device__ float g_xb[32 * XLD];
__device__ float g_ybuf[1280 * FINAL];   // 40 layers * 32 ch * FINAL tail
__device__ float g_skip[256 * FINAL];

// ---------------------------------------------------------------------------
// start conv: x0[c][t*16+b] = sum_f sw[c][f] * input[b][f][t]
// block: 16 t x 16 b = 256 contiguous flat positions
// ---------------------------------------------------------------------------
__global__ void k_start(const float* __restrict__ in, const float* __restrict__ sw,
                        float* __restrict__ x0)
{
    __shared__ float s_w[4096];          // [c*128+f]
    __shared__ float s_in[16 * 272];     // [f'][tt*17 + bb] (pad 17 avoids conflicts)
    int tid = threadIdx.x;               // 256
    for (int l = tid; l < 4096; l += 256) s_w[l] = sw[l];
    int t0 = blockIdx.x * 16;
    int b = tid & 15, dt = tid >> 4;
    float acc[32];
#pragma unroll
    for (int c = 0; c < 32; c++) acc[c] = 0.f;
    int tt = tid & 15, rhalf = tid >> 4;
    for (int fc = 0; fc < 8; fc++) {
        __syncthreads();
#pragma unroll
        for (int pass = 0; pass < 16; pass++) {
            int row = pass * 16 + rhalf;
            int bb = row >> 4, ff = row & 15;
            s_in[ff * 272 + tt * 17 + bb] =
                in[(bb * 128 + fc * 16 + ff) * 16384 + t0 + tt];
        }
        __syncthreads();
#pragma unroll
        for (int f = 0; f < 16; f++) {
            float v = s_in[f * 272 + dt * 17 + b];
#pragma unroll
            for (int c = 0; c < 32; c++)
                acc[c] += s_w[c * 128 + fc * 16 + f] * v;
        }
    }
    int m = t0 * 16 + tid;
#pragma unroll
    for (int c = 0; c < 32; c++)
        x0[c * XLD + m] = acc[c];
}

// ---------------------------------------------------------------------------
// fused dilated layer: filter+gate GEMM (64x64), tanh*sigmoid, res GEMM,
// residual add, y-tail store.  Tile: 64 flat positions per block, 256 thr.
// ---------------------------------------------------------------------------
__global__ void k_layer(const float* __restrict__ xin, float* __restrict__ xout,
                        float* __restrict__ ytail,
                        const float* __restrict__ fw, const float* __restrict__ gw,
                        const float* __restrict__ rw,
                        int Min, int Mout, int P, int S, int ofs)
{
    __shared__ float Ws[64][64];   // [k][r] weights, later reused as U[r][m]
    __shared__ float Xs[64][68];   // [k][m]  rows 0..31: xA, 32..63: xB; rows 0..31 reused for y
    __shared__ float Wr[32][32];   // [k][c]
    int tid = threadIdx.x;         // 256
    int m0 = blockIdx.x * 64;

    for (int l = tid; l < 4096; l += 256) {
        int r = l & 63, j = l >> 6;
        const float* w = (r < 32) ? fw : gw;
        Ws[j][r] = w[((r & 31) * 32 + (j & 31)) * 2 + (j >> 5)];
    }
    for (int l = tid; l < 1024; l += 256)
        Wr[l >> 5][l & 31] = rw[(l & 31) * 32 + (l >> 5)];
    for (int l = tid; l < 4096; l += 256) {
        int mm = l & 63, j = l >> 6;
        int idx = m0 + mm + ((j < 32) ? -P : (S - P));
        float v = 0.f;
        if (idx >= 0 && idx < Min) v = xin[(j & 31) * XLD + idx];
        Xs[j][mm] = v;
    }
    __syncthreads();

    // GEMM1: U[64][64] = W64 * Xcat
    int tr = tid & 15, tc = tid >> 4;
    float a[4][4];
#pragma unroll
    for (int i = 0; i < 4; i++)
#pragma unroll
        for (int j = 0; j < 4; j++) a[i][j] = 0.f;
#pragma unroll
    for (int k = 0; k < 64; k++) {
        float4 wv = *(const float4*)&Ws[k][tr * 4];
        float4 xv = *(const float4*)&Xs[k][tc * 4];
        float wr[4] = {wv.x, wv.y, wv.z, wv.w};
        float xr[4] = {xv.x, xv.y, xv.z, xv.w};
#pragma unroll
        for (int i = 0; i < 4; i++)
#pragma unroll
            for (int j = 0; j < 4; j++) a[i][j] += wr[i] * xr[j];
    }
    __syncthreads();
#pragma unroll
    for (int i = 0; i < 4; i++)
#pragma unroll
        for (int j = 0; j < 4; j++)
            Ws[tr * 4 + i][tc * 4 + j] = a[i][j];
    __syncthreads();

    // y = tanh(uf) * sigmoid(ug); store into Xs rows 0..31; write tail to ybuf
    for (int l = tid; l < 2048; l += 256) {
        int mm = l & 63, c = l >> 6;
        float uf = Ws[c][mm], ug = Ws[c + 32][mm];
        float y = tanhf(uf) * (1.f / (1.f + expf(-ug)));
        Xs[c][mm] = y;
        int m = m0 + mm;
        if (m >= ofs && m < Mout) ytail[c * FINAL + (m - ofs)] = y;
    }
    __syncthreads();

    // GEMM2: xn = Wres * y + xB
    int m2 = tid & 31, c4 = tid >> 5;
    float b0[4], b1v[4];
#pragma unroll
    for (int i = 0; i < 4; i++) { b0[i] = 0.f; b1v[i] = 0.f; }
#pragma unroll
    for (int k = 0; k < 32; k++) {
        float ya = Xs[k][m2], yb2 = Xs[k][m2 + 32];
        float4 wv = *(const float4*)&Wr[k][c4 * 4];
        float wr[4] = {wv.x, wv.y, wv.z, wv.w};
#pragma unroll
        for (int i = 0; i < 4; i++) {
            b0[i]  += wr[i] * ya;
            b1v[i] += wr[i] * yb2;
        }
    }
    int ma = m0 + m2, mb = m0 + m2 + 32;
#pragma unroll
    for (int i = 0; i < 4; i++) {
        int c = c4 * 4 + i;
        if (ma < Mout) xout[c * XLD + ma] = b0[i]  + Xs[32 + c][m2];
        if (mb < Mout) xout[c * XLD + mb] = b1v[i] + Xs[32 + c][m2 + 32];
    }
}

// ---------------------------------------------------------------------------
// skip GEMM: skip[256][FINAL] = skip_w(256 x 1280) * ytails(1280 x FINAL)
// block tile 64(o) x 64(p), K chunk = 32 (exactly one layer per chunk)
// ---------------------------------------------------------------------------
__global__ void k_skip(const float* __restrict__ yb, const float* __restrict__ sw,
                       float* __restrict__ skip)
{
    __shared__ float As[32][68];   // [c][o]
    __shared__ float Bs[32][64];   // [c][p]
    int tid = threadIdx.x;         // 256
    int p0 = blockIdx.x * 64, o0 = blockIdx.y * 64;
    int tr = tid & 15, tc = tid >> 4;
    float a[4][4];
#pragma unroll
    for (int i = 0; i < 4; i++)
#pragma unroll
        for (int j = 0; j < 4; j++) a[i][j] = 0.f;

    for (int kc = 0; kc < 40; kc++) {
        __syncthreads();
        for (int l = tid; l < 2048; l += 256) {
            int c = l & 31, o = l >> 5;
            As[c][o] = sw[(kc * 256 + o0 + o) * 32 + c];
        }
        for (int l = tid; l < 2048; l += 256) {
            int p = l & 63, c = l >> 6;
            Bs[c][p] = yb[(kc * 32 + c) * FINAL + p0 + p];
        }
        __syncthreads();
#pragma unroll
        for (int k = 0; k < 32; k++) {
            float4 wv = *(const float4*)&As[k][tr * 4];
            float4 xv = *(const float4*)&Bs[k][tc * 4];
            float wr[4] = {wv.x, wv.y, wv.z, wv.w};
            float xr[4] = {xv.x, xv.y, xv.z, xv.w};
#pragma unroll
            for (int i = 0; i < 4; i++)
#pragma unroll
                for (int j = 0; j < 4; j++) a[i][j] += wr[i] * xr[j];
        }
    }
#pragma unroll
    for (int i = 0; i < 4; i++)
#pragma unroll
        for (int j = 0; j < 4; j++)
            skip[(o0 + tr * 4 + i) * FINAL + p0 + tc * 4 + j] = a[i][j];
}

// ---------------------------------------------------------------------------
// end: out[p] = e2 . relu(e1 . relu(skip[:,p]) + b1) + b2
// block = 64 positions, 512 threads, full 256 h-rows per block
// ---------------------------------------------------------------------------
__global__ void k_end(const float* __restrict__ skip, const float* __restrict__ e1w,
                      const float* __restrict__ e1b, const float* __restrict__ e2w,
                      const float* __restrict__ e2b, float* __restrict__ out)
{
    __shared__ float E1s[32][264];  // [k][o] ; reused as part[32][64] at the end
    __shared__ float Vs[32][68];    // [k][p] relu(skip)
    __shared__ float s_e2[256];
    float* part = &E1s[0][0];
    int tid = threadIdx.x;          // 512
    int p0 = blockIdx.x * 64;
    int pg = tid & 15, rg = tid >> 4;
    for (int l = tid; l < 256; l += 512) s_e2[l] = e2w[l];

    float acc[8][4];
#pragma unroll
    for (int i = 0; i < 8; i++)
#pragma unroll
        for (int j = 0; j < 4; j++) acc[i][j] = 0.f;

    for (int kc = 0; kc < 8; kc++) {
        __syncthreads();
        for (int l = tid; l < 2048; l += 512) {
            int p = l & 63, k = l >> 6;
            float v = skip[(kc * 32 + k) * FINAL + p0 + p];
            Vs[k][p] = v > 0.f ? v : 0.f;
        }
        for (int f4 = tid; f4 < 2048; f4 += 512) {
            int o = f4 >> 3, k4 = f4 & 7;
            float4 w = *(const float4*)&e1w[o * 256 + kc * 32 + k4 * 4];
            E1s[k4 * 4 + 0][o] = w.x; E1s[k4 * 4 + 1][o] = w.y;
            E1s[k4 * 4 + 2][o] = w.z; E1s[k4 * 4 + 3][o] = w.w;
        }
        __syncthreads();
#pragma unroll
        for (int k = 0; k < 32; k++) {
            float4 v  = *(const float4*)&Vs[k][pg * 4];
            float4 w0 = *(const float4*)&E1s[k][rg * 8];
            float4 w1 = *(const float4*)&E1s[k][rg * 8 + 4];
            float vr[4] = {v.x, v.y, v.z, v.w};
            float wr[8] = {w0.x, w0.y, w0.z, w0.w, w1.x, w1.y, w1.z, w1.w};
#pragma unroll
            for (int i = 0; i < 8; i++)
#pragma unroll
                for (int j = 0; j < 4; j++) acc[i][j] += wr[i] * vr[j];
        }
    }
    __syncthreads();

    float pp[4] = {0.f, 0.f, 0.f, 0.f};
#pragma unroll
    for (int rr = 0; rr < 8; rr++) {
        int row = rg * 8 + rr;
        float bb = e1b[row], w2 = s_e2[row];
#pragma unroll
        for (int j = 0; j < 4; j++) {
            float h = acc[rr][j] + bb;
            h = h > 0.f ? h : 0.f;
            pp[j] += w2 * h;
        }
    }
#pragma unroll
    for (int j = 0; j < 4; j++) part[rg * 64 + pg * 4 + j] = pp[j];
    __syncthreads();
    if (tid < 64) {
        float s = e2b[0];
#pragma unroll
        for (int r = 0; r < 32; r++) s += part[r * 64 + tid];
        int p = p0 + tid;
        out[(p & 15) * TOUT + (p >> 4)] = s;
    }
}

// ---------------------------------------------------------------------------
extern "C" void kernel_launch(void* const* d_in, const int* in_sizes, int n_in,
                              void* d_out, int out_size)
{
    const float* input    = (const float*)d_in[0];
    const float* start_w  = (const float*)d_in[1];
    const float* filter_w = (const float*)d_in[2];
    const float* gate_w   = (const float*)d_in[3];
    const float* res_w    = (const float*)d_in[4];
    const float* skip_w   = (const float*)d_in[5];
    const float* e1w      = (const float*)d_in[6];
    const float* e1b      = (const float*)d_in[7];
    const float* e2w      = (const float*)d_in[8];
    const float* e2b      = (const float*)d_in[9];
    float* out = (float*)d_out;
    (void)in_sizes; (void)n_in; (void)out_size;

    float *bufA, *bufB, *ybuf, *skipbuf;
    cudaGetSymbolAddress((void**)&bufA, g_xa);
    cudaGetSymbolAddress((void**)&bufB, g_xb);
    cudaGetSymbolAddress((void**)&ybuf, g_ybuf);
    cudaGetSymbolAddress((void**)&skipbuf, g_skip);

    k_start<<<1024, 256>>>(input, start_w, bufA);

    float* cur = bufA;
    float* nxt = bufB;
    for (int i = 0; i < 40; i++) {
        int b = i / 10, k = i % 10;
        int Mb = 262144 - 8192 * b;
        int Min, Mout, P, S;
        if (k == 0) { Min = Mb; Mout = Mb - 16; P = 0; S = 16; }
        else {
            int d = 1 << k;
            Min = Mb - 8 * d;       // M after previous layer
            Mout = Mb - 16 * d;
            P = 8 * d;
            S = 16 * d;
        }
        int ofs = Mout - FINAL;
        int grid = (Mout + 63) / 64;
        k_layer<<<grid, 256>>>(cur, nxt, ybuf + (size_t)i * 32 * FINAL,
                               filter_w + i * 2048, gate_w + i * 2048,
                               res_w + i * 1024,
                               Min, Mout, P, S, ofs);
        float* t = cur; cur = nxt; nxt = t;
    }

    dim3 gs(FINAL / 64, 4);
    k_skip<<<gs, 256>>>(ybuf, skip_w, skipbuf);
    k_end<<<FINAL / 64, 512>>>(skipbuf, e1w, e1b, e2w, e2b, out);
}

// round 3
// speedup vs baseline: 1.7287x; 1.7287x over previous
#include <cuda_runtime.h>
#include <math.h>

#define FINAL 229376        // 16 * 14336 final flat length
#define XLD   262144        // fixed channel stride for x buffers
#define TOUT  14336

// Scratch (device globals; no allocation anywhere)
__device__ float g_xa[32 * XLD];
__device__ float g_xb[32 * XLD];
__device__ float g_ybuf[1280 * FINAL];   // 40 layers * 32 ch * FINAL tail (tf32-rounded)
__device__ float g_skip[256 * FINAL];

// ---------------------------------------------------------------------------
// TF32 helpers
// ---------------------------------------------------------------------------
__device__ __forceinline__ unsigned f2tf(float f) {
    unsigned u;
    asm("cvt.rna.tf32.f32 %0, %1;" : "=r"(u) : "f"(f));
    return u;
}
__device__ __forceinline__ float tf32r(float f) {
    return __uint_as_float(f2tf(f));
}
__device__ __forceinline__ void mma8(float d[4], const unsigned a[4], const unsigned b[2]) {
    asm volatile(
        "mma.sync.aligned.m16n8k8.row.col.f32.tf32.tf32.f32 "
        "{%0,%1,%2,%3},{%4,%5,%6,%7},{%8,%9},{%0,%1,%2,%3};"
        : "+f"(d[0]), "+f"(d[1]), "+f"(d[2]), "+f"(d[3])
        : "r"(a[0]), "r"(a[1]), "r"(a[2]), "r"(a[3]), "r"(b[0]), "r"(b[1]));
}
__device__ __forceinline__ float sigmoidf_(float x) { return 1.f / (1.f + expf(-x)); }

// ---------------------------------------------------------------------------
// start conv: x0[c][t*16+b] = sum_f sw[c][f] * input[b][f][t]
// ---------------------------------------------------------------------------
__global__ void k_start(const float* __restrict__ in, const float* __restrict__ sw,
                        float* __restrict__ x0)
{
    __shared__ float s_w[4096];          // [c*128+f]
    __shared__ float s_in[16 * 272];     // [f'][tt*17 + bb]
    int tid = threadIdx.x;               // 256
    for (int l = tid; l < 4096; l += 256) s_w[l] = sw[l];
    int t0 = blockIdx.x * 16;
    int b = tid & 15, dt = tid >> 4;
    float acc[32];
#pragma unroll
    for (int c = 0; c < 32; c++) acc[c] = 0.f;
    int tt = tid & 15, rhalf = tid >> 4;
    for (int fc = 0; fc < 8; fc++) {
        __syncthreads();
#pragma unroll
        for (int pass = 0; pass < 16; pass++) {
            int row = pass * 16 + rhalf;
            int bb = row >> 4, ff = row & 15;
            s_in[ff * 272 + tt * 17 + bb] =
                in[(bb * 128 + fc * 16 + ff) * 16384 + t0 + tt];
        }
        __syncthreads();
#pragma unroll
        for (int f = 0; f < 16; f++) {
            float v = s_in[f * 272 + dt * 17 + b];
#pragma unroll
            for (int c = 0; c < 32; c++)
                acc[c] += s_w[c * 128 + fc * 16 + f] * v;
        }
    }
    int m = t0 * 16 + tid;
#pragma unroll
    for (int c = 0; c < 32; c++)
        x0[c * XLD + m] = acc[c];
}

// ---------------------------------------------------------------------------
// fused dilated layer (TF32 mma): tile = 64 output rows x 64 positions.
// GEMM1 (64x64x64) -> tanh*sigmoid in registers (row-permuted weights pair
// filter row c with gate row c in one m16 fragment) -> GEMM2 (32x64x32)
// + fp32 residual add.  256 threads = 8 warps.
// ---------------------------------------------------------------------------
__global__ void k_layer(const float* __restrict__ xin, float* __restrict__ xout,
                        float* __restrict__ ytail,
                        const float* __restrict__ fw, const float* __restrict__ gw,
                        const float* __restrict__ rw,
                        int Min, int Mout, int P, int S, int ofs)
{
    __shared__ float Ws[64][68];   // permuted [s][k]  (s pairs filter/gate rows)
    __shared__ float Xs[64][68];   // [k][m]: rows 0..31 xA, 32..63 xB (fp32)
    __shared__ float Ys[32][68];   // y (tf32-rounded floats)
    __shared__ float Wr[32][36];   // [c][ch] row-major

    int tid = threadIdx.x;          // 256
    int m0 = blockIdx.x * 64;
    int lane = tid & 31, w = tid >> 5;
    int grp = lane >> 2, t4 = lane & 3;

    // --- stage weights (permuted rows: s = (c>>3)*16 + isgate*8 + (c&7)) ---
    for (int l = tid; l < 4096; l += 256) {
        int k = l & 63, r = l >> 6;
        int c = r & 31, isg = r >> 5;
        const float* wsrc = isg ? gw : fw;
        float v = wsrc[(c * 32 + (k & 31)) * 2 + (k >> 5)];
        int s = ((c >> 3) << 4) + (isg << 3) + (c & 7);
        Ws[s][k] = v;
    }
    for (int l = tid; l < 1024; l += 256) Wr[l >> 5][l & 31] = rw[l];

    // --- stage x (two taps), fp32, zero-padded out of range ---
    for (int v = tid; v < 1024; v += 256) {
        int j = v >> 4, q = v & 15;
        int off = (j < 32) ? -P : (S - P);
        int ch = j & 31;
        int idx = m0 + q * 4 + off;
        float4 val;
        if (idx >= 0 && idx + 3 < Min) {
            val = *(const float4*)&xin[ch * XLD + idx];
        } else {
            val.x = (idx     >= 0 && idx     < Min) ? xin[ch * XLD + idx]     : 0.f;
            val.y = (idx + 1 >= 0 && idx + 1 < Min) ? xin[ch * XLD + idx + 1] : 0.f;
            val.z = (idx + 2 >= 0 && idx + 2 < Min) ? xin[ch * XLD + idx + 2] : 0.f;
            val.w = (idx + 3 >= 0 && idx + 3 < Min) ? xin[ch * XLD + idx + 3] : 0.f;
        }
        *(float4*)&Xs[j][q * 4] = val;
    }
    __syncthreads();

    // --- GEMM1: warps = 4 m-rows x 2 n-cols ---
    int wr1 = w >> 1, wc1 = w & 1;
    float d[4][4];
#pragma unroll
    for (int i = 0; i < 4; i++)
#pragma unroll
        for (int j = 0; j < 4; j++) d[i][j] = 0.f;

#pragma unroll
    for (int kc = 0; kc < 8; kc++) {
        int k0 = kc * 8;
        unsigned a[4];
        a[0] = f2tf(Ws[wr1 * 16 + grp][k0 + t4]);
        a[1] = f2tf(Ws[wr1 * 16 + grp + 8][k0 + t4]);
        a[2] = f2tf(Ws[wr1 * 16 + grp][k0 + t4 + 4]);
        a[3] = f2tf(Ws[wr1 * 16 + grp + 8][k0 + t4 + 4]);
#pragma unroll
        for (int nt = 0; nt < 4; nt++) {
            int n0 = wc1 * 32 + nt * 8;
            unsigned b[2];
            b[0] = f2tf(Xs[k0 + t4][n0 + grp]);
            b[1] = f2tf(Xs[k0 + t4 + 4][n0 + grp]);
            mma8(d[nt], a, b);
        }
    }

    // --- gated activation in registers; store y (tf32-rounded) ---
    {
        int c = wr1 * 8 + grp;
#pragma unroll
        for (int nt = 0; nt < 4; nt++) {
            int col = wc1 * 32 + nt * 8 + 2 * t4;
            float y0 = tanhf(d[nt][0]) * sigmoidf_(d[nt][2]);
            float y1 = tanhf(d[nt][1]) * sigmoidf_(d[nt][3]);
            Ys[c][col]     = tf32r(y0);
            Ys[c][col + 1] = tf32r(y1);
        }
    }
    __syncthreads();

    // --- ytail copy (coalesced) ---
    for (int v = tid; v < 512; v += 256) {
        int row = v >> 4, q = v & 15;
        int m = m0 + q * 4;
        if (m >= ofs && m < Mout) {
            float4 val = *(float4*)&Ys[row][q * 4];
            *(float4*)&ytail[row * FINAL + (m - ofs)] = val;
        }
    }

    // --- GEMM2: 32x64x32, warps = 2 m-rows x 4 n-cols; + fp32 residual ---
    int wr2 = w >> 2, wc2 = w & 3;
    float e[2][4];
#pragma unroll
    for (int i = 0; i < 2; i++)
#pragma unroll
        for (int j = 0; j < 4; j++) e[i][j] = 0.f;

#pragma unroll
    for (int kc = 0; kc < 4; kc++) {
        int k0 = kc * 8;
        unsigned a[4];
        a[0] = f2tf(Wr[wr2 * 16 + grp][k0 + t4]);
        a[1] = f2tf(Wr[wr2 * 16 + grp + 8][k0 + t4]);
        a[2] = f2tf(Wr[wr2 * 16 + grp][k0 + t4 + 4]);
        a[3] = f2tf(Wr[wr2 * 16 + grp + 8][k0 + t4 + 4]);
#pragma unroll
        for (int nt = 0; nt < 2; nt++) {
            int n0 = wc2 * 16 + nt * 8;
            unsigned b[2];
            b[0] = __float_as_uint(Ys[k0 + t4][n0 + grp]);       // already tf32
            b[1] = __float_as_uint(Ys[k0 + t4 + 4][n0 + grp]);
            mma8(e[nt], a, b);
        }
    }
#pragma unroll
    for (int nt = 0; nt < 2; nt++) {
        int n0 = wc2 * 16 + nt * 8;
        int col = n0 + 2 * t4;
        int m = m0 + col;
        if (m < Mout) {
            int c = wr2 * 16 + grp;
            xout[c * XLD + m]     = e[nt][0] + Xs[32 + c][col];
            xout[c * XLD + m + 1] = e[nt][1] + Xs[32 + c][col + 1];
            int c2 = c + 8;
            xout[c2 * XLD + m]     = e[nt][2] + Xs[32 + c2][col];
            xout[c2 * XLD + m + 1] = e[nt][3] + Xs[32 + c2][col + 1];
        }
    }
}

// ---------------------------------------------------------------------------
// skip GEMM (TF32 mma): skip[256][FINAL] = skip_w(256x1280) * ytails(1280xFINAL)
// tile 128(o) x 128(p), K chunk = 32 (one layer).  8 warps, each m16 x n128.
// ---------------------------------------------------------------------------
__global__ void k_skip(const float* __restrict__ yb, const float* __restrict__ sw,
                       float* __restrict__ skip)
{
    __shared__ float As[128][36];   // [o][k] (tf32-rounded)
    __shared__ float Bs[32][132];   // [k][p] (already tf32-rounded by producer)
    int tid = threadIdx.x;          // 256
    int lane = tid & 31, w = tid >> 5;
    int grp = lane >> 2, t4 = lane & 3;
    int p0 = blockIdx.x * 128, o0 = blockIdx.y * 128;

    float d[16][4];
#pragma unroll
    for (int i = 0; i < 16; i++)
#pragma unroll
        for (int j = 0; j < 4; j++) d[i][j] = 0.f;

    for (int kc = 0; kc < 40; kc++) {
        __syncthreads();
        for (int l = tid; l < 1024; l += 256) {
            int o = l >> 3, q = l & 7;
            float4 v = *(const float4*)&sw[(kc * 256 + o0 + o) * 32 + q * 4];
            As[o][q * 4]     = tf32r(v.x);
            As[o][q * 4 + 1] = tf32r(v.y);
            As[o][q * 4 + 2] = tf32r(v.z);
            As[o][q * 4 + 3] = tf32r(v.w);
        }
        for (int l = tid; l < 1024; l += 256) {
            int kk = l >> 5, q = l & 31;
            float4 v = *(const float4*)&yb[(size_t)(kc * 32 + kk) * FINAL + p0 + q * 4];
            *(float4*)&Bs[kk][q * 4] = v;
        }
        __syncthreads();
#pragma unroll
        for (int kq = 0; kq < 4; kq++) {
            int k0 = kq * 8;
            unsigned a[4];
            a[0] = __float_as_uint(As[w * 16 + grp][k0 + t4]);
            a[1] = __float_as_uint(As[w * 16 + grp + 8][k0 + t4]);
            a[2] = __float_as_uint(As[w * 16 + grp][k0 + t4 + 4]);
            a[3] = __float_as_uint(As[w * 16 + grp + 8][k0 + t4 + 4]);
#pragma unroll
            for (int nt = 0; nt < 16; nt++) {
                int n0 = nt * 8;
                unsigned b[2];
                b[0] = __float_as_uint(Bs[k0 + t4][n0 + grp]);
                b[1] = __float_as_uint(Bs[k0 + t4 + 4][n0 + grp]);
                mma8(d[nt], a, b);
            }
        }
    }
#pragma unroll
    for (int nt = 0; nt < 16; nt++) {
        int col = p0 + nt * 8 + 2 * t4;
        int r0 = o0 + w * 16 + grp;
        skip[(size_t)r0 * FINAL + col]       = d[nt][0];
        skip[(size_t)r0 * FINAL + col + 1]   = d[nt][1];
        skip[(size_t)(r0 + 8) * FINAL + col]     = d[nt][2];
        skip[(size_t)(r0 + 8) * FINAL + col + 1] = d[nt][3];
    }
}

// ---------------------------------------------------------------------------
// end: out[p] = e2 . relu(e1 . relu(skip[:,p]) + b1) + b2   (unchanged)
// ---------------------------------------------------------------------------
__global__ void k_end(const float* __restrict__ skip, const float* __restrict__ e1w,
                      const float* __restrict__ e1b, const float* __restrict__ e2w,
                      const float* __restrict__ e2b, float* __restrict__ out)
{
    __shared__ float E1s[32][264];
    __shared__ float Vs[32][68];
    __shared__ float s_e2[256];
    float* part = &E1s[0][0];
    int tid = threadIdx.x;          // 512
    int p0 = blockIdx.x * 64;
    int pg = tid & 15, rg = tid >> 4;
    for (int l = tid; l < 256; l += 512) s_e2[l] = e2w[l];

    float acc[8][4];
#pragma unroll
    for (int i = 0; i < 8; i++)
#pragma unroll
        for (int j = 0; j < 4; j++) acc[i][j] = 0.f;

    for (int kc = 0; kc < 8; kc++) {
        __syncthreads();
        for (int l = tid; l < 2048; l += 512) {
            int p = l & 63, k = l >> 6;
            float v = skip[(size_t)(kc * 32 + k) * FINAL + p0 + p];
            Vs[k][p] = v > 0.f ? v : 0.f;
        }
        for (int f4 = tid; f4 < 2048; f4 += 512) {
            int o = f4 >> 3, k4 = f4 & 7;
            float4 w = *(const float4*)&e1w[o * 256 + kc * 32 + k4 * 4];
            E1s[k4 * 4 + 0][o] = w.x; E1s[k4 * 4 + 1][o] = w.y;
            E1s[k4 * 4 + 2][o] = w.z; E1s[k4 * 4 + 3][o] = w.w;
        }
        __syncthreads();
#pragma unroll
        for (int k = 0; k < 32; k++) {
            float4 v  = *(const float4*)&Vs[k][pg * 4];
            float4 w0 = *(const float4*)&E1s[k][rg * 8];
            float4 w1 = *(const float4*)&E1s[k][rg * 8 + 4];
            float vr[4] = {v.x, v.y, v.z, v.w};
            float wr[8] = {w0.x, w0.y, w0.z, w0.w, w1.x, w1.y, w1.z, w1.w};
#pragma unroll
            for (int i = 0; i < 8; i++)
#pragma unroll
                for (int j = 0; j < 4; j++) acc[i][j] += wr[i] * vr[j];
        }
    }
    __syncthreads();

    float pp[4] = {0.f, 0.f, 0.f, 0.f};
#pragma unroll
    for (int rr = 0; rr < 8; rr++) {
        int row = rg * 8 + rr;
        float bb = e1b[row], w2 = s_e2[row];
#pragma unroll
        for (int j = 0; j < 4; j++) {
            float h = acc[rr][j] + bb;
            h = h > 0.f ? h : 0.f;
            pp[j] += w2 * h;
        }
    }
#pragma unroll
    for (int j = 0; j < 4; j++) part[rg * 64 + pg * 4 + j] = pp[j];
    __syncthreads();
    if (tid < 64) {
        float s = e2b[0];
#pragma unroll
        for (int r = 0; r < 32; r++) s += part[r * 64 + tid];
        int p = p0 + tid;
        out[(p & 15) * TOUT + (p >> 4)] = s;
    }
}

// ---------------------------------------------------------------------------
extern "C" void kernel_launch(void* const* d_in, const int* in_sizes, int n_in,
                              void* d_out, int out_size)
{
    const float* input    = (const float*)d_in[0];
    const float* start_w  = (const float*)d_in[1];
    const float* filter_w = (const float*)d_in[2];
    const float* gate_w   = (const float*)d_in[3];
    const float* res_w    = (const float*)d_in[4];
    const float* skip_w   = (const float*)d_in[5];
    const float* e1w      = (const float*)d_in[6];
    const float* e1b      = (const float*)d_in[7];
    const float* e2w      = (const float*)d_in[8];
    const float* e2b      = (const float*)d_in[9];
    float* out = (float*)d_out;
    (void)in_sizes; (void)n_in; (void)out_size;

    float *bufA, *bufB, *ybuf, *skipbuf;
    cudaGetSymbolAddress((void**)&bufA, g_xa);
    cudaGetSymbolAddress((void**)&bufB, g_xb);
    cudaGetSymbolAddress((void**)&ybuf, g_ybuf);
    cudaGetSymbolAddress((void**)&skipbuf, g_skip);

    k_start<<<1024, 256>>>(input, start_w, bufA);

    float* cur = bufA;
    float* nxt = bufB;
    for (int i = 0; i < 40; i++) {
        int b = i / 10, k = i % 10;
        int Mb = 262144 - 8192 * b;
        int Min, Mout, P, S;
        if (k == 0) { Min = Mb; Mout = Mb - 16; P = 0; S = 16; }
        else {
            int d = 1 << k;
            Min = Mb - 8 * d;
            Mout = Mb - 16 * d;
            P = 8 * d;
            S = 16 * d;
        }
        int ofs = Mout - FINAL;
        int grid = (Mout + 63) / 64;
        k_layer<<<grid, 256>>>(cur, nxt, ybuf + (size_t)i * 32 * FINAL,
                               filter_w + i * 2048, gate_w + i * 2048,
                               res_w + i * 1024,
                               Min, Mout, P, S, ofs);
        float* t = cur; cur = nxt; nxt = t;
    }

    dim3 gs(FINAL / 128, 2);
    k_skip<<<gs, 256>>>(ybuf, skip_w, skipbuf);
    k_end<<<FINAL / 64, 512>>>(skipbuf, e1w, e1b, e2w, e2b, out);
}

// round 4
// speedup vs baseline: 1.8005x; 1.0415x over previous
#include <cuda_runtime.h>
#include <math.h>

#define FINAL 229376        // 16 * 14336 final flat length
#define XLD   262144        // fixed channel stride for x buffers
#define TOUT  14336

// Scratch (device globals; no allocation anywhere)
__device__ float g_xa[32 * XLD];
__device__ float g_xb[32 * XLD];
__device__ float g_ybuf[1280 * FINAL];   // 40 layers * 32 ch * FINAL tail (tf32-rounded)
__device__ float g_w1[40 * 8192];        // per layer: hi[64][64], lo[64][64] (permuted)
__device__ float g_wr[40 * 2048];        // per layer: hi[32][32], lo[32][32]
__device__ float g_swr[40 * 256 * 32];   // skip_w tf32-rounded
__device__ float g_e1r[256 * 256];       // e1w tf32-rounded

// ---------------------------------------------------------------------------
// TF32 helpers
// ---------------------------------------------------------------------------
__device__ __forceinline__ unsigned f2tf(float f) {
    unsigned u;
    asm("cvt.rna.tf32.f32 %0, %1;" : "=r"(u) : "f"(f));
    return u;
}
__device__ __forceinline__ float tf32r(float f) { return __uint_as_float(f2tf(f)); }
__device__ __forceinline__ unsigned ubits(float f) { return __float_as_uint(f); }
__device__ __forceinline__ void mma8(float d[4], const unsigned a[4], const unsigned b[2]) {
    asm volatile(
        "mma.sync.aligned.m16n8k8.row.col.f32.tf32.tf32.f32 "
        "{%0,%1,%2,%3},{%4,%5,%6,%7},{%8,%9},{%0,%1,%2,%3};"
        : "+f"(d[0]), "+f"(d[1]), "+f"(d[2]), "+f"(d[3])
        : "r"(a[0]), "r"(a[1]), "r"(a[2]), "r"(a[3]), "r"(b[0]), "r"(b[1]));
}
__device__ __forceinline__ float sigmoidf_(float x) { return 1.f / (1.f + expf(-x)); }

// ---------------------------------------------------------------------------
// prep: split/permute weights (runs every launch; deterministic)
// ---------------------------------------------------------------------------
__global__ void k_prep(const float* __restrict__ fw, const float* __restrict__ gw,
                       const float* __restrict__ rw, const float* __restrict__ sw,
                       const float* __restrict__ e1w)
{
    int i = blockIdx.x;
    int tid = threadIdx.x;
    if (i < 40) {
        for (int l = tid; l < 4096; l += 256) {
            int k = l & 63, r = l >> 6;
            int c = r & 31, isg = r >> 5;
            const float* src = (isg ? gw : fw) + i * 2048;
            float v = src[(c * 32 + (k & 31)) * 2 + (k >> 5)];
            int s = ((c >> 3) << 4) + (isg << 3) + (c & 7);
            float h = tf32r(v);
            g_w1[i * 8192 + s * 64 + k] = h;
            g_w1[i * 8192 + 4096 + s * 64 + k] = tf32r(v - h);
        }
        for (int l = tid; l < 1024; l += 256) {
            float v = rw[i * 1024 + l];
            float h = tf32r(v);
            g_wr[i * 2048 + l] = h;
            g_wr[i * 2048 + 1024 + l] = tf32r(v - h);
        }
    } else {
        int bi = i - 40;   // 0..7
        for (int l = bi * 256 + tid; l < 327680; l += 2048) g_swr[l] = tf32r(sw[l]);
        for (int l = bi * 256 + tid; l < 65536;  l += 2048) g_e1r[l] = tf32r(e1w[l]);
    }
}

// ---------------------------------------------------------------------------
// start conv: x0[c][t*16+b] = sum_f sw[c][f] * input[b][f][t]
// ---------------------------------------------------------------------------
__global__ void k_start(const float* __restrict__ in, const float* __restrict__ sw,
                        float* __restrict__ x0)
{
    __shared__ float s_w[4096];
    __shared__ float s_in[16 * 272];
    int tid = threadIdx.x;               // 256
    for (int l = tid; l < 4096; l += 256) s_w[l] = sw[l];
    int t0 = blockIdx.x * 16;
    int b = tid & 15, dt = tid >> 4;
    float acc[32];
#pragma unroll
    for (int c = 0; c < 32; c++) acc[c] = 0.f;
    int tt = tid & 15, rhalf = tid >> 4;
    for (int fc = 0; fc < 8; fc++) {
        __syncthreads();
#pragma unroll
        for (int pass = 0; pass < 16; pass++) {
            int row = pass * 16 + rhalf;
            int bb = row >> 4, ff = row & 15;
            s_in[ff * 272 + tt * 17 + bb] =
                in[(bb * 128 + fc * 16 + ff) * 16384 + t0 + tt];
        }
        __syncthreads();
#pragma unroll
        for (int f = 0; f < 16; f++) {
            float v = s_in[f * 272 + dt * 17 + b];
#pragma unroll
            for (int c = 0; c < 32; c++)
                acc[c] += s_w[c * 128 + fc * 16 + f] * v;
        }
    }
    int m = t0 * 16 + tid;
#pragma unroll
    for (int c = 0; c < 32; c++)
        x0[c * XLD + m] = acc[c];
}

// ---------------------------------------------------------------------------
// fused dilated layer, split-TF32 (3 mma): tile 64 u-rows x 128 positions.
// dynamic smem layout (floats):
//  Whi[64][68] @0, Wlo @4352, Wrh[32][36] @8704, Wrl @9856,
//  Xhi[64][132] @11008, Xlo @19456   (total 27904 floats = 111616 B)
// Xhi/Xlo rows 0..31 are overlaid with y hi/lo after GEMM1.
// ---------------------------------------------------------------------------
__global__ void __launch_bounds__(256, 2)
k_layer(const float* __restrict__ xin, float* __restrict__ xout,
        float* __restrict__ ytail, int layer,
        int Min, int Mout, int P, int S, int ofs)
{
    extern __shared__ float sm[];
    float* Whi = sm;
    float* Wlo = sm + 4352;
    float* Wrh = sm + 8704;
    float* Wrl = sm + 9856;
    float* Xhi = sm + 11008;
    float* Xlo = sm + 19456;

    int tid = threadIdx.x;          // 256
    int m0 = blockIdx.x * 128;
    int lane = tid & 31, w = tid >> 5;
    int grp = lane >> 2, t4 = lane & 3;

    // ---- stage pre-split weights (pure copies) ----
    const float* wb = g_w1 + (size_t)layer * 8192;
    for (int l = tid; l < 1024; l += 256) {
        int s = l >> 4, q = (l & 15) * 4;
        *(float4*)&Whi[s * 68 + q] = *(const float4*)&wb[s * 64 + q];
        *(float4*)&Wlo[s * 68 + q] = *(const float4*)&wb[4096 + s * 64 + q];
    }
    const float* rb = g_wr + (size_t)layer * 2048;
    {
        int l = tid;
        if (l < 256) {
            int o = l >> 3, q = (l & 7) * 4;
            *(float4*)&Wrh[o * 36 + q] = *(const float4*)&rb[o * 32 + q];
            *(float4*)&Wrl[o * 36 + q] = *(const float4*)&rb[1024 + o * 32 + q];
        }
    }

    // ---- stage x (two taps), split hi/lo at staging ----
    for (int v = tid; v < 2048; v += 256) {
        int j = v >> 5, q = (v & 31) * 4;
        int off = (j < 32) ? -P : (S - P);
        int ch = j & 31;
        int idx = m0 + q + off;
        float4 val;
        if (idx >= 0 && idx + 3 < Min) {
            val = *(const float4*)&xin[ch * XLD + idx];
        } else {
            val.x = (idx     >= 0 && idx     < Min) ? xin[ch * XLD + idx]     : 0.f;
            val.y = (idx + 1 >= 0 && idx + 1 < Min) ? xin[ch * XLD + idx + 1] : 0.f;
            val.z = (idx + 2 >= 0 && idx + 2 < Min) ? xin[ch * XLD + idx + 2] : 0.f;
            val.w = (idx + 3 >= 0 && idx + 3 < Min) ? xin[ch * XLD + idx + 3] : 0.f;
        }
        float4 h, lo;
        h.x = tf32r(val.x); lo.x = tf32r(val.x - h.x);
        h.y = tf32r(val.y); lo.y = tf32r(val.y - h.y);
        h.z = tf32r(val.z); lo.z = tf32r(val.z - h.z);
        h.w = tf32r(val.w); lo.w = tf32r(val.w - h.w);
        *(float4*)&Xhi[j * 132 + q] = h;
        *(float4*)&Xlo[j * 132 + q] = lo;
    }
    __syncthreads();

    // ---- GEMM1: 64x128 over K=64; warps 4m x 2n; 3-mma split ----
    int wr1 = w >> 1, wc1 = w & 1;
    float d[8][4];
#pragma unroll
    for (int i = 0; i < 8; i++)
#pragma unroll
        for (int j = 0; j < 4; j++) d[i][j] = 0.f;

#pragma unroll
    for (int kc = 0; kc < 8; kc++) {
        int k0 = kc * 8;
        const float* wh = &Whi[(wr1 * 16 + grp) * 68 + k0 + t4];
        const float* wl = &Wlo[(wr1 * 16 + grp) * 68 + k0 + t4];
        unsigned ah[4], al[4];
        ah[0] = ubits(wh[0]);      ah[1] = ubits(wh[8 * 68]);
        ah[2] = ubits(wh[4]);      ah[3] = ubits(wh[8 * 68 + 4]);
        al[0] = ubits(wl[0]);      al[1] = ubits(wl[8 * 68]);
        al[2] = ubits(wl[4]);      al[3] = ubits(wl[8 * 68 + 4]);
#pragma unroll
        for (int nt = 0; nt < 8; nt++) {
            int n0 = wc1 * 64 + nt * 8 + grp;
            unsigned bh[2], bl[2];
            bh[0] = ubits(Xhi[(k0 + t4) * 132 + n0]);
            bh[1] = ubits(Xhi[(k0 + t4 + 4) * 132 + n0]);
            bl[0] = ubits(Xlo[(k0 + t4) * 132 + n0]);
            bl[1] = ubits(Xlo[(k0 + t4 + 4) * 132 + n0]);
            mma8(d[nt], ah, bh);
            mma8(d[nt], ah, bl);
            mma8(d[nt], al, bh);
        }
    }

    // ---- activation in registers ----
    float yv[8][2];
#pragma unroll
    for (int nt = 0; nt < 8; nt++) {
        yv[nt][0] = tanhf(d[nt][0]) * sigmoidf_(d[nt][2]);
        yv[nt][1] = tanhf(d[nt][1]) * sigmoidf_(d[nt][3]);
    }
    __syncthreads();   // all GEMM1 reads of Xhi/Xlo rows 0..31 done

    {
        int c = wr1 * 8 + grp;
#pragma unroll
        for (int nt = 0; nt < 8; nt++) {
            int col = wc1 * 64 + nt * 8 + 2 * t4;
            float h0 = tf32r(yv[nt][0]);
            float h1 = tf32r(yv[nt][1]);
            Xhi[c * 132 + col]     = h0;
            Xhi[c * 132 + col + 1] = h1;
            Xlo[c * 132 + col]     = tf32r(yv[nt][0] - h0);
            Xlo[c * 132 + col + 1] = tf32r(yv[nt][1] - h1);
        }
    }
    __syncthreads();

    // ---- ytail copy (y_hi, coalesced) ----
    for (int v = tid; v < 1024; v += 256) {
        int row = v >> 5, q = (v & 31) * 4;
        int m = m0 + q;
        if (m >= ofs && m < Mout)
            *(float4*)&ytail[row * FINAL + (m - ofs)] = *(float4*)&Xhi[row * 132 + q];
    }

    // ---- GEMM2: 32x128 over K=32; warps 2m x 4n; 3-mma split; + residual ----
    int wr2 = w >> 2, wc2 = w & 3;
    float e[4][4];
#pragma unroll
    for (int i = 0; i < 4; i++)
#pragma unroll
        for (int j = 0; j < 4; j++) e[i][j] = 0.f;

#pragma unroll
    for (int kc = 0; kc < 4; kc++) {
        int k0 = kc * 8;
        const float* wh = &Wrh[(wr2 * 16 + grp) * 36 + k0 + t4];
        const float* wl = &Wrl[(wr2 * 16 + grp) * 36 + k0 + t4];
        unsigned ah[4], al[4];
        ah[0] = ubits(wh[0]);      ah[1] = ubits(wh[8 * 36]);
        ah[2] = ubits(wh[4]);      ah[3] = ubits(wh[8 * 36 + 4]);
        al[0] = ubits(wl[0]);      al[1] = ubits(wl[8 * 36]);
        al[2] = ubits(wl[4]);      al[3] = ubits(wl[8 * 36 + 4]);
#pragma unroll
        for (int nt = 0; nt < 4; nt++) {
            int n0 = wc2 * 32 + nt * 8 + grp;
            unsigned bh[2], bl[2];
            bh[0] = ubits(Xhi[(k0 + t4) * 132 + n0]);
            bh[1] = ubits(Xhi[(k0 + t4 + 4) * 132 + n0]);
            bl[0] = ubits(Xlo[(k0 + t4) * 132 + n0]);
            bl[1] = ubits(Xlo[(k0 + t4 + 4) * 132 + n0]);
            mma8(e[nt], ah, bh);
            mma8(e[nt], ah, bl);
            mma8(e[nt], al, bh);
        }
    }
#pragma unroll
    for (int nt = 0; nt < 4; nt++) {
        int col = wc2 * 32 + nt * 8 + 2 * t4;
        int m = m0 + col;
        if (m < Mout) {
            int c = wr2 * 16 + grp;
            xout[c * XLD + m]     = e[nt][0] + Xhi[(32 + c) * 132 + col]     + Xlo[(32 + c) * 132 + col];
            xout[c * XLD + m + 1] = e[nt][1] + Xhi[(32 + c) * 132 + col + 1] + Xlo[(32 + c) * 132 + col + 1];
            int c2 = c + 8;
            xout[c2 * XLD + m]     = e[nt][2] + Xhi[(32 + c2) * 132 + col]     + Xlo[(32 + c2) * 132 + col];
            xout[c2 * XLD + m + 1] = e[nt][3] + Xhi[(32 + c2) * 132 + col + 1] + Xlo[(32 + c2) * 132 + col + 1];
        }
    }
}

// ---------------------------------------------------------------------------
// fused tail: skip GEMM (256x1280 x K-chunks) + relu + e1 + bias + relu + e2
// per block: 64 positions, all 256 skip rows. A operands straight from L2.
// dynamic smem: Bs[32][68] @0 (2176), Hs[256][68] @2176 (17408) = 78336 B
// ---------------------------------------------------------------------------
__global__ void __launch_bounds__(256, 2)
k_tail(const float* __restrict__ yb, const float* __restrict__ e1b,
       const float* __restrict__ e2w, const float* __restrict__ e2b,
       float* __restrict__ out)
{
    extern __shared__ float sm[];
    float* Bs = sm;            // [32][68]
    float* Hs = sm + 2176;     // [256][68]
    float* part = sm;          // reuse Bs region at the end

    int tid = threadIdx.x;     // 256
    int lane = tid & 31, w = tid >> 5;
    int grp = lane >> 2, t4 = lane & 3;
    int p0 = blockIdx.x * 64;

    float d[2][8][4];
#pragma unroll
    for (int mt = 0; mt < 2; mt++)
#pragma unroll
        for (int nt = 0; nt < 8; nt++)
#pragma unroll
            for (int j = 0; j < 4; j++) d[mt][nt][j] = 0.f;

    // ---- phase A: skip GEMM over 40 K-chunks of 32 ----
    for (int kc = 0; kc < 40; kc++) {
        __syncthreads();
        for (int l = tid; l < 512; l += 256) {
            int kk = l >> 4, q = (l & 15) * 4;
            *(float4*)&Bs[kk * 68 + q] =
                *(const float4*)&yb[(size_t)(kc * 32 + kk) * FINAL + p0 + q];
        }
        __syncthreads();
        const float* ap = g_swr + (size_t)(kc * 256 + w * 32) * 32;
#pragma unroll
        for (int ks = 0; ks < 4; ks++) {
            int k0 = ks * 8;
            unsigned a0[4], a1[4];
            a0[0] = ubits(ap[grp * 32 + k0 + t4]);
            a0[1] = ubits(ap[(grp + 8) * 32 + k0 + t4]);
            a0[2] = ubits(ap[grp * 32 + k0 + t4 + 4]);
            a0[3] = ubits(ap[(grp + 8) * 32 + k0 + t4 + 4]);
            a1[0] = ubits(ap[(16 + grp) * 32 + k0 + t4]);
            a1[1] = ubits(ap[(24 + grp) * 32 + k0 + t4]);
            a1[2] = ubits(ap[(16 + grp) * 32 + k0 + t4 + 4]);
            a1[3] = ubits(ap[(24 + grp) * 32 + k0 + t4 + 4]);
#pragma unroll
            for (int nt = 0; nt < 8; nt++) {
                unsigned b[2];
                b[0] = ubits(Bs[(k0 + t4) * 68 + nt * 8 + grp]);
                b[1] = ubits(Bs[(k0 + t4 + 4) * 68 + nt * 8 + grp]);
                mma8(d[0][nt], a0, b);
                mma8(d[1][nt], a1, b);
            }
        }
    }

    // ---- relu + tf32-round into Hs ----
    __syncthreads();
#pragma unroll
    for (int mt = 0; mt < 2; mt++)
#pragma unroll
        for (int nt = 0; nt < 8; nt++) {
            int r = w * 32 + mt * 16 + grp;
            int col = nt * 8 + 2 * t4;
            float v0 = d[mt][nt][0]; v0 = v0 > 0.f ? v0 : 0.f;
            float v1 = d[mt][nt][1]; v1 = v1 > 0.f ? v1 : 0.f;
            float v2 = d[mt][nt][2]; v2 = v2 > 0.f ? v2 : 0.f;
            float v3 = d[mt][nt][3]; v3 = v3 > 0.f ? v3 : 0.f;
            Hs[r * 68 + col]           = tf32r(v0);
            Hs[r * 68 + col + 1]       = tf32r(v1);
            Hs[(r + 8) * 68 + col]     = tf32r(v2);
            Hs[(r + 8) * 68 + col + 1] = tf32r(v3);
        }
    __syncthreads();

    // ---- phase B: e1 GEMM (256x64, K=256) ----
#pragma unroll
    for (int mt = 0; mt < 2; mt++)
#pragma unroll
        for (int nt = 0; nt < 8; nt++)
#pragma unroll
            for (int j = 0; j < 4; j++) d[mt][nt][j] = 0.f;

    for (int kc = 0; kc < 8; kc++) {
        const float* ep = g_e1r + (w * 32) * 256 + kc * 32;
#pragma unroll
        for (int ks = 0; ks < 4; ks++) {
            int k0 = ks * 8;
            unsigned a0[4], a1[4];
            a0[0] = ubits(ep[grp * 256 + k0 + t4]);
            a0[1] = ubits(ep[(grp + 8) * 256 + k0 + t4]);
            a0[2] = ubits(ep[grp * 256 + k0 + t4 + 4]);
            a0[3] = ubits(ep[(grp + 8) * 256 + k0 + t4 + 4]);
            a1[0] = ubits(ep[(16 + grp) * 256 + k0 + t4]);
            a1[1] = ubits(ep[(24 + grp) * 256 + k0 + t4]);
            a1[2] = ubits(ep[(16 + grp) * 256 + k0 + t4 + 4]);
            a1[3] = ubits(ep[(24 + grp) * 256 + k0 + t4 + 4]);
#pragma unroll
            for (int nt = 0; nt < 8; nt++) {
                unsigned b[2];
                b[0] = ubits(Hs[(kc * 32 + k0 + t4) * 68 + nt * 8 + grp]);
                b[1] = ubits(Hs[(kc * 32 + k0 + t4 + 4) * 68 + nt * 8 + grp]);
                mma8(d[0][nt], a0, b);
                mma8(d[1][nt], a1, b);
            }
        }
    }

    // ---- epilogue: bias + relu + e2 dot + reduce ----
    int r0 = w * 32 + grp;
    float eb0 = e1b[r0],      eb1 = e1b[r0 + 8];
    float eb2 = e1b[r0 + 16], eb3 = e1b[r0 + 24];
    float ew0 = e2w[r0],      ew1 = e2w[r0 + 8];
    float ew2 = e2w[r0 + 16], ew3 = e2w[r0 + 24];

    float pc[16];
#pragma unroll
    for (int nt = 0; nt < 8; nt++) {
#pragma unroll
        for (int j = 0; j < 2; j++) {
            float h0 = d[0][nt][j]     + eb0; h0 = h0 > 0.f ? h0 : 0.f;
            float h1 = d[0][nt][2 + j] + eb1; h1 = h1 > 0.f ? h1 : 0.f;
            float h2 = d[1][nt][j]     + eb2; h2 = h2 > 0.f ? h2 : 0.f;
            float h3 = d[1][nt][2 + j] + eb3; h3 = h3 > 0.f ? h3 : 0.f;
            pc[nt * 2 + j] = ew0 * h0 + ew1 * h1 + ew2 * h2 + ew3 * h3;
        }
    }
#pragma unroll
    for (int off = 16; off >= 4; off >>= 1)
#pragma unroll
        for (int t = 0; t < 16; t++)
            pc[t] += __shfl_xor_sync(0xffffffff, pc[t], off);

    if (lane < 4) {
#pragma unroll
        for (int nt = 0; nt < 8; nt++) {
            part[w * 64 + nt * 8 + 2 * lane]     = pc[nt * 2];
            part[w * 64 + nt * 8 + 2 * lane + 1] = pc[nt * 2 + 1];
        }
    }
    __syncthreads();
    if (tid < 64) {
        float s = e2b[0];
#pragma unroll
        for (int ww = 0; ww < 8; ww++) s += part[ww * 64 + tid];
        int p = p0 + tid;
        out[(p & 15) * TOUT + (p >> 4)] = s;
    }
}

// ---------------------------------------------------------------------------
extern "C" void kernel_launch(void* const* d_in, const int* in_sizes, int n_in,
                              void* d_out, int out_size)
{
    const float* input    = (const float*)d_in[0];
    const float* start_w  = (const float*)d_in[1];
    const float* filter_w = (const float*)d_in[2];
    const float* gate_w   = (const float*)d_in[3];
    const float* res_w    = (const float*)d_in[4];
    const float* skip_w   = (const float*)d_in[5];
    const float* e1w      = (const float*)d_in[6];
    const float* e1b      = (const float*)d_in[7];
    const float* e2w      = (const float*)d_in[8];
    const float* e2b      = (const float*)d_in[9];
    float* out = (float*)d_out;
    (void)in_sizes; (void)n_in; (void)out_size;

    static int attr_done = 0;
    if (!attr_done) {
        cudaFuncSetAttribute(k_layer, cudaFuncAttributeMaxDynamicSharedMemorySize, 111616);
        cudaFuncSetAttribute(k_tail,  cudaFuncAttributeMaxDynamicSharedMemorySize, 78336);
        attr_done = 1;
    }

    float *bufA, *bufB, *ybuf;
    cudaGetSymbolAddress((void**)&bufA, g_xa);
    cudaGetSymbolAddress((void**)&bufB, g_xb);
    cudaGetSymbolAddress((void**)&ybuf, g_ybuf);

    k_prep<<<48, 256>>>(filter_w, gate_w, res_w, skip_w, e1w);
    k_start<<<1024, 256>>>(input, start_w, bufA);

    float* cur = bufA;
    float* nxt = bufB;
    for (int i = 0; i < 40; i++) {
        int b = i / 10, k = i % 10;
        int Mb = 262144 - 8192 * b;
        int Min, Mout, P, S;
        if (k == 0) { Min = Mb; Mout = Mb - 16; P = 0; S = 16; }
        else {
            int d = 1 << k;
            Min = Mb - 8 * d;
            Mout = Mb - 16 * d;
            P = 8 * d;
            S = 16 * d;
        }
        int ofs = Mout - FINAL;
        int grid = (Mout + 127) / 128;
        k_layer<<<grid, 256, 111616>>>(cur, nxt, ybuf + (size_t)i * 32 * FINAL,
                                       i, Min, Mout, P, S, ofs);
        float* t = cur; cur = nxt; nxt = t;
    }

    k_tail<<<FINAL / 64, 256, 78336>>>(ybuf, e1b, e2w, e2b, out);
}

// round 6
// speedup vs baseline: 2.9752x; 1.6525x over previous
#include <cuda_runtime.h>
#include <cuda_bf16.h>
#include <math.h>

#define FINAL 229376        // 16 * 14336 final flat length
#define XLD   262144        // fixed channel stride for x buffers
#define TOUT  14336

// Scratch (device globals; no allocation anywhere)
__device__ float    g_xa[32 * XLD];
__device__ float    g_xb[32 * XLD];
__device__ unsigned g_ybh[640 * FINAL];     // y hi, packed bf16 pairs (k2 x pos)
__device__ unsigned g_ybl[640 * FINAL];     // y lo
__device__ unsigned g_w1h[40 * 2048], g_w1l[40 * 2048];   // [s=64][k2=32] per layer
__device__ unsigned g_wrh[40 * 512],  g_wrl[40 * 512];    // [c=32][k2=16]
__device__ unsigned g_swrh[163840],   g_swrl[163840];     // [40*256][k2=16]
__device__ unsigned g_e1rh[32768],    g_e1rl[32768];      // [256][k2=128]

// ---------------------------------------------------------------------------
// helpers
// ---------------------------------------------------------------------------
__device__ __forceinline__ void mma16(float d[4], const unsigned a[4], const unsigned b[2]) {
    asm volatile(
        "mma.sync.aligned.m16n8k16.row.col.f32.bf16.bf16.f32 "
        "{%0,%1,%2,%3},{%4,%5,%6,%7},{%8,%9},{%0,%1,%2,%3};"
        : "+f"(d[0]), "+f"(d[1]), "+f"(d[2]), "+f"(d[3])
        : "r"(a[0]), "r"(a[1]), "r"(a[2]), "r"(a[3]), "r"(b[0]), "r"(b[1]));
}
__device__ __forceinline__ float sigmoidf_(float x) { return 1.f / (1.f + expf(-x)); }

// pack two floats (even ch -> low half) into bf16x2 hi and lo components
__device__ __forceinline__ void split_pack(float a, float b, unsigned& h, unsigned& l) {
    __nv_bfloat16 ah = __float2bfloat16(a), bh = __float2bfloat16(b);
    float ar = a - __bfloat162float(ah), br = b - __bfloat162float(bh);
    __nv_bfloat162 th; th.x = ah; th.y = bh; h = *(unsigned*)&th;
    __nv_bfloat162 tl; tl.x = __float2bfloat16(ar); tl.y = __float2bfloat16(br);
    l = *(unsigned*)&tl;
}
__device__ __forceinline__ void split1(float v, unsigned short& h, unsigned short& l) {
    __nv_bfloat16 vh = __float2bfloat16(v);
    float r = v - __bfloat162float(vh);
    __nv_bfloat16 vl = __float2bfloat16(r);
    h = *(unsigned short*)&vh;
    l = *(unsigned short*)&vl;
}
__device__ __forceinline__ float bf_half(unsigned u, int hi) {
    __nv_bfloat162 t = *(__nv_bfloat162*)&u;
    return hi ? __bfloat162float(t.y) : __bfloat162float(t.x);
}

// ---------------------------------------------------------------------------
// prep: split weights into packed bf16 hi/lo pairs (permuted for fragments)
// ---------------------------------------------------------------------------
__global__ void k_prep(const float* __restrict__ fw, const float* __restrict__ gw,
                       const float* __restrict__ rw, const float* __restrict__ sw,
                       const float* __restrict__ e1w)
{
    int i = blockIdx.x, tid = threadIdx.x;
    if (i < 40) {
        for (int l = tid; l < 2048; l += 256) {
            int s = l >> 5, k2 = l & 31;
            int c = ((s >> 4) << 3) + (s & 7);
            int isg = (s >> 3) & 1;
            const float* src = (isg ? gw : fw) + i * 2048;
            int k0 = 2 * k2;
            float v0 = src[(c * 32 + (k0 & 31)) * 2 + (k0 >> 5)];
            float v1 = src[(c * 32 + ((k0 + 1) & 31)) * 2 + ((k0 + 1) >> 5)];
            unsigned h, lo;
            split_pack(v0, v1, h, lo);
            g_w1h[i * 2048 + l] = h;
            g_w1l[i * 2048 + l] = lo;
        }
        for (int l = tid; l < 512; l += 256) {
            int co = l >> 4, k2 = l & 15;
            float v0 = rw[i * 1024 + co * 32 + 2 * k2];
            float v1 = rw[i * 1024 + co * 32 + 2 * k2 + 1];
            unsigned h, lo;
            split_pack(v0, v1, h, lo);
            g_wrh[i * 512 + l] = h;
            g_wrl[i * 512 + l] = lo;
        }
    } else {
        int bi = i - 40;  // 0..7
        for (int l = bi * 256 + tid; l < 163840; l += 2048) {
            int og = l >> 4, k2 = l & 15;
            unsigned h, lo;
            split_pack(sw[og * 32 + 2 * k2], sw[og * 32 + 2 * k2 + 1], h, lo);
            g_swrh[l] = h; g_swrl[l] = lo;
        }
        for (int l = bi * 256 + tid; l < 32768; l += 2048) {
            int o = l >> 7, k2 = l & 127;
            unsigned h, lo;
            split_pack(e1w[o * 256 + 2 * k2], e1w[o * 256 + 2 * k2 + 1], h, lo);
            g_e1rh[l] = h; g_e1rl[l] = lo;
        }
    }
}

// ---------------------------------------------------------------------------
// start conv: x0[c][t*16+b] = sum_f sw[c][f] * input[b][f][t]
// ---------------------------------------------------------------------------
__global__ void k_start(const float* __restrict__ in, const float* __restrict__ sw,
                        float* __restrict__ x0)
{
    __shared__ float s_w[4096];
    __shared__ float s_in[16 * 272];
    int tid = threadIdx.x;               // 256
    for (int l = tid; l < 4096; l += 256) s_w[l] = sw[l];
    int t0 = blockIdx.x * 16;
    int b = tid & 15, dt = tid >> 4;
    float acc[32];
#pragma unroll
    for (int c = 0; c < 32; c++) acc[c] = 0.f;
    int tt = tid & 15, rhalf = tid >> 4;
    for (int fc = 0; fc < 8; fc++) {
        __syncthreads();
#pragma unroll
        for (int pass = 0; pass < 16; pass++) {
            int row = pass * 16 + rhalf;
            int bb = row >> 4, ff = row & 15;
            s_in[ff * 272 + tt * 17 + bb] =
                in[(bb * 128 + fc * 16 + ff) * 16384 + t0 + tt];
        }
        __syncthreads();
#pragma unroll
        for (int f = 0; f < 16; f++) {
            float v = s_in[f * 272 + dt * 17 + b];
#pragma unroll
            for (int c = 0; c < 32; c++)
                acc[c] += s_w[c * 128 + fc * 16 + f] * v;
        }
    }
    int m = t0 * 16 + tid;
#pragma unroll
    for (int c = 0; c < 32; c++)
        x0[c * XLD + m] = acc[c];
}

// ---------------------------------------------------------------------------
// fused dilated layer, bf16x3 split: tile 64 u-rows x 128 positions.
// smem (u32): Wh[64][36]@0, Wl@2304, Rh[32][20]@4608, Rl@5248,
//             Xh[32][132]@5888, Xl[32][132]@10112  -> 14336 u32 = 57344 B
// X rows = k2 pairs: 0..15 = xA channels, 16..31 = xB channels (128 pos + 4 pad).
// Y (packed bf16 pairs) overlays X rows 0..15 after GEMM1.
// ---------------------------------------------------------------------------
__global__ void __launch_bounds__(256, 3)
k_layer(const float* __restrict__ xin, float* __restrict__ xout,
        unsigned* __restrict__ yth, unsigned* __restrict__ ytl, int layer,
        int Min, int Mout, int P, int S, int ofs)
{
    extern __shared__ unsigned smu[];
    unsigned* Wh = smu;
    unsigned* Wl = smu + 2304;
    unsigned* Rh = smu + 4608;
    unsigned* Rl = smu + 5248;
    unsigned* Xh = smu + 5888;
    unsigned* Xl = smu + 10112;

    int tid = threadIdx.x;          // 256
    int m0 = blockIdx.x * 128;
    int lane = tid & 31, w = tid >> 5;
    int grp = lane >> 2, t4 = lane & 3;

    // ---- stage weights (straight u32 copies into padded layout) ----
    const unsigned* wsh = g_w1h + layer * 2048;
    const unsigned* wsl = g_w1l + layer * 2048;
    for (int l = tid; l < 512; l += 256) {
        int row = l >> 3, q = (l & 7) * 4;
        *(uint4*)&Wh[row * 36 + q] = *(const uint4*)&wsh[row * 32 + q];
        *(uint4*)&Wl[row * 36 + q] = *(const uint4*)&wsl[row * 32 + q];
    }
    const unsigned* rsh = g_wrh + layer * 512;
    const unsigned* rsl = g_wrl + layer * 512;
    for (int l = tid; l < 128; l += 256) {
        int row = l >> 2, q = (l & 3) * 4;
        *(uint4*)&Rh[row * 20 + q] = *(const uint4*)&rsh[row * 16 + q];
        *(uint4*)&Rl[row * 20 + q] = *(const uint4*)&rsl[row * 16 + q];
    }

    // ---- stage x: split fp32 -> packed bf16 pairs (channel pairs) ----
    for (int v = tid; v < 1024; v += 256) {
        int j2 = v >> 5, q4 = (v & 31) * 4;
        int tap = j2 >> 4, ch = (j2 & 15) * 2;
        int off = tap ? (S - P) : -P;
        int idx = m0 + q4 + off;
        const float* pa = xin + (size_t)ch * XLD;
        const float* pb = pa + XLD;
        float4 va, vb;
        if (idx >= 0 && idx + 3 < Min) {
            va = *(const float4*)(pa + idx);
            vb = *(const float4*)(pb + idx);
        } else {
            va.x = (idx     >= 0 && idx     < Min) ? pa[idx]     : 0.f;
            va.y = (idx + 1 >= 0 && idx + 1 < Min) ? pa[idx + 1] : 0.f;
            va.z = (idx + 2 >= 0 && idx + 2 < Min) ? pa[idx + 2] : 0.f;
            va.w = (idx + 3 >= 0 && idx + 3 < Min) ? pa[idx + 3] : 0.f;
            vb.x = (idx     >= 0 && idx     < Min) ? pb[idx]     : 0.f;
            vb.y = (idx + 1 >= 0 && idx + 1 < Min) ? pb[idx + 1] : 0.f;
            vb.z = (idx + 2 >= 0 && idx + 2 < Min) ? pb[idx + 2] : 0.f;
            vb.w = (idx + 3 >= 0 && idx + 3 < Min) ? pb[idx + 3] : 0.f;
        }
        uint4 H, L;
        split_pack(va.x, vb.x, H.x, L.x);
        split_pack(va.y, vb.y, H.y, L.y);
        split_pack(va.z, vb.z, H.z, L.z);
        split_pack(va.w, vb.w, H.w, L.w);
        *(uint4*)&Xh[j2 * 132 + q4] = H;
        *(uint4*)&Xl[j2 * 132 + q4] = L;
    }
    __syncthreads();

    // ---- GEMM1: 64x128, K=64 (4 k16 chunks); warps 2m x 4n; 3-mma split ----
    int wr1 = w >> 2, wc1 = w & 3;
    float d[2][4][4];
#pragma unroll
    for (int a = 0; a < 2; a++)
#pragma unroll
        for (int b = 0; b < 4; b++)
#pragma unroll
            for (int c = 0; c < 4; c++) d[a][b][c] = 0.f;

#pragma unroll
    for (int kc = 0; kc < 4; kc++) {
        int k2b = kc * 8;
        unsigned ah[2][4], al[2][4];
#pragma unroll
        for (int mf = 0; mf < 2; mf++) {
            int r0 = wr1 * 32 + mf * 16 + grp;
            const unsigned* ph = &Wh[r0 * 36 + k2b + t4];
            const unsigned* pl = &Wl[r0 * 36 + k2b + t4];
            ah[mf][0] = ph[0]; ah[mf][1] = ph[8 * 36]; ah[mf][2] = ph[4]; ah[mf][3] = ph[8 * 36 + 4];
            al[mf][0] = pl[0]; al[mf][1] = pl[8 * 36]; al[mf][2] = pl[4]; al[mf][3] = pl[8 * 36 + 4];
        }
#pragma unroll
        for (int nt = 0; nt < 4; nt++) {
            int n = wc1 * 32 + nt * 8 + grp;
            unsigned bh[2], bl[2];
            bh[0] = Xh[(k2b + t4) * 132 + n];     bh[1] = Xh[(k2b + t4 + 4) * 132 + n];
            bl[0] = Xl[(k2b + t4) * 132 + n];     bl[1] = Xl[(k2b + t4 + 4) * 132 + n];
#pragma unroll
            for (int mf = 0; mf < 2; mf++) {
                mma16(d[mf][nt], ah[mf], bh);
                mma16(d[mf][nt], ah[mf], bl);
                mma16(d[mf][nt], al[mf], bh);
            }
        }
    }

    // ---- gated activation in registers ----
    float yv[2][4][2];
#pragma unroll
    for (int mf = 0; mf < 2; mf++)
#pragma unroll
        for (int nt = 0; nt < 4; nt++) {
            yv[mf][nt][0] = tanhf(d[mf][nt][0]) * sigmoidf_(d[mf][nt][2]);
            yv[mf][nt][1] = tanhf(d[mf][nt][1]) * sigmoidf_(d[mf][nt][3]);
        }
    __syncthreads();    // all GEMM1 smem reads complete

    // ---- store y as packed bf16 halves into X rows 0..15 overlay ----
    unsigned short* Yh16 = (unsigned short*)Xh;
    unsigned short* Yl16 = (unsigned short*)Xl;
#pragma unroll
    for (int mf = 0; mf < 2; mf++) {
        int c = (wr1 * 2 + mf) * 8 + grp;
#pragma unroll
        for (int nt = 0; nt < 4; nt++) {
            int col = wc1 * 32 + nt * 8 + 2 * t4;
            int base = ((c >> 1) * 132 + col) * 2 + (c & 1);
            unsigned short h, lo;
            split1(yv[mf][nt][0], h, lo); Yh16[base] = h;     Yl16[base] = lo;
            split1(yv[mf][nt][1], h, lo); Yh16[base + 2] = h; Yl16[base + 2] = lo;
        }
    }
    __syncthreads();

    // ---- ytail copy (coalesced u32 rows) ----
    for (int v = tid; v < 512; v += 256) {
        int row = v >> 5, colq = (v & 31) * 4;
        int m = m0 + colq;
        if (m >= ofs && m < Mout) {
            *(uint4*)&yth[(size_t)row * FINAL + (m - ofs)] = *(uint4*)&Xh[row * 132 + colq];
            *(uint4*)&ytl[(size_t)row * FINAL + (m - ofs)] = *(uint4*)&Xl[row * 132 + colq];
        }
    }

    // ---- GEMM2: 32x128, K=32 (2 k16 chunks); warps 2m x 4n; + fp32 residual ----
    int wr2 = w >> 2, wc2 = w & 3;
    float e[4][4];
#pragma unroll
    for (int a = 0; a < 4; a++)
#pragma unroll
        for (int b = 0; b < 4; b++) e[a][b] = 0.f;

#pragma unroll
    for (int kc = 0; kc < 2; kc++) {
        int k2b = kc * 8;
        int r0 = wr2 * 16 + grp;
        const unsigned* ph = &Rh[r0 * 20 + k2b + t4];
        const unsigned* pl = &Rl[r0 * 20 + k2b + t4];
        unsigned ah[4], al[4];
        ah[0] = ph[0]; ah[1] = ph[8 * 20]; ah[2] = ph[4]; ah[3] = ph[8 * 20 + 4];
        al[0] = pl[0]; al[1] = pl[8 * 20]; al[2] = pl[4]; al[3] = pl[8 * 20 + 4];
#pragma unroll
        for (int nt = 0; nt < 4; nt++) {
            int n = wc2 * 32 + nt * 8 + grp;
            unsigned bh[2], bl[2];
            bh[0] = Xh[(k2b + t4) * 132 + n];     bh[1] = Xh[(k2b + t4 + 4) * 132 + n];
            bl[0] = Xl[(k2b + t4) * 132 + n];     bl[1] = Xl[(k2b + t4 + 4) * 132 + n];
            mma16(e[nt], ah, bh);
            mma16(e[nt], ah, bl);
            mma16(e[nt], al, bh);
        }
    }
#pragma unroll
    for (int nt = 0; nt < 4; nt++) {
        int col = wc2 * 32 + nt * 8 + 2 * t4;
        int m = m0 + col;
        if (m < Mout) {
            int c = wr2 * 16 + grp;
            int c2 = c + 8;
            // residual from xB region (rows 16..31), reconstruct hi+lo
            unsigned uh0 = Xh[(16 + (c  >> 1)) * 132 + col],     ul0 = Xl[(16 + (c  >> 1)) * 132 + col];
            unsigned uh1 = Xh[(16 + (c  >> 1)) * 132 + col + 1], ul1 = Xl[(16 + (c  >> 1)) * 132 + col + 1];
            unsigned vh0 = Xh[(16 + (c2 >> 1)) * 132 + col],     vl0 = Xl[(16 + (c2 >> 1)) * 132 + col];
            unsigned vh1 = Xh[(16 + (c2 >> 1)) * 132 + col + 1], vl1 = Xl[(16 + (c2 >> 1)) * 132 + col + 1];
            int hsel = c & 1, hsel2 = c2 & 1;
            xout[c  * XLD + m]     = e[nt][0] + bf_half(uh0, hsel)  + bf_half(ul0, hsel);
            xout[c  * XLD + m + 1] = e[nt][1] + bf_half(uh1, hsel)  + bf_half(ul1, hsel);
            xout[c2 * XLD + m]     = e[nt][2] + bf_half(vh0, hsel2) + bf_half(vl0, hsel2);
            xout[c2 * XLD + m + 1] = e[nt][3] + bf_half(vh1, hsel2) + bf_half(vl1, hsel2);
        }
    }
}

// ---------------------------------------------------------------------------
// fused tail (bf16x3): skip GEMM + relu + e1 + bias + relu + e2
// per block: 64 positions, all 256 skip rows.
// smem (u32): Bh[16][72]@0, Bl@1152, Hh[128][72]@2304, Hl@11520 -> 20736 u32
// ---------------------------------------------------------------------------
__global__ void __launch_bounds__(256, 2)
k_tail(const unsigned* __restrict__ ybh, const unsigned* __restrict__ ybl,
       const float* __restrict__ e1b, const float* __restrict__ e2w,
       const float* __restrict__ e2b, float* __restrict__ out)
{
    extern __shared__ unsigned smu[];
    unsigned* Bh = smu;
    unsigned* Bl = smu + 1152;
    unsigned* Hh = smu + 2304;
    unsigned* Hl = smu + 11520;
    float* part = (float*)smu;

    int tid = threadIdx.x;     // 256
    int lane = tid & 31, w = tid >> 5;
    int grp = lane >> 2, t4 = lane & 3;
    int p0 = blockIdx.x * 64;

    float d[2][8][4];
#pragma unroll
    for (int mt = 0; mt < 2; mt++)
#pragma unroll
        for (int nt = 0; nt < 8; nt++)
#pragma unroll
            for (int j = 0; j < 4; j++) d[mt][nt][j] = 0.f;

    // ---- phase A: skip GEMM over 40 layer-chunks (K=32 each) ----
    for (int kc = 0; kc < 40; kc++) {
        __syncthreads();
        {
            int row = tid >> 4, q4 = (tid & 15) * 4;
            size_t g = (size_t)(kc * 16 + row) * FINAL + p0 + q4;
            *(uint4*)&Bh[row * 72 + q4] = *(const uint4*)&ybh[g];
            *(uint4*)&Bl[row * 72 + q4] = *(const uint4*)&ybl[g];
        }
        __syncthreads();
#pragma unroll
        for (int ck = 0; ck < 2; ck++) {
            int k2b = ck * 8;
            unsigned ah[2][4], al[2][4];
#pragma unroll
            for (int mt = 0; mt < 2; mt++) {
                int ro = kc * 256 + w * 32 + mt * 16 + grp;
                const unsigned* ph = &g_swrh[ro * 16 + k2b + t4];
                const unsigned* pl = &g_swrl[ro * 16 + k2b + t4];
                ah[mt][0] = ph[0]; ah[mt][1] = ph[8 * 16]; ah[mt][2] = ph[4]; ah[mt][3] = ph[8 * 16 + 4];
                al[mt][0] = pl[0]; al[mt][1] = pl[8 * 16]; al[mt][2] = pl[4]; al[mt][3] = pl[8 * 16 + 4];
            }
#pragma unroll
            for (int nt = 0; nt < 8; nt++) {
                unsigned bh[2], bl[2];
                bh[0] = Bh[(k2b + t4) * 72 + nt * 8 + grp];
                bh[1] = Bh[(k2b + t4 + 4) * 72 + nt * 8 + grp];
                bl[0] = Bl[(k2b + t4) * 72 + nt * 8 + grp];
                bl[1] = Bl[(k2b + t4 + 4) * 72 + nt * 8 + grp];
#pragma unroll
                for (int mt = 0; mt < 2; mt++) {
                    mma16(d[mt][nt], ah[mt], bh);
                    mma16(d[mt][nt], ah[mt], bl);
                    mma16(d[mt][nt], al[mt], bh);
                }
            }
        }
    }

    // ---- relu + split into Hh/Hl (bf16 halves, k-paired rows) ----
    __syncthreads();
    unsigned short* Hh16 = (unsigned short*)Hh;
    unsigned short* Hl16 = (unsigned short*)Hl;
#pragma unroll
    for (int mt = 0; mt < 2; mt++)
#pragma unroll
        for (int nt = 0; nt < 8; nt++) {
            int r = w * 32 + mt * 16 + grp;
            int col = nt * 8 + 2 * t4;
            unsigned short h, lo;
            float v;
            v = d[mt][nt][0]; v = v > 0.f ? v : 0.f; split1(v, h, lo);
            Hh16[((r >> 1) * 72 + col) * 2 + (r & 1)] = h;
            Hl16[((r >> 1) * 72 + col) * 2 + (r & 1)] = lo;
            v = d[mt][nt][1]; v = v > 0.f ? v : 0.f; split1(v, h, lo);
            Hh16[((r >> 1) * 72 + col + 1) * 2 + (r & 1)] = h;
            Hl16[((r >> 1) * 72 + col + 1) * 2 + (r & 1)] = lo;
            int r2 = r + 8;
            v = d[mt][nt][2]; v = v > 0.f ? v : 0.f; split1(v, h, lo);
            Hh16[((r2 >> 1) * 72 + col) * 2 + (r2 & 1)] = h;
            Hl16[((r2 >> 1) * 72 + col) * 2 + (r2 & 1)] = lo;
            v = d[mt][nt][3]; v = v > 0.f ? v : 0.f; split1(v, h, lo);
            Hh16[((r2 >> 1) * 72 + col + 1) * 2 + (r2 & 1)] = h;
            Hl16[((r2 >> 1) * 72 + col + 1) * 2 + (r2 & 1)] = lo;
        }
    __syncthreads();

    // ---- phase B: e1 GEMM (256x64, K=256 = 16 k16 chunks) ----
#pragma unroll
    for (int mt = 0; mt < 2; mt++)
#pragma unroll
        for (int nt = 0; nt < 8; nt++)
#pragma unroll
            for (int j = 0; j < 4; j++) d[mt][nt][j] = 0.f;

    for (int kk = 0; kk < 16; kk++) {
        unsigned ah[2][4], al[2][4];
#pragma unroll
        for (int mt = 0; mt < 2; mt++) {
            int ro = w * 32 + mt * 16 + grp;
            const unsigned* ph = &g_e1rh[ro * 128 + kk * 8 + t4];
            const unsigned* pl = &g_e1rl[ro * 128 + kk * 8 + t4];
            ah[mt][0] = ph[0]; ah[mt][1] = ph[8 * 128]; ah[mt][2] = ph[4]; ah[mt][3] = ph[8 * 128 + 4];
            al[mt][0] = pl[0]; al[mt][1] = pl[8 * 128]; al[mt][2] = pl[4]; al[mt][3] = pl[8 * 128 + 4];
        }
#pragma unroll
        for (int nt = 0; nt < 8; nt++) {
            unsigned bh[2], bl[2];
            bh[0] = Hh[(kk * 8 + t4) * 72 + nt * 8 + grp];
            bh[1] = Hh[(kk * 8 + t4 + 4) * 72 + nt * 8 + grp];
            bl[0] = Hl[(kk * 8 + t4) * 72 + nt * 8 + grp];
            bl[1] = Hl[(kk * 8 + t4 + 4) * 72 + nt * 8 + grp];
#pragma unroll
            for (int mt = 0; mt < 2; mt++) {
                mma16(d[mt][nt], ah[mt], bh);
                mma16(d[mt][nt], ah[mt], bl);
                mma16(d[mt][nt], al[mt], bh);
            }
        }
    }

    // ---- epilogue: bias + relu + e2 dot + reduce ----
    int r0 = w * 32 + grp;
    float eb0 = e1b[r0],      eb1 = e1b[r0 + 8];
    float eb2 = e1b[r0 + 16], eb3 = e1b[r0 + 24];
    float ew0 = e2w[r0],      ew1 = e2w[r0 + 8];
    float ew2 = e2w[r0 + 16], ew3 = e2w[r0 + 24];

    float pc[16];
#pragma unroll
    for (int nt = 0; nt < 8; nt++) {
#pragma unroll
        for (int j = 0; j < 2; j++) {
            float h0 = d[0][nt][j]     + eb0; h0 = h0 > 0.f ? h0 : 0.f;
            float h1 = d[0][nt][2 + j] + eb1; h1 = h1 > 0.f ? h1 : 0.f;
            float h2 = d[1][nt][j]     + eb2; h2 = h2 > 0.f ? h2 : 0.f;
            float h3 = d[1][nt][2 + j] + eb3; h3 = h3 > 0.f ? h3 : 0.f;
            pc[nt * 2 + j] = ew0 * h0 + ew1 * h1 + ew2 * h2 + ew3 * h3;
        }
    }
#pragma unroll
    for (int off = 16; off >= 4; off >>= 1)
#pragma unroll
        for (int t = 0; t < 16; t++)
            pc[t] += __shfl_xor_sync(0xffffffff, pc[t], off);

    if (lane < 4) {
#pragma unroll
        for (int nt = 0; nt < 8; nt++) {
            part[w * 64 + nt * 8 + 2 * lane]     = pc[nt * 2];
            part[w * 64 + nt * 8 + 2 * lane + 1] = pc[nt * 2 + 1];
        }
    }
    __syncthreads();
    if (tid < 64) {
        float s = e2b[0];
#pragma unroll
        for (int ww = 0; ww < 8; ww++) s += part[ww * 64 + tid];
        int p = p0 + tid;
        out[(p & 15) * TOUT + (p >> 4)] = s;
    }
}

// ---------------------------------------------------------------------------
extern "C" void kernel_launch(void* const* d_in, const int* in_sizes, int n_in,
                              void* d_out, int out_size)
{
    const float* input    = (const float*)d_in[0];
    const float* start_w  = (const float*)d_in[1];
    const float* filter_w = (const float*)d_in[2];
    const float* gate_w   = (const float*)d_in[3];
    const float* res_w    = (const float*)d_in[4];
    const float* skip_w   = (const float*)d_in[5];
    const float* e1w      = (const float*)d_in[6];
    const float* e1b      = (const float*)d_in[7];
    const float* e2w      = (const float*)d_in[8];
    const float* e2b      = (const float*)d_in[9];
    float* out = (float*)d_out;
    (void)in_sizes; (void)n_in; (void)out_size;

    static int attr_done = 0;
    if (!attr_done) {
        cudaFuncSetAttribute(k_layer, cudaFuncAttributeMaxDynamicSharedMemorySize, 57344);
        cudaFuncSetAttribute(k_tail,  cudaFuncAttributeMaxDynamicSharedMemorySize, 82944);
        attr_done = 1;
    }

    float *bufA, *bufB;
    unsigned *ybh, *ybl;
    cudaGetSymbolAddress((void**)&bufA, g_xa);
    cudaGetSymbolAddress((void**)&bufB, g_xb);
    cudaGetSymbolAddress((void**)&ybh, g_ybh);
    cudaGetSymbolAddress((void**)&ybl, g_ybl);

    k_prep<<<48, 256>>>(filter_w, gate_w, res_w, skip_w, e1w);
    k_start<<<1024, 256>>>(input, start_w, bufA);

    float* cur = bufA;
    float* nxt = bufB;
    for (int i = 0; i < 40; i++) {
        int b = i / 10, k = i % 10;
        int Mb = 262144 - 8192 * b;
        int Min, Mout, P, S;
        if (k == 0) { Min = Mb; Mout = Mb - 16; P = 0; S = 16; }
        else {
            int d = 1 << k;
            Min = Mb - 8 * d;
            Mout = Mb - 16 * d;
            P = 8 * d;
            S = 16 * d;
        }
        int ofs = Mout - FINAL;
        int grid = (Mout + 127) / 128;
        k_layer<<<grid, 256, 57344>>>(cur, nxt,
                                      ybh + (size_t)i * 16 * FINAL,
                                      ybl + (size_t)i * 16 * FINAL,
                                      i, Min, Mout, P, S, ofs);
        float* t = cur; cur = nxt; nxt = t;
    }

    k_tail<<<FINAL / 64, 256, 82944>>>(ybh, ybl, e1b, e2w, e2b, out);
}

// round 7
// speedup vs baseline: 3.5653x; 1.1983x over previous
#include <cuda_runtime.h>
#include <cuda_fp16.h>
#include <math.h>

#define FINAL 229376        // 16 * 14336 final flat length
#define XLD   262144        // fixed channel stride for x buffers
#define TOUT  14336

// Scratch (device globals; no allocation anywhere)
__device__ float    g_xa[32 * XLD];
__device__ float    g_xb[32 * XLD];
__device__ unsigned g_ybf[640 * FINAL];     // y hi, packed fp16 pairs (k2 x pos)
__device__ unsigned g_w1h[40 * 2048], g_w1l[40 * 2048];   // [s=64][k2=32] per layer
__device__ unsigned g_wrh[40 * 512],  g_wrl[40 * 512];    // [c=32][k2=16]
__device__ unsigned g_swf[163840];                        // skip_w single fp16 [40*256][k2=16]
__device__ unsigned g_e1fh[32768],    g_e1fl[32768];      // e1w fp16 pairs [256][k2=128]

// ---------------------------------------------------------------------------
// helpers (fp16 limbs)
// ---------------------------------------------------------------------------
__device__ __forceinline__ void mma16(float d[4], const unsigned a[4], const unsigned b[2]) {
    asm volatile(
        "mma.sync.aligned.m16n8k16.row.col.f32.f16.f16.f32 "
        "{%0,%1,%2,%3},{%4,%5,%6,%7},{%8,%9},{%0,%1,%2,%3};"
        : "+f"(d[0]), "+f"(d[1]), "+f"(d[2]), "+f"(d[3])
        : "r"(a[0]), "r"(a[1]), "r"(a[2]), "r"(a[3]), "r"(b[0]), "r"(b[1]));
}
__device__ __forceinline__ float sigmoidf_(float x) { return 1.f / (1.f + expf(-x)); }

// pack two floats (even ch -> low half) into fp16x2 hi and lo components
__device__ __forceinline__ void split_pack(float a, float b, unsigned& h, unsigned& l) {
    __half ah = __float2half(a), bh = __float2half(b);
    float ar = a - __half2float(ah), br = b - __half2float(bh);
    __half2 th; th.x = ah; th.y = bh; h = *(unsigned*)&th;
    __half2 tl; tl.x = __float2half(ar); tl.y = __float2half(br);
    l = *(unsigned*)&tl;
}
__device__ __forceinline__ unsigned pack1(float a, float b) {
    __half2 t; t.x = __float2half(a); t.y = __float2half(b);
    return *(unsigned*)&t;
}
__device__ __forceinline__ void split1(float v, unsigned short& h, unsigned short& l) {
    __half vh = __float2half(v);
    float r = v - __half2float(vh);
    __half vl = __float2half(r);
    h = *(unsigned short*)&vh;
    l = *(unsigned short*)&vl;
}
__device__ __forceinline__ float fp_half(unsigned u, int hi) {
    __half2 t = *(__half2*)&u;
    return hi ? __half2float(t.y) : __half2float(t.x);
}

// ---------------------------------------------------------------------------
// prep: split weights into packed fp16 hi/lo pairs (permuted for fragments)
// ---------------------------------------------------------------------------
__global__ void k_prep(const float* __restrict__ fw, const float* __restrict__ gw,
                       const float* __restrict__ rw, const float* __restrict__ sw,
                       const float* __restrict__ e1w)
{
    int i = blockIdx.x, tid = threadIdx.x;
    if (i < 40) {
        for (int l = tid; l < 2048; l += 256) {
            int s = l >> 5, k2 = l & 31;
            int c = ((s >> 4) << 3) + (s & 7);
            int isg = (s >> 3) & 1;
            const float* src = (isg ? gw : fw) + i * 2048;
            int k0 = 2 * k2;
            float v0 = src[(c * 32 + (k0 & 31)) * 2 + (k0 >> 5)];
            float v1 = src[(c * 32 + ((k0 + 1) & 31)) * 2 + ((k0 + 1) >> 5)];
            unsigned h, lo;
            split_pack(v0, v1, h, lo);
            g_w1h[i * 2048 + l] = h;
            g_w1l[i * 2048 + l] = lo;
        }
        for (int l = tid; l < 512; l += 256) {
            int co = l >> 4, k2 = l & 15;
            float v0 = rw[i * 1024 + co * 32 + 2 * k2];
            float v1 = rw[i * 1024 + co * 32 + 2 * k2 + 1];
            unsigned h, lo;
            split_pack(v0, v1, h, lo);
            g_wrh[i * 512 + l] = h;
            g_wrl[i * 512 + l] = lo;
        }
    } else {
        int bi = i - 40;  // 0..7
        for (int l = bi * 256 + tid; l < 163840; l += 2048) {
            int og = l >> 4, k2 = l & 15;
            g_swf[l] = pack1(sw[og * 32 + 2 * k2], sw[og * 32 + 2 * k2 + 1]);
        }
        for (int l = bi * 256 + tid; l < 32768; l += 2048) {
            int o = l >> 7, k2 = l & 127;
            unsigned h, lo;
            split_pack(e1w[o * 256 + 2 * k2], e1w[o * 256 + 2 * k2 + 1], h, lo);
            g_e1fh[l] = h; g_e1fl[l] = lo;
        }
    }
}

// ---------------------------------------------------------------------------
// start conv: x0[c][t*16+b] = sum_f sw[c][f] * input[b][f][t]
// ---------------------------------------------------------------------------
__global__ void k_start(const float* __restrict__ in, const float* __restrict__ sw,
                        float* __restrict__ x0)
{
    __shared__ float s_w[4096];
    __shared__ float s_in[16 * 272];
    int tid = threadIdx.x;               // 256
    for (int l = tid; l < 4096; l += 256) s_w[l] = sw[l];
    int t0 = blockIdx.x * 16;
    int b = tid & 15, dt = tid >> 4;
    float acc[32];
#pragma unroll
    for (int c = 0; c < 32; c++) acc[c] = 0.f;
    int tt = tid & 15, rhalf = tid >> 4;
    for (int fc = 0; fc < 8; fc++) {
        __syncthreads();
#pragma unroll
        for (int pass = 0; pass < 16; pass++) {
            int row = pass * 16 + rhalf;
            int bb = row >> 4, ff = row & 15;
            s_in[ff * 272 + tt * 17 + bb] =
                in[(bb * 128 + fc * 16 + ff) * 16384 + t0 + tt];
        }
        __syncthreads();
#pragma unroll
        for (int f = 0; f < 16; f++) {
            float v = s_in[f * 272 + dt * 17 + b];
#pragma unroll
            for (int c = 0; c < 32; c++)
                acc[c] += s_w[c * 128 + fc * 16 + f] * v;
        }
    }
    int m = t0 * 16 + tid;
#pragma unroll
    for (int c = 0; c < 32; c++)
        x0[c * XLD + m] = acc[c];
}

// ---------------------------------------------------------------------------
// fused dilated layer, fp16x3 split: tile 64 u-rows x 128 positions.
// smem (u32): Wh[64][36]@0, Wl@2304, Rh[32][20]@4608, Rl@5248,
//             Xh[32][132]@5888, Xl[32][132]@10112  -> 14336 u32 = 57344 B
// X rows = k2 pairs: 0..15 = xA channels, 16..31 = xB channels (128 pos + 4 pad).
// Y (packed fp16 pairs) overlays X rows 0..15 after GEMM1.
// ---------------------------------------------------------------------------
__global__ void __launch_bounds__(256, 3)
k_layer(const float* __restrict__ xin, float* __restrict__ xout,
        unsigned* __restrict__ ytf, int layer,
        int Min, int Mout, int P, int S, int ofs)
{
    extern __shared__ unsigned smu[];
    unsigned* Wh = smu;
    unsigned* Wl = smu + 2304;
    unsigned* Rh = smu + 4608;
    unsigned* Rl = smu + 5248;
    unsigned* Xh = smu + 5888;
    unsigned* Xl = smu + 10112;

    int tid = threadIdx.x;          // 256
    int m0 = blockIdx.x * 128;
    int lane = tid & 31, w = tid >> 5;
    int grp = lane >> 2, t4 = lane & 3;

    // ---- stage weights (straight u32 copies into padded layout) ----
    const unsigned* wsh = g_w1h + layer * 2048;
    const unsigned* wsl = g_w1l + layer * 2048;
    for (int l = tid; l < 512; l += 256) {
        int row = l >> 3, q = (l & 7) * 4;
        *(uint4*)&Wh[row * 36 + q] = *(const uint4*)&wsh[row * 32 + q];
        *(uint4*)&Wl[row * 36 + q] = *(const uint4*)&wsl[row * 32 + q];
    }
    const unsigned* rsh = g_wrh + layer * 512;
    const unsigned* rsl = g_wrl + layer * 512;
    for (int l = tid; l < 128; l += 256) {
        int row = l >> 2, q = (l & 3) * 4;
        *(uint4*)&Rh[row * 20 + q] = *(const uint4*)&rsh[row * 16 + q];
        *(uint4*)&Rl[row * 20 + q] = *(const uint4*)&rsl[row * 16 + q];
    }

    // ---- stage x: split fp32 -> packed fp16 pairs (channel pairs) ----
    for (int v = tid; v < 1024; v += 256) {
        int j2 = v >> 5, q4 = (v & 31) * 4;
        int tap = j2 >> 4, ch = (j2 & 15) * 2;
        int off = tap ? (S - P) : -P;
        int idx = m0 + q4 + off;
        const float* pa = xin + (size_t)ch * XLD;
        const float* pb = pa + XLD;
        float4 va, vb;
        if (idx >= 0 && idx + 3 < Min) {
            va = *(const float4*)(pa + idx);
            vb = *(const float4*)(pb + idx);
        } else {
            va.x = (idx     >= 0 && idx     < Min) ? pa[idx]     : 0.f;
            va.y = (idx + 1 >= 0 && idx + 1 < Min) ? pa[idx + 1] : 0.f;
            va.z = (idx + 2 >= 0 && idx + 2 < Min) ? pa[idx + 2] : 0.f;
            va.w = (idx + 3 >= 0 && idx + 3 < Min) ? pa[idx + 3] : 0.f;
            vb.x = (idx     >= 0 && idx     < Min) ? pb[idx]     : 0.f;
            vb.y = (idx + 1 >= 0 && idx + 1 < Min) ? pb[idx + 1] : 0.f;
            vb.z = (idx + 2 >= 0 && idx + 2 < Min) ? pb[idx + 2] : 0.f;
            vb.w = (idx + 3 >= 0 && idx + 3 < Min) ? pb[idx + 3] : 0.f;
        }
        uint4 H, L;
        split_pack(va.x, vb.x, H.x, L.x);
        split_pack(va.y, vb.y, H.y, L.y);
        split_pack(va.z, vb.z, H.z, L.z);
        split_pack(va.w, vb.w, H.w, L.w);
        *(uint4*)&Xh[j2 * 132 + q4] = H;
        *(uint4*)&Xl[j2 * 132 + q4] = L;
    }
    __syncthreads();

    // ---- GEMM1: 64x128, K=64 (4 k16 chunks); warps 2m x 4n; 3-mma split ----
    int wr1 = w >> 2, wc1 = w & 3;
    float d[2][4][4];
#pragma unroll
    for (int a = 0; a < 2; a++)
#pragma unroll
        for (int b = 0; b < 4; b++)
#pragma unroll
            for (int c = 0; c < 4; c++) d[a][b][c] = 0.f;

#pragma unroll
    for (int kc = 0; kc < 4; kc++) {
        int k2b = kc * 8;
        unsigned ah[2][4], al[2][4];
#pragma unroll
        for (int mf = 0; mf < 2; mf++) {
            int r0 = wr1 * 32 + mf * 16 + grp;
            const unsigned* ph = &Wh[r0 * 36 + k2b + t4];
            const unsigned* pl = &Wl[r0 * 36 + k2b + t4];
            ah[mf][0] = ph[0]; ah[mf][1] = ph[8 * 36]; ah[mf][2] = ph[4]; ah[mf][3] = ph[8 * 36 + 4];
            al[mf][0] = pl[0]; al[mf][1] = pl[8 * 36]; al[mf][2] = pl[4]; al[mf][3] = pl[8 * 36 + 4];
        }
#pragma unroll
        for (int nt = 0; nt < 4; nt++) {
            int n = wc1 * 32 + nt * 8 + grp;
            unsigned bh[2], bl[2];
            bh[0] = Xh[(k2b + t4) * 132 + n];     bh[1] = Xh[(k2b + t4 + 4) * 132 + n];
            bl[0] = Xl[(k2b + t4) * 132 + n];     bl[1] = Xl[(k2b + t4 + 4) * 132 + n];
#pragma unroll
            for (int mf = 0; mf < 2; mf++) {
                mma16(d[mf][nt], ah[mf], bh);
                mma16(d[mf][nt], ah[mf], bl);
                mma16(d[mf][nt], al[mf], bh);
            }
        }
    }

    // ---- gated activation in registers ----
    float yv[2][4][2];
#pragma unroll
    for (int mf = 0; mf < 2; mf++)
#pragma unroll
        for (int nt = 0; nt < 4; nt++) {
            yv[mf][nt][0] = tanhf(d[mf][nt][0]) * sigmoidf_(d[mf][nt][2]);
            yv[mf][nt][1] = tanhf(d[mf][nt][1]) * sigmoidf_(d[mf][nt][3]);
        }
    __syncthreads();    // all GEMM1 smem reads complete

    // ---- store y as packed fp16 halves into X rows 0..15 overlay ----
    unsigned short* Yh16 = (unsigned short*)Xh;
    unsigned short* Yl16 = (unsigned short*)Xl;
#pragma unroll
    for (int mf = 0; mf < 2; mf++) {
        int c = (wr1 * 2 + mf) * 8 + grp;
#pragma unroll
        for (int nt = 0; nt < 4; nt++) {
            int col = wc1 * 32 + nt * 8 + 2 * t4;
            int base = ((c >> 1) * 132 + col) * 2 + (c & 1);
            unsigned short h, lo;
            split1(yv[mf][nt][0], h, lo); Yh16[base] = h;     Yl16[base] = lo;
            split1(yv[mf][nt][1], h, lo); Yh16[base + 2] = h; Yl16[base + 2] = lo;
        }
    }
    __syncthreads();

    // ---- ytail copy (hi only, coalesced u32 rows) ----
    for (int v = tid; v < 512; v += 256) {
        int row = v >> 5, colq = (v & 31) * 4;
        int m = m0 + colq;
        if (m >= ofs && m < Mout)
            *(uint4*)&ytf[(size_t)row * FINAL + (m - ofs)] = *(uint4*)&Xh[row * 132 + colq];
    }

    // ---- GEMM2: 32x128, K=32 (2 k16 chunks); warps 2m x 4n; + fp32 residual ----
    int wr2 = w >> 2, wc2 = w & 3;
    float e[4][4];
#pragma unroll
    for (int a = 0; a < 4; a++)
#pragma unroll
        for (int b = 0; b < 4; b++) e[a][b] = 0.f;

#pragma unroll
    for (int kc = 0; kc < 2; kc++) {
        int k2b = kc * 8;
        int r0 = wr2 * 16 + grp;
        const unsigned* ph = &Rh[r0 * 20 + k2b + t4];
        const unsigned* pl = &Rl[r0 * 20 + k2b + t4];
        unsigned ah[4], al[4];
        ah[0] = ph[0]; ah[1] = ph[8 * 20]; ah[2] = ph[4]; ah[3] = ph[8 * 20 + 4];
        al[0] = pl[0]; al[1] = pl[8 * 20]; al[2] = pl[4]; al[3] = pl[8 * 20 + 4];
#pragma unroll
        for (int nt = 0; nt < 4; nt++) {
            int n = wc2 * 32 + nt * 8 + grp;
            unsigned bh[2], bl[2];
            bh[0] = Xh[(k2b + t4) * 132 + n];     bh[1] = Xh[(k2b + t4 + 4) * 132 + n];
            bl[0] = Xl[(k2b + t4) * 132 + n];     bl[1] = Xl[(k2b + t4 + 4) * 132 + n];
            mma16(e[nt], ah, bh);
            mma16(e[nt], ah, bl);
            mma16(e[nt], al, bh);
        }
    }
#pragma unroll
    for (int nt = 0; nt < 4; nt++) {
        int col = wc2 * 32 + nt * 8 + 2 * t4;
        int m = m0 + col;
        if (m < Mout) {
            int c = wr2 * 16 + grp;
            int c2 = c + 8;
            // residual from xB region (rows 16..31), reconstruct hi+lo
            unsigned uh0 = Xh[(16 + (c  >> 1)) * 132 + col],     ul0 = Xl[(16 + (c  >> 1)) * 132 + col];
            unsigned uh1 = Xh[(16 + (c  >> 1)) * 132 + col + 1], ul1 = Xl[(16 + (c  >> 1)) * 132 + col + 1];
            unsigned vh0 = Xh[(16 + (c2 >> 1)) * 132 + col],     vl0 = Xl[(16 + (c2 >> 1)) * 132 + col];
            unsigned vh1 = Xh[(16 + (c2 >> 1)) * 132 + col + 1], vl1 = Xl[(16 + (c2 >> 1)) * 132 + col + 1];
            int hsel = c & 1, hsel2 = c2 & 1;
            xout[c  * XLD + m]     = e[nt][0] + fp_half(uh0, hsel)  + fp_half(ul0, hsel);
            xout[c  * XLD + m + 1] = e[nt][1] + fp_half(uh1, hsel)  + fp_half(ul1, hsel);
            xout[c2 * XLD + m]     = e[nt][2] + fp_half(vh0, hsel2) + fp_half(vl0, hsel2);
            xout[c2 * XLD + m + 1] = e[nt][3] + fp_half(vh1, hsel2) + fp_half(vl1, hsel2);
        }
    }
}

// ---------------------------------------------------------------------------
// fused tail: skip GEMM (single fp16) + relu + e1 (fp16x3) + bias + relu + e2
// per block: 64 positions, all 256 skip rows.
// smem (u32): Bs[16][72]@0 (1152), Hh[128][72]@1152, Hl@10368 -> 19584 u32
// ---------------------------------------------------------------------------
__global__ void __launch_bounds__(256, 2)
k_tail(const unsigned* __restrict__ ybf,
       const float* __restrict__ e1b, const float* __restrict__ e2w,
       const float* __restrict__ e2b, float* __restrict__ out)
{
    extern __shared__ unsigned smu[];
    unsigned* Bs = smu;
    unsigned* Hh = smu + 1152;
    unsigned* Hl = smu + 10368;
    float* part = (float*)smu;

    int tid = threadIdx.x;     // 256
    int lane = tid & 31, w = tid >> 5;
    int grp = lane >> 2, t4 = lane & 3;
    int p0 = blockIdx.x * 64;

    float d[2][8][4];
#pragma unroll
    for (int mt = 0; mt < 2; mt++)
#pragma unroll
        for (int nt = 0; nt < 8; nt++)
#pragma unroll
            for (int j = 0; j < 4; j++) d[mt][nt][j] = 0.f;

    // ---- phase A: skip GEMM over 40 layer-chunks (K=32 each), single fp16 ----
    for (int kc = 0; kc < 40; kc++) {
        __syncthreads();
        {
            int row = tid >> 4, q4 = (tid & 15) * 4;
            size_t g = (size_t)(kc * 16 + row) * FINAL + p0 + q4;
            *(uint4*)&Bs[row * 72 + q4] = *(const uint4*)&ybf[g];
        }
        __syncthreads();
#pragma unroll
        for (int ck = 0; ck < 2; ck++) {
            int k2b = ck * 8;
            unsigned a0[4], a1[4];
            {
                int ro = kc * 256 + w * 32 + grp;
                const unsigned* pw = &g_swf[ro * 16 + k2b + t4];
                a0[0] = pw[0]; a0[1] = pw[8 * 16]; a0[2] = pw[4]; a0[3] = pw[8 * 16 + 4];
                const unsigned* pw2 = &g_swf[(ro + 16) * 16 + k2b + t4];
                a1[0] = pw2[0]; a1[1] = pw2[8 * 16]; a1[2] = pw2[4]; a1[3] = pw2[8 * 16 + 4];
            }
#pragma unroll
            for (int nt = 0; nt < 8; nt++) {
                unsigned b[2];
                b[0] = Bs[(k2b + t4) * 72 + nt * 8 + grp];
                b[1] = Bs[(k2b + t4 + 4) * 72 + nt * 8 + grp];
                mma16(d[0][nt], a0, b);
                mma16(d[1][nt], a1, b);
            }
        }
    }

    // ---- relu + split into Hh/Hl (fp16 halves, k-paired rows) ----
    __syncthreads();
    unsigned short* Hh16 = (unsigned short*)Hh;
    unsigned short* Hl16 = (unsigned short*)Hl;
#pragma unroll
    for (int mt = 0; mt < 2; mt++)
#pragma unroll
        for (int nt = 0; nt < 8; nt++) {
            int r = w * 32 + mt * 16 + grp;
            int col = nt * 8 + 2 * t4;
            unsigned short h, lo;
            float v;
            v = d[mt][nt][0]; v = v > 0.f ? v : 0.f; split1(v, h, lo);
            Hh16[((r >> 1) * 72 + col) * 2 + (r & 1)] = h;
            Hl16[((r >> 1) * 72 + col) * 2 + (r & 1)] = lo;
            v = d[mt][nt][1]; v = v > 0.f ? v : 0.f; split1(v, h, lo);
            Hh16[((r >> 1) * 72 + col + 1) * 2 + (r & 1)] = h;
            Hl16[((r >> 1) * 72 + col + 1) * 2 + (r & 1)] = lo;
            int r2 = r + 8;
            v = d[mt][nt][2]; v = v > 0.f ? v : 0.f; split1(v, h, lo);
            Hh16[((r2 >> 1) * 72 + col) * 2 + (r2 & 1)] = h;
            Hl16[((r2 >> 1) * 72 + col) * 2 + (r2 & 1)] = lo;
            v = d[mt][nt][3]; v = v > 0.f ? v : 0.f; split1(v, h, lo);
            Hh16[((r2 >> 1) * 72 + col + 1) * 2 + (r2 & 1)] = h;
            Hl16[((r2 >> 1) * 72 + col + 1) * 2 + (r2 & 1)] = lo;
        }
    __syncthreads();

    // ---- phase B: e1 GEMM (256x64, K=256 = 16 k16 chunks), fp16x3 ----
#pragma unroll
    for (int mt = 0; mt < 2; mt++)
#pragma unroll
        for (int nt = 0; nt < 8; nt++)
#pragma unroll
            for (int j = 0; j < 4; j++) d[mt][nt][j] = 0.f;

    for (int kk = 0; kk < 16; kk++) {
        unsigned ah[2][4], al[2][4];
#pragma unroll
        for (int mt = 0; mt < 2; mt++) {
            int ro = w * 32 + mt * 16 + grp;
            const unsigned* ph = &g_e1fh[ro * 128 + kk * 8 + t4];
            const unsigned* pl = &g_e1fl[ro * 128 + kk * 8 + t4];
            ah[mt][0] = ph[0]; ah[mt][1] = ph[8 * 128]; ah[mt][2] = ph[4]; ah[mt][3] = ph[8 * 128 + 4];
            al[mt][0] = pl[0]; al[mt][1] = pl[8 * 128]; al[mt][2] = pl[4]; al[mt][3] = pl[8 * 128 + 4];
        }
#pragma unroll
        for (int nt = 0; nt < 8; nt++) {
            unsigned bh[2], bl[2];
            bh[0] = Hh[(kk * 8 + t4) * 72 + nt * 8 + grp];
            bh[1] = Hh[(kk * 8 + t4 + 4) * 72 + nt * 8 + grp];
            bl[0] = Hl[(kk * 8 + t4) * 72 + nt * 8 + grp];
            bl[1] = Hl[(kk * 8 + t4 + 4) * 72 + nt * 8 + grp];
#pragma unroll
            for (int mt = 0; mt < 2; mt++) {
                mma16(d[mt][nt], ah[mt], bh);
                mma16(d[mt][nt], ah[mt], bl);
                mma16(d[mt][nt], al[mt], bh);
            }
        }
    }

    // ---- epilogue: bias + relu + e2 dot + reduce ----
    int r0 = w * 32 + grp;
    float eb0 = e1b[r0],      eb1 = e1b[r0 + 8];
    float eb2 = e1b[r0 + 16], eb3 = e1b[r0 + 24];
    float ew0 = e2w[r0],      ew1 = e2w[r0 + 8];
    float ew2 = e2w[r0 + 16], ew3 = e2w[r0 + 24];

    float pc[16];
#pragma unroll
    for (int nt = 0; nt < 8; nt++) {
#pragma unroll
        for (int j = 0; j < 2; j++) {
            float h0 = d[0][nt][j]     + eb0; h0 = h0 > 0.f ? h0 : 0.f;
            float h1 = d[0][nt][2 + j] + eb1; h1 = h1 > 0.f ? h1 : 0.f;
            float h2 = d[1][nt][j]     + eb2; h2 = h2 > 0.f ? h2 : 0.f;
            float h3 = d[1][nt][2 + j] + eb3; h3 = h3 > 0.f ? h3 : 0.f;
            pc[nt * 2 + j] = ew0 * h0 + ew1 * h1 + ew2 * h2 + ew3 * h3;
        }
    }
#pragma unroll
    for (int off = 16; off >= 4; off >>= 1)
#pragma unroll
        for (int t = 0; t < 16; t++)
            pc[t] += __shfl_xor_sync(0xffffffff, pc[t], off);

    if (lane < 4) {
#pragma unroll
        for (int nt = 0; nt < 8; nt++) {
            part[w * 64 + nt * 8 + 2 * lane]     = pc[nt * 2];
            part[w * 64 + nt * 8 + 2 * lane + 1] = pc[nt * 2 + 1];
        }
    }
    __syncthreads();
    if (tid < 64) {
        float s = e2b[0];
#pragma unroll
        for (int ww = 0; ww < 8; ww++) s += part[ww * 64 + tid];
        int p = p0 + tid;
        out[(p & 15) * TOUT + (p >> 4)] = s;
    }
}

// ---------------------------------------------------------------------------
extern "C" void kernel_launch(void* const* d_in, const int* in_sizes, int n_in,
                              void* d_out, int out_size)
{
    const float* input    = (const float*)d_in[0];
    const float* start_w  = (const float*)d_in[1];
    const float* filter_w = (const float*)d_in[2];
    const float* gate_w   = (const float*)d_in[3];
    const float* res_w    = (const float*)d_in[4];
    const float* skip_w   = (const float*)d_in[5];
    const float* e1w      = (const float*)d_in[6];
    const float* e1b      = (const float*)d_in[7];
    const float* e2w      = (const float*)d_in[8];
    const float* e2b      = (const float*)d_in[9];
    float* out = (float*)d_out;
    (void)in_sizes; (void)n_in; (void)out_size;

    static int attr_done = 0;
    if (!attr_done) {
        cudaFuncSetAttribute(k_layer, cudaFuncAttributeMaxDynamicSharedMemorySize, 57344);
        cudaFuncSetAttribute(k_tail,  cudaFuncAttributeMaxDynamicSharedMemorySize, 78336);
        attr_done = 1;
    }

    float *bufA, *bufB;
    unsigned *ybf;
    cudaGetSymbolAddress((void**)&bufA, g_xa);
    cudaGetSymbolAddress((void**)&bufB, g_xb);
    cudaGetSymbolAddress((void**)&ybf, g_ybf);

    k_prep<<<48, 256>>>(filter_w, gate_w, res_w, skip_w, e1w);
    k_start<<<1024, 256>>>(input, start_w, bufA);

    float* cur = bufA;
    float* nxt = bufB;
    for (int i = 0; i < 40; i++) {
        int b = i / 10, k = i % 10;
        int Mb = 262144 - 8192 * b;
        int Min, Mout, P, S;
        if (k == 0) { Min = Mb; Mout = Mb - 16; P = 0; S = 16; }
        else {
            int d = 1 << k;
            Min = Mb - 8 * d;
            Mout = Mb - 16 * d;
            P = 8 * d;
            S = 16 * d;
        }
        int ofs = Mout - FINAL;
        int grid = (Mout + 127) / 128;
        k_layer<<<grid, 256, 57344>>>(cur, nxt,
                                      ybf + (size_t)i * 16 * FINAL,
                                      i, Min, Mout, P, S, ofs);
        float* t = cur; cur = nxt; nxt = t;
    }

    k_tail<<<FINAL / 64, 256, 78336>>>(ybf, e1b, e2w, e2b, out);
}

// round 8
// speedup vs baseline: 3.6727x; 1.0301x over previous
#include <cuda_runtime.h>
#include <cuda_fp16.h>
#include <math.h>

#define FINAL 229376        // 16 * 14336 final flat length
#define XLD   262144        // fixed channel stride for x buffers
#define TOUT  14336

// Scratch (device globals; no allocation anywhere)
__device__ unsigned g_xah[16 * XLD], g_xal[16 * XLD];   // x ping (fp16 hi/lo pairs)
__device__ unsigned g_xbh[16 * XLD], g_xbl[16 * XLD];   // x pong
__device__ unsigned g_ybf[640 * FINAL];     // y hi, packed fp16 pairs (k2 x pos)
__device__ unsigned g_w1h[40 * 2048], g_w1l[40 * 2048];   // [s=64][k2=32] per layer
__device__ unsigned g_wrh[40 * 512],  g_wrl[40 * 512];    // [row=32][k2=16] (rows permuted)
__device__ unsigned g_swf[163840];                        // skip_w single fp16 [40*256][k2=16]
__device__ unsigned g_e1fh[32768],    g_e1fl[32768];      // e1w fp16 pairs [256][k2=128]

// ---------------------------------------------------------------------------
// helpers (fp16 limbs)
// ---------------------------------------------------------------------------
__device__ __forceinline__ void mma16(float d[4], const unsigned a[4], const unsigned b[2]) {
    asm volatile(
        "mma.sync.aligned.m16n8k16.row.col.f32.f16.f16.f32 "
        "{%0,%1,%2,%3},{%4,%5,%6,%7},{%8,%9},{%0,%1,%2,%3};"
        : "+f"(d[0]), "+f"(d[1]), "+f"(d[2]), "+f"(d[3])
        : "r"(a[0]), "r"(a[1]), "r"(a[2]), "r"(a[3]), "r"(b[0]), "r"(b[1]));
}
__device__ __forceinline__ void ldsm_x4(unsigned a[4], unsigned saddr) {
    asm volatile("ldmatrix.sync.aligned.m8n8.x4.shared.b16 {%0,%1,%2,%3}, [%4];"
        : "=r"(a[0]), "=r"(a[1]), "=r"(a[2]), "=r"(a[3]) : "r"(saddr));
}
__device__ __forceinline__ unsigned smaddr(const void* p) {
    return (unsigned)__cvta_generic_to_shared(p);
}
__device__ __forceinline__ float sigmoidf_(float x) { return 1.f / (1.f + expf(-x)); }

// pack two floats (even ch -> low half) into fp16x2 hi and lo components
__device__ __forceinline__ void split_pack(float a, float b, unsigned& h, unsigned& l) {
    __half ah = __float2half(a), bh = __float2half(b);
    float ar = a - __half2float(ah), br = b - __half2float(bh);
    __half2 th; th.x = ah; th.y = bh; h = *(unsigned*)&th;
    __half2 tl; tl.x = __float2half(ar); tl.y = __float2half(br);
    l = *(unsigned*)&tl;
}
__device__ __forceinline__ unsigned pack1(float a, float b) {
    __half2 t; t.x = __float2half(a); t.y = __float2half(b);
    return *(unsigned*)&t;
}
__device__ __forceinline__ void split1(float v, unsigned short& h, unsigned short& l) {
    __half vh = __float2half(v);
    float r = v - __half2float(vh);
    __half vl = __float2half(r);
    h = *(unsigned short*)&vh;
    l = *(unsigned short*)&vl;
}
__device__ __forceinline__ float fp_half(unsigned u, int hi) {
    __half2 t = *(__half2*)&u;
    return hi ? __half2float(t.y) : __half2float(t.x);
}

// ---------------------------------------------------------------------------
// prep: split weights into packed fp16 hi/lo pairs (permuted for fragments)
// ---------------------------------------------------------------------------
__global__ void k_prep(const float* __restrict__ fw, const float* __restrict__ gw,
                       const float* __restrict__ rw, const float* __restrict__ sw,
                       const float* __restrict__ e1w)
{
    int i = blockIdx.x, tid = threadIdx.x;
    if (i < 40) {
        for (int l = tid; l < 2048; l += 256) {
            int s = l >> 5, k2 = l & 31;
            int c = ((s >> 4) << 3) + (s & 7);
            int isg = (s >> 3) & 1;
            const float* src = (isg ? gw : fw) + i * 2048;
            int k0 = 2 * k2;
            float v0 = src[(c * 32 + (k0 & 31)) * 2 + (k0 >> 5)];
            float v1 = src[(c * 32 + ((k0 + 1) & 31)) * 2 + ((k0 + 1) >> 5)];
            unsigned h, lo;
            split_pack(v0, v1, h, lo);
            g_w1h[i * 2048 + l] = h;
            g_w1l[i * 2048 + l] = lo;
        }
        for (int l = tid; l < 512; l += 256) {
            int r = l >> 4, k2 = l & 15;
            // row permutation: row g <-> ch 2g, row g+8 <-> ch 2g+1 (per 16-row tile)
            int t = r >> 4, s = r & 15;
            int chan = t * 16 + (s & 7) * 2 + (s >> 3);
            float v0 = rw[i * 1024 + chan * 32 + 2 * k2];
            float v1 = rw[i * 1024 + chan * 32 + 2 * k2 + 1];
            unsigned h, lo;
            split_pack(v0, v1, h, lo);
            g_wrh[i * 512 + l] = h;
            g_wrl[i * 512 + l] = lo;
        }
    } else {
        int bi = i - 40;  // 0..7
        for (int l = bi * 256 + tid; l < 163840; l += 2048) {
            int og = l >> 4, k2 = l & 15;
            g_swf[l] = pack1(sw[og * 32 + 2 * k2], sw[og * 32 + 2 * k2 + 1]);
        }
        for (int l = bi * 256 + tid; l < 32768; l += 2048) {
            int o = l >> 7, k2 = l & 127;
            unsigned h, lo;
            split_pack(e1w[o * 256 + 2 * k2], e1w[o * 256 + 2 * k2 + 1], h, lo);
            g_e1fh[l] = h; g_e1fl[l] = lo;
        }
    }
}

// ---------------------------------------------------------------------------
// start conv: x0[c][t*16+b] = sum_f sw[c][f] * input[b][f][t]; emits split fp16
// ---------------------------------------------------------------------------
__global__ void k_start(const float* __restrict__ in, const float* __restrict__ sw,
                        unsigned* __restrict__ xh, unsigned* __restrict__ xl)
{
    __shared__ float s_w[4096];
    __shared__ float s_in[16 * 272];
    int tid = threadIdx.x;               // 256
    for (int l = tid; l < 4096; l += 256) s_w[l] = sw[l];
    int t0 = blockIdx.x * 16;
    int b = tid & 15, dt = tid >> 4;
    float acc[32];
#pragma unroll
    for (int c = 0; c < 32; c++) acc[c] = 0.f;
    int tt = tid & 15, rhalf = tid >> 4;
    for (int fc = 0; fc < 8; fc++) {
        __syncthreads();
#pragma unroll
        for (int pass = 0; pass < 16; pass++) {
            int row = pass * 16 + rhalf;
            int bb = row >> 4, ff = row & 15;
            s_in[ff * 272 + tt * 17 + bb] =
                in[(bb * 128 + fc * 16 + ff) * 16384 + t0 + tt];
        }
        __syncthreads();
#pragma unroll
        for (int f = 0; f < 16; f++) {
            float v = s_in[f * 272 + dt * 17 + b];
#pragma unroll
            for (int c = 0; c < 32; c++)
                acc[c] += s_w[c * 128 + fc * 16 + f] * v;
        }
    }
    int m = t0 * 16 + tid;
#pragma unroll
    for (int c2 = 0; c2 < 16; c2++) {
        unsigned H, L;
        split_pack(acc[2 * c2], acc[2 * c2 + 1], H, L);
        xh[c2 * XLD + m] = H;
        xl[c2 * XLD + m] = L;
    }
}

// ---------------------------------------------------------------------------
// fused dilated layer, fp16x3 split: tile 64 u-rows x 128 positions.
// smem (u32): Wh[64][36]@0, Wl@2304, Rh[32][20]@4608, Rl@5248,
//             Xh[32][132]@5888, Xl[32][132]@10112  -> 14336 u32 = 57344 B
// X rows = k2 pairs: 0..15 = xA channels, 16..31 = xB channels (128 pos + 4 pad).
// Y (packed fp16 pairs) overlays X rows 0..15 after GEMM1.
// ---------------------------------------------------------------------------
__global__ void __launch_bounds__(256, 3)
k_layer(const unsigned* __restrict__ xinh, const unsigned* __restrict__ xinl,
        unsigned* __restrict__ xouth, unsigned* __restrict__ xoutl,
        unsigned* __restrict__ ytf, int layer,
        int Min, int Mout, int P, int S, int ofs)
{
    extern __shared__ unsigned smu[];
    unsigned* Wh = smu;
    unsigned* Wl = smu + 2304;
    unsigned* Rh = smu + 4608;
    unsigned* Rl = smu + 5248;
    unsigned* Xh = smu + 5888;
    unsigned* Xl = smu + 10112;

    int tid = threadIdx.x;          // 256
    int m0 = blockIdx.x * 128;
    int lane = tid & 31, w = tid >> 5;
    int grp = lane >> 2, t4 = lane & 3;
    unsigned lr = ((lane >> 3) & 1) * 8 + (lane & 7);   // ldmatrix row select
    unsigned lc = (lane >> 4) * 4;                      // ldmatrix col select (u32)

    // ---- stage weights (straight u32 copies into padded layout) ----
    const unsigned* wsh = g_w1h + layer * 2048;
    const unsigned* wsl = g_w1l + layer * 2048;
    for (int l = tid; l < 512; l += 256) {
        int row = l >> 3, q = (l & 7) * 4;
        *(uint4*)&Wh[row * 36 + q] = *(const uint4*)&wsh[row * 32 + q];
        *(uint4*)&Wl[row * 36 + q] = *(const uint4*)&wsl[row * 32 + q];
    }
    const unsigned* rsh = g_wrh + layer * 512;
    const unsigned* rsl = g_wrl + layer * 512;
    for (int l = tid; l < 128; l += 256) {
        int row = l >> 2, q = (l & 3) * 4;
        *(uint4*)&Rh[row * 20 + q] = *(const uint4*)&rsh[row * 16 + q];
        *(uint4*)&Rl[row * 20 + q] = *(const uint4*)&rsl[row * 16 + q];
    }

    // ---- stage x: pure copies (already split fp16 hi/lo) ----
    for (int v = tid; v < 1024; v += 256) {
        int j2 = v >> 5, q4 = (v & 31) * 4;
        int tap = j2 >> 4, ch2 = j2 & 15;
        int off = tap ? (S - P) : -P;
        int idx = m0 + q4 + off;
        const unsigned* ph = xinh + (size_t)ch2 * XLD;
        const unsigned* pl = xinl + (size_t)ch2 * XLD;
        uint4 H, L;
        if (idx >= 0 && idx + 3 < Min) {
            H = *(const uint4*)(ph + idx);
            L = *(const uint4*)(pl + idx);
        } else {
            H.x = (idx     >= 0 && idx     < Min) ? ph[idx]     : 0u;
            H.y = (idx + 1 >= 0 && idx + 1 < Min) ? ph[idx + 1] : 0u;
            H.z = (idx + 2 >= 0 && idx + 2 < Min) ? ph[idx + 2] : 0u;
            H.w = (idx + 3 >= 0 && idx + 3 < Min) ? ph[idx + 3] : 0u;
            L.x = (idx     >= 0 && idx     < Min) ? pl[idx]     : 0u;
            L.y = (idx + 1 >= 0 && idx + 1 < Min) ? pl[idx + 1] : 0u;
            L.z = (idx + 2 >= 0 && idx + 2 < Min) ? pl[idx + 2] : 0u;
            L.w = (idx + 3 >= 0 && idx + 3 < Min) ? pl[idx + 3] : 0u;
        }
        *(uint4*)&Xh[j2 * 132 + q4] = H;
        *(uint4*)&Xl[j2 * 132 + q4] = L;
    }
    __syncthreads();

    // ---- GEMM1: 64x128, K=64 (4 k16 chunks); warps 2m x 4n; 3-mma split ----
    int wr1 = w >> 2, wc1 = w & 3;
    unsigned whb = smaddr(Wh) + ((wr1 * 32 + lr) * 36 + lc) * 4;
    unsigned wlb = smaddr(Wl) + ((wr1 * 32 + lr) * 36 + lc) * 4;
    float d[2][4][4];
#pragma unroll
    for (int a = 0; a < 2; a++)
#pragma unroll
        for (int b = 0; b < 4; b++)
#pragma unroll
            for (int c = 0; c < 4; c++) d[a][b][c] = 0.f;

#pragma unroll
    for (int kc = 0; kc < 4; kc++) {
        int k2b = kc * 8;
        unsigned ah[2][4], al[2][4];
#pragma unroll
        for (int mf = 0; mf < 2; mf++) {
            ldsm_x4(ah[mf], whb + (mf * 576 + k2b) * 4);
            ldsm_x4(al[mf], wlb + (mf * 576 + k2b) * 4);
        }
#pragma unroll
        for (int nt = 0; nt < 4; nt++) {
            int n = wc1 * 32 + nt * 8 + grp;
            unsigned bh[2], bl[2];
            bh[0] = Xh[(k2b + t4) * 132 + n];     bh[1] = Xh[(k2b + t4 + 4) * 132 + n];
            bl[0] = Xl[(k2b + t4) * 132 + n];     bl[1] = Xl[(k2b + t4 + 4) * 132 + n];
#pragma unroll
            for (int mf = 0; mf < 2; mf++) {
                mma16(d[mf][nt], ah[mf], bh);
                mma16(d[mf][nt], ah[mf], bl);
                mma16(d[mf][nt], al[mf], bh);
            }
        }
    }

    // ---- gated activation in registers ----
    float yv[2][4][2];
#pragma unroll
    for (int mf = 0; mf < 2; mf++)
#pragma unroll
        for (int nt = 0; nt < 4; nt++) {
            yv[mf][nt][0] = tanhf(d[mf][nt][0]) * sigmoidf_(d[mf][nt][2]);
            yv[mf][nt][1] = tanhf(d[mf][nt][1]) * sigmoidf_(d[mf][nt][3]);
        }
    __syncthreads();    // all GEMM1 smem reads complete

    // ---- store y as packed fp16 halves into X rows 0..15 overlay ----
    unsigned short* Yh16 = (unsigned short*)Xh;
    unsigned short* Yl16 = (unsigned short*)Xl;
#pragma unroll
    for (int mf = 0; mf < 2; mf++) {
        int c = (wr1 * 2 + mf) * 8 + grp;
#pragma unroll
        for (int nt = 0; nt < 4; nt++) {
            int col = wc1 * 32 + nt * 8 + 2 * t4;
            int base = ((c >> 1) * 132 + col) * 2 + (c & 1);
            unsigned short h, lo;
            split1(yv[mf][nt][0], h, lo); Yh16[base] = h;     Yl16[base] = lo;
            split1(yv[mf][nt][1], h, lo); Yh16[base + 2] = h; Yl16[base + 2] = lo;
        }
    }
    __syncthreads();

    // ---- ytail copy (hi only, coalesced u32 rows) ----
    for (int v = tid; v < 512; v += 256) {
        int row = v >> 5, colq = (v & 31) * 4;
        int m = m0 + colq;
        if (m >= ofs && m < Mout)
            *(uint4*)&ytf[(size_t)row * FINAL + (m - ofs)] = *(uint4*)&Xh[row * 132 + colq];
    }

    // ---- GEMM2: 32x128, K=32 (2 k16 chunks); + fp32 residual; split store ----
    int wr2 = w >> 2, wc2 = w & 3;
    unsigned rhb = smaddr(Rh) + ((wr2 * 16 + lr) * 20 + lc) * 4;
    unsigned rlb = smaddr(Rl) + ((wr2 * 16 + lr) * 20 + lc) * 4;
    float e[4][4];
#pragma unroll
    for (int a = 0; a < 4; a++)
#pragma unroll
        for (int b = 0; b < 4; b++) e[a][b] = 0.f;

#pragma unroll
    for (int kc = 0; kc < 2; kc++) {
        int k2b = kc * 8;
        unsigned ah[4], al[4];
        ldsm_x4(ah, rhb + k2b * 4);
        ldsm_x4(al, rlb + k2b * 4);
#pragma unroll
        for (int nt = 0; nt < 4; nt++) {
            int n = wc2 * 32 + nt * 8 + grp;
            unsigned bh[2], bl[2];
            bh[0] = Xh[(k2b + t4) * 132 + n];     bh[1] = Xh[(k2b + t4 + 4) * 132 + n];
            bl[0] = Xl[(k2b + t4) * 132 + n];     bl[1] = Xl[(k2b + t4 + 4) * 132 + n];
            mma16(e[nt], ah, bh);
            mma16(e[nt], ah, bl);
            mma16(e[nt], al, bh);
        }
    }
    // rows permuted: lane holds channel pair (2*ch2, 2*ch2+1) in (d0/d1, d2/d3)
    {
        int ch2 = wr2 * 8 + grp;
        int rowB = 16 + ch2;
#pragma unroll
        for (int nt = 0; nt < 4; nt++) {
            int col = wc2 * 32 + nt * 8 + 2 * t4;
            int m = m0 + col;
            if (m < Mout) {
                unsigned rh0 = Xh[rowB * 132 + col],     rl0 = Xl[rowB * 132 + col];
                unsigned rh1 = Xh[rowB * 132 + col + 1], rl1 = Xl[rowB * 132 + col + 1];
                float v0e = e[nt][0] + fp_half(rh0, 0) + fp_half(rl0, 0);
                float v0o = e[nt][2] + fp_half(rh0, 1) + fp_half(rl0, 1);
                float v1e = e[nt][1] + fp_half(rh1, 0) + fp_half(rl1, 0);
                float v1o = e[nt][3] + fp_half(rh1, 1) + fp_half(rl1, 1);
                unsigned H, L;
                split_pack(v0e, v0o, H, L);
                xouth[(size_t)ch2 * XLD + m] = H;
                xoutl[(size_t)ch2 * XLD + m] = L;
                split_pack(v1e, v1o, H, L);
                xouth[(size_t)ch2 * XLD + m + 1] = H;
                xoutl[(size_t)ch2 * XLD + m + 1] = L;
            }
        }
    }
}

// ---------------------------------------------------------------------------
// fused tail: skip GEMM (single fp16) + relu + e1 (fp16x3) + bias + relu + e2
// per block: 64 positions, all 256 skip rows.
// smem (u32): Bs[16][72]@0 (1152), Hh[128][72]@1152, Hl@10368 -> 19584 u32
// ---------------------------------------------------------------------------
__global__ void __launch_bounds__(256, 2)
k_tail(const unsigned* __restrict__ ybf,
       const float* __restrict__ e1b, const float* __restrict__ e2w,
       const float* __restrict__ e2b, float* __restrict__ out)
{
    extern __shared__ unsigned smu[];
    unsigned* Bs = smu;
    unsigned* Hh = smu + 1152;
    unsigned* Hl = smu + 10368;
    float* part = (float*)smu;

    int tid = threadIdx.x;     // 256
    int lane = tid & 31, w = tid >> 5;
    int grp = lane >> 2, t4 = lane & 3;
    int p0 = blockIdx.x * 64;

    float d[2][8][4];
#pragma unroll
    for (int mt = 0; mt < 2; mt++)
#pragma unroll
        for (int nt = 0; nt < 8; nt++)
#pragma unroll
            for (int j = 0; j < 4; j++) d[mt][nt][j] = 0.f;

    // ---- phase A: skip GEMM over 40 layer-chunks (K=32 each), single fp16 ----
    for (int kc = 0; kc < 40; kc++) {
        __syncthreads();
        {
            int row = tid >> 4, q4 = (tid & 15) * 4;
            size_t g = (size_t)(kc * 16 + row) * FINAL + p0 + q4;
            *(uint4*)&Bs[row * 72 + q4] = *(const uint4*)&ybf[g];
        }
        __syncthreads();
#pragma unroll
        for (int ck = 0; ck < 2; ck++) {
            int k2b = ck * 8;
            unsigned a0[4], a1[4];
            {
                int ro = kc * 256 + w * 32 + grp;
                const unsigned* pw = &g_swf[ro * 16 + k2b + t4];
                a0[0] = pw[0]; a0[1] = pw[8 * 16]; a0[2] = pw[4]; a0[3] = pw[8 * 16 + 4];
                const unsigned* pw2 = &g_swf[(ro + 16) * 16 + k2b + t4];
                a1[0] = pw2[0]; a1[1] = pw2[8 * 16]; a1[2] = pw2[4]; a1[3] = pw2[8 * 16 + 4];
            }
#pragma unroll
            for (int nt = 0; nt < 8; nt++) {
                unsigned b[2];
                b[0] = Bs[(k2b + t4) * 72 + nt * 8 + grp];
                b[1] = Bs[(k2b + t4 + 4) * 72 + nt * 8 + grp];
                mma16(d[0][nt], a0, b);
                mma16(d[1][nt], a1, b);
            }
        }
    }

    // ---- relu + split into Hh/Hl (fp16 halves, k-paired rows) ----
    __syncthreads();
    unsigned short* Hh16 = (unsigned short*)Hh;
    unsigned short* Hl16 = (unsigned short*)Hl;
#pragma unroll
    for (int mt = 0; mt < 2; mt++)
#pragma unroll
        for (int nt = 0; nt < 8; nt++) {
            int r = w * 32 + mt * 16 + grp;
            int col = nt * 8 + 2 * t4;
            unsigned short h, lo;
            float v;
            v = d[mt][nt][0]; v = v > 0.f ? v : 0.f; split1(v, h, lo);
            Hh16[((r >> 1) * 72 + col) * 2 + (r & 1)] = h;
            Hl16[((r >> 1) * 72 + col) * 2 + (r & 1)] = lo;
            v = d[mt][nt][1]; v = v > 0.f ? v : 0.f; split1(v, h, lo);
            Hh16[((r >> 1) * 72 + col + 1) * 2 + (r & 1)] = h;
            Hl16[((r >> 1) * 72 + col + 1) * 2 + (r & 1)] = lo;
            int r2 = r + 8;
            v = d[mt][nt][2]; v = v > 0.f ? v : 0.f; split1(v, h, lo);
            Hh16[((r2 >> 1) * 72 + col) * 2 + (r2 & 1)] = h;
            Hl16[((r2 >> 1) * 72 + col) * 2 + (r2 & 1)] = lo;
            v = d[mt][nt][3]; v = v > 0.f ? v : 0.f; split1(v, h, lo);
            Hh16[((r2 >> 1) * 72 + col + 1) * 2 + (r2 & 1)] = h;
            Hl16[((r2 >> 1) * 72 + col + 1) * 2 + (r2 & 1)] = lo;
        }
    __syncthreads();

    // ---- phase B: e1 GEMM (256x64, K=256 = 16 k16 chunks), fp16x3 ----
#pragma unroll
    for (int mt = 0; mt < 2; mt++)
#pragma unroll
        for (int nt = 0; nt < 8; nt++)
#pragma unroll
            for (int j = 0; j < 4; j++) d[mt][nt][j] = 0.f;

    for (int kk = 0; kk < 16; kk++) {
        unsigned ah[2][4], al[2][4];
#pragma unroll
        for (int mt = 0; mt < 2; mt++) {
            int ro = w * 32 + mt * 16 + grp;
            const unsigned* ph = &g_e1fh[ro * 128 + kk * 8 + t4];
            const unsigned* pl = &g_e1fl[ro * 128 + kk * 8 + t4];
            ah[mt][0] = ph[0]; ah[mt][1] = ph[8 * 128]; ah[mt][2] = ph[4]; ah[mt][3] = ph[8 * 128 + 4];
            al[mt][0] = pl[0]; al[mt][1] = pl[8 * 128]; al[mt][2] = pl[4]; al[mt][3] = pl[8 * 128 + 4];
        }
#pragma unroll
        for (int nt = 0; nt < 8; nt++) {
            unsigned bh[2], bl[2];
            bh[0] = Hh[(kk * 8 + t4) * 72 + nt * 8 + grp];
            bh[1] = Hh[(kk * 8 + t4 + 4) * 72 + nt * 8 + grp];
            bl[0] = Hl[(kk * 8 + t4) * 72 + nt * 8 + grp];
            bl[1] = Hl[(kk * 8 + t4 + 4) * 72 + nt * 8 + grp];
#pragma unroll
            for (int mt = 0; mt < 2; mt++) {
                mma16(d[mt][nt], ah[mt], bh);
                mma16(d[mt][nt], ah[mt], bl);
                mma16(d[mt][nt], al[mt], bh);
            }
        }
    }

    // ---- epilogue: bias + relu + e2 dot + reduce ----
    int r0 = w * 32 + grp;
    float eb0 = e1b[r0],      eb1 = e1b[r0 + 8];
    float eb2 = e1b[r0 + 16], eb3 = e1b[r0 + 24];
    float ew0 = e2w[r0],      ew1 = e2w[r0 + 8];
    float ew2 = e2w[r0 + 16], ew3 = e2w[r0 + 24];

    float pc[16];
#pragma unroll
    for (int nt = 0; nt < 8; nt++) {
#pragma unroll
        for (int j = 0; j < 2; j++) {
            float h0 = d[0][nt][j]     + eb0; h0 = h0 > 0.f ? h0 : 0.f;
            float h1 = d[0][nt][2 + j] + eb1; h1 = h1 > 0.f ? h1 : 0.f;
            float h2 = d[1][nt][j]     + eb2; h2 = h2 > 0.f ? h2 : 0.f;
            float h3 = d[1][nt][2 + j] + eb3; h3 = h3 > 0.f ? h3 : 0.f;
            pc[nt * 2 + j] = ew0 * h0 + ew1 * h1 + ew2 * h2 + ew3 * h3;
        }
    }
#pragma unroll
    for (int off = 16; off >= 4; off >>= 1)
#pragma unroll
        for (int t = 0; t < 16; t++)
            pc[t] += __shfl_xor_sync(0xffffffff, pc[t], off);

    if (lane < 4) {
#pragma unroll
        for (int nt = 0; nt < 8; nt++) {
            part[w * 64 + nt * 8 + 2 * lane]     = pc[nt * 2];
            part[w * 64 + nt * 8 + 2 * lane + 1] = pc[nt * 2 + 1];
        }
    }
    __syncthreads();
    if (tid < 64) {
        float s = e2b[0];
#pragma unroll
        for (int ww = 0; ww < 8; ww++) s += part[ww * 64 + tid];
        int p = p0 + tid;
        out[(p & 15) * TOUT + (p >> 4)] = s;
    }
}

// ---------------------------------------------------------------------------
extern "C" void kernel_launch(void* const* d_in, const int* in_sizes, int n_in,
                              void* d_out, int out_size)
{
    const float* input    = (const float*)d_in[0];
    const float* start_w  = (const float*)d_in[1];
    const float* filter_w = (const float*)d_in[2];
    const float* gate_w   = (const float*)d_in[3];
    const float* res_w    = (const float*)d_in[4];
    const float* skip_w   = (const float*)d_in[5];
    const float* e1w      = (const float*)d_in[6];
    const float* e1b      = (const float*)d_in[7];
    const float* e2w      = (const float*)d_in[8];
    const float* e2b      = (const float*)d_in[9];
    float* out = (float*)d_out;
    (void)in_sizes; (void)n_in; (void)out_size;

    static int attr_done = 0;
    if (!attr_done) {
        cudaFuncSetAttribute(k_layer, cudaFuncAttributeMaxDynamicSharedMemorySize, 57344);
        cudaFuncSetAttribute(k_tail,  cudaFuncAttributeMaxDynamicSharedMemorySize, 78336);
        attr_done = 1;
    }

    unsigned *xah, *xal, *xbh, *xbl, *ybf;
    cudaGetSymbolAddress((void**)&xah, g_xah);
    cudaGetSymbolAddress((void**)&xal, g_xal);
    cudaGetSymbolAddress((void**)&xbh, g_xbh);
    cudaGetSymbolAddress((void**)&xbl, g_xbl);
    cudaGetSymbolAddress((void**)&ybf, g_ybf);

    k_prep<<<48, 256>>>(filter_w, gate_w, res_w, skip_w, e1w);
    k_start<<<1024, 256>>>(input, start_w, xah, xal);

    unsigned *curh = xah, *curl = xal, *nxth = xbh, *nxtl = xbl;
    for (int i = 0; i < 40; i++) {
        int b = i / 10, k = i % 10;
        int Mb = 262144 - 8192 * b;
        int Min, Mout, P, S;
        if (k == 0) { Min = Mb; Mout = Mb - 16; P = 0; S = 16; }
        else {
            int d = 1 << k;
            Min = Mb - 8 * d;
            Mout = Mb - 16 * d;
            P = 8 * d;
            S = 16 * d;
        }
        int ofs = Mout - FINAL;
        int grid = (Mout + 127) / 128;
        k_layer<<<grid, 256, 57344>>>(curh, curl, nxth, nxtl,
                                      ybf + (size_t)i * 16 * FINAL,
                                      i, Min, Mout, P, S, ofs);
        unsigned* t;
        t = curh; curh = nxth; nxth = t;
        t = curl; curl = nxtl; nxtl = t;
    }

    k_tail<<<FINAL / 64, 256, 78336>>>(ybf, e1b, e2w, e2b, out);
}

// round 9
// speedup vs baseline: 3.7926x; 1.0326x over previous
#include <cuda_runtime.h>
#include <cuda_fp16.h>
#include <math.h>

#define FINAL 229376        // 16 * 14336 final flat length
#define XLD   262144        // fixed channel stride for x buffers
#define TOUT  14336

// Scratch (device globals; no allocation anywhere)
__device__ unsigned g_xah[16 * XLD], g_xal[16 * XLD];   // x ping (fp16 hi/lo pairs)
__device__ unsigned g_xbh[16 * XLD], g_xbl[16 * XLD];   // x pong
__device__ unsigned g_ybf[640 * FINAL];     // y hi, packed fp16 pairs (k2 x pos)
__device__ unsigned g_w1h[40 * 2048], g_w1l[40 * 2048];   // [s=64][k2=32] per layer
__device__ unsigned g_wrh[40 * 512],  g_wrl[40 * 512];    // [row=32][k2=16] (rows permuted)
__device__ unsigned g_swf[163840];                        // skip_w single fp16 [40*256][k2=16]
__device__ unsigned g_e1fh[32768],    g_e1fl[32768];      // e1w fp16 pairs [256][k2=128]

// ---------------------------------------------------------------------------
// helpers (fp16 limbs)
// ---------------------------------------------------------------------------
__device__ __forceinline__ void mma16(float d[4], const unsigned a[4], const unsigned b[2]) {
    asm volatile(
        "mma.sync.aligned.m16n8k16.row.col.f32.f16.f16.f32 "
        "{%0,%1,%2,%3},{%4,%5,%6,%7},{%8,%9},{%0,%1,%2,%3};"
        : "+f"(d[0]), "+f"(d[1]), "+f"(d[2]), "+f"(d[3])
        : "r"(a[0]), "r"(a[1]), "r"(a[2]), "r"(a[3]), "r"(b[0]), "r"(b[1]));
}
__device__ __forceinline__ void ldsm_x4(unsigned a[4], unsigned saddr) {
    asm volatile("ldmatrix.sync.aligned.m8n8.x4.shared.b16 {%0,%1,%2,%3}, [%4];"
        : "=r"(a[0]), "=r"(a[1]), "=r"(a[2]), "=r"(a[3]) : "r"(saddr));
}
__device__ __forceinline__ unsigned smaddr(const void* p) {
    return (unsigned)__cvta_generic_to_shared(p);
}

// ---- fast activations via MUFU (ex2/rcp approx, ~2 ulp: far below fp16-split noise)
__device__ __forceinline__ float fast_ex2(float x) {
    float y; asm("ex2.approx.f32 %0, %1;" : "=f"(y) : "f"(x)); return y;
}
__device__ __forceinline__ float fast_rcp(float x) {
    float y; asm("rcp.approx.f32 %0, %1;" : "=f"(y) : "f"(x)); return y;
}
__device__ __forceinline__ float fast_sigmoid(float x) {
    return fast_rcp(1.f + fast_ex2(-1.4426950408889634f * x));
}
__device__ __forceinline__ float fast_tanh(float x) {
    return 2.f * fast_rcp(1.f + fast_ex2(-2.8853900817779268f * x)) - 1.f;
}

// pack two floats (even ch -> low half) into fp16x2 hi and lo components
__device__ __forceinline__ void split_pack(float a, float b, unsigned& h, unsigned& l) {
    __half ah = __float2half(a), bh = __float2half(b);
    float ar = a - __half2float(ah), br = b - __half2float(bh);
    __half2 th; th.x = ah; th.y = bh; h = *(unsigned*)&th;
    __half2 tl; tl.x = __float2half(ar); tl.y = __float2half(br);
    l = *(unsigned*)&tl;
}
__device__ __forceinline__ unsigned pack1(float a, float b) {
    __half2 t; t.x = __float2half(a); t.y = __float2half(b);
    return *(unsigned*)&t;
}
__device__ __forceinline__ void split1(float v, unsigned short& h, unsigned short& l) {
    __half vh = __float2half(v);
    float r = v - __half2float(vh);
    __half vl = __float2half(r);
    h = *(unsigned short*)&vh;
    l = *(unsigned short*)&vl;
}
__device__ __forceinline__ float fp_half(unsigned u, int hi) {
    __half2 t = *(__half2*)&u;
    return hi ? __half2float(t.y) : __half2float(t.x);
}

// ---------------------------------------------------------------------------
// prep: split weights into packed fp16 hi/lo pairs (permuted for fragments)
// ---------------------------------------------------------------------------
__global__ void k_prep(const float* __restrict__ fw, const float* __restrict__ gw,
                       const float* __restrict__ rw, const float* __restrict__ sw,
                       const float* __restrict__ e1w)
{
    int i = blockIdx.x, tid = threadIdx.x;
    if (i < 40) {
        for (int l = tid; l < 2048; l += 256) {
            int s = l >> 5, k2 = l & 31;
            int c = ((s >> 4) << 3) + (s & 7);
            int isg = (s >> 3) & 1;
            const float* src = (isg ? gw : fw) + i * 2048;
            int k0 = 2 * k2;
            float v0 = src[(c * 32 + (k0 & 31)) * 2 + (k0 >> 5)];
            float v1 = src[(c * 32 + ((k0 + 1) & 31)) * 2 + ((k0 + 1) >> 5)];
            unsigned h, lo;
            split_pack(v0, v1, h, lo);
            g_w1h[i * 2048 + l] = h;
            g_w1l[i * 2048 + l] = lo;
        }
        for (int l = tid; l < 512; l += 256) {
            int r = l >> 4, k2 = l & 15;
            // row permutation: row g <-> ch 2g, row g+8 <-> ch 2g+1 (per 16-row tile)
            int t = r >> 4, s = r & 15;
            int chan = t * 16 + (s & 7) * 2 + (s >> 3);
            float v0 = rw[i * 1024 + chan * 32 + 2 * k2];
            float v1 = rw[i * 1024 + chan * 32 + 2 * k2 + 1];
            unsigned h, lo;
            split_pack(v0, v1, h, lo);
            g_wrh[i * 512 + l] = h;
            g_wrl[i * 512 + l] = lo;
        }
    } else {
        int bi = i - 40;  // 0..7
        for (int l = bi * 256 + tid; l < 163840; l += 2048) {
            int og = l >> 4, k2 = l & 15;
            g_swf[l] = pack1(sw[og * 32 + 2 * k2], sw[og * 32 + 2 * k2 + 1]);
        }
        for (int l = bi * 256 + tid; l < 32768; l += 2048) {
            int o = l >> 7, k2 = l & 127;
            unsigned h, lo;
            split_pack(e1w[o * 256 + 2 * k2], e1w[o * 256 + 2 * k2 + 1], h, lo);
            g_e1fh[l] = h; g_e1fl[l] = lo;
        }
    }
}

// ---------------------------------------------------------------------------
// start conv: x0[c][t*16+b] = sum_f sw[c][f] * input[b][f][t]; emits split fp16
// ---------------------------------------------------------------------------
__global__ void k_start(const float* __restrict__ in, const float* __restrict__ sw,
                        unsigned* __restrict__ xh, unsigned* __restrict__ xl)
{
    __shared__ float s_w[4096];
    __shared__ float s_in[16 * 272];
    int tid = threadIdx.x;               // 256
    for (int l = tid; l < 4096; l += 256) s_w[l] = sw[l];
    int t0 = blockIdx.x * 16;
    int b = tid & 15, dt = tid >> 4;
    float acc[32];
#pragma unroll
    for (int c = 0; c < 32; c++) acc[c] = 0.f;
    int tt = tid & 15, rhalf = tid >> 4;
    for (int fc = 0; fc < 8; fc++) {
        __syncthreads();
#pragma unroll
        for (int pass = 0; pass < 16; pass++) {
            int row = pass * 16 + rhalf;
            int bb = row >> 4, ff = row & 15;
            s_in[ff * 272 + tt * 17 + bb] =
                in[(bb * 128 + fc * 16 + ff) * 16384 + t0 + tt];
        }
        __syncthreads();
#pragma unroll
        for (int f = 0; f < 16; f++) {
            float v = s_in[f * 272 + dt * 17 + b];
#pragma unroll
            for (int c = 0; c < 32; c++)
                acc[c] += s_w[c * 128 + fc * 16 + f] * v;
        }
    }
    int m = t0 * 16 + tid;
#pragma unroll
    for (int c2 = 0; c2 < 16; c2++) {
        unsigned H, L;
        split_pack(acc[2 * c2], acc[2 * c2 + 1], H, L);
        xh[c2 * XLD + m] = H;
        xl[c2 * XLD + m] = L;
    }
}

// ---------------------------------------------------------------------------
// fused dilated layer, fp16x3 split: tile 64 u-rows x 128 positions.
// smem (u32): Wh[64][36]@0, Wl@2304, Rh[32][20]@4608, Rl@5248,
//             Xh[32][132]@5888, Xl[32][132]@10112  -> 14336 u32 = 57344 B
// X rows = k2 pairs: 0..15 = xA channels, 16..31 = xB channels (128 pos + 4 pad).
// Y (packed fp16 pairs) overlays X rows 0..15 after GEMM1.
// ---------------------------------------------------------------------------
__global__ void __launch_bounds__(256, 3)
k_layer(const unsigned* __restrict__ xinh, const unsigned* __restrict__ xinl,
        unsigned* __restrict__ xouth, unsigned* __restrict__ xoutl,
        unsigned* __restrict__ ytf, int layer,
        int Min, int Mout, int P, int S, int ofs)
{
    extern __shared__ unsigned smu[];
    unsigned* Wh = smu;
    unsigned* Wl = smu + 2304;
    unsigned* Rh = smu + 4608;
    unsigned* Rl = smu + 5248;
    unsigned* Xh = smu + 5888;
    unsigned* Xl = smu + 10112;

    int tid = threadIdx.x;          // 256
    int m0 = blockIdx.x * 128;
    int lane = tid & 31, w = tid >> 5;
    int grp = lane >> 2, t4 = lane & 3;
    unsigned lr = ((lane >> 3) & 1) * 8 + (lane & 7);   // ldmatrix row select
    unsigned lc = (lane >> 4) * 4;                      // ldmatrix col select (u32)

    // ---- stage weights (straight u32 copies into padded layout) ----
    const unsigned* wsh = g_w1h + layer * 2048;
    const unsigned* wsl = g_w1l + layer * 2048;
    for (int l = tid; l < 512; l += 256) {
        int row = l >> 3, q = (l & 7) * 4;
        *(uint4*)&Wh[row * 36 + q] = *(const uint4*)&wsh[row * 32 + q];
        *(uint4*)&Wl[row * 36 + q] = *(const uint4*)&wsl[row * 32 + q];
    }
    const unsigned* rsh = g_wrh + layer * 512;
    const unsigned* rsl = g_wrl + layer * 512;
    for (int l = tid; l < 128; l += 256) {
        int row = l >> 2, q = (l & 3) * 4;
        *(uint4*)&Rh[row * 20 + q] = *(const uint4*)&rsh[row * 16 + q];
        *(uint4*)&Rl[row * 20 + q] = *(const uint4*)&rsl[row * 16 + q];
    }

    // ---- stage x: pure copies (already split fp16 hi/lo) ----
    for (int v = tid; v < 1024; v += 256) {
        int j2 = v >> 5, q4 = (v & 31) * 4;
        int tap = j2 >> 4, ch2 = j2 & 15;
        int off = tap ? (S - P) : -P;
        int idx = m0 + q4 + off;
        const unsigned* ph = xinh + (size_t)ch2 * XLD;
        const unsigned* pl = xinl + (size_t)ch2 * XLD;
        uint4 H, L;
        if (idx >= 0 && idx + 3 < Min) {
            H = *(const uint4*)(ph + idx);
            L = *(const uint4*)(pl + idx);
        } else {
            H.x = (idx     >= 0 && idx     < Min) ? ph[idx]     : 0u;
            H.y = (idx + 1 >= 0 && idx + 1 < Min) ? ph[idx + 1] : 0u;
            H.z = (idx + 2 >= 0 && idx + 2 < Min) ? ph[idx + 2] : 0u;
            H.w = (idx + 3 >= 0 && idx + 3 < Min) ? ph[idx + 3] : 0u;
            L.x = (idx     >= 0 && idx     < Min) ? pl[idx]     : 0u;
            L.y = (idx + 1 >= 0 && idx + 1 < Min) ? pl[idx + 1] : 0u;
            L.z = (idx + 2 >= 0 && idx + 2 < Min) ? pl[idx + 2] : 0u;
            L.w = (idx + 3 >= 0 && idx + 3 < Min) ? pl[idx + 3] : 0u;
        }
        *(uint4*)&Xh[j2 * 132 + q4] = H;
        *(uint4*)&Xl[j2 * 132 + q4] = L;
    }
    __syncthreads();

    // ---- GEMM1: 64x128, K=64 (4 k16 chunks); warps 2m x 4n; 3-mma split ----
    int wr1 = w >> 2, wc1 = w & 3;
    unsigned whb = smaddr(Wh) + ((wr1 * 32 + lr) * 36 + lc) * 4;
    unsigned wlb = smaddr(Wl) + ((wr1 * 32 + lr) * 36 + lc) * 4;
    float d[2][4][4];
#pragma unroll
    for (int a = 0; a < 2; a++)
#pragma unroll
        for (int b = 0; b < 4; b++)
#pragma unroll
            for (int c = 0; c < 4; c++) d[a][b][c] = 0.f;

#pragma unroll
    for (int kc = 0; kc < 4; kc++) {
        int k2b = kc * 8;
        unsigned ah[2][4], al[2][4];
#pragma unroll
        for (int mf = 0; mf < 2; mf++) {
            ldsm_x4(ah[mf], whb + (mf * 576 + k2b) * 4);
            ldsm_x4(al[mf], wlb + (mf * 576 + k2b) * 4);
        }
#pragma unroll
        for (int nt = 0; nt < 4; nt++) {
            int n = wc1 * 32 + nt * 8 + grp;
            unsigned bh[2], bl[2];
            bh[0] = Xh[(k2b + t4) * 132 + n];     bh[1] = Xh[(k2b + t4 + 4) * 132 + n];
            bl[0] = Xl[(k2b + t4) * 132 + n];     bl[1] = Xl[(k2b + t4 + 4) * 132 + n];
#pragma unroll
            for (int mf = 0; mf < 2; mf++) {
                mma16(d[mf][nt], ah[mf], bh);
                mma16(d[mf][nt], ah[mf], bl);
                mma16(d[mf][nt], al[mf], bh);
            }
        }
    }

    // ---- gated activation in registers (fast MUFU path) ----
    float yv[2][4][2];
#pragma unroll
    for (int mf = 0; mf < 2; mf++)
#pragma unroll
        for (int nt = 0; nt < 4; nt++) {
            yv[mf][nt][0] = fast_tanh(d[mf][nt][0]) * fast_sigmoid(d[mf][nt][2]);
            yv[mf][nt][1] = fast_tanh(d[mf][nt][1]) * fast_sigmoid(d[mf][nt][3]);
        }
    __syncthreads();    // all GEMM1 smem reads complete

    // ---- store y as packed fp16 halves into X rows 0..15 overlay ----
    unsigned short* Yh16 = (unsigned short*)Xh;
    unsigned short* Yl16 = (unsigned short*)Xl;
#pragma unroll
    for (int mf = 0; mf < 2; mf++) {
        int c = (wr1 * 2 + mf) * 8 + grp;
#pragma unroll
        for (int nt = 0; nt < 4; nt++) {
            int col = wc1 * 32 + nt * 8 + 2 * t4;
            int base = ((c >> 1) * 132 + col) * 2 + (c & 1);
            unsigned short h, lo;
            split1(yv[mf][nt][0], h, lo); Yh16[base] = h;     Yl16[base] = lo;
            split1(yv[mf][nt][1], h, lo); Yh16[base + 2] = h; Yl16[base + 2] = lo;
        }
    }
    __syncthreads();

    // ---- ytail copy (hi only, coalesced u32 rows) ----
    for (int v = tid; v < 512; v += 256) {
        int row = v >> 5, colq = (v & 31) * 4;
        int m = m0 + colq;
        if (m >= ofs && m < Mout)
            *(uint4*)&ytf[(size_t)row * FINAL + (m - ofs)] = *(uint4*)&Xh[row * 132 + colq];
    }

    // ---- GEMM2: 32x128, K=32 (2 k16 chunks); + fp32 residual; split store ----
    int wr2 = w >> 2, wc2 = w & 3;
    unsigned rhb = smaddr(Rh) + ((wr2 * 16 + lr) * 20 + lc) * 4;
    unsigned rlb = smaddr(Rl) + ((wr2 * 16 + lr) * 20 + lc) * 4;
    float e[4][4];
#pragma unroll
    for (int a = 0; a < 4; a++)
#pragma unroll
        for (int b = 0; b < 4; b++) e[a][b] = 0.f;

#pragma unroll
    for (int kc = 0; kc < 2; kc++) {
        int k2b = kc * 8;
        unsigned ah[4], al[4];
        ldsm_x4(ah, rhb + k2b * 4);
        ldsm_x4(al, rlb + k2b * 4);
#pragma unroll
        for (int nt = 0; nt < 4; nt++) {
            int n = wc2 * 32 + nt * 8 + grp;
            unsigned bh[2], bl[2];
            bh[0] = Xh[(k2b + t4) * 132 + n];     bh[1] = Xh[(k2b + t4 + 4) * 132 + n];
            bl[0] = Xl[(k2b + t4) * 132 + n];     bl[1] = Xl[(k2b + t4 + 4) * 132 + n];
            mma16(e[nt], ah, bh);
            mma16(e[nt], ah, bl);
            mma16(e[nt], al, bh);
        }
    }
    // rows permuted: lane holds channel pair (2*ch2, 2*ch2+1) in (d0/d1, d2/d3)
    {
        int ch2 = wr2 * 8 + grp;
        int rowB = 16 + ch2;
#pragma unroll
        for (int nt = 0; nt < 4; nt++) {
            int col = wc2 * 32 + nt * 8 + 2 * t4;
            int m = m0 + col;
            if (m < Mout) {
                unsigned rh0 = Xh[rowB * 132 + col],     rl0 = Xl[rowB * 132 + col];
                unsigned rh1 = Xh[rowB * 132 + col + 1], rl1 = Xl[rowB * 132 + col + 1];
                float v0e = e[nt][0] + fp_half(rh0, 0) + fp_half(rl0, 0);
                float v0o = e[nt][2] + fp_half(rh0, 1) + fp_half(rl0, 1);
                float v1e = e[nt][1] + fp_half(rh1, 0) + fp_half(rl1, 0);
                float v1o = e[nt][3] + fp_half(rh1, 1) + fp_half(rl1, 1);
                unsigned H, L;
                split_pack(v0e, v0o, H, L);
                xouth[(size_t)ch2 * XLD + m] = H;
                xoutl[(size_t)ch2 * XLD + m] = L;
                split_pack(v1e, v1o, H, L);
                xouth[(size_t)ch2 * XLD + m + 1] = H;
                xoutl[(size_t)ch2 * XLD + m + 1] = L;
            }
        }
    }
}

// ---------------------------------------------------------------------------
// fused tail: skip GEMM (single fp16) + relu + e1 (fp16x3) + bias + relu + e2
// per block: 64 positions, all 256 skip rows.
// smem (u32): Bs[16][72]@0 (1152), Hh[128][72]@1152, Hl@10368 -> 19584 u32
// ---------------------------------------------------------------------------
__global__ void __launch_bounds__(256, 2)
k_tail(const unsigned* __restrict__ ybf,
       const float* __restrict__ e1b, const float* __restrict__ e2w,
       const float* __restrict__ e2b, float* __restrict__ out)
{
    extern __shared__ unsigned smu[];
    unsigned* Bs = smu;
    unsigned* Hh = smu + 1152;
    unsigned* Hl = smu + 10368;
    float* part = (float*)smu;

    int tid = threadIdx.x;     // 256
    int lane = tid & 31, w = tid >> 5;
    int grp = lane >> 2, t4 = lane & 3;
    int p0 = blockIdx.x * 64;

    float d[2][8][4];
#pragma unroll
    for (int mt = 0; mt < 2; mt++)
#pragma unroll
        for (int nt = 0; nt < 8; nt++)
#pragma unroll
            for (int j = 0; j < 4; j++) d[mt][nt][j] = 0.f;

    // ---- phase A: skip GEMM over 40 layer-chunks (K=32 each), single fp16 ----
    for (int kc = 0; kc < 40; kc++) {
        __syncthreads();
        {
            int row = tid >> 4, q4 = (tid & 15) * 4;
            size_t g = (size_t)(kc * 16 + row) * FINAL + p0 + q4;
            *(uint4*)&Bs[row * 72 + q4] = *(const uint4*)&ybf[g];
        }
        __syncthreads();
#pragma unroll
        for (int ck = 0; ck < 2; ck++) {
            int k2b = ck * 8;
            unsigned a0[4], a1[4];
            {
                int ro = kc * 256 + w * 32 + grp;
                const unsigned* pw = &g_swf[ro * 16 + k2b + t4];
                a0[0] = pw[0]; a0[1] = pw[8 * 16]; a0[2] = pw[4]; a0[3] = pw[8 * 16 + 4];
                const unsigned* pw2 = &g_swf[(ro + 16) * 16 + k2b + t4];
                a1[0] = pw2[0]; a1[1] = pw2[8 * 16]; a1[2] = pw2[4]; a1[3] = pw2[8 * 16 + 4];
            }
#pragma unroll
            for (int nt = 0; nt < 8; nt++) {
                unsigned b[2];
                b[0] = Bs[(k2b + t4) * 72 + nt * 8 + grp];
                b[1] = Bs[(k2b + t4 + 4) * 72 + nt * 8 + grp];
                mma16(d[0][nt], a0, b);
                mma16(d[1][nt], a1, b);
            }
        }
    }

    // ---- relu + split into Hh/Hl (fp16 halves, k-paired rows) ----
    __syncthreads();
    unsigned short* Hh16 = (unsigned short*)Hh;
    unsigned short* Hl16 = (unsigned short*)Hl;
#pragma unroll
    for (int mt = 0; mt < 2; mt++)
#pragma unroll
        for (int nt = 0; nt < 8; nt++) {
            int r = w * 32 + mt * 16 + grp;
            int col = nt * 8 + 2 * t4;
            unsigned short h, lo;
            float v;
            v = d[mt][nt][0]; v = v > 0.f ? v : 0.f; split1(v, h, lo);
            Hh16[((r >> 1) * 72 + col) * 2 + (r & 1)] = h;
            Hl16[((r >> 1) * 72 + col) * 2 + (r & 1)] = lo;
            v = d[mt][nt][1]; v = v > 0.f ? v : 0.f; split1(v, h, lo);
            Hh16[((r >> 1) * 72 + col + 1) * 2 + (r & 1)] = h;
            Hl16[((r >> 1) * 72 + col + 1) * 2 + (r & 1)] = lo;
            int r2 = r + 8;
            v = d[mt][nt][2]; v = v > 0.f ? v : 0.f; split1(v, h, lo);
            Hh16[((r2 >> 1) * 72 + col) * 2 + (r2 & 1)] = h;
            Hl16[((r2 >> 1) * 72 + col) * 2 + (r2 & 1)] = lo;
            v = d[mt][nt][3]; v = v > 0.f ? v : 0.f; split1(v, h, lo);
            Hh16[((r2 >> 1) * 72 + col + 1) * 2 + (r2 & 1)] = h;
            Hl16[((r2 >> 1) * 72 + col + 1) * 2 + (r2 & 1)] = lo;
        }
    __syncthreads();

    // ---- phase B: e1 GEMM (256x64, K=256 = 16 k16 chunks), fp16x3 ----
#pragma unroll
    for (int mt = 0; mt < 2; mt++)
#pragma unroll
        for (int nt = 0; nt < 8; nt++)
#pragma unroll
            for (int j = 0; j < 4; j++) d[mt][nt][j] = 0.f;

    for (int kk = 0; kk < 16; kk++) {
        unsigned ah[2][4], al[2][4];
#pragma unroll
        for (int mt = 0; mt < 2; mt++) {
            int ro = w * 32 + mt * 16 + grp;
            const unsigned* ph = &g_e1fh[ro * 128 + kk * 8 + t4];
            const unsigned* pl = &g_e1fl[ro * 128 + kk * 8 + t4];
            ah[mt][0] = ph[0]; ah[mt][1] = ph[8 * 128]; ah[mt][2] = ph[4]; ah[mt][3] = ph[8 * 128 + 4];
            al[mt][0] = pl[0]; al[mt][1] = pl[8 * 128]; al[mt][2] = pl[4]; al[mt][3] = pl[8 * 128 + 4];
        }
#pragma unroll
        for (int nt = 0; nt < 8; nt++) {
            unsigned bh[2], bl[2];
            bh[0] = Hh[(kk * 8 + t4) * 72 + nt * 8 + grp];
            bh[1] = Hh[(kk * 8 + t4 + 4) * 72 + nt * 8 + grp];
            bl[0] = Hl[(kk * 8 + t4) * 72 + nt * 8 + grp];
            bl[1] = Hl[(kk * 8 + t4 + 4) * 72 + nt * 8 + grp];
#pragma unroll
            for (int mt = 0; mt < 2; mt++) {
                mma16(d[mt][nt], ah[mt], bh);
                mma16(d[mt][nt], ah[mt], bl);
                mma16(d[mt][nt], al[mt], bh);
            }
        }
    }

    // ---- epilogue: bias + relu + e2 dot + reduce ----
    int r0 = w * 32 + grp;
    float eb0 = e1b[r0],      eb1 = e1b[r0 + 8];
    float eb2 = e1b[r0 + 16], eb3 = e1b[r0 + 24];
    float ew0 = e2w[r0],      ew1 = e2w[r0 + 8];
    float ew2 = e2w[r0 + 16], ew3 = e2w[r0 + 24];

    float pc[16];
#pragma unroll
    for (int nt = 0; nt < 8; nt++) {
#pragma unroll
        for (int j = 0; j < 2; j++) {
            float h0 = d[0][nt][j]     + eb0; h0 = h0 > 0.f ? h0 : 0.f;
            float h1 = d[0][nt][2 + j] + eb1; h1 = h1 > 0.f ? h1 : 0.f;
            float h2 = d[1][nt][j]     + eb2; h2 = h2 > 0.f ? h2 : 0.f;
            float h3 = d[1][nt][2 + j] + eb3; h3 = h3 > 0.f ? h3 : 0.f;
            pc[nt * 2 + j] = ew0 * h0 + ew1 * h1 + ew2 * h2 + ew3 * h3;
        }
    }
#pragma unroll
    for (int off = 16; off >= 4; off >>= 1)
#pragma unroll
        for (int t = 0; t < 16; t++)
            pc[t] += __shfl_xor_sync(0xffffffff, pc[t], off);

    if (lane < 4) {
#pragma unroll
        for (int nt = 0; nt < 8; nt++) {
            part[w * 64 + nt * 8 + 2 * lane]     = pc[nt * 2];
            part[w * 64 + nt * 8 + 2 * lane + 1] = pc[nt * 2 + 1];
        }
    }
    __syncthreads();
    if (tid < 64) {
        float s = e2b[0];
#pragma unroll
        for (int ww = 0; ww < 8; ww++) s += part[ww * 64 + tid];
        int p = p0 + tid;
        out[(p & 15) * TOUT + (p >> 4)] = s;
    }
}

// ---------------------------------------------------------------------------
extern "C" void kernel_launch(void* const* d_in, const int* in_sizes, int n_in,
                              void* d_out, int out_size)
{
    const float* input    = (const float*)d_in[0];
    const float* start_w  = (const float*)d_in[1];
    const float* filter_w = (const float*)d_in[2];
    const float* gate_w   = (const float*)d_in[3];
    const float* res_w    = (const float*)d_in[4];
    const float* skip_w   = (const float*)d_in[5];
    const float* e1w      = (const float*)d_in[6];
    const float* e1b      = (const float*)d_in[7];
    const float* e2w      = (const float*)d_in[8];
    const float* e2b      = (const float*)d_in[9];
    float* out = (float*)d_out;
    (void)in_sizes; (void)n_in; (void)out_size;

    static int attr_done = 0;
    if (!attr_done) {
        cudaFuncSetAttribute(k_layer, cudaFuncAttributeMaxDynamicSharedMemorySize, 57344);
        cudaFuncSetAttribute(k_tail,  cudaFuncAttributeMaxDynamicSharedMemorySize, 78336);
        attr_done = 1;
    }

    unsigned *xah, *xal, *xbh, *xbl, *ybf;
    cudaGetSymbolAddress((void**)&xah, g_xah);
    cudaGetSymbolAddress((void**)&xal, g_xal);
    cudaGetSymbolAddress((void**)&xbh, g_xbh);
    cudaGetSymbolAddress((void**)&xbl, g_xbl);
    cudaGetSymbolAddress((void**)&ybf, g_ybf);

    k_prep<<<48, 256>>>(filter_w, gate_w, res_w, skip_w, e1w);
    k_start<<<1024, 256>>>(input, start_w, xah, xal);

    unsigned *curh = xah, *curl = xal, *nxth = xbh, *nxtl = xbl;
    for (int i = 0; i < 40; i++) {
        int b = i / 10, k = i % 10;
        int Mb = 262144 - 8192 * b;
        int Min, Mout, P, S;
        if (k == 0) { Min = Mb; Mout = Mb - 16; P = 0; S = 16; }
        else {
            int d = 1 << k;
            Min = Mb - 8 * d;
            Mout = Mb - 16 * d;
            P = 8 * d;
            S = 16 * d;
        }
        int ofs = Mout - FINAL;
        int grid = (Mout + 127) / 128;
        k_layer<<<grid, 256, 57344>>>(curh, curl, nxth, nxtl,
                                      ybf + (size_t)i * 16 * FINAL,
                                      i, Min, Mout, P, S, ofs);
        unsigned* t;
        t = curh; curh = nxth; nxth = t;
        t = curl; curl = nxtl; nxtl = t;
    }

    k_tail<<<FINAL / 64, 256, 78336>>>(ybf, e1b, e2w, e2b, out);
}

// round 10
// speedup vs baseline: 4.0579x; 1.0700x over previous
#include <cuda_runtime.h>
#include <cuda_fp16.h>
#include <math.h>

#define FINAL 229376        // 16 * 14336 final flat length
#define XLD   262144        // fixed channel stride for x buffers
#define TOUT  14336

// Scratch (device globals; no allocation anywhere)
__device__ unsigned g_xah[16 * XLD], g_xal[16 * XLD];   // x ping (fp16 hi/lo pairs)
__device__ unsigned g_xbh[16 * XLD], g_xbl[16 * XLD];   // x pong
__device__ unsigned g_ybf[640 * FINAL];     // y hi: per layer [FINAL pos][16 k2]
__device__ unsigned g_w1h[40 * 2048], g_w1l[40 * 2048];   // [s=64][k2=32] per layer
__device__ unsigned g_wrh[40 * 512],  g_wrl[40 * 512];    // [row=32][k2=16] (rows permuted)
__device__ unsigned g_swf[163840];                        // skip_w single fp16 [40*256][k2=16]
__device__ unsigned g_e1fh[32768],    g_e1fl[32768];      // e1w fp16 pairs [256][k2=128]

// ---------------------------------------------------------------------------
// helpers (fp16 limbs)
// ---------------------------------------------------------------------------
__device__ __forceinline__ void mma16(float d[4], const unsigned a[4], const unsigned b[2]) {
    asm volatile(
        "mma.sync.aligned.m16n8k16.row.col.f32.f16.f16.f32 "
        "{%0,%1,%2,%3},{%4,%5,%6,%7},{%8,%9},{%0,%1,%2,%3};"
        : "+f"(d[0]), "+f"(d[1]), "+f"(d[2]), "+f"(d[3])
        : "r"(a[0]), "r"(a[1]), "r"(a[2]), "r"(a[3]), "r"(b[0]), "r"(b[1]));
}
__device__ __forceinline__ void ldsm_x4(unsigned a[4], unsigned saddr) {
    asm volatile("ldmatrix.sync.aligned.m8n8.x4.shared.b16 {%0,%1,%2,%3}, [%4];"
        : "=r"(a[0]), "=r"(a[1]), "=r"(a[2]), "=r"(a[3]) : "r"(saddr));
}
__device__ __forceinline__ unsigned smaddr(const void* p) {
    return (unsigned)__cvta_generic_to_shared(p);
}

// ---- fast activations via MUFU (ex2/rcp approx)
__device__ __forceinline__ float fast_ex2(float x) {
    float y; asm("ex2.approx.f32 %0, %1;" : "=f"(y) : "f"(x)); return y;
}
__device__ __forceinline__ float fast_rcp(float x) {
    float y; asm("rcp.approx.f32 %0, %1;" : "=f"(y) : "f"(x)); return y;
}
__device__ __forceinline__ float fast_sigmoid(float x) {
    return fast_rcp(1.f + fast_ex2(-1.4426950408889634f * x));
}
__device__ __forceinline__ float fast_tanh(float x) {
    return 2.f * fast_rcp(1.f + fast_ex2(-2.8853900817779268f * x)) - 1.f;
}

// pack two floats (even ch -> low half) into fp16x2 hi and lo components
__device__ __forceinline__ void split_pack(float a, float b, unsigned& h, unsigned& l) {
    __half ah = __float2half(a), bh = __float2half(b);
    float ar = a - __half2float(ah), br = b - __half2float(bh);
    __half2 th; th.x = ah; th.y = bh; h = *(unsigned*)&th;
    __half2 tl; tl.x = __float2half(ar); tl.y = __float2half(br);
    l = *(unsigned*)&tl;
}
__device__ __forceinline__ unsigned pack1(float a, float b) {
    __half2 t; t.x = __float2half(a); t.y = __float2half(b);
    return *(unsigned*)&t;
}
__device__ __forceinline__ void split1(float v, unsigned short& h, unsigned short& l) {
    __half vh = __float2half(v);
    float r = v - __half2float(vh);
    __half vl = __float2half(r);
    h = *(unsigned short*)&vh;
    l = *(unsigned short*)&vl;
}
__device__ __forceinline__ float fp_half(unsigned u, int hi) {
    __half2 t = *(__half2*)&u;
    return hi ? __half2float(t.y) : __half2float(t.x);
}

// ---------------------------------------------------------------------------
// prep: split weights into packed fp16 hi/lo pairs (permuted for fragments)
// ---------------------------------------------------------------------------
__global__ void k_prep(const float* __restrict__ fw, const float* __restrict__ gw,
                       const float* __restrict__ rw, const float* __restrict__ sw,
                       const float* __restrict__ e1w)
{
    int i = blockIdx.x, tid = threadIdx.x;
    if (i < 40) {
        for (int l = tid; l < 2048; l += 256) {
            int s = l >> 5, k2 = l & 31;
            int c = ((s >> 4) << 3) + (s & 7);
            int isg = (s >> 3) & 1;
            const float* src = (isg ? gw : fw) + i * 2048;
            int k0 = 2 * k2;
            float v0 = src[(c * 32 + (k0 & 31)) * 2 + (k0 >> 5)];
            float v1 = src[(c * 32 + ((k0 + 1) & 31)) * 2 + ((k0 + 1) >> 5)];
            unsigned h, lo;
            split_pack(v0, v1, h, lo);
            g_w1h[i * 2048 + l] = h;
            g_w1l[i * 2048 + l] = lo;
        }
        for (int l = tid; l < 512; l += 256) {
            int r = l >> 4, k2 = l & 15;
            int t = r >> 4, s = r & 15;
            int chan = t * 16 + (s & 7) * 2 + (s >> 3);
            float v0 = rw[i * 1024 + chan * 32 + 2 * k2];
            float v1 = rw[i * 1024 + chan * 32 + 2 * k2 + 1];
            unsigned h, lo;
            split_pack(v0, v1, h, lo);
            g_wrh[i * 512 + l] = h;
            g_wrl[i * 512 + l] = lo;
        }
    } else {
        int bi = i - 40;  // 0..7
        for (int l = bi * 256 + tid; l < 163840; l += 2048) {
            int og = l >> 4, k2 = l & 15;
            g_swf[l] = pack1(sw[og * 32 + 2 * k2], sw[og * 32 + 2 * k2 + 1]);
        }
        for (int l = bi * 256 + tid; l < 32768; l += 2048) {
            int o = l >> 7, k2 = l & 127;
            unsigned h, lo;
            split_pack(e1w[o * 256 + 2 * k2], e1w[o * 256 + 2 * k2 + 1], h, lo);
            g_e1fh[l] = h; g_e1fl[l] = lo;
        }
    }
}

// ---------------------------------------------------------------------------
// start conv: x0[c][t*16+b] = sum_f sw[c][f] * input[b][f][t]; emits split fp16
// ---------------------------------------------------------------------------
__global__ void k_start(const float* __restrict__ in, const float* __restrict__ sw,
                        unsigned* __restrict__ xh, unsigned* __restrict__ xl)
{
    __shared__ float s_w[4096];
    __shared__ float s_in[16 * 272];
    int tid = threadIdx.x;               // 256
    for (int l = tid; l < 4096; l += 256) s_w[l] = sw[l];
    int t0 = blockIdx.x * 16;
    int b = tid & 15, dt = tid >> 4;
    float acc[32];
#pragma unroll
    for (int c = 0; c < 32; c++) acc[c] = 0.f;
    int tt = tid & 15, rhalf = tid >> 4;
    for (int fc = 0; fc < 8; fc++) {
        __syncthreads();
#pragma unroll
        for (int pass = 0; pass < 16; pass++) {
            int row = pass * 16 + rhalf;
            int bb = row >> 4, ff = row & 15;
            s_in[ff * 272 + tt * 17 + bb] =
                in[(bb * 128 + fc * 16 + ff) * 16384 + t0 + tt];
        }
        __syncthreads();
#pragma unroll
        for (int f = 0; f < 16; f++) {
            float v = s_in[f * 272 + dt * 17 + b];
#pragma unroll
            for (int c = 0; c < 32; c++)
                acc[c] += s_w[c * 128 + fc * 16 + f] * v;
        }
    }
    int m = t0 * 16 + tid;
#pragma unroll
    for (int c2 = 0; c2 < 16; c2++) {
        unsigned H, L;
        split_pack(acc[2 * c2], acc[2 * c2 + 1], H, L);
        xh[c2 * XLD + m] = H;
        xl[c2 * XLD + m] = L;
    }
}

// ---------------------------------------------------------------------------
// fused dilated layer, fp16x3 split: tile 64 u-rows x 128 positions.
// smem (u32): Wh[64][36]@0, Wl@2304, Rh[32][20]@4608, Rl@5248,
//             Xth[128][36]@5888, Xtl[128][36]@10496 -> 15104 u32 = 60416 B
// Xt rows = positions; cols 0..15 = xA k2-pairs (y overlay), 16..31 = xB.
// B operands (x taps, y) loaded via ldmatrix.x4 from the transposed tile.
// ---------------------------------------------------------------------------
__global__ void __launch_bounds__(256, 3)
k_layer(const unsigned* __restrict__ xinh, const unsigned* __restrict__ xinl,
        unsigned* __restrict__ xouth, unsigned* __restrict__ xoutl,
        unsigned* __restrict__ ytf, int layer,
        int Min, int Mout, int P, int S, int ofs)
{
    extern __shared__ unsigned smu[];
    unsigned* Wh  = smu;
    unsigned* Wl  = smu + 2304;
    unsigned* Rh  = smu + 4608;
    unsigned* Rl  = smu + 5248;
    unsigned* Xth = smu + 5888;
    unsigned* Xtl = smu + 10496;

    int tid = threadIdx.x;          // 256
    int m0 = blockIdx.x * 128;
    int lane = tid & 31, w = tid >> 5;
    int grp = lane >> 2, t4 = lane & 3;
    unsigned lr = ((lane >> 3) & 1) * 8 + (lane & 7);   // A-ldmatrix row select
    unsigned lc = (lane >> 4) * 4;                      // A-ldmatrix col select (u32)
    // B-ldmatrix lane offset: matrices (n0,k2b),(n0,k2b+4),(n0+8,k2b),(n0+8,k2b+4)
    int bm = lane >> 3, br = lane & 7;
    unsigned bloff = ((unsigned)((bm >> 1) * 8 + br)) * 36 + (unsigned)(bm & 1) * 4;

    // ---- stage weights (straight u32 copies into padded layout) ----
    const unsigned* wsh = g_w1h + layer * 2048;
    const unsigned* wsl = g_w1l + layer * 2048;
    for (int l = tid; l < 512; l += 256) {
        int row = l >> 3, q = (l & 7) * 4;
        *(uint4*)&Wh[row * 36 + q] = *(const uint4*)&wsh[row * 32 + q];
        *(uint4*)&Wl[row * 36 + q] = *(const uint4*)&wsl[row * 32 + q];
    }
    const unsigned* rsh = g_wrh + layer * 512;
    const unsigned* rsl = g_wrl + layer * 512;
    for (int l = tid; l < 128; l += 256) {
        int row = l >> 2, q = (l & 3) * 4;
        *(uint4*)&Rh[row * 20 + q] = *(const uint4*)&rsh[row * 16 + q];
        *(uint4*)&Rl[row * 20 + q] = *(const uint4*)&rsl[row * 16 + q];
    }

    // ---- stage x transposed: row = pos, col group g (4 ch-pairs) ----
    for (int v = tid; v < 1024; v += 256) {
        int g = v >> 7;           // 0..7 (0..3 = tap A, 4..7 = tap B)
        int p = v & 127;
        int tap = g >> 2;
        int ch2b = (g & 3) * 4;
        int off = tap ? (S - P) : -P;
        int idx = m0 + p + off;
        uint4 H, L;
        if (idx >= 0 && idx < Min) {
            const unsigned* ph = xinh + idx;
            const unsigned* pl = xinl + idx;
            H.x = ph[(size_t)(ch2b    ) * XLD]; L.x = pl[(size_t)(ch2b    ) * XLD];
            H.y = ph[(size_t)(ch2b + 1) * XLD]; L.y = pl[(size_t)(ch2b + 1) * XLD];
            H.z = ph[(size_t)(ch2b + 2) * XLD]; L.z = pl[(size_t)(ch2b + 2) * XLD];
            H.w = ph[(size_t)(ch2b + 3) * XLD]; L.w = pl[(size_t)(ch2b + 3) * XLD];
        } else {
            H.x = H.y = H.z = H.w = 0u;
            L.x = L.y = L.z = L.w = 0u;
        }
        *(uint4*)&Xth[p * 36 + g * 4] = H;
        *(uint4*)&Xtl[p * 36 + g * 4] = L;
    }
    __syncthreads();

    // ---- GEMM1: 64x128, K=64 (4 k16 chunks); warps 2m x 4n; 3-mma split ----
    int wr1 = w >> 2, wc1 = w & 3;
    unsigned whb = smaddr(Wh) + ((wr1 * 32 + lr) * 36 + lc) * 4;
    unsigned wlb = smaddr(Wl) + ((wr1 * 32 + lr) * 36 + lc) * 4;
    unsigned xhb = smaddr(Xth), xlb = smaddr(Xtl);
    float d[2][4][4];
#pragma unroll
    for (int a = 0; a < 2; a++)
#pragma unroll
        for (int b = 0; b < 4; b++)
#pragma unroll
            for (int c = 0; c < 4; c++) d[a][b][c] = 0.f;

#pragma unroll
    for (int kc = 0; kc < 4; kc++) {
        int k2b = kc * 8;
        unsigned ah[2][4], al[2][4];
#pragma unroll
        for (int mf = 0; mf < 2; mf++) {
            ldsm_x4(ah[mf], whb + (mf * 576 + k2b) * 4);
            ldsm_x4(al[mf], wlb + (mf * 576 + k2b) * 4);
        }
#pragma unroll
        for (int ntp = 0; ntp < 2; ntp++) {
            unsigned bo = (((unsigned)(wc1 * 32 + ntp * 16)) * 36 + k2b + bloff) * 4;
            unsigned qh[4], ql[4];
            ldsm_x4(qh, xhb + bo);
            ldsm_x4(ql, xlb + bo);
            unsigned bh0[2] = {qh[0], qh[1]}, bl0[2] = {ql[0], ql[1]};
            unsigned bh1[2] = {qh[2], qh[3]}, bl1[2] = {ql[2], ql[3]};
#pragma unroll
            for (int mf = 0; mf < 2; mf++) {
                mma16(d[mf][2 * ntp], ah[mf], bh0);
                mma16(d[mf][2 * ntp], ah[mf], bl0);
                mma16(d[mf][2 * ntp], al[mf], bh0);
                mma16(d[mf][2 * ntp + 1], ah[mf], bh1);
                mma16(d[mf][2 * ntp + 1], ah[mf], bl1);
                mma16(d[mf][2 * ntp + 1], al[mf], bh1);
            }
        }
    }

    // ---- gated activation in registers (fast MUFU path) ----
    float yv[2][4][2];
#pragma unroll
    for (int mf = 0; mf < 2; mf++)
#pragma unroll
        for (int nt = 0; nt < 4; nt++) {
            yv[mf][nt][0] = fast_tanh(d[mf][nt][0]) * fast_sigmoid(d[mf][nt][2]);
            yv[mf][nt][1] = fast_tanh(d[mf][nt][1]) * fast_sigmoid(d[mf][nt][3]);
        }
    __syncthreads();    // all GEMM1 smem reads complete

    // ---- store y as fp16 halves into Xt cols 0..15 (row = pos) ----
    unsigned short* Yh16 = (unsigned short*)Xth;
    unsigned short* Yl16 = (unsigned short*)Xtl;
#pragma unroll
    for (int mf = 0; mf < 2; mf++) {
        int c = (wr1 * 2 + mf) * 8 + grp;
        int c2 = c >> 1, sel = c & 1;
#pragma unroll
        for (int nt = 0; nt < 4; nt++) {
            int col = wc1 * 32 + nt * 8 + 2 * t4;
            int base = col * 72 + c2 * 2 + sel;
            unsigned short h, lo;
            split1(yv[mf][nt][0], h, lo); Yh16[base] = h;       Yl16[base] = lo;
            split1(yv[mf][nt][1], h, lo); Yh16[base + 72] = h;  Yl16[base + 72] = lo;
        }
    }
    __syncthreads();

    // ---- ytail copy (hi only): global [pos][16 k2], coalesced uint4 ----
    for (int v = tid; v < 512; v += 256) {
        int p = v >> 2, qg = v & 3;
        int m = m0 + p;
        if (m >= ofs && m < Mout)
            *(uint4*)&ytf[(size_t)(m - ofs) * 16 + qg * 4] = *(uint4*)&Xth[p * 36 + qg * 4];
    }

    // ---- GEMM2: 32x128, K=32 (2 k16 chunks); + fp32 residual; split store ----
    int wr2 = w >> 2, wc2 = w & 3;
    unsigned rhb = smaddr(Rh) + ((wr2 * 16 + lr) * 20 + lc) * 4;
    unsigned rlb = smaddr(Rl) + ((wr2 * 16 + lr) * 20 + lc) * 4;
    float e[4][4];
#pragma unroll
    for (int a = 0; a < 4; a++)
#pragma unroll
        for (int b = 0; b < 4; b++) e[a][b] = 0.f;

#pragma unroll
    for (int kc = 0; kc < 2; kc++) {
        int k2b = kc * 8;
        unsigned ah[4], al[4];
        ldsm_x4(ah, rhb + k2b * 4);
        ldsm_x4(al, rlb + k2b * 4);
#pragma unroll
        for (int ntp = 0; ntp < 2; ntp++) {
            unsigned bo = (((unsigned)(wc2 * 32 + ntp * 16)) * 36 + k2b + bloff) * 4;
            unsigned qh[4], ql[4];
            ldsm_x4(qh, xhb + bo);
            ldsm_x4(ql, xlb + bo);
            unsigned bh0[2] = {qh[0], qh[1]}, bl0[2] = {ql[0], ql[1]};
            unsigned bh1[2] = {qh[2], qh[3]}, bl1[2] = {ql[2], ql[3]};
            mma16(e[2 * ntp], ah, bh0);
            mma16(e[2 * ntp], ah, bl0);
            mma16(e[2 * ntp], al, bh0);
            mma16(e[2 * ntp + 1], ah, bh1);
            mma16(e[2 * ntp + 1], ah, bl1);
            mma16(e[2 * ntp + 1], al, bh1);
        }
    }
    // rows permuted: lane holds channel pair (2*ch2, 2*ch2+1) in (d0/d1, d2/d3)
    {
        int ch2 = wr2 * 8 + grp;
        int colB = 16 + ch2;
#pragma unroll
        for (int nt = 0; nt < 4; nt++) {
            int col = wc2 * 32 + nt * 8 + 2 * t4;
            int m = m0 + col;
            if (m < Mout) {
                unsigned rh0 = Xth[col * 36 + colB],       rl0 = Xtl[col * 36 + colB];
                unsigned rh1 = Xth[(col + 1) * 36 + colB], rl1 = Xtl[(col + 1) * 36 + colB];
                float v0e = e[nt][0] + fp_half(rh0, 0) + fp_half(rl0, 0);
                float v0o = e[nt][2] + fp_half(rh0, 1) + fp_half(rl0, 1);
                float v1e = e[nt][1] + fp_half(rh1, 0) + fp_half(rl1, 0);
                float v1o = e[nt][3] + fp_half(rh1, 1) + fp_half(rl1, 1);
                unsigned H, L;
                split_pack(v0e, v0o, H, L);
                xouth[(size_t)ch2 * XLD + m] = H;
                xoutl[(size_t)ch2 * XLD + m] = L;
                split_pack(v1e, v1o, H, L);
                xouth[(size_t)ch2 * XLD + m + 1] = H;
                xoutl[(size_t)ch2 * XLD + m + 1] = L;
            }
        }
    }
}

// ---------------------------------------------------------------------------
// fused tail: skip GEMM (single fp16) + relu + e1 (fp16x3) + bias + relu + e2
// per block: 64 positions, all 256 skip rows.
// smem (u32): Bst[64][20]@0 (1280), Hh[128][72]@1280, Hl@10496 -> 19712 u32
// ---------------------------------------------------------------------------
__global__ void __launch_bounds__(256, 2)
k_tail(const unsigned* __restrict__ ybf,
       const float* __restrict__ e1b, const float* __restrict__ e2w,
       const float* __restrict__ e2b, float* __restrict__ out)
{
    extern __shared__ unsigned smu[];
    unsigned* Bst = smu;           // [64 pos][20] (16 k2 + pad)
    unsigned* Hh = smu + 1280;
    unsigned* Hl = smu + 10496;
    float* part = (float*)smu;

    int tid = threadIdx.x;     // 256
    int lane = tid & 31, w = tid >> 5;
    int grp = lane >> 2, t4 = lane & 3;
    int p0 = blockIdx.x * 64;

    float d[2][8][4];
#pragma unroll
    for (int mt = 0; mt < 2; mt++)
#pragma unroll
        for (int nt = 0; nt < 8; nt++)
#pragma unroll
            for (int j = 0; j < 4; j++) d[mt][nt][j] = 0.f;

    // ---- phase A: skip GEMM over 40 layer-chunks (K=32 each), single fp16 ----
    int sp = tid >> 2, sq = (tid & 3) * 4;   // staging: pos, k2 group
    for (int kc = 0; kc < 40; kc++) {
        __syncthreads();
        {
            size_t g = (size_t)kc * 16 * FINAL + (size_t)(p0 + sp) * 16 + sq;
            *(uint4*)&Bst[sp * 20 + sq] = *(const uint4*)&ybf[g];
        }
        __syncthreads();
#pragma unroll
        for (int ck = 0; ck < 2; ck++) {
            int k2b = ck * 8;
            unsigned a0[4], a1[4];
            {
                int ro = kc * 256 + w * 32 + grp;
                const unsigned* pw = &g_swf[ro * 16 + k2b + t4];
                a0[0] = pw[0]; a0[1] = pw[8 * 16]; a0[2] = pw[4]; a0[3] = pw[8 * 16 + 4];
                const unsigned* pw2 = &g_swf[(ro + 16) * 16 + k2b + t4];
                a1[0] = pw2[0]; a1[1] = pw2[8 * 16]; a1[2] = pw2[4]; a1[3] = pw2[8 * 16 + 4];
            }
#pragma unroll
            for (int nt = 0; nt < 8; nt++) {
                unsigned b[2];
                int n = nt * 8 + grp;
                b[0] = Bst[n * 20 + k2b + t4];
                b[1] = Bst[n * 20 + k2b + t4 + 4];
                mma16(d[0][nt], a0, b);
                mma16(d[1][nt], a1, b);
            }
        }
    }

    // ---- relu + split into Hh/Hl (fp16 halves, k-paired rows) ----
    __syncthreads();
    unsigned short* Hh16 = (unsigned short*)Hh;
    unsigned short* Hl16 = (unsigned short*)Hl;
#pragma unroll
    for (int mt = 0; mt < 2; mt++)
#pragma unroll
        for (int nt = 0; nt < 8; nt++) {
            int r = w * 32 + mt * 16 + grp;
            int col = nt * 8 + 2 * t4;
            unsigned short h, lo;
            float v;
            v = d[mt][nt][0]; v = v > 0.f ? v : 0.f; split1(v, h, lo);
            Hh16[((r >> 1) * 72 + col) * 2 + (r & 1)] = h;
            Hl16[((r >> 1) * 72 + col) * 2 + (r & 1)] = lo;
            v = d[mt][nt][1]; v = v > 0.f ? v : 0.f; split1(v, h, lo);
            Hh16[((r >> 1) * 72 + col + 1) * 2 + (r & 1)] = h;
            Hl16[((r >> 1) * 72 + col + 1) * 2 + (r & 1)] = lo;
            int r2 = r + 8;
            v = d[mt][nt][2]; v = v > 0.f ? v : 0.f; split1(v, h, lo);
            Hh16[((r2 >> 1) * 72 + col) * 2 + (r2 & 1)] = h;
            Hl16[((r2 >> 1) * 72 + col) * 2 + (r2 & 1)] = lo;
            v = d[mt][nt][3]; v = v > 0.f ? v : 0.f; split1(v, h, lo);
            Hh16[((r2 >> 1) * 72 + col + 1) * 2 + (r2 & 1)] = h;
            Hl16[((r2 >> 1) * 72 + col + 1) * 2 + (r2 & 1)] = lo;
        }
    __syncthreads();

    // ---- phase B: e1 GEMM (256x64, K=256 = 16 k16 chunks), fp16x3 ----
#pragma unroll
    for (int mt = 0; mt < 2; mt++)
#pragma unroll
        for (int nt = 0; nt < 8; nt++)
#pragma unroll
            for (int j = 0; j < 4; j++) d[mt][nt][j] = 0.f;

    for (int kk = 0; kk < 16; kk++) {
        unsigned ah[2][4], al[2][4];
#pragma unroll
        for (int mt = 0; mt < 2; mt++) {
            int ro = w * 32 + mt * 16 + grp;
            const unsigned* ph = &g_e1fh[ro * 128 + kk * 8 + t4];
            const unsigned* pl = &g_e1fl[ro * 128 + kk * 8 + t4];
            ah[mt][0] = ph[0]; ah[mt][1] = ph[8 * 128]; ah[mt][2] = ph[4]; ah[mt][3] = ph[8 * 128 + 4];
            al[mt][0] = pl[0]; al[mt][1] = pl[8 * 128]; al[mt][2] = pl[4]; al[mt][3] = pl[8 * 128 + 4];
        }
#pragma unroll
        for (int nt = 0; nt < 8; nt++) {
            unsigned bh[2], bl[2];
            bh[0] = Hh[(kk * 8 + t4) * 72 + nt * 8 + grp];
            bh[1] = Hh[(kk * 8 + t4 + 4) * 72 + nt * 8 + grp];
            bl[0] = Hl[(kk * 8 + t4) * 72 + nt * 8 + grp];
            bl[1] = Hl[(kk * 8 + t4 + 4) * 72 + nt * 8 + grp];
#pragma unroll
            for (int mt = 0; mt < 2; mt++) {
                mma16(d[mt][nt], ah[mt], bh);
                mma16(d[mt][nt], ah[mt], bl);
                mma16(d[mt][nt], al[mt], bh);
            }
        }
    }

    // ---- epilogue: bias + relu + e2 dot + reduce ----
    int r0 = w * 32 + grp;
    float eb0 = e1b[r0],      eb1 = e1b[r0 + 8];
    float eb2 = e1b[r0 + 16], eb3 = e1b[r0 + 24];
    float ew0 = e2w[r0],      ew1 = e2w[r0 + 8];
    float ew2 = e2w[r0 + 16], ew3 = e2w[r0 + 24];

    float pc[16];
#pragma unroll
    for (int nt = 0; nt < 8; nt++) {
#pragma unroll
        for (int j = 0; j < 2; j++) {
            float h0 = d[0][nt][j]     + eb0; h0 = h0 > 0.f ? h0 : 0.f;
            float h1 = d[0][nt][2 + j] + eb1; h1 = h1 > 0.f ? h1 : 0.f;
            float h2 = d[1][nt][j]     + eb2; h2 = h2 > 0.f ? h2 : 0.f;
            float h3 = d[1][nt][2 + j] + eb3; h3 = h3 > 0.f ? h3 : 0.f;
            pc[nt * 2 + j] = ew0 * h0 + ew1 * h1 + ew2 * h2 + ew3 * h3;
        }
    }
#pragma unroll
    for (int off = 16; off >= 4; off >>= 1)
#pragma unroll
        for (int t = 0; t < 16; t++)
            pc[t] += __shfl_xor_sync(0xffffffff, pc[t], off);

    if (lane < 4) {
#pragma unroll
        for (int nt = 0; nt < 8; nt++) {
            part[w * 64 + nt * 8 + 2 * lane]     = pc[nt * 2];
            part[w * 64 + nt * 8 + 2 * lane + 1] = pc[nt * 2 + 1];
        }
    }
    __syncthreads();
    if (tid < 64) {
        float s = e2b[0];
#pragma unroll
        for (int ww = 0; ww < 8; ww++) s += part[ww * 64 + tid];
        int p = p0 + tid;
        out[(p & 15) * TOUT + (p >> 4)] = s;
    }
}

// ---------------------------------------------------------------------------
extern "C" void kernel_launch(void* const* d_in, const int* in_sizes, int n_in,
                              void* d_out, int out_size)
{
    const float* input    = (const float*)d_in[0];
    const float* start_w  = (const float*)d_in[1];
    const float* filter_w = (const float*)d_in[2];
    const float* gate_w   = (const float*)d_in[3];
    const float* res_w    = (const float*)d_in[4];
    const float* skip_w   = (const float*)d_in[5];
    const float* e1w      = (const float*)d_in[6];
    const float* e1b      = (const float*)d_in[7];
    const float* e2w      = (const float*)d_in[8];
    const float* e2b      = (const float*)d_in[9];
    float* out = (float*)d_out;
    (void)in_sizes; (void)n_in; (void)out_size;

    static int attr_done = 0;
    if (!attr_done) {
        cudaFuncSetAttribute(k_layer, cudaFuncAttributeMaxDynamicSharedMemorySize, 60416);
        cudaFuncSetAttribute(k_tail,  cudaFuncAttributeMaxDynamicSharedMemorySize, 78848);
        attr_done = 1;
    }

    unsigned *xah, *xal, *xbh, *xbl, *ybf;
    cudaGetSymbolAddress((void**)&xah, g_xah);
    cudaGetSymbolAddress((void**)&xal, g_xal);
    cudaGetSymbolAddress((void**)&xbh, g_xbh);
    cudaGetSymbolAddress((void**)&xbl, g_xbl);
    cudaGetSymbolAddress((void**)&ybf, g_ybf);

    k_prep<<<48, 256>>>(filter_w, gate_w, res_w, skip_w, e1w);
    k_start<<<1024, 256>>>(input, start_w, xah, xal);

    unsigned *curh = xah, *curl = xal, *nxth = xbh, *nxtl = xbl;
    for (int i = 0; i < 40; i++) {
        int b = i / 10, k = i % 10;
        int Mb = 262144 - 8192 * b;
        int Min, Mout, P, S;
        if (k == 0) { Min = Mb; Mout = Mb - 16; P = 0; S = 16; }
        else {
            int d = 1 << k;
            Min = Mb - 8 * d;
            Mout = Mb - 16 * d;
            P = 8 * d;
            S = 16 * d;
        }
        int ofs = Mout - FINAL;
        int grid = (Mout + 127) / 128;
        k_layer<<<grid, 256, 60416>>>(curh, curl, nxth, nxtl,
                                      ybf + (size_t)i * 16 * FINAL,
                                      i, Min, Mout, P, S, ofs);
        unsigned* t;
        t = curh; curh = nxth; nxth = t;
        t = curl; curl = nxtl; nxtl = t;
    }

    k_tail<<<FINAL / 64, 256, 78848>>>(ybf, e1b, e2w, e2b, out);
}

// round 11
// speedup vs baseline: 4.3236x; 1.0655x over previous
#include <cuda_runtime.h>
#include <cuda_fp16.h>
#include <math.h>

#define FINAL 229376        // 16 * 14336 final flat length
#define XLD   262144        // fixed channel stride for x buffers
#define TOUT  14336

// Scratch (device globals; no allocation anywhere)
__device__ unsigned g_xah[16 * XLD], g_xal[16 * XLD];   // x ping (fp16 hi/lo pairs)
__device__ unsigned g_xbh[16 * XLD], g_xbl[16 * XLD];   // x pong
__device__ unsigned g_ybf[640 * FINAL];     // y hi: per layer [FINAL pos][16 k2]
__device__ unsigned g_w1h[40 * 2048], g_w1l[40 * 2048];   // [s=64][k2=32] per layer
__device__ unsigned g_wrh[40 * 512],  g_wrl[40 * 512];    // [row=32][k2=16] (rows permuted)
__device__ unsigned g_swf[163840];                        // skip_w single fp16 [40*256][k2=16]
__device__ unsigned g_e1fh[32768],    g_e1fl[32768];      // e1w fp16 pairs [256][k2=128]

// ---------------------------------------------------------------------------
// helpers (fp16 limbs)
// ---------------------------------------------------------------------------
__device__ __forceinline__ void mma16(float d[4], const unsigned a[4], const unsigned b[2]) {
    asm volatile(
        "mma.sync.aligned.m16n8k16.row.col.f32.f16.f16.f32 "
        "{%0,%1,%2,%3},{%4,%5,%6,%7},{%8,%9},{%0,%1,%2,%3};"
        : "+f"(d[0]), "+f"(d[1]), "+f"(d[2]), "+f"(d[3])
        : "r"(a[0]), "r"(a[1]), "r"(a[2]), "r"(a[3]), "r"(b[0]), "r"(b[1]));
}
__device__ __forceinline__ void ldsm_x4(unsigned a[4], unsigned saddr) {
    asm volatile("ldmatrix.sync.aligned.m8n8.x4.shared.b16 {%0,%1,%2,%3}, [%4];"
        : "=r"(a[0]), "=r"(a[1]), "=r"(a[2]), "=r"(a[3]) : "r"(saddr));
}
__device__ __forceinline__ unsigned smaddr(const void* p) {
    return (unsigned)__cvta_generic_to_shared(p);
}
__device__ __forceinline__ void cp16(unsigned dst, const unsigned* src) {
    asm volatile("cp.async.ca.shared.global [%0], [%1], 16;" :: "r"(dst), "l"(src));
}
#define CP_COMMIT() asm volatile("cp.async.commit_group;")
#define CP_WAIT0()  asm volatile("cp.async.wait_group 0;")

// ---- fast activations via MUFU (ex2/rcp approx)
__device__ __forceinline__ float fast_ex2(float x) {
    float y; asm("ex2.approx.f32 %0, %1;" : "=f"(y) : "f"(x)); return y;
}
__device__ __forceinline__ float fast_rcp(float x) {
    float y; asm("rcp.approx.f32 %0, %1;" : "=f"(y) : "f"(x)); return y;
}
__device__ __forceinline__ float fast_sigmoid(float x) {
    return fast_rcp(1.f + fast_ex2(-1.4426950408889634f * x));
}
__device__ __forceinline__ float fast_tanh(float x) {
    return 2.f * fast_rcp(1.f + fast_ex2(-2.8853900817779268f * x)) - 1.f;
}

// pack two floats (even ch -> low half) into fp16x2 hi and lo components
__device__ __forceinline__ void split_pack(float a, float b, unsigned& h, unsigned& l) {
    __half ah = __float2half(a), bh = __float2half(b);
    float ar = a - __half2float(ah), br = b - __half2float(bh);
    __half2 th; th.x = ah; th.y = bh; h = *(unsigned*)&th;
    __half2 tl; tl.x = __float2half(ar); tl.y = __float2half(br);
    l = *(unsigned*)&tl;
}
__device__ __forceinline__ unsigned pack1(float a, float b) {
    __half2 t; t.x = __float2half(a); t.y = __float2half(b);
    return *(unsigned*)&t;
}
__device__ __forceinline__ void split1(float v, unsigned short& h, unsigned short& l) {
    __half vh = __float2half(v);
    float r = v - __half2float(vh);
    __half vl = __float2half(r);
    h = *(unsigned short*)&vh;
    l = *(unsigned short*)&vl;
}
__device__ __forceinline__ float fp_half(unsigned u, int hi) {
    __half2 t = *(__half2*)&u;
    return hi ? __half2float(t.y) : __half2float(t.x);
}

// ---------------------------------------------------------------------------
// prep: split weights into packed fp16 hi/lo pairs (permuted for fragments)
// ---------------------------------------------------------------------------
__global__ void k_prep(const float* __restrict__ fw, const float* __restrict__ gw,
                       const float* __restrict__ rw, const float* __restrict__ sw,
                       const float* __restrict__ e1w)
{
    int i = blockIdx.x, tid = threadIdx.x;
    if (i < 40) {
        for (int l = tid; l < 2048; l += 256) {
            int s = l >> 5, k2 = l & 31;
            int c = ((s >> 4) << 3) + (s & 7);
            int isg = (s >> 3) & 1;
            const float* src = (isg ? gw : fw) + i * 2048;
            int k0 = 2 * k2;
            float v0 = src[(c * 32 + (k0 & 31)) * 2 + (k0 >> 5)];
            float v1 = src[(c * 32 + ((k0 + 1) & 31)) * 2 + ((k0 + 1) >> 5)];
            unsigned h, lo;
            split_pack(v0, v1, h, lo);
            g_w1h[i * 2048 + l] = h;
            g_w1l[i * 2048 + l] = lo;
        }
        for (int l = tid; l < 512; l += 256) {
            int r = l >> 4, k2 = l & 15;
            int t = r >> 4, s = r & 15;
            int chan = t * 16 + (s & 7) * 2 + (s >> 3);
            float v0 = rw[i * 1024 + chan * 32 + 2 * k2];
            float v1 = rw[i * 1024 + chan * 32 + 2 * k2 + 1];
            unsigned h, lo;
            split_pack(v0, v1, h, lo);
            g_wrh[i * 512 + l] = h;
            g_wrl[i * 512 + l] = lo;
        }
    } else {
        int bi = i - 40;  // 0..7
        for (int l = bi * 256 + tid; l < 163840; l += 2048) {
            int og = l >> 4, k2 = l & 15;
            g_swf[l] = pack1(sw[og * 32 + 2 * k2], sw[og * 32 + 2 * k2 + 1]);
        }
        for (int l = bi * 256 + tid; l < 32768; l += 2048) {
            int o = l >> 7, k2 = l & 127;
            unsigned h, lo;
            split_pack(e1w[o * 256 + 2 * k2], e1w[o * 256 + 2 * k2 + 1], h, lo);
            g_e1fh[l] = h; g_e1fl[l] = lo;
        }
    }
}

// ---------------------------------------------------------------------------
// start conv: x0[c][t*16+b] = sum_f sw[c][f] * input[b][f][t]; emits split fp16
// ---------------------------------------------------------------------------
__global__ void k_start(const float* __restrict__ in, const float* __restrict__ sw,
                        unsigned* __restrict__ xh, unsigned* __restrict__ xl)
{
    __shared__ float s_w[4096];
    __shared__ float s_in[16 * 272];
    int tid = threadIdx.x;               // 256
    for (int l = tid; l < 4096; l += 256) s_w[l] = sw[l];
    int t0 = blockIdx.x * 16;
    int b = tid & 15, dt = tid >> 4;
    float acc[32];
#pragma unroll
    for (int c = 0; c < 32; c++) acc[c] = 0.f;
    int tt = tid & 15, rhalf = tid >> 4;
    for (int fc = 0; fc < 8; fc++) {
        __syncthreads();
#pragma unroll
        for (int pass = 0; pass < 16; pass++) {
            int row = pass * 16 + rhalf;
            int bb = row >> 4, ff = row & 15;
            s_in[ff * 272 + tt * 17 + bb] =
                in[(bb * 128 + fc * 16 + ff) * 16384 + t0 + tt];
        }
        __syncthreads();
#pragma unroll
        for (int f = 0; f < 16; f++) {
            float v = s_in[f * 272 + dt * 17 + b];
#pragma unroll
            for (int c = 0; c < 32; c++)
                acc[c] += s_w[c * 128 + fc * 16 + f] * v;
        }
    }
    int m = t0 * 16 + tid;
#pragma unroll
    for (int c2 = 0; c2 < 16; c2++) {
        unsigned H, L;
        split_pack(acc[2 * c2], acc[2 * c2 + 1], H, L);
        xh[c2 * XLD + m] = H;
        xl[c2 * XLD + m] = L;
    }
}

// ---------------------------------------------------------------------------
// fused dilated layer (UNCHANGED from R10)
// ---------------------------------------------------------------------------
__global__ void __launch_bounds__(256, 3)
k_layer(const unsigned* __restrict__ xinh, const unsigned* __restrict__ xinl,
        unsigned* __restrict__ xouth, unsigned* __restrict__ xoutl,
        unsigned* __restrict__ ytf, int layer,
        int Min, int Mout, int P, int S, int ofs)
{
    extern __shared__ unsigned smu[];
    unsigned* Wh  = smu;
    unsigned* Wl  = smu + 2304;
    unsigned* Rh  = smu + 4608;
    unsigned* Rl  = smu + 5248;
    unsigned* Xth = smu + 5888;
    unsigned* Xtl = smu + 10496;

    int tid = threadIdx.x;          // 256
    int m0 = blockIdx.x * 128;
    int lane = tid & 31, w = tid >> 5;
    int grp = lane >> 2, t4 = lane & 3;
    unsigned lr = ((lane >> 3) & 1) * 8 + (lane & 7);
    unsigned lc = (lane >> 4) * 4;
    int bm = lane >> 3, br = lane & 7;
    unsigned bloff = ((unsigned)((bm >> 1) * 8 + br)) * 36 + (unsigned)(bm & 1) * 4;

    const unsigned* wsh = g_w1h + layer * 2048;
    const unsigned* wsl = g_w1l + layer * 2048;
    for (int l = tid; l < 512; l += 256) {
        int row = l >> 3, q = (l & 7) * 4;
        *(uint4*)&Wh[row * 36 + q] = *(const uint4*)&wsh[row * 32 + q];
        *(uint4*)&Wl[row * 36 + q] = *(const uint4*)&wsl[row * 32 + q];
    }
    const unsigned* rsh = g_wrh + layer * 512;
    const unsigned* rsl = g_wrl + layer * 512;
    for (int l = tid; l < 128; l += 256) {
        int row = l >> 2, q = (l & 3) * 4;
        *(uint4*)&Rh[row * 20 + q] = *(const uint4*)&rsh[row * 16 + q];
        *(uint4*)&Rl[row * 20 + q] = *(const uint4*)&rsl[row * 16 + q];
    }

    for (int v = tid; v < 1024; v += 256) {
        int g = v >> 7;
        int p = v & 127;
        int tap = g >> 2;
        int ch2b = (g & 3) * 4;
        int off = tap ? (S - P) : -P;
        int idx = m0 + p + off;
        uint4 H, L;
        if (idx >= 0 && idx < Min) {
            const unsigned* ph = xinh + idx;
            const unsigned* pl = xinl + idx;
            H.x = ph[(size_t)(ch2b    ) * XLD]; L.x = pl[(size_t)(ch2b    ) * XLD];
            H.y = ph[(size_t)(ch2b + 1) * XLD]; L.y = pl[(size_t)(ch2b + 1) * XLD];
            H.z = ph[(size_t)(ch2b + 2) * XLD]; L.z = pl[(size_t)(ch2b + 2) * XLD];
            H.w = ph[(size_t)(ch2b + 3) * XLD]; L.w = pl[(size_t)(ch2b + 3) * XLD];
        } else {
            H.x = H.y = H.z = H.w = 0u;
            L.x = L.y = L.z = L.w = 0u;
        }
        *(uint4*)&Xth[p * 36 + g * 4] = H;
        *(uint4*)&Xtl[p * 36 + g * 4] = L;
    }
    __syncthreads();

    int wr1 = w >> 2, wc1 = w & 3;
    unsigned whb = smaddr(Wh) + ((wr1 * 32 + lr) * 36 + lc) * 4;
    unsigned wlb = smaddr(Wl) + ((wr1 * 32 + lr) * 36 + lc) * 4;
    unsigned xhb = smaddr(Xth), xlb = smaddr(Xtl);
    float d[2][4][4];
#pragma unroll
    for (int a = 0; a < 2; a++)
#pragma unroll
        for (int b = 0; b < 4; b++)
#pragma unroll
            for (int c = 0; c < 4; c++) d[a][b][c] = 0.f;

#pragma unroll
    for (int kc = 0; kc < 4; kc++) {
        int k2b = kc * 8;
        unsigned ah[2][4], al[2][4];
#pragma unroll
        for (int mf = 0; mf < 2; mf++) {
            ldsm_x4(ah[mf], whb + (mf * 576 + k2b) * 4);
            ldsm_x4(al[mf], wlb + (mf * 576 + k2b) * 4);
        }
#pragma unroll
        for (int ntp = 0; ntp < 2; ntp++) {
            unsigned bo = (((unsigned)(wc1 * 32 + ntp * 16)) * 36 + k2b + bloff) * 4;
            unsigned qh[4], ql[4];
            ldsm_x4(qh, xhb + bo);
            ldsm_x4(ql, xlb + bo);
            unsigned bh0[2] = {qh[0], qh[1]}, bl0[2] = {ql[0], ql[1]};
            unsigned bh1[2] = {qh[2], qh[3]}, bl1[2] = {ql[2], ql[3]};
#pragma unroll
            for (int mf = 0; mf < 2; mf++) {
                mma16(d[mf][2 * ntp], ah[mf], bh0);
                mma16(d[mf][2 * ntp], ah[mf], bl0);
                mma16(d[mf][2 * ntp], al[mf], bh0);
                mma16(d[mf][2 * ntp + 1], ah[mf], bh1);
                mma16(d[mf][2 * ntp + 1], ah[mf], bl1);
                mma16(d[mf][2 * ntp + 1], al[mf], bh1);
            }
        }
    }

    float yv[2][4][2];
#pragma unroll
    for (int mf = 0; mf < 2; mf++)
#pragma unroll
        for (int nt = 0; nt < 4; nt++) {
            yv[mf][nt][0] = fast_tanh(d[mf][nt][0]) * fast_sigmoid(d[mf][nt][2]);
            yv[mf][nt][1] = fast_tanh(d[mf][nt][1]) * fast_sigmoid(d[mf][nt][3]);
        }
    __syncthreads();

    unsigned short* Yh16 = (unsigned short*)Xth;
    unsigned short* Yl16 = (unsigned short*)Xtl;
#pragma unroll
    for (int mf = 0; mf < 2; mf++) {
        int c = (wr1 * 2 + mf) * 8 + grp;
        int c2 = c >> 1, sel = c & 1;
#pragma unroll
        for (int nt = 0; nt < 4; nt++) {
            int col = wc1 * 32 + nt * 8 + 2 * t4;
            int base = col * 72 + c2 * 2 + sel;
            unsigned short h, lo;
            split1(yv[mf][nt][0], h, lo); Yh16[base] = h;       Yl16[base] = lo;
            split1(yv[mf][nt][1], h, lo); Yh16[base + 72] = h;  Yl16[base + 72] = lo;
        }
    }
    __syncthreads();

    for (int v = tid; v < 512; v += 256) {
        int p = v >> 2, qg = v & 3;
        int m = m0 + p;
        if (m >= ofs && m < Mout)
            *(uint4*)&ytf[(size_t)(m - ofs) * 16 + qg * 4] = *(uint4*)&Xth[p * 36 + qg * 4];
    }

    int wr2 = w >> 2, wc2 = w & 3;
    unsigned rhb = smaddr(Rh) + ((wr2 * 16 + lr) * 20 + lc) * 4;
    unsigned rlb = smaddr(Rl) + ((wr2 * 16 + lr) * 20 + lc) * 4;
    float e[4][4];
#pragma unroll
    for (int a = 0; a < 4; a++)
#pragma unroll
        for (int b = 0; b < 4; b++) e[a][b] = 0.f;

#pragma unroll
    for (int kc = 0; kc < 2; kc++) {
        int k2b = kc * 8;
        unsigned ah[4], al[4];
        ldsm_x4(ah, rhb + k2b * 4);
        ldsm_x4(al, rlb + k2b * 4);
#pragma unroll
        for (int ntp = 0; ntp < 2; ntp++) {
            unsigned bo = (((unsigned)(wc2 * 32 + ntp * 16)) * 36 + k2b + bloff) * 4;
            unsigned qh[4], ql[4];
            ldsm_x4(qh, xhb + bo);
            ldsm_x4(ql, xlb + bo);
            unsigned bh0[2] = {qh[0], qh[1]}, bl0[2] = {ql[0], ql[1]};
            unsigned bh1[2] = {qh[2], qh[3]}, bl1[2] = {ql[2], ql[3]};
            mma16(e[2 * ntp], ah, bh0);
            mma16(e[2 * ntp], ah, bl0);
            mma16(e[2 * ntp], al, bh0);
            mma16(e[2 * ntp + 1], ah, bh1);
            mma16(e[2 * ntp + 1], ah, bl1);
            mma16(e[2 * ntp + 1], al, bh1);
        }
    }
    {
        int ch2 = wr2 * 8 + grp;
        int colB = 16 + ch2;
#pragma unroll
        for (int nt = 0; nt < 4; nt++) {
            int col = wc2 * 32 + nt * 8 + 2 * t4;
            int m = m0 + col;
            if (m < Mout) {
                unsigned rh0 = Xth[col * 36 + colB],       rl0 = Xtl[col * 36 + colB];
                unsigned rh1 = Xth[(col + 1) * 36 + colB], rl1 = Xtl[(col + 1) * 36 + colB];
                float v0e = e[nt][0] + fp_half(rh0, 0) + fp_half(rl0, 0);
                float v0o = e[nt][2] + fp_half(rh0, 1) + fp_half(rl0, 1);
                float v1e = e[nt][1] + fp_half(rh1, 0) + fp_half(rl1, 0);
                float v1o = e[nt][3] + fp_half(rh1, 1) + fp_half(rl1, 1);
                unsigned H, L;
                split_pack(v0e, v0o, H, L);
                xouth[(size_t)ch2 * XLD + m] = H;
                xoutl[(size_t)ch2 * XLD + m] = L;
                split_pack(v1e, v1o, H, L);
                xouth[(size_t)ch2 * XLD + m + 1] = H;
                xoutl[(size_t)ch2 * XLD + m + 1] = L;
            }
        }
    }
}

// ---------------------------------------------------------------------------
// fused tail v2: 128 positions/block, 512 threads (warps 8m x 2n).
// All weights staged through smem via double-buffered cp.async.
// smem (u32): [2] x (Bst[128][20] + Ws[256][20]) = 15360
//             Hh[128][136] @15360, Hl @32768   -> 50176 u32 = 200704 B
// Phase B reuses the first region for double-buffered Eh[256][12]+El per kk.
// ---------------------------------------------------------------------------
__global__ void __launch_bounds__(512, 1)
k_tail(const unsigned* __restrict__ ybf,
       const float* __restrict__ e1b, const float* __restrict__ e2w,
       const float* __restrict__ e2b, float* __restrict__ out)
{
    extern __shared__ unsigned smu[];
    unsigned* Hh = smu + 15360;
    unsigned* Hl = smu + 32768;
    float* part = (float*)smu;       // 1024 floats, overlays buf0 (dead regions)

    int tid = threadIdx.x;     // 512
    int lane = tid & 31, w = tid >> 5;   // 16 warps
    int wm = w >> 1, wn = w & 1;
    int grp = lane >> 2, t4 = lane & 3;
    int p0 = blockIdx.x * 128;
    unsigned smb = smaddr(smu);

    float d[2][8][4];
#pragma unroll
    for (int mt = 0; mt < 2; mt++)
#pragma unroll
        for (int nt = 0; nt < 8; nt++)
#pragma unroll
            for (int j = 0; j < 4; j++) d[mt][nt][j] = 0.f;

    // staging indices
    int sp = tid >> 2, sq = (tid & 3) * 4;           // ybf: pos, k2 group

    // ---- phase A: skip GEMM, double-buffered (Bst + Ws) cp.async ----
    {   // prefetch kc = 0
        cp16(smb + (0 * 7680 + sp * 20 + sq) * 4,
             &ybf[(size_t)(p0 + sp) * 16 + sq]);
        for (int l = tid; l < 1024; l += 512) {
            int row = l >> 2, qg = (l & 3) * 4;
            cp16(smb + (0 * 7680 + 2560 + row * 20 + qg) * 4,
                 &g_swf[row * 16 + qg]);
        }
        CP_COMMIT();
    }
    for (int kc = 0; kc < 40; kc++) {
        CP_WAIT0();
        __syncthreads();
        if (kc < 39) {
            int nb = (kc + 1) & 1;
            cp16(smb + (nb * 7680 + sp * 20 + sq) * 4,
                 &ybf[(size_t)(kc + 1) * 16 * FINAL + (size_t)(p0 + sp) * 16 + sq]);
            for (int l = tid; l < 1024; l += 512) {
                int row = l >> 2, qg = (l & 3) * 4;
                cp16(smb + (nb * 7680 + 2560 + row * 20 + qg) * 4,
                     &g_swf[((kc + 1) * 256 + row) * 16 + qg]);
            }
            CP_COMMIT();
        }
        const unsigned* Bc = smu + (kc & 1) * 7680;
        const unsigned* Wc = Bc + 2560;
#pragma unroll
        for (int ck = 0; ck < 2; ck++) {
            int k2b = ck * 8;
            unsigned a0[4], a1[4];
            {
                const unsigned* pw = &Wc[(wm * 32 + grp) * 20 + k2b + t4];
                a0[0] = pw[0]; a0[1] = pw[8 * 20]; a0[2] = pw[4]; a0[3] = pw[8 * 20 + 4];
                const unsigned* pw2 = pw + 16 * 20;
                a1[0] = pw2[0]; a1[1] = pw2[8 * 20]; a1[2] = pw2[4]; a1[3] = pw2[8 * 20 + 4];
            }
#pragma unroll
            for (int nt = 0; nt < 8; nt++) {
                unsigned b[2];
                int n = wn * 64 + nt * 8 + grp;
                b[0] = Bc[n * 20 + k2b + t4];
                b[1] = Bc[n * 20 + k2b + t4 + 4];
                mma16(d[0][nt], a0, b);
                mma16(d[1][nt], a1, b);
            }
        }
    }

    // ---- relu + split into Hh/Hl (fp16 halves, k-paired rows, stride 136) ----
    __syncthreads();
    unsigned short* Hh16 = (unsigned short*)Hh;
    unsigned short* Hl16 = (unsigned short*)Hl;
#pragma unroll
    for (int mt = 0; mt < 2; mt++)
#pragma unroll
        for (int nt = 0; nt < 8; nt++) {
            int r = wm * 32 + mt * 16 + grp;
            int col = wn * 64 + nt * 8 + 2 * t4;
            unsigned short h, lo;
            float v;
            v = d[mt][nt][0]; v = v > 0.f ? v : 0.f; split1(v, h, lo);
            Hh16[((r >> 1) * 136 + col) * 2 + (r & 1)] = h;
            Hl16[((r >> 1) * 136 + col) * 2 + (r & 1)] = lo;
            v = d[mt][nt][1]; v = v > 0.f ? v : 0.f; split1(v, h, lo);
            Hh16[((r >> 1) * 136 + col + 1) * 2 + (r & 1)] = h;
            Hl16[((r >> 1) * 136 + col + 1) * 2 + (r & 1)] = lo;
            int r2 = r + 8;
            v = d[mt][nt][2]; v = v > 0.f ? v : 0.f; split1(v, h, lo);
            Hh16[((r2 >> 1) * 136 + col) * 2 + (r2 & 1)] = h;
            Hl16[((r2 >> 1) * 136 + col) * 2 + (r2 & 1)] = lo;
            v = d[mt][nt][3]; v = v > 0.f ? v : 0.f; split1(v, h, lo);
            Hh16[((r2 >> 1) * 136 + col + 1) * 2 + (r2 & 1)] = h;
            Hl16[((r2 >> 1) * 136 + col + 1) * 2 + (r2 & 1)] = lo;
        }

    // ---- phase B: e1 GEMM (256x128, K=256), double-buffered E staging ----
#pragma unroll
    for (int mt = 0; mt < 2; mt++)
#pragma unroll
        for (int nt = 0; nt < 8; nt++)
#pragma unroll
            for (int j = 0; j < 4; j++) d[mt][nt][j] = 0.f;

    // E buffer kb: Eh at kb*6144, El at kb*6144+3072; layout [256][12] (8 valid)
    {   // prefetch kk = 0   (safe: issued after the sync below? -> need H sync first)
        __syncthreads();     // H writes complete; buf0 region free
        int row = tid >> 1, qg = (tid & 1) * 4;
        cp16(smb + (0 * 6144 + row * 12 + qg) * 4,        &g_e1fh[row * 128 + qg]);
        cp16(smb + (0 * 6144 + 3072 + row * 12 + qg) * 4, &g_e1fl[row * 128 + qg]);
        CP_COMMIT();
    }
    for (int kk = 0; kk < 16; kk++) {
        CP_WAIT0();
        __syncthreads();
        if (kk < 15) {
            int nb = (kk + 1) & 1;
            int row = tid >> 1, qg = (tid & 1) * 4;
            cp16(smb + (nb * 6144 + row * 12 + qg) * 4,
                 &g_e1fh[row * 128 + (kk + 1) * 8 + qg]);
            cp16(smb + (nb * 6144 + 3072 + row * 12 + qg) * 4,
                 &g_e1fl[row * 128 + (kk + 1) * 8 + qg]);
            CP_COMMIT();
        }
        const unsigned* Eh = smu + (kk & 1) * 6144;
        const unsigned* El = Eh + 3072;
        unsigned ah[2][4], al[2][4];
#pragma unroll
        for (int mt = 0; mt < 2; mt++) {
            const unsigned* ph = &Eh[(wm * 32 + mt * 16 + grp) * 12 + t4];
            const unsigned* pl = &El[(wm * 32 + mt * 16 + grp) * 12 + t4];
            ah[mt][0] = ph[0]; ah[mt][1] = ph[8 * 12]; ah[mt][2] = ph[4]; ah[mt][3] = ph[8 * 12 + 4];
            al[mt][0] = pl[0]; al[mt][1] = pl[8 * 12]; al[mt][2] = pl[4]; al[mt][3] = pl[8 * 12 + 4];
        }
#pragma unroll
        for (int nt = 0; nt < 8; nt++) {
            int col = wn * 64 + nt * 8 + grp;
            unsigned bh[2], bl[2];
            bh[0] = Hh[(kk * 8 + t4) * 136 + col];
            bh[1] = Hh[(kk * 8 + t4 + 4) * 136 + col];
            bl[0] = Hl[(kk * 8 + t4) * 136 + col];
            bl[1] = Hl[(kk * 8 + t4 + 4) * 136 + col];
#pragma unroll
            for (int mt = 0; mt < 2; mt++) {
                mma16(d[mt][nt], ah[mt], bh);
                mma16(d[mt][nt], ah[mt], bl);
                mma16(d[mt][nt], al[mt], bh);
            }
        }
    }

    // ---- epilogue: bias + relu + e2 dot + reduce ----
    int r0 = wm * 32 + grp;
    float eb0 = e1b[r0],      eb1 = e1b[r0 + 8];
    float eb2 = e1b[r0 + 16], eb3 = e1b[r0 + 24];
    float ew0 = e2w[r0],      ew1 = e2w[r0 + 8];
    float ew2 = e2w[r0 + 16], ew3 = e2w[r0 + 24];

    float pc[16];
#pragma unroll
    for (int nt = 0; nt < 8; nt++) {
#pragma unroll
        for (int j = 0; j < 2; j++) {
            float h0 = d[0][nt][j]     + eb0; h0 = h0 > 0.f ? h0 : 0.f;
            float h1 = d[0][nt][2 + j] + eb1; h1 = h1 > 0.f ? h1 : 0.f;
            float h2 = d[1][nt][j]     + eb2; h2 = h2 > 0.f ? h2 : 0.f;
            float h3 = d[1][nt][2 + j] + eb3; h3 = h3 > 0.f ? h3 : 0.f;
            pc[nt * 2 + j] = ew0 * h0 + ew1 * h1 + ew2 * h2 + ew3 * h3;
        }
    }
#pragma unroll
    for (int off = 16; off >= 4; off >>= 1)
#pragma unroll
        for (int t = 0; t < 16; t++)
            pc[t] += __shfl_xor_sync(0xffffffff, pc[t], off);

    if (lane < 4) {
#pragma unroll
        for (int nt = 0; nt < 8; nt++) {
            part[wm * 128 + wn * 64 + nt * 8 + 2 * lane]     = pc[nt * 2];
            part[wm * 128 + wn * 64 + nt * 8 + 2 * lane + 1] = pc[nt * 2 + 1];
        }
    }
    __syncthreads();
    if (tid < 128) {
        float s = e2b[0];
#pragma unroll
        for (int ww = 0; ww < 8; ww++) s += part[ww * 128 + tid];
        int p = p0 + tid;
        out[(p & 15) * TOUT + (p >> 4)] = s;
    }
}

// ---------------------------------------------------------------------------
extern "C" void kernel_launch(void* const* d_in, const int* in_sizes, int n_in,
                              void* d_out, int out_size)
{
    const float* input    = (const float*)d_in[0];
    const float* start_w  = (const float*)d_in[1];
    const float* filter_w = (const float*)d_in[2];
    const float* gate_w   = (const float*)d_in[3];
    const float* res_w    = (const float*)d_in[4];
    const float* skip_w   = (const float*)d_in[5];
    const float* e1w      = (const float*)d_in[6];
    const float* e1b      = (const float*)d_in[7];
    const float* e2w      = (const float*)d_in[8];
    const float* e2b      = (const float*)d_in[9];
    float* out = (float*)d_out;
    (void)in_sizes; (void)n_in; (void)out_size;

    static int attr_done = 0;
    if (!attr_done) {
        cudaFuncSetAttribute(k_layer, cudaFuncAttributeMaxDynamicSharedMemorySize, 60416);
        cudaFuncSetAttribute(k_tail,  cudaFuncAttributeMaxDynamicSharedMemorySize, 200704);
        attr_done = 1;
    }

    unsigned *xah, *xal, *xbh, *xbl, *ybf;
    cudaGetSymbolAddress((void**)&xah, g_xah);
    cudaGetSymbolAddress((void**)&xal, g_xal);
    cudaGetSymbolAddress((void**)&xbh, g_xbh);
    cudaGetSymbolAddress((void**)&xbl, g_xbl);
    cudaGetSymbolAddress((void**)&ybf, g_ybf);

    k_prep<<<48, 256>>>(filter_w, gate_w, res_w, skip_w, e1w);
    k_start<<<1024, 256>>>(input, start_w, xah, xal);

    unsigned *curh = xah, *curl = xal, *nxth = xbh, *nxtl = xbl;
    for (int i = 0; i < 40; i++) {
        int b = i / 10, k = i % 10;
        int Mb = 262144 - 8192 * b;
        int Min, Mout, P, S;
        if (k == 0) { Min = Mb; Mout = Mb - 16; P = 0; S = 16; }
        else {
            int d = 1 << k;
            Min = Mb - 8 * d;
            Mout = Mb - 16 * d;
            P = 8 * d;
            S = 16 * d;
        }
        int ofs = Mout - FINAL;
        int grid = (Mout + 127) / 128;
        k_layer<<<grid, 256, 60416>>>(curh, curl, nxth, nxtl,
                                      ybf + (size_t)i * 16 * FINAL,
                                      i, Min, Mout, P, S, ofs);
        unsigned* t;
        t = curh; curh = nxth; nxth = t;
        t = curl; curl = nxtl; nxtl = t;
    }

    k_tail<<<FINAL / 128, 512, 200704>>>(ybf, e1b, e2w, e2b, out);
}

// round 12
// speedup vs baseline: 4.6709x; 1.0803x over previous
#include <cuda_runtime.h>
#include <cuda_fp16.h>
#include <math.h>

#define FINAL 229376        // 16 * 14336 final flat length
#define XLD   262144        // fixed channel stride for x buffers
#define TOUT  14336

// Scratch (device globals; no allocation anywhere)
__device__ unsigned g_xah[16 * XLD], g_xal[16 * XLD];   // x ping (fp16 hi/lo pairs)
__device__ unsigned g_xbh[16 * XLD], g_xbl[16 * XLD];   // x pong
__device__ unsigned g_ybf[640 * FINAL];     // y hi: per layer [FINAL pos][16 k2]
__device__ unsigned g_w1h[40 * 2048];                     // [s=64][k2=32] per layer (hi only)
__device__ unsigned g_wrh[40 * 512],  g_wrl[40 * 512];    // [row=32][k2=16] (rows permuted)
__device__ unsigned g_swf[163840];                        // skip_w single fp16 [40*256][k2=16]
__device__ unsigned g_e1fh[32768],    g_e1fl[32768];      // e1w fp16 pairs [256][k2=128]

// ---------------------------------------------------------------------------
// helpers (fp16 limbs)
// ---------------------------------------------------------------------------
__device__ __forceinline__ void mma16(float d[4], const unsigned a[4], const unsigned b[2]) {
    asm volatile(
        "mma.sync.aligned.m16n8k16.row.col.f32.f16.f16.f32 "
        "{%0,%1,%2,%3},{%4,%5,%6,%7},{%8,%9},{%0,%1,%2,%3};"
        : "+f"(d[0]), "+f"(d[1]), "+f"(d[2]), "+f"(d[3])
        : "r"(a[0]), "r"(a[1]), "r"(a[2]), "r"(a[3]), "r"(b[0]), "r"(b[1]));
}
__device__ __forceinline__ void ldsm_x4(unsigned a[4], unsigned saddr) {
    asm volatile("ldmatrix.sync.aligned.m8n8.x4.shared.b16 {%0,%1,%2,%3}, [%4];"
        : "=r"(a[0]), "=r"(a[1]), "=r"(a[2]), "=r"(a[3]) : "r"(saddr));
}
__device__ __forceinline__ unsigned smaddr(const void* p) {
    return (unsigned)__cvta_generic_to_shared(p);
}
__device__ __forceinline__ void cp16(unsigned dst, const unsigned* src) {
    asm volatile("cp.async.ca.shared.global [%0], [%1], 16;" :: "r"(dst), "l"(src));
}
#define CP_COMMIT() asm volatile("cp.async.commit_group;")
#define CP_WAIT0()  asm volatile("cp.async.wait_group 0;")

// ---- fast activations via MUFU (ex2/rcp approx)
__device__ __forceinline__ float fast_ex2(float x) {
    float y; asm("ex2.approx.f32 %0, %1;" : "=f"(y) : "f"(x)); return y;
}
__device__ __forceinline__ float fast_rcp(float x) {
    float y; asm("rcp.approx.f32 %0, %1;" : "=f"(y) : "f"(x)); return y;
}
__device__ __forceinline__ float fast_sigmoid(float x) {
    return fast_rcp(1.f + fast_ex2(-1.4426950408889634f * x));
}
__device__ __forceinline__ float fast_tanh(float x) {
    return 2.f * fast_rcp(1.f + fast_ex2(-2.8853900817779268f * x)) - 1.f;
}

// pack two floats (even ch -> low half) into fp16x2 hi and lo components
__device__ __forceinline__ void split_pack(float a, float b, unsigned& h, unsigned& l) {
    __half ah = __float2half(a), bh = __float2half(b);
    float ar = a - __half2float(ah), br = b - __half2float(bh);
    __half2 th; th.x = ah; th.y = bh; h = *(unsigned*)&th;
    __half2 tl; tl.x = __float2half(ar); tl.y = __float2half(br);
    l = *(unsigned*)&tl;
}
__device__ __forceinline__ unsigned pack1(float a, float b) {
    __half2 t; t.x = __float2half(a); t.y = __float2half(b);
    return *(unsigned*)&t;
}
__device__ __forceinline__ void split1(float v, unsigned short& h, unsigned short& l) {
    __half vh = __float2half(v);
    float r = v - __half2float(vh);
    __half vl = __float2half(r);
    h = *(unsigned short*)&vh;
    l = *(unsigned short*)&vl;
}
__device__ __forceinline__ float fp_half(unsigned u, int hi) {
    __half2 t = *(__half2*)&u;
    return hi ? __half2float(t.y) : __half2float(t.x);
}

// ---------------------------------------------------------------------------
// prep: split weights into packed fp16 hi/lo pairs (permuted for fragments)
// ---------------------------------------------------------------------------
__global__ void k_prep(const float* __restrict__ fw, const float* __restrict__ gw,
                       const float* __restrict__ rw, const float* __restrict__ sw,
                       const float* __restrict__ e1w)
{
    int i = blockIdx.x, tid = threadIdx.x;
    if (i < 40) {
        for (int l = tid; l < 2048; l += 256) {
            int s = l >> 5, k2 = l & 31;
            int c = ((s >> 4) << 3) + (s & 7);
            int isg = (s >> 3) & 1;
            const float* src = (isg ? gw : fw) + i * 2048;
            int k0 = 2 * k2;
            float v0 = src[(c * 32 + (k0 & 31)) * 2 + (k0 >> 5)];
            float v1 = src[(c * 32 + ((k0 + 1) & 31)) * 2 + ((k0 + 1) >> 5)];
            g_w1h[i * 2048 + l] = pack1(v0, v1);
        }
        for (int l = tid; l < 512; l += 256) {
            int r = l >> 4, k2 = l & 15;
            int t = r >> 4, s = r & 15;
            int chan = t * 16 + (s & 7) * 2 + (s >> 3);
            float v0 = rw[i * 1024 + chan * 32 + 2 * k2];
            float v1 = rw[i * 1024 + chan * 32 + 2 * k2 + 1];
            unsigned h, lo;
            split_pack(v0, v1, h, lo);
            g_wrh[i * 512 + l] = h;
            g_wrl[i * 512 + l] = lo;
        }
    } else {
        int bi = i - 40;  // 0..7
        for (int l = bi * 256 + tid; l < 163840; l += 2048) {
            int og = l >> 4, k2 = l & 15;
            g_swf[l] = pack1(sw[og * 32 + 2 * k2], sw[og * 32 + 2 * k2 + 1]);
        }
        for (int l = bi * 256 + tid; l < 32768; l += 2048) {
            int o = l >> 7, k2 = l & 127;
            unsigned h, lo;
            split_pack(e1w[o * 256 + 2 * k2], e1w[o * 256 + 2 * k2 + 1], h, lo);
            g_e1fh[l] = h; g_e1fl[l] = lo;
        }
    }
}

// ---------------------------------------------------------------------------
// start conv: x0[c][t*16+b] = sum_f sw[c][f] * input[b][f][t]; emits split fp16
// ---------------------------------------------------------------------------
__global__ void k_start(const float* __restrict__ in, const float* __restrict__ sw,
                        unsigned* __restrict__ xh, unsigned* __restrict__ xl)
{
    __shared__ float s_w[4096];
    __shared__ float s_in[16 * 272];
    int tid = threadIdx.x;               // 256
    for (int l = tid; l < 4096; l += 256) s_w[l] = sw[l];
    int t0 = blockIdx.x * 16;
    int b = tid & 15, dt = tid >> 4;
    float acc[32];
#pragma unroll
    for (int c = 0; c < 32; c++) acc[c] = 0.f;
    int tt = tid & 15, rhalf = tid >> 4;
    for (int fc = 0; fc < 8; fc++) {
        __syncthreads();
#pragma unroll
        for (int pass = 0; pass < 16; pass++) {
            int row = pass * 16 + rhalf;
            int bb = row >> 4, ff = row & 15;
            s_in[ff * 272 + tt * 17 + bb] =
                in[(bb * 128 + fc * 16 + ff) * 16384 + t0 + tt];
        }
        __syncthreads();
#pragma unroll
        for (int f = 0; f < 16; f++) {
            float v = s_in[f * 272 + dt * 17 + b];
#pragma unroll
            for (int c = 0; c < 32; c++)
                acc[c] += s_w[c * 128 + fc * 16 + f] * v;
        }
    }
    int m = t0 * 16 + tid;
#pragma unroll
    for (int c2 = 0; c2 < 16; c2++) {
        unsigned H, L;
        split_pack(acc[2 * c2], acc[2 * c2 + 1], H, L);
        xh[c2 * XLD + m] = H;
        xl[c2 * XLD + m] = L;
    }
}

// ---------------------------------------------------------------------------
// fused dilated layer: GEMM1 2-term (11-bit weights), GEMM2 3-term.
// smem (u32): Wh[64][36]@0, Rh[32][20]@2304, Rl@2944,
//             Xth[128][36]@3584, Xtl[128][36]@8192 -> 12800 u32 = 51200 B
// 4 CTAs/SM (204.8 KB), regs capped at 64.
// ---------------------------------------------------------------------------
__global__ void __launch_bounds__(256, 4)
k_layer(const unsigned* __restrict__ xinh, const unsigned* __restrict__ xinl,
        unsigned* __restrict__ xouth, unsigned* __restrict__ xoutl,
        unsigned* __restrict__ ytf, int layer,
        int Min, int Mout, int P, int S, int ofs)
{
    extern __shared__ unsigned smu[];
    unsigned* Wh  = smu;
    unsigned* Rh  = smu + 2304;
    unsigned* Rl  = smu + 2944;
    unsigned* Xth = smu + 3584;
    unsigned* Xtl = smu + 8192;

    int tid = threadIdx.x;          // 256
    int m0 = blockIdx.x * 128;
    int lane = tid & 31, w = tid >> 5;
    int grp = lane >> 2, t4 = lane & 3;
    unsigned lr = ((lane >> 3) & 1) * 8 + (lane & 7);
    unsigned lc = (lane >> 4) * 4;
    int bm = lane >> 3, br = lane & 7;
    unsigned bloff = ((unsigned)((bm >> 1) * 8 + br)) * 36 + (unsigned)(bm & 1) * 4;

    const unsigned* wsh = g_w1h + layer * 2048;
    for (int l = tid; l < 512; l += 256) {
        int row = l >> 3, q = (l & 7) * 4;
        *(uint4*)&Wh[row * 36 + q] = *(const uint4*)&wsh[row * 32 + q];
    }
    const unsigned* rsh = g_wrh + layer * 512;
    const unsigned* rsl = g_wrl + layer * 512;
    for (int l = tid; l < 128; l += 256) {
        int row = l >> 2, q = (l & 3) * 4;
        *(uint4*)&Rh[row * 20 + q] = *(const uint4*)&rsh[row * 16 + q];
        *(uint4*)&Rl[row * 20 + q] = *(const uint4*)&rsl[row * 16 + q];
    }

    for (int v = tid; v < 1024; v += 256) {
        int g = v >> 7;
        int p = v & 127;
        int tap = g >> 2;
        int ch2b = (g & 3) * 4;
        int off = tap ? (S - P) : -P;
        int idx = m0 + p + off;
        uint4 H, L;
        if (idx >= 0 && idx < Min) {
            const unsigned* ph = xinh + idx;
            const unsigned* pl = xinl + idx;
            H.x = ph[(size_t)(ch2b    ) * XLD]; L.x = pl[(size_t)(ch2b    ) * XLD];
            H.y = ph[(size_t)(ch2b + 1) * XLD]; L.y = pl[(size_t)(ch2b + 1) * XLD];
            H.z = ph[(size_t)(ch2b + 2) * XLD]; L.z = pl[(size_t)(ch2b + 2) * XLD];
            H.w = ph[(size_t)(ch2b + 3) * XLD]; L.w = pl[(size_t)(ch2b + 3) * XLD];
        } else {
            H.x = H.y = H.z = H.w = 0u;
            L.x = L.y = L.z = L.w = 0u;
        }
        *(uint4*)&Xth[p * 36 + g * 4] = H;
        *(uint4*)&Xtl[p * 36 + g * 4] = L;
    }
    __syncthreads();

    // ---- GEMM1: 64x128, K=64; 2-term split (weights hi only) ----
    int wr1 = w >> 2, wc1 = w & 3;
    unsigned whb = smaddr(Wh) + ((wr1 * 32 + lr) * 36 + lc) * 4;
    unsigned xhb = smaddr(Xth), xlb = smaddr(Xtl);
    float d[2][4][4];
#pragma unroll
    for (int a = 0; a < 2; a++)
#pragma unroll
        for (int b = 0; b < 4; b++)
#pragma unroll
            for (int c = 0; c < 4; c++) d[a][b][c] = 0.f;

#pragma unroll
    for (int kc = 0; kc < 4; kc++) {
        int k2b = kc * 8;
        unsigned ah[2][4];
#pragma unroll
        for (int mf = 0; mf < 2; mf++)
            ldsm_x4(ah[mf], whb + (mf * 576 + k2b) * 4);
#pragma unroll
        for (int ntp = 0; ntp < 2; ntp++) {
            unsigned bo = (((unsigned)(wc1 * 32 + ntp * 16)) * 36 + k2b + bloff) * 4;
            unsigned qh[4], ql[4];
            ldsm_x4(qh, xhb + bo);
            ldsm_x4(ql, xlb + bo);
            unsigned bh0[2] = {qh[0], qh[1]}, bl0[2] = {ql[0], ql[1]};
            unsigned bh1[2] = {qh[2], qh[3]}, bl1[2] = {ql[2], ql[3]};
#pragma unroll
            for (int mf = 0; mf < 2; mf++) {
                mma16(d[mf][2 * ntp], ah[mf], bh0);
                mma16(d[mf][2 * ntp], ah[mf], bl0);
                mma16(d[mf][2 * ntp + 1], ah[mf], bh1);
                mma16(d[mf][2 * ntp + 1], ah[mf], bl1);
            }
        }
    }

    float yv[2][4][2];
#pragma unroll
    for (int mf = 0; mf < 2; mf++)
#pragma unroll
        for (int nt = 0; nt < 4; nt++) {
            yv[mf][nt][0] = fast_tanh(d[mf][nt][0]) * fast_sigmoid(d[mf][nt][2]);
            yv[mf][nt][1] = fast_tanh(d[mf][nt][1]) * fast_sigmoid(d[mf][nt][3]);
        }
    __syncthreads();

    unsigned short* Yh16 = (unsigned short*)Xth;
    unsigned short* Yl16 = (unsigned short*)Xtl;
#pragma unroll
    for (int mf = 0; mf < 2; mf++) {
        int c = (wr1 * 2 + mf) * 8 + grp;
        int c2 = c >> 1, sel = c & 1;
#pragma unroll
        for (int nt = 0; nt < 4; nt++) {
            int col = wc1 * 32 + nt * 8 + 2 * t4;
            int base = col * 72 + c2 * 2 + sel;
            unsigned short h, lo;
            split1(yv[mf][nt][0], h, lo); Yh16[base] = h;       Yl16[base] = lo;
            split1(yv[mf][nt][1], h, lo); Yh16[base + 72] = h;  Yl16[base + 72] = lo;
        }
    }
    __syncthreads();

    for (int v = tid; v < 512; v += 256) {
        int p = v >> 2, qg = v & 3;
        int m = m0 + p;
        if (m >= ofs && m < Mout)
            *(uint4*)&ytf[(size_t)(m - ofs) * 16 + qg * 4] = *(uint4*)&Xth[p * 36 + qg * 4];
    }

    // ---- GEMM2: 32x128, K=32; 3-term split (protect residual chain) ----
    int wr2 = w >> 2, wc2 = w & 3;
    unsigned rhb = smaddr(Rh) + ((wr2 * 16 + lr) * 20 + lc) * 4;
    unsigned rlb = smaddr(Rl) + ((wr2 * 16 + lr) * 20 + lc) * 4;
    float e[4][4];
#pragma unroll
    for (int a = 0; a < 4; a++)
#pragma unroll
        for (int b = 0; b < 4; b++) e[a][b] = 0.f;

#pragma unroll
    for (int kc = 0; kc < 2; kc++) {
        int k2b = kc * 8;
        unsigned ah[4], al[4];
        ldsm_x4(ah, rhb + k2b * 4);
        ldsm_x4(al, rlb + k2b * 4);
#pragma unroll
        for (int ntp = 0; ntp < 2; ntp++) {
            unsigned bo = (((unsigned)(wc2 * 32 + ntp * 16)) * 36 + k2b + bloff) * 4;
            unsigned qh[4], ql[4];
            ldsm_x4(qh, xhb + bo);
            ldsm_x4(ql, xlb + bo);
            unsigned bh0[2] = {qh[0], qh[1]}, bl0[2] = {ql[0], ql[1]};
            unsigned bh1[2] = {qh[2], qh[3]}, bl1[2] = {ql[2], ql[3]};
            mma16(e[2 * ntp], ah, bh0);
            mma16(e[2 * ntp], ah, bl0);
            mma16(e[2 * ntp], al, bh0);
            mma16(e[2 * ntp + 1], ah, bh1);
            mma16(e[2 * ntp + 1], ah, bl1);
            mma16(e[2 * ntp + 1], al, bh1);
        }
    }
    {
        int ch2 = wr2 * 8 + grp;
        int colB = 16 + ch2;
#pragma unroll
        for (int nt = 0; nt < 4; nt++) {
            int col = wc2 * 32 + nt * 8 + 2 * t4;
            int m = m0 + col;
            if (m < Mout) {
                unsigned rh0 = Xth[col * 36 + colB],       rl0 = Xtl[col * 36 + colB];
                unsigned rh1 = Xth[(col + 1) * 36 + colB], rl1 = Xtl[(col + 1) * 36 + colB];
                float v0e = e[nt][0] + fp_half(rh0, 0) + fp_half(rl0, 0);
                float v0o = e[nt][2] + fp_half(rh0, 1) + fp_half(rl0, 1);
                float v1e = e[nt][1] + fp_half(rh1, 0) + fp_half(rl1, 0);
                float v1o = e[nt][3] + fp_half(rh1, 1) + fp_half(rl1, 1);
                unsigned H, L;
                split_pack(v0e, v0o, H, L);
                xouth[(size_t)ch2 * XLD + m] = H;
                xoutl[(size_t)ch2 * XLD + m] = L;
                split_pack(v1e, v1o, H, L);
                xouth[(size_t)ch2 * XLD + m + 1] = H;
                xoutl[(size_t)ch2 * XLD + m + 1] = L;
            }
        }
    }
}

// ---------------------------------------------------------------------------
// fused tail v2 (UNCHANGED from R11): 128 positions/block, 512 threads.
// ---------------------------------------------------------------------------
__global__ void __launch_bounds__(512, 1)
k_tail(const unsigned* __restrict__ ybf,
       const float* __restrict__ e1b, const float* __restrict__ e2w,
       const float* __restrict__ e2b, float* __restrict__ out)
{
    extern __shared__ unsigned smu[];
    unsigned* Hh = smu + 15360;
    unsigned* Hl = smu + 32768;
    float* part = (float*)smu;

    int tid = threadIdx.x;     // 512
    int lane = tid & 31, w = tid >> 5;
    int wm = w >> 1, wn = w & 1;
    int grp = lane >> 2, t4 = lane & 3;
    int p0 = blockIdx.x * 128;
    unsigned smb = smaddr(smu);

    float d[2][8][4];
#pragma unroll
    for (int mt = 0; mt < 2; mt++)
#pragma unroll
        for (int nt = 0; nt < 8; nt++)
#pragma unroll
            for (int j = 0; j < 4; j++) d[mt][nt][j] = 0.f;

    int sp = tid >> 2, sq = (tid & 3) * 4;

    {   // prefetch kc = 0
        cp16(smb + (0 * 7680 + sp * 20 + sq) * 4,
             &ybf[(size_t)(p0 + sp) * 16 + sq]);
        for (int l = tid; l < 1024; l += 512) {
            int row = l >> 2, qg = (l & 3) * 4;
            cp16(smb + (0 * 7680 + 2560 + row * 20 + qg) * 4,
                 &g_swf[row * 16 + qg]);
        }
        CP_COMMIT();
    }
    for (int kc = 0; kc < 40; kc++) {
        CP_WAIT0();
        __syncthreads();
        if (kc < 39) {
            int nb = (kc + 1) & 1;
            cp16(smb + (nb * 7680 + sp * 20 + sq) * 4,
                 &ybf[(size_t)(kc + 1) * 16 * FINAL + (size_t)(p0 + sp) * 16 + sq]);
            for (int l = tid; l < 1024; l += 512) {
                int row = l >> 2, qg = (l & 3) * 4;
                cp16(smb + (nb * 7680 + 2560 + row * 20 + qg) * 4,
                     &g_swf[((kc + 1) * 256 + row) * 16 + qg]);
            }
            CP_COMMIT();
        }
        const unsigned* Bc = smu + (kc & 1) * 7680;
        const unsigned* Wc = Bc + 2560;
#pragma unroll
        for (int ck = 0; ck < 2; ck++) {
            int k2b = ck * 8;
            unsigned a0[4], a1[4];
            {
                const unsigned* pw = &Wc[(wm * 32 + grp) * 20 + k2b + t4];
                a0[0] = pw[0]; a0[1] = pw[8 * 20]; a0[2] = pw[4]; a0[3] = pw[8 * 20 + 4];
                const unsigned* pw2 = pw + 16 * 20;
                a1[0] = pw2[0]; a1[1] = pw2[8 * 20]; a1[2] = pw2[4]; a1[3] = pw2[8 * 20 + 4];
            }
#pragma unroll
            for (int nt = 0; nt < 8; nt++) {
                unsigned b[2];
                int n = wn * 64 + nt * 8 + grp;
                b[0] = Bc[n * 20 + k2b + t4];
                b[1] = Bc[n * 20 + k2b + t4 + 4];
                mma16(d[0][nt], a0, b);
                mma16(d[1][nt], a1, b);
            }
        }
    }

    __syncthreads();
    unsigned short* Hh16 = (unsigned short*)Hh;
    unsigned short* Hl16 = (unsigned short*)Hl;
#pragma unroll
    for (int mt = 0; mt < 2; mt++)
#pragma unroll
        for (int nt = 0; nt < 8; nt++) {
            int r = wm * 32 + mt * 16 + grp;
            int col = wn * 64 + nt * 8 + 2 * t4;
            unsigned short h, lo;
            float v;
            v = d[mt][nt][0]; v = v > 0.f ? v : 0.f; split1(v, h, lo);
            Hh16[((r >> 1) * 136 + col) * 2 + (r & 1)] = h;
            Hl16[((r >> 1) * 136 + col) * 2 + (r & 1)] = lo;
            v = d[mt][nt][1]; v = v > 0.f ? v : 0.f; split1(v, h, lo);
            Hh16[((r >> 1) * 136 + col + 1) * 2 + (r & 1)] = h;
            Hl16[((r >> 1) * 136 + col + 1) * 2 + (r & 1)] = lo;
            int r2 = r + 8;
            v = d[mt][nt][2]; v = v > 0.f ? v : 0.f; split1(v, h, lo);
            Hh16[((r2 >> 1) * 136 + col) * 2 + (r2 & 1)] = h;
            Hl16[((r2 >> 1) * 136 + col) * 2 + (r2 & 1)] = lo;
            v = d[mt][nt][3]; v = v > 0.f ? v : 0.f; split1(v, h, lo);
            Hh16[((r2 >> 1) * 136 + col + 1) * 2 + (r2 & 1)] = h;
            Hl16[((r2 >> 1) * 136 + col + 1) * 2 + (r2 & 1)] = lo;
        }

#pragma unroll
    for (int mt = 0; mt < 2; mt++)
#pragma unroll
        for (int nt = 0; nt < 8; nt++)
#pragma unroll
            for (int j = 0; j < 4; j++) d[mt][nt][j] = 0.f;

    {
        __syncthreads();
        int row = tid >> 1, qg = (tid & 1) * 4;
        cp16(smb + (0 * 6144 + row * 12 + qg) * 4,        &g_e1fh[row * 128 + qg]);
        cp16(smb + (0 * 6144 + 3072 + row * 12 + qg) * 4, &g_e1fl[row * 128 + qg]);
        CP_COMMIT();
    }
    for (int kk = 0; kk < 16; kk++) {
        CP_WAIT0();
        __syncthreads();
        if (kk < 15) {
            int nb = (kk + 1) & 1;
            int row = tid >> 1, qg = (tid & 1) * 4;
            cp16(smb + (nb * 6144 + row * 12 + qg) * 4,
                 &g_e1fh[row * 128 + (kk + 1) * 8 + qg]);
            cp16(smb + (nb * 6144 + 3072 + row * 12 + qg) * 4,
                 &g_e1fl[row * 128 + (kk + 1) * 8 + qg]);
            CP_COMMIT();
        }
        const unsigned* Eh = smu + (kk & 1) * 6144;
        const unsigned* El = Eh + 3072;
        unsigned ah[2][4], al[2][4];
#pragma unroll
        for (int mt = 0; mt < 2; mt++) {
            const unsigned* ph = &Eh[(wm * 32 + mt * 16 + grp) * 12 + t4];
            const unsigned* pl = &El[(wm * 32 + mt * 16 + grp) * 12 + t4];
            ah[mt][0] = ph[0]; ah[mt][1] = ph[8 * 12]; ah[mt][2] = ph[4]; ah[mt][3] = ph[8 * 12 + 4];
            al[mt][0] = pl[0]; al[mt][1] = pl[8 * 12]; al[mt][2] = pl[4]; al[mt][3] = pl[8 * 12 + 4];
        }
#pragma unroll
        for (int nt = 0; nt < 8; nt++) {
            int col = wn * 64 + nt * 8 + grp;
            unsigned bh[2], bl[2];
            bh[0] = Hh[(kk * 8 + t4) * 136 + col];
            bh[1] = Hh[(kk * 8 + t4 + 4) * 136 + col];
            bl[0] = Hl[(kk * 8 + t4) * 136 + col];
            bl[1] = Hl[(kk * 8 + t4 + 4) * 136 + col];
#pragma unroll
            for (int mt = 0; mt < 2; mt++) {
                mma16(d[mt][nt], ah[mt], bh);
                mma16(d[mt][nt], ah[mt], bl);
                mma16(d[mt][nt], al[mt], bh);
            }
        }
    }

    int r0 = wm * 32 + grp;
    float eb0 = e1b[r0],      eb1 = e1b[r0 + 8];
    float eb2 = e1b[r0 + 16], eb3 = e1b[r0 + 24];
    float ew0 = e2w[r0],      ew1 = e2w[r0 + 8];
    float ew2 = e2w[r0 + 16], ew3 = e2w[r0 + 24];

    float pc[16];
#pragma unroll
    for (int nt = 0; nt < 8; nt++) {
#pragma unroll
        for (int j = 0; j < 2; j++) {
            float h0 = d[0][nt][j]     + eb0; h0 = h0 > 0.f ? h0 : 0.f;
            float h1 = d[0][nt][2 + j] + eb1; h1 = h1 > 0.f ? h1 : 0.f;
            float h2 = d[1][nt][j]     + eb2; h2 = h2 > 0.f ? h2 : 0.f;
            float h3 = d[1][nt][2 + j] + eb3; h3 = h3 > 0.f ? h3 : 0.f;
            pc[nt * 2 + j] = ew0 * h0 + ew1 * h1 + ew2 * h2 + ew3 * h3;
        }
    }
#pragma unroll
    for (int off = 16; off >= 4; off >>= 1)
#pragma unroll
        for (int t = 0; t < 16; t++)
            pc[t] += __shfl_xor_sync(0xffffffff, pc[t], off);

    if (lane < 4) {
#pragma unroll
        for (int nt = 0; nt < 8; nt++) {
            part[wm * 128 + wn * 64 + nt * 8 + 2 * lane]     = pc[nt * 2];
            part[wm * 128 + wn * 64 + nt * 8 + 2 * lane + 1] = pc[nt * 2 + 1];
        }
    }
    __syncthreads();
    if (tid < 128) {
        float s = e2b[0];
#pragma unroll
        for (int ww = 0; ww < 8; ww++) s += part[ww * 128 + tid];
        int p = p0 + tid;
        out[(p & 15) * TOUT + (p >> 4)] = s;
    }
}

// ---------------------------------------------------------------------------
extern "C" void kernel_launch(void* const* d_in, const int* in_sizes, int n_in,
                              void* d_out, int out_size)
{
    const float* input    = (const float*)d_in[0];
    const float* start_w  = (const float*)d_in[1];
    const float* filter_w = (const float*)d_in[2];
    const float* gate_w   = (const float*)d_in[3];
    const float* res_w    = (const float*)d_in[4];
    const float* skip_w   = (const float*)d_in[5];
    const float* e1w      = (const float*)d_in[6];
    const float* e1b      = (const float*)d_in[7];
    const float* e2w      = (const float*)d_in[8];
    const float* e2b      = (const float*)d_in[9];
    float* out = (float*)d_out;
    (void)in_sizes; (void)n_in; (void)out_size;

    static int attr_done = 0;
    if (!attr_done) {
        cudaFuncSetAttribute(k_layer, cudaFuncAttributeMaxDynamicSharedMemorySize, 51200);
        cudaFuncSetAttribute(k_tail,  cudaFuncAttributeMaxDynamicSharedMemorySize, 200704);
        attr_done = 1;
    }

    unsigned *xah, *xal, *xbh, *xbl, *ybf;
    cudaGetSymbolAddress((void**)&xah, g_xah);
    cudaGetSymbolAddress((void**)&xal, g_xal);
    cudaGetSymbolAddress((void**)&xbh, g_xbh);
    cudaGetSymbolAddress((void**)&xbl, g_xbl);
    cudaGetSymbolAddress((void**)&ybf, g_ybf);

    k_prep<<<48, 256>>>(filter_w, gate_w, res_w, skip_w, e1w);
    k_start<<<1024, 256>>>(input, start_w, xah, xal);

    unsigned *curh = xah, *curl = xal, *nxth = xbh, *nxtl = xbl;
    for (int i = 0; i < 40; i++) {
        int b = i / 10, k = i % 10;
        int Mb = 262144 - 8192 * b;
        int Min, Mout, P, S;
        if (k == 0) { Min = Mb; Mout = Mb - 16; P = 0; S = 16; }
        else {
            int d = 1 << k;
            Min = Mb - 8 * d;
            Mout = Mb - 16 * d;
            P = 8 * d;
            S = 16 * d;
        }
        int ofs = Mout - FINAL;
        int grid = (Mout + 127) / 128;
        k_layer<<<grid, 256, 51200>>>(curh, curl, nxth, nxtl,
                                      ybf + (size_t)i * 16 * FINAL,
                                      i, Min, Mout, P, S, ofs);
        unsigned* t;
        t = curh; curh = nxth; nxth = t;
        t = curl; curl = nxtl; nxtl = t;
    }

    k_tail<<<FINAL / 128, 512, 200704>>>(ybf, e1b, e2w, e2b, out);
}

// round 13
// speedup vs baseline: 4.9908x; 1.0685x over previous
#include <cuda_runtime.h>
#include <cuda_fp16.h>
#include <math.h>

#define FINAL 229376        // 16 * 14336 final flat length
#define XLD   262144        // fixed channel stride for x buffers
#define TOUT  14336

// Scratch (device globals; no allocation anywhere)
__device__ uint2    g_xa[16 * XLD];                       // x ping: {hi,lo} fp16x2 pairs
__device__ uint2    g_xb[16 * XLD];                       // x pong
__device__ unsigned g_ybf[640 * FINAL];     // y hi: per layer [FINAL pos][16 k2] (pairs (c,c+8))
__device__ unsigned g_w1h[40 * 2048];                     // [s=64][k2=32] per layer (hi only)
__device__ unsigned g_wrh[40 * 512],  g_wrl[40 * 512];    // [row=32][k2=16] (rows+k permuted)
__device__ unsigned g_swf[163840];                        // skip_w fp16 [40*256][k2=16] (pairs (c,c+8))
__device__ unsigned g_e1fh[32768],    g_e1fl[32768];      // e1w fp16 pairs [256][k2=128]

// ---------------------------------------------------------------------------
// helpers (fp16 limbs)
// ---------------------------------------------------------------------------
__device__ __forceinline__ void mma16(float d[4], const unsigned a[4], const unsigned b[2]) {
    asm volatile(
        "mma.sync.aligned.m16n8k16.row.col.f32.f16.f16.f32 "
        "{%0,%1,%2,%3},{%4,%5,%6,%7},{%8,%9},{%0,%1,%2,%3};"
        : "+f"(d[0]), "+f"(d[1]), "+f"(d[2]), "+f"(d[3])
        : "r"(a[0]), "r"(a[1]), "r"(a[2]), "r"(a[3]), "r"(b[0]), "r"(b[1]));
}
__device__ __forceinline__ void ldsm_x4(unsigned a[4], unsigned saddr) {
    asm volatile("ldmatrix.sync.aligned.m8n8.x4.shared.b16 {%0,%1,%2,%3}, [%4];"
        : "=r"(a[0]), "=r"(a[1]), "=r"(a[2]), "=r"(a[3]) : "r"(saddr));
}
__device__ __forceinline__ unsigned smaddr(const void* p) {
    return (unsigned)__cvta_generic_to_shared(p);
}
__device__ __forceinline__ void cp16(unsigned dst, const unsigned* src) {
    asm volatile("cp.async.ca.shared.global [%0], [%1], 16;" :: "r"(dst), "l"(src));
}
#define CP_COMMIT() asm volatile("cp.async.commit_group;")
#define CP_WAIT0()  asm volatile("cp.async.wait_group 0;")

// ---- fast activations via MUFU (ex2/rcp approx)
__device__ __forceinline__ float fast_ex2(float x) {
    float y; asm("ex2.approx.f32 %0, %1;" : "=f"(y) : "f"(x)); return y;
}
__device__ __forceinline__ float fast_rcp(float x) {
    float y; asm("rcp.approx.f32 %0, %1;" : "=f"(y) : "f"(x)); return y;
}
__device__ __forceinline__ float fast_sigmoid(float x) {
    return fast_rcp(1.f + fast_ex2(-1.4426950408889634f * x));
}
__device__ __forceinline__ float fast_tanh(float x) {
    return 2.f * fast_rcp(1.f + fast_ex2(-2.8853900817779268f * x)) - 1.f;
}

// pack two floats into fp16x2 hi and lo components
__device__ __forceinline__ void split_pack(float a, float b, unsigned& h, unsigned& l) {
    __half ah = __float2half(a), bh = __float2half(b);
    float ar = a - __half2float(ah), br = b - __half2float(bh);
    __half2 th; th.x = ah; th.y = bh; h = *(unsigned*)&th;
    __half2 tl; tl.x = __float2half(ar); tl.y = __float2half(br);
    l = *(unsigned*)&tl;
}
__device__ __forceinline__ unsigned pack1(float a, float b) {
    __half2 t; t.x = __float2half(a); t.y = __float2half(b);
    return *(unsigned*)&t;
}
__device__ __forceinline__ void split1(float v, unsigned short& h, unsigned short& l) {
    __half vh = __float2half(v);
    float r = v - __half2float(vh);
    __half vl = __float2half(r);
    h = *(unsigned short*)&vh;
    l = *(unsigned short*)&vl;
}
__device__ __forceinline__ float fp_half(unsigned u, int hi) {
    __half2 t = *(__half2*)&u;
    return hi ? __half2float(t.y) : __half2float(t.x);
}

// ---------------------------------------------------------------------------
// prep: split weights into packed fp16 hi/lo pairs (permuted for fragments)
// y-side k2 pairing is (c, c+8): lo ch = (p>>3)*16 + (p&7), hi ch = lo+8.
// ---------------------------------------------------------------------------
__global__ void k_prep(const float* __restrict__ fw, const float* __restrict__ gw,
                       const float* __restrict__ rw, const float* __restrict__ sw,
                       const float* __restrict__ e1w)
{
    int i = blockIdx.x, tid = threadIdx.x;
    if (i < 40) {
        for (int l = tid; l < 2048; l += 256) {
            int s = l >> 5, k2 = l & 31;
            int c = ((s >> 4) << 3) + (s & 7);
            int isg = (s >> 3) & 1;
            const float* src = (isg ? gw : fw) + i * 2048;
            int k0 = 2 * k2;
            float v0 = src[(c * 32 + (k0 & 31)) * 2 + (k0 >> 5)];
            float v1 = src[(c * 32 + ((k0 + 1) & 31)) * 2 + ((k0 + 1) >> 5)];
            g_w1h[i * 2048 + l] = pack1(v0, v1);
        }
        for (int l = tid; l < 512; l += 256) {
            int r = l >> 4, p = l & 15;
            int t = r >> 4, s = r & 15;
            int chan = t * 16 + (s & 7) * 2 + (s >> 3);
            int klo = ((p >> 3) << 4) + (p & 7);       // (c, c+8) pairing
            float v0 = rw[i * 1024 + chan * 32 + klo];
            float v1 = rw[i * 1024 + chan * 32 + klo + 8];
            unsigned h, lo;
            split_pack(v0, v1, h, lo);
            g_wrh[i * 512 + l] = h;
            g_wrl[i * 512 + l] = lo;
        }
    } else {
        int bi = i - 40;  // 0..7
        for (int l = bi * 256 + tid; l < 163840; l += 2048) {
            int og = l >> 4, p = l & 15;
            int klo = ((p >> 3) << 4) + (p & 7);       // (c, c+8) pairing
            g_swf[l] = pack1(sw[og * 32 + klo], sw[og * 32 + klo + 8]);
        }
        for (int l = bi * 256 + tid; l < 32768; l += 2048) {
            int o = l >> 7, k2 = l & 127;
            unsigned h, lo;
            split_pack(e1w[o * 256 + 2 * k2], e1w[o * 256 + 2 * k2 + 1], h, lo);
            g_e1fh[l] = h; g_e1fl[l] = lo;
        }
    }
}

// ---------------------------------------------------------------------------
// start conv: x0[c][t*16+b] = sum_f sw[c][f] * input[b][f][t]; emits uint2{hi,lo}
// ---------------------------------------------------------------------------
__global__ void k_start(const float* __restrict__ in, const float* __restrict__ sw,
                        uint2* __restrict__ xo)
{
    __shared__ float s_w[4096];
    __shared__ float s_in[16 * 272];
    int tid = threadIdx.x;               // 256
    for (int l = tid; l < 4096; l += 256) s_w[l] = sw[l];
    int t0 = blockIdx.x * 16;
    int b = tid & 15, dt = tid >> 4;
    float acc[32];
#pragma unroll
    for (int c = 0; c < 32; c++) acc[c] = 0.f;
    int tt = tid & 15, rhalf = tid >> 4;
    for (int fc = 0; fc < 8; fc++) {
        __syncthreads();
#pragma unroll
        for (int pass = 0; pass < 16; pass++) {
            int row = pass * 16 + rhalf;
            int bb = row >> 4, ff = row & 15;
            s_in[ff * 272 + tt * 17 + bb] =
                in[(bb * 128 + fc * 16 + ff) * 16384 + t0 + tt];
        }
        __syncthreads();
#pragma unroll
        for (int f = 0; f < 16; f++) {
            float v = s_in[f * 272 + dt * 17 + b];
#pragma unroll
            for (int c = 0; c < 32; c++)
                acc[c] += s_w[c * 128 + fc * 16 + f] * v;
        }
    }
    int m = t0 * 16 + tid;
#pragma unroll
    for (int c2 = 0; c2 < 16; c2++) {
        unsigned H, L;
        split_pack(acc[2 * c2], acc[2 * c2 + 1], H, L);
        xo[(size_t)c2 * XLD + m] = make_uint2(H, L);
    }
}

// ---------------------------------------------------------------------------
// fused dilated layer: GEMM1 2-term (11-bit weights), GEMM2 3-term.
// smem (u32): Wh[64][36]@0, Rh[32][20]@2304, Rl@2944,
//             Xth[128][36]@3584, Xtl[128][36]@8192 -> 12800 u32 = 51200 B
// x global buffers: uint2 {hi,lo}.  y overlay pairs (c, c+8) in-thread.
// ---------------------------------------------------------------------------
__global__ void __launch_bounds__(256, 4)
k_layer(const uint2* __restrict__ xin, uint2* __restrict__ xout,
        unsigned* __restrict__ ytf, int layer,
        int Min, int Mout, int P, int S, int ofs)
{
    extern __shared__ unsigned smu[];
    unsigned* Wh  = smu;
    unsigned* Rh  = smu + 2304;
    unsigned* Rl  = smu + 2944;
    unsigned* Xth = smu + 3584;
    unsigned* Xtl = smu + 8192;

    int tid = threadIdx.x;          // 256
    int m0 = blockIdx.x * 128;
    int lane = tid & 31, w = tid >> 5;
    int grp = lane >> 2, t4 = lane & 3;
    unsigned lr = ((lane >> 3) & 1) * 8 + (lane & 7);
    unsigned lc = (lane >> 4) * 4;
    int bm = lane >> 3, br = lane & 7;
    unsigned bloff = ((unsigned)((bm >> 1) * 8 + br)) * 36 + (unsigned)(bm & 1) * 4;

    const unsigned* wsh = g_w1h + layer * 2048;
    for (int l = tid; l < 512; l += 256) {
        int row = l >> 3, q = (l & 7) * 4;
        *(uint4*)&Wh[row * 36 + q] = *(const uint4*)&wsh[row * 32 + q];
    }
    const unsigned* rsh = g_wrh + layer * 512;
    const unsigned* rsl = g_wrl + layer * 512;
    for (int l = tid; l < 128; l += 256) {
        int row = l >> 2, q = (l & 3) * 4;
        *(uint4*)&Rh[row * 20 + q] = *(const uint4*)&rsh[row * 16 + q];
        *(uint4*)&Rl[row * 20 + q] = *(const uint4*)&rsl[row * 16 + q];
    }

    // ---- stage x: uint2 loads (hi,lo interleaved) ----
    for (int v = tid; v < 1024; v += 256) {
        int g = v >> 7;
        int p = v & 127;
        int tap = g >> 2;
        int ch2b = (g & 3) * 4;
        int off = tap ? (S - P) : -P;
        int idx = m0 + p + off;
        uint4 H, L;
        if (idx >= 0 && idx < Min) {
            const uint2* px = xin + idx;
            uint2 v0 = px[(size_t)(ch2b    ) * XLD];
            uint2 v1 = px[(size_t)(ch2b + 1) * XLD];
            uint2 v2 = px[(size_t)(ch2b + 2) * XLD];
            uint2 v3 = px[(size_t)(ch2b + 3) * XLD];
            H.x = v0.x; L.x = v0.y;
            H.y = v1.x; L.y = v1.y;
            H.z = v2.x; L.z = v2.y;
            H.w = v3.x; L.w = v3.y;
        } else {
            H.x = H.y = H.z = H.w = 0u;
            L.x = L.y = L.z = L.w = 0u;
        }
        *(uint4*)&Xth[p * 36 + g * 4] = H;
        *(uint4*)&Xtl[p * 36 + g * 4] = L;
    }
    __syncthreads();

    // ---- GEMM1: 64x128, K=64; 2-term split (weights hi only) ----
    int wr1 = w >> 2, wc1 = w & 3;
    unsigned whb = smaddr(Wh) + ((wr1 * 32 + lr) * 36 + lc) * 4;
    unsigned xhb = smaddr(Xth), xlb = smaddr(Xtl);
    float d[2][4][4];
#pragma unroll
    for (int a = 0; a < 2; a++)
#pragma unroll
        for (int b = 0; b < 4; b++)
#pragma unroll
            for (int c = 0; c < 4; c++) d[a][b][c] = 0.f;

#pragma unroll
    for (int kc = 0; kc < 4; kc++) {
        int k2b = kc * 8;
        unsigned ah[2][4];
#pragma unroll
        for (int mf = 0; mf < 2; mf++)
            ldsm_x4(ah[mf], whb + (mf * 576 + k2b) * 4);
#pragma unroll
        for (int ntp = 0; ntp < 2; ntp++) {
            unsigned bo = (((unsigned)(wc1 * 32 + ntp * 16)) * 36 + k2b + bloff) * 4;
            unsigned qh[4], ql[4];
            ldsm_x4(qh, xhb + bo);
            ldsm_x4(ql, xlb + bo);
            unsigned bh0[2] = {qh[0], qh[1]}, bl0[2] = {ql[0], ql[1]};
            unsigned bh1[2] = {qh[2], qh[3]}, bl1[2] = {ql[2], ql[3]};
#pragma unroll
            for (int mf = 0; mf < 2; mf++) {
                mma16(d[mf][2 * ntp], ah[mf], bh0);
                mma16(d[mf][2 * ntp], ah[mf], bl0);
                mma16(d[mf][2 * ntp + 1], ah[mf], bh1);
                mma16(d[mf][2 * ntp + 1], ah[mf], bl1);
            }
        }
    }

    float yv[2][4][2];
#pragma unroll
    for (int mf = 0; mf < 2; mf++)
#pragma unroll
        for (int nt = 0; nt < 4; nt++) {
            yv[mf][nt][0] = fast_tanh(d[mf][nt][0]) * fast_sigmoid(d[mf][nt][2]);
            yv[mf][nt][1] = fast_tanh(d[mf][nt][1]) * fast_sigmoid(d[mf][nt][3]);
        }
    __syncthreads();

    // ---- store y: in-thread pair (c, c+8) -> one u32 per col, conflict-free ----
    {
        int p_idx = wr1 * 8 + grp;
#pragma unroll
        for (int nt = 0; nt < 4; nt++) {
            int col = wc1 * 32 + nt * 8 + 2 * t4;
            unsigned H, L;
            split_pack(yv[0][nt][0], yv[1][nt][0], H, L);
            Xth[col * 36 + p_idx] = H;
            Xtl[col * 36 + p_idx] = L;
            split_pack(yv[0][nt][1], yv[1][nt][1], H, L);
            Xth[(col + 1) * 36 + p_idx] = H;
            Xtl[(col + 1) * 36 + p_idx] = L;
        }
    }
    __syncthreads();

    // ---- ytail copy (hi only): global [pos][16 k2], coalesced uint4 ----
    for (int v = tid; v < 512; v += 256) {
        int p = v >> 2, qg = v & 3;
        int m = m0 + p;
        if (m >= ofs && m < Mout)
            *(uint4*)&ytf[(size_t)(m - ofs) * 16 + qg * 4] = *(uint4*)&Xth[p * 36 + qg * 4];
    }

    // ---- GEMM2: 32x128, K=32; 3-term split (protect residual chain) ----
    int wr2 = w >> 2, wc2 = w & 3;
    unsigned rhb = smaddr(Rh) + ((wr2 * 16 + lr) * 20 + lc) * 4;
    unsigned rlb = smaddr(Rl) + ((wr2 * 16 + lr) * 20 + lc) * 4;
    float e[4][4];
#pragma unroll
    for (int a = 0; a < 4; a++)
#pragma unroll
        for (int b = 0; b < 4; b++) e[a][b] = 0.f;

#pragma unroll
    for (int kc = 0; kc < 2; kc++) {
        int k2b = kc * 8;
        unsigned ah[4], al[4];
        ldsm_x4(ah, rhb + k2b * 4);
        ldsm_x4(al, rlb + k2b * 4);
#pragma unroll
        for (int ntp = 0; ntp < 2; ntp++) {
            unsigned bo = (((unsigned)(wc2 * 32 + ntp * 16)) * 36 + k2b + bloff) * 4;
            unsigned qh[4], ql[4];
            ldsm_x4(qh, xhb + bo);
            ldsm_x4(ql, xlb + bo);
            unsigned bh0[2] = {qh[0], qh[1]}, bl0[2] = {ql[0], ql[1]};
            unsigned bh1[2] = {qh[2], qh[3]}, bl1[2] = {ql[2], ql[3]};
            mma16(e[2 * ntp], ah, bh0);
            mma16(e[2 * ntp], ah, bl0);
            mma16(e[2 * ntp], al, bh0);
            mma16(e[2 * ntp + 1], ah, bh1);
            mma16(e[2 * ntp + 1], ah, bl1);
            mma16(e[2 * ntp + 1], al, bh1);
        }
    }
    {
        int ch2 = wr2 * 8 + grp;
        int colB = 16 + ch2;
#pragma unroll
        for (int nt = 0; nt < 4; nt++) {
            int col = wc2 * 32 + nt * 8 + 2 * t4;
            int m = m0 + col;
            if (m < Mout) {
                unsigned rh0 = Xth[col * 36 + colB],       rl0 = Xtl[col * 36 + colB];
                unsigned rh1 = Xth[(col + 1) * 36 + colB], rl1 = Xtl[(col + 1) * 36 + colB];
                float v0e = e[nt][0] + fp_half(rh0, 0) + fp_half(rl0, 0);
                float v0o = e[nt][2] + fp_half(rh0, 1) + fp_half(rl0, 1);
                float v1e = e[nt][1] + fp_half(rh1, 0) + fp_half(rl1, 0);
                float v1o = e[nt][3] + fp_half(rh1, 1) + fp_half(rl1, 1);
                unsigned H, L;
                split_pack(v0e, v0o, H, L);
                xout[(size_t)ch2 * XLD + m] = make_uint2(H, L);
                split_pack(v1e, v1o, H, L);
                xout[(size_t)ch2 * XLD + m + 1] = make_uint2(H, L);
            }
        }
    }
}

// ---------------------------------------------------------------------------
// fused tail v2 (UNCHANGED from R12): 128 positions/block, 512 threads.
// ---------------------------------------------------------------------------
__global__ void __launch_bounds__(512, 1)
k_tail(const unsigned* __restrict__ ybf,
       const float* __restrict__ e1b, const float* __restrict__ e2w,
       const float* __restrict__ e2b, float* __restrict__ out)
{
    extern __shared__ unsigned smu[];
    unsigned* Hh = smu + 15360;
    unsigned* Hl = smu + 32768;
    float* part = (float*)smu;

    int tid = threadIdx.x;     // 512
    int lane = tid & 31, w = tid >> 5;
    int wm = w >> 1, wn = w & 1;
    int grp = lane >> 2, t4 = lane & 3;
    int p0 = blockIdx.x * 128;
    unsigned smb = smaddr(smu);

    float d[2][8][4];
#pragma unroll
    for (int mt = 0; mt < 2; mt++)
#pragma unroll
        for (int nt = 0; nt < 8; nt++)
#pragma unroll
            for (int j = 0; j < 4; j++) d[mt][nt][j] = 0.f;

    int sp = tid >> 2, sq = (tid & 3) * 4;

    {   // prefetch kc = 0
        cp16(smb + (0 * 7680 + sp * 20 + sq) * 4,
             &ybf[(size_t)(p0 + sp) * 16 + sq]);
        for (int l = tid; l < 1024; l += 512) {
            int row = l >> 2, qg = (l & 3) * 4;
            cp16(smb + (0 * 7680 + 2560 + row * 20 + qg) * 4,
                 &g_swf[row * 16 + qg]);
        }
        CP_COMMIT();
    }
    for (int kc = 0; kc < 40; kc++) {
        CP_WAIT0();
        __syncthreads();
        if (kc < 39) {
            int nb = (kc + 1) & 1;
            cp16(smb + (nb * 7680 + sp * 20 + sq) * 4,
                 &ybf[(size_t)(kc + 1) * 16 * FINAL + (size_t)(p0 + sp) * 16 + sq]);
            for (int l = tid; l < 1024; l += 512) {
                int row = l >> 2, qg = (l & 3) * 4;
                cp16(smb + (nb * 7680 + 2560 + row * 20 + qg) * 4,
                     &g_swf[((kc + 1) * 256 + row) * 16 + qg]);
            }
            CP_COMMIT();
        }
        const unsigned* Bc = smu + (kc & 1) * 7680;
        const unsigned* Wc = Bc + 2560;
#pragma unroll
        for (int ck = 0; ck < 2; ck++) {
            int k2b = ck * 8;
            unsigned a0[4], a1[4];
            {
                const unsigned* pw = &Wc[(wm * 32 + grp) * 20 + k2b + t4];
                a0[0] = pw[0]; a0[1] = pw[8 * 20]; a0[2] = pw[4]; a0[3] = pw[8 * 20 + 4];
                const unsigned* pw2 = pw + 16 * 20;
                a1[0] = pw2[0]; a1[1] = pw2[8 * 20]; a1[2] = pw2[4]; a1[3] = pw2[8 * 20 + 4];
            }
#pragma unroll
            for (int nt = 0; nt < 8; nt++) {
                unsigned b[2];
                int n = wn * 64 + nt * 8 + grp;
                b[0] = Bc[n * 20 + k2b + t4];
                b[1] = Bc[n * 20 + k2b + t4 + 4];
                mma16(d[0][nt], a0, b);
                mma16(d[1][nt], a1, b);
            }
        }
    }

    __syncthreads();
    unsigned short* Hh16 = (unsigned short*)Hh;
    unsigned short* Hl16 = (unsigned short*)Hl;
#pragma unroll
    for (int mt = 0; mt < 2; mt++)
#pragma unroll
        for (int nt = 0; nt < 8; nt++) {
            int r = wm * 32 + mt * 16 + grp;
            int col = wn * 64 + nt * 8 + 2 * t4;
            unsigned short h, lo;
            float v;
            v = d[mt][nt][0]; v = v > 0.f ? v : 0.f; split1(v, h, lo);
            Hh16[((r >> 1) * 136 + col) * 2 + (r & 1)] = h;
            Hl16[((r >> 1) * 136 + col) * 2 + (r & 1)] = lo;
            v = d[mt][nt][1]; v = v > 0.f ? v : 0.f; split1(v, h, lo);
            Hh16[((r >> 1) * 136 + col + 1) * 2 + (r & 1)] = h;
            Hl16[((r >> 1) * 136 + col + 1) * 2 + (r & 1)] = lo;
            int r2 = r + 8;
            v = d[mt][nt][2]; v = v > 0.f ? v : 0.f; split1(v, h, lo);
            Hh16[((r2 >> 1) * 136 + col) * 2 + (r2 & 1)] = h;
            Hl16[((r2 >> 1) * 136 + col) * 2 + (r2 & 1)] = lo;
            v = d[mt][nt][3]; v = v > 0.f ? v : 0.f; split1(v, h, lo);
            Hh16[((r2 >> 1) * 136 + col + 1) * 2 + (r2 & 1)] = h;
            Hl16[((r2 >> 1) * 136 + col + 1) * 2 + (r2 & 1)] = lo;
        }

#pragma unroll
    for (int mt = 0; mt < 2; mt++)
#pragma unroll
        for (int nt = 0; nt < 8; nt++)
#pragma unroll
            for (int j = 0; j < 4; j++) d[mt][nt][j] = 0.f;

    {
        __syncthreads();
        int row = tid >> 1, qg = (tid & 1) * 4;
        cp16(smb + (0 * 6144 + row * 12 + qg) * 4,        &g_e1fh[row * 128 + qg]);
        cp16(smb + (0 * 6144 + 3072 + row * 12 + qg) * 4, &g_e1fl[row * 128 + qg]);
        CP_COMMIT();
    }
    for (int kk = 0; kk < 16; kk++) {
        CP_WAIT0();
        __syncthreads();
        if (kk < 15) {
            int nb = (kk + 1) & 1;
            int row = tid >> 1, qg = (tid & 1) * 4;
            cp16(smb + (nb * 6144 + row * 12 + qg) * 4,
                 &g_e1fh[row * 128 + (kk + 1) * 8 + qg]);
            cp16(smb + (nb * 6144 + 3072 + row * 12 + qg) * 4,
                 &g_e1fl[row * 128 + (kk + 1) * 8 + qg]);
            CP_COMMIT();
        }
        const unsigned* Eh = smu + (kk & 1) * 6144;
        const unsigned* El = Eh + 3072;
        unsigned ah[2][4], al[2][4];
#pragma unroll
        for (int mt = 0; mt < 2; mt++) {
            const unsigned* ph = &Eh[(wm * 32 + mt * 16 + grp) * 12 + t4];
            const unsigned* pl = &El[(wm * 32 + mt * 16 + grp) * 12 + t4];
            ah[mt][0] = ph[0]; ah[mt][1] = ph[8 * 12]; ah[mt][2] = ph[4]; ah[mt][3] = ph[8 * 12 + 4];
            al[mt][0] = pl[0]; al[mt][1] = pl[8 * 12]; al[mt][2] = pl[4]; al[mt][3] = pl[8 * 12 + 4];
        }
#pragma unroll
        for (int nt = 0; nt < 8; nt++) {
            int col = wn * 64 + nt * 8 + grp;
            unsigned bh[2], bl[2];
            bh[0] = Hh[(kk * 8 + t4) * 136 + col];
            bh[1] = Hh[(kk * 8 + t4 + 4) * 136 + col];
            bl[0] = Hl[(kk * 8 + t4) * 136 + col];
            bl[1] = Hl[(kk * 8 + t4 + 4) * 136 + col];
#pragma unroll
            for (int mt = 0; mt < 2; mt++) {
                mma16(d[mt][nt], ah[mt], bh);
                mma16(d[mt][nt], ah[mt], bl);
                mma16(d[mt][nt], al[mt], bh);
            }
        }
    }

    int r0 = wm * 32 + grp;
    float eb0 = e1b[r0],      eb1 = e1b[r0 + 8];
    float eb2 = e1b[r0 + 16], eb3 = e1b[r0 + 24];
    float ew0 = e2w[r0],      ew1 = e2w[r0 + 8];
    float ew2 = e2w[r0 + 16], ew3 = e2w[r0 + 24];

    float pc[16];
#pragma unroll
    for (int nt = 0; nt < 8; nt++) {
#pragma unroll
        for (int j = 0; j < 2; j++) {
            float h0 = d[0][nt][j]     + eb0; h0 = h0 > 0.f ? h0 : 0.f;
            float h1 = d[0][nt][2 + j] + eb1; h1 = h1 > 0.f ? h1 : 0.f;
            float h2 = d[1][nt][j]     + eb2; h2 = h2 > 0.f ? h2 : 0.f;
            float h3 = d[1][nt][2 + j] + eb3; h3 = h3 > 0.f ? h3 : 0.f;
            pc[nt * 2 + j] = ew0 * h0 + ew1 * h1 + ew2 * h2 + ew3 * h3;
        }
    }
#pragma unroll
    for (int off = 16; off >= 4; off >>= 1)
#pragma unroll
        for (int t = 0; t < 16; t++)
            pc[t] += __shfl_xor_sync(0xffffffff, pc[t], off);

    if (lane < 4) {
#pragma unroll
        for (int nt = 0; nt < 8; nt++) {
            part[wm * 128 + wn * 64 + nt * 8 + 2 * lane]     = pc[nt * 2];
            part[wm * 128 + wn * 64 + nt * 8 + 2 * lane + 1] = pc[nt * 2 + 1];
        }
    }
    __syncthreads();
    if (tid < 128) {
        float s = e2b[0];
#pragma unroll
        for (int ww = 0; ww < 8; ww++) s += part[ww * 128 + tid];
        int p = p0 + tid;
        out[(p & 15) * TOUT + (p >> 4)] = s;
    }
}

// ---------------------------------------------------------------------------
extern "C" void kernel_launch(void* const* d_in, const int* in_sizes, int n_in,
                              void* d_out, int out_size)
{
    const float* input    = (const float*)d_in[0];
    const float* start_w  = (const float*)d_in[1];
    const float* filter_w = (const float*)d_in[2];
    const float* gate_w   = (const float*)d_in[3];
    const float* res_w    = (const float*)d_in[4];
    const float* skip_w   = (const float*)d_in[5];
    const float* e1w      = (const float*)d_in[6];
    const float* e1b      = (const float*)d_in[7];
    const float* e2w      = (const float*)d_in[8];
    const float* e2b      = (const float*)d_in[9];
    float* out = (float*)d_out;
    (void)in_sizes; (void)n_in; (void)out_size;

    static int attr_done = 0;
    if (!attr_done) {
        cudaFuncSetAttribute(k_layer, cudaFuncAttributeMaxDynamicSharedMemorySize, 51200);
        cudaFuncSetAttribute(k_tail,  cudaFuncAttributeMaxDynamicSharedMemorySize, 200704);
        attr_done = 1;
    }

    uint2 *xa, *xb;
    unsigned *ybf;
    cudaGetSymbolAddress((void**)&xa, g_xa);
    cudaGetSymbolAddress((void**)&xb, g_xb);
    cudaGetSymbolAddress((void**)&ybf, g_ybf);

    k_prep<<<48, 256>>>(filter_w, gate_w, res_w, skip_w, e1w);
    k_start<<<1024, 256>>>(input, start_w, xa);

    uint2 *cur = xa, *nxt = xb;
    for (int i = 0; i < 40; i++) {
        int b = i / 10, k = i % 10;
        int Mb = 262144 - 8192 * b;
        int Min, Mout, P, S;
        if (k == 0) { Min = Mb; Mout = Mb - 16; P = 0; S = 16; }
        else {
            int d = 1 << k;
            Min = Mb - 8 * d;
            Mout = Mb - 16 * d;
            P = 8 * d;
            S = 16 * d;
        }
        int ofs = Mout - FINAL;
        int grid = (Mout + 127) / 128;
        k_layer<<<grid, 256, 51200>>>(cur, nxt,
                                      ybf + (size_t)i * 16 * FINAL,
                                      i, Min, Mout, P, S, ofs);
        uint2* t = cur; cur = nxt; nxt = t;
    }

    k_tail<<<FINAL / 128, 512, 200704>>>(ybf, e1b, e2w, e2b, out);
}

// round 14
// speedup vs baseline: 5.4693x; 1.0959x over previous
#include <cuda_runtime.h>
#include <cuda_fp16.h>
#include <math.h>

#define FINAL 229376        // 16 * 14336 final flat length
#define XLD   262144        // fixed channel stride for x buffers
#define TOUT  14336

// Scratch (device globals; no allocation anywhere)
__device__ uint2    g_xa[16 * XLD];                       // x ping: {hi,lo} fp16x2 pairs
__device__ uint2    g_xb[16 * XLD];                       // x pong
__device__ unsigned g_ybf[640 * FINAL];     // y hi: per layer [FINAL pos][16 k2] (pairs (c,c+8))
__device__ unsigned g_w1h[40 * 2048];                     // [s=64][k2=32] per layer (hi only)
__device__ unsigned g_wrh[40 * 512],  g_wrl[40 * 512];    // [row=32][k2=16] (rows+k permuted)
__device__ unsigned g_swf[163840];                        // skip_w fp16 [40*256][k2=16] (pairs (c,c+8))
__device__ unsigned g_e1fh[32768];                        // e1w fp16 hi [256][k2=128] (pairs (r,r+8))

// ---------------------------------------------------------------------------
// helpers (fp16 limbs)
// ---------------------------------------------------------------------------
__device__ __forceinline__ void mma16(float d[4], const unsigned a[4], const unsigned b[2]) {
    asm volatile(
        "mma.sync.aligned.m16n8k16.row.col.f32.f16.f16.f32 "
        "{%0,%1,%2,%3},{%4,%5,%6,%7},{%8,%9},{%0,%1,%2,%3};"
        : "+f"(d[0]), "+f"(d[1]), "+f"(d[2]), "+f"(d[3])
        : "r"(a[0]), "r"(a[1]), "r"(a[2]), "r"(a[3]), "r"(b[0]), "r"(b[1]));
}
__device__ __forceinline__ void ldsm_x4(unsigned a[4], unsigned saddr) {
    asm volatile("ldmatrix.sync.aligned.m8n8.x4.shared.b16 {%0,%1,%2,%3}, [%4];"
        : "=r"(a[0]), "=r"(a[1]), "=r"(a[2]), "=r"(a[3]) : "r"(saddr));
}
__device__ __forceinline__ unsigned smaddr(const void* p) {
    return (unsigned)__cvta_generic_to_shared(p);
}
__device__ __forceinline__ void cp16(unsigned dst, const unsigned* src) {
    asm volatile("cp.async.ca.shared.global [%0], [%1], 16;" :: "r"(dst), "l"(src));
}
#define CP_COMMIT() asm volatile("cp.async.commit_group;")
#define CP_WAIT0()  asm volatile("cp.async.wait_group 0;")

// ---- fast activations via MUFU (ex2/rcp approx)
__device__ __forceinline__ float fast_ex2(float x) {
    float y; asm("ex2.approx.f32 %0, %1;" : "=f"(y) : "f"(x)); return y;
}
__device__ __forceinline__ float fast_rcp(float x) {
    float y; asm("rcp.approx.f32 %0, %1;" : "=f"(y) : "f"(x)); return y;
}
__device__ __forceinline__ float fast_sigmoid(float x) {
    return fast_rcp(1.f + fast_ex2(-1.4426950408889634f * x));
}
__device__ __forceinline__ float fast_tanh(float x) {
    return 2.f * fast_rcp(1.f + fast_ex2(-2.8853900817779268f * x)) - 1.f;
}

// pack two floats into fp16x2 hi and lo components
__device__ __forceinline__ void split_pack(float a, float b, unsigned& h, unsigned& l) {
    __half ah = __float2half(a), bh = __float2half(b);
    float ar = a - __half2float(ah), br = b - __half2float(bh);
    __half2 th; th.x = ah; th.y = bh; h = *(unsigned*)&th;
    __half2 tl; tl.x = __float2half(ar); tl.y = __float2half(br);
    l = *(unsigned*)&tl;
}
__device__ __forceinline__ unsigned pack1(float a, float b) {
    __half2 t; t.x = __float2half(a); t.y = __float2half(b);
    return *(unsigned*)&t;
}
__device__ __forceinline__ float fp_half(unsigned u, int hi) {
    __half2 t = *(__half2*)&u;
    return hi ? __half2float(t.y) : __half2float(t.x);
}

// ---------------------------------------------------------------------------
// prep: split weights into packed fp16 pairs (permuted for fragments)
// ---------------------------------------------------------------------------
__global__ void k_prep(const float* __restrict__ fw, const float* __restrict__ gw,
                       const float* __restrict__ rw, const float* __restrict__ sw,
                       const float* __restrict__ e1w)
{
    int i = blockIdx.x, tid = threadIdx.x;
    if (i < 40) {
        for (int l = tid; l < 2048; l += 256) {
            int s = l >> 5, k2 = l & 31;
            int c = ((s >> 4) << 3) + (s & 7);
            int isg = (s >> 3) & 1;
            const float* src = (isg ? gw : fw) + i * 2048;
            int k0 = 2 * k2;
            float v0 = src[(c * 32 + (k0 & 31)) * 2 + (k0 >> 5)];
            float v1 = src[(c * 32 + ((k0 + 1) & 31)) * 2 + ((k0 + 1) >> 5)];
            g_w1h[i * 2048 + l] = pack1(v0, v1);
        }
        for (int l = tid; l < 512; l += 256) {
            int r = l >> 4, p = l & 15;
            int t = r >> 4, s = r & 15;
            int chan = t * 16 + (s & 7) * 2 + (s >> 3);
            int klo = ((p >> 3) << 4) + (p & 7);       // (c, c+8) pairing
            float v0 = rw[i * 1024 + chan * 32 + klo];
            float v1 = rw[i * 1024 + chan * 32 + klo + 8];
            unsigned h, lo;
            split_pack(v0, v1, h, lo);
            g_wrh[i * 512 + l] = h;
            g_wrl[i * 512 + l] = lo;
        }
    } else {
        int bi = i - 40;  // 0..7
        for (int l = bi * 256 + tid; l < 163840; l += 2048) {
            int og = l >> 4, p = l & 15;
            int klo = ((p >> 3) << 4) + (p & 7);       // (c, c+8) pairing
            g_swf[l] = pack1(sw[og * 32 + klo], sw[og * 32 + klo + 8]);
        }
        for (int l = bi * 256 + tid; l < 32768; l += 2048) {
            int o = l >> 7, p = l & 127;
            int rlo = ((p >> 3) << 4) + (p & 7);       // (r, r+8) pairing
            g_e1fh[l] = pack1(e1w[o * 256 + rlo], e1w[o * 256 + rlo + 8]);
        }
    }
}

// ---------------------------------------------------------------------------
// start conv: x0[c][t*16+b] = sum_f sw[c][f] * input[b][f][t]; emits uint2{hi,lo}
// ---------------------------------------------------------------------------
__global__ void k_start(const float* __restrict__ in, const float* __restrict__ sw,
                        uint2* __restrict__ xo)
{
    __shared__ float s_w[4096];
    __shared__ float s_in[16 * 272];
    int tid = threadIdx.x;               // 256
    for (int l = tid; l < 4096; l += 256) s_w[l] = sw[l];
    int t0 = blockIdx.x * 16;
    int b = tid & 15, dt = tid >> 4;
    float acc[32];
#pragma unroll
    for (int c = 0; c < 32; c++) acc[c] = 0.f;
    int tt = tid & 15, rhalf = tid >> 4;
    for (int fc = 0; fc < 8; fc++) {
        __syncthreads();
#pragma unroll
        for (int pass = 0; pass < 16; pass++) {
            int row = pass * 16 + rhalf;
            int bb = row >> 4, ff = row & 15;
            s_in[ff * 272 + tt * 17 + bb] =
                in[(bb * 128 + fc * 16 + ff) * 16384 + t0 + tt];
        }
        __syncthreads();
#pragma unroll
        for (int f = 0; f < 16; f++) {
            float v = s_in[f * 272 + dt * 17 + b];
#pragma unroll
            for (int c = 0; c < 32; c++)
                acc[c] += s_w[c * 128 + fc * 16 + f] * v;
        }
    }
    int m = t0 * 16 + tid;
#pragma unroll
    for (int c2 = 0; c2 < 16; c2++) {
        unsigned H, L;
        split_pack(acc[2 * c2], acc[2 * c2 + 1], H, L);
        xo[(size_t)c2 * XLD + m] = make_uint2(H, L);
    }
}

// ---------------------------------------------------------------------------
// fused dilated layer (UNCHANGED from R13)
// ---------------------------------------------------------------------------
__global__ void __launch_bounds__(256, 4)
k_layer(const uint2* __restrict__ xin, uint2* __restrict__ xout,
        unsigned* __restrict__ ytf, int layer,
        int Min, int Mout, int P, int S, int ofs)
{
    extern __shared__ unsigned smu[];
    unsigned* Wh  = smu;
    unsigned* Rh  = smu + 2304;
    unsigned* Rl  = smu + 2944;
    unsigned* Xth = smu + 3584;
    unsigned* Xtl = smu + 8192;

    int tid = threadIdx.x;          // 256
    int m0 = blockIdx.x * 128;
    int lane = tid & 31, w = tid >> 5;
    int grp = lane >> 2, t4 = lane & 3;
    unsigned lr = ((lane >> 3) & 1) * 8 + (lane & 7);
    unsigned lc = (lane >> 4) * 4;
    int bm = lane >> 3, br = lane & 7;
    unsigned bloff = ((unsigned)((bm >> 1) * 8 + br)) * 36 + (unsigned)(bm & 1) * 4;

    const unsigned* wsh = g_w1h + layer * 2048;
    for (int l = tid; l < 512; l += 256) {
        int row = l >> 3, q = (l & 7) * 4;
        *(uint4*)&Wh[row * 36 + q] = *(const uint4*)&wsh[row * 32 + q];
    }
    const unsigned* rsh = g_wrh + layer * 512;
    const unsigned* rsl = g_wrl + layer * 512;
    for (int l = tid; l < 128; l += 256) {
        int row = l >> 2, q = (l & 3) * 4;
        *(uint4*)&Rh[row * 20 + q] = *(const uint4*)&rsh[row * 16 + q];
        *(uint4*)&Rl[row * 20 + q] = *(const uint4*)&rsl[row * 16 + q];
    }

    for (int v = tid; v < 1024; v += 256) {
        int g = v >> 7;
        int p = v & 127;
        int tap = g >> 2;
        int ch2b = (g & 3) * 4;
        int off = tap ? (S - P) : -P;
        int idx = m0 + p + off;
        uint4 H, L;
        if (idx >= 0 && idx < Min) {
            const uint2* px = xin + idx;
            uint2 v0 = px[(size_t)(ch2b    ) * XLD];
            uint2 v1 = px[(size_t)(ch2b + 1) * XLD];
            uint2 v2 = px[(size_t)(ch2b + 2) * XLD];
            uint2 v3 = px[(size_t)(ch2b + 3) * XLD];
            H.x = v0.x; L.x = v0.y;
            H.y = v1.x; L.y = v1.y;
            H.z = v2.x; L.z = v2.y;
            H.w = v3.x; L.w = v3.y;
        } else {
            H.x = H.y = H.z = H.w = 0u;
            L.x = L.y = L.z = L.w = 0u;
        }
        *(uint4*)&Xth[p * 36 + g * 4] = H;
        *(uint4*)&Xtl[p * 36 + g * 4] = L;
    }
    __syncthreads();

    int wr1 = w >> 2, wc1 = w & 3;
    unsigned whb = smaddr(Wh) + ((wr1 * 32 + lr) * 36 + lc) * 4;
    unsigned xhb = smaddr(Xth), xlb = smaddr(Xtl);
    float d[2][4][4];
#pragma unroll
    for (int a = 0; a < 2; a++)
#pragma unroll
        for (int b = 0; b < 4; b++)
#pragma unroll
            for (int c = 0; c < 4; c++) d[a][b][c] = 0.f;

#pragma unroll
    for (int kc = 0; kc < 4; kc++) {
        int k2b = kc * 8;
        unsigned ah[2][4];
#pragma unroll
        for (int mf = 0; mf < 2; mf++)
            ldsm_x4(ah[mf], whb + (mf * 576 + k2b) * 4);
#pragma unroll
        for (int ntp = 0; ntp < 2; ntp++) {
            unsigned bo = (((unsigned)(wc1 * 32 + ntp * 16)) * 36 + k2b + bloff) * 4;
            unsigned qh[4], ql[4];
            ldsm_x4(qh, xhb + bo);
            ldsm_x4(ql, xlb + bo);
            unsigned bh0[2] = {qh[0], qh[1]}, bl0[2] = {ql[0], ql[1]};
            unsigned bh1[2] = {qh[2], qh[3]}, bl1[2] = {ql[2], ql[3]};
#pragma unroll
            for (int mf = 0; mf < 2; mf++) {
                mma16(d[mf][2 * ntp], ah[mf], bh0);
                mma16(d[mf][2 * ntp], ah[mf], bl0);
                mma16(d[mf][2 * ntp + 1], ah[mf], bh1);
                mma16(d[mf][2 * ntp + 1], ah[mf], bl1);
            }
        }
    }

    float yv[2][4][2];
#pragma unroll
    for (int mf = 0; mf < 2; mf++)
#pragma unroll
        for (int nt = 0; nt < 4; nt++) {
            yv[mf][nt][0] = fast_tanh(d[mf][nt][0]) * fast_sigmoid(d[mf][nt][2]);
            yv[mf][nt][1] = fast_tanh(d[mf][nt][1]) * fast_sigmoid(d[mf][nt][3]);
        }
    __syncthreads();

    {
        int p_idx = wr1 * 8 + grp;
#pragma unroll
        for (int nt = 0; nt < 4; nt++) {
            int col = wc1 * 32 + nt * 8 + 2 * t4;
            unsigned H, L;
            split_pack(yv[0][nt][0], yv[1][nt][0], H, L);
            Xth[col * 36 + p_idx] = H;
            Xtl[col * 36 + p_idx] = L;
            split_pack(yv[0][nt][1], yv[1][nt][1], H, L);
            Xth[(col + 1) * 36 + p_idx] = H;
            Xtl[(col + 1) * 36 + p_idx] = L;
        }
    }
    __syncthreads();

    for (int v = tid; v < 512; v += 256) {
        int p = v >> 2, qg = v & 3;
        int m = m0 + p;
        if (m >= ofs && m < Mout)
            *(uint4*)&ytf[(size_t)(m - ofs) * 16 + qg * 4] = *(uint4*)&Xth[p * 36 + qg * 4];
    }

    int wr2 = w >> 2, wc2 = w & 3;
    unsigned rhb = smaddr(Rh) + ((wr2 * 16 + lr) * 20 + lc) * 4;
    unsigned rlb = smaddr(Rl) + ((wr2 * 16 + lr) * 20 + lc) * 4;
    float e[4][4];
#pragma unroll
    for (int a = 0; a < 4; a++)
#pragma unroll
        for (int b = 0; b < 4; b++) e[a][b] = 0.f;

#pragma unroll
    for (int kc = 0; kc < 2; kc++) {
        int k2b = kc * 8;
        unsigned ah[4], al[4];
        ldsm_x4(ah, rhb + k2b * 4);
        ldsm_x4(al, rlb + k2b * 4);
#pragma unroll
        for (int ntp = 0; ntp < 2; ntp++) {
            unsigned bo = (((unsigned)(wc2 * 32 + ntp * 16)) * 36 + k2b + bloff) * 4;
            unsigned qh[4], ql[4];
            ldsm_x4(qh, xhb + bo);
            ldsm_x4(ql, xlb + bo);
            unsigned bh0[2] = {qh[0], qh[1]}, bl0[2] = {ql[0], ql[1]};
            unsigned bh1[2] = {qh[2], qh[3]}, bl1[2] = {ql[2], ql[3]};
            mma16(e[2 * ntp], ah, bh0);
            mma16(e[2 * ntp], ah, bl0);
            mma16(e[2 * ntp], al, bh0);
            mma16(e[2 * ntp + 1], ah, bh1);
            mma16(e[2 * ntp + 1], ah, bl1);
            mma16(e[2 * ntp + 1], al, bh1);
        }
    }
    {
        int ch2 = wr2 * 8 + grp;
        int colB = 16 + ch2;
#pragma unroll
        for (int nt = 0; nt < 4; nt++) {
            int col = wc2 * 32 + nt * 8 + 2 * t4;
            int m = m0 + col;
            if (m < Mout) {
                unsigned rh0 = Xth[col * 36 + colB],       rl0 = Xtl[col * 36 + colB];
                unsigned rh1 = Xth[(col + 1) * 36 + colB], rl1 = Xtl[(col + 1) * 36 + colB];
                float v0e = e[nt][0] + fp_half(rh0, 0) + fp_half(rl0, 0);
                float v0o = e[nt][2] + fp_half(rh0, 1) + fp_half(rl0, 1);
                float v1e = e[nt][1] + fp_half(rh1, 0) + fp_half(rl1, 0);
                float v1o = e[nt][3] + fp_half(rh1, 1) + fp_half(rl1, 1);
                unsigned H, L;
                split_pack(v0e, v0o, H, L);
                xout[(size_t)ch2 * XLD + m] = make_uint2(H, L);
                split_pack(v1e, v1o, H, L);
                xout[(size_t)ch2 * XLD + m + 1] = make_uint2(H, L);
            }
        }
    }
}

// ---------------------------------------------------------------------------
// fused tail v3: 128 positions/block, 512 threads.
// Phase A: ldmatrix operands.  H stored [col 128][k2 128 + pad4] (pairs (r,r+8)).
// Phase B: 2-term (e1 hi only), all operands via ldmatrix.
// smem (u32): [2] x (Bst[128][20] + Ws[256][20]) = 15360 (phase B: 2 x Eh[256][12])
//             Hh[128][132] @15360, Hl @32256 -> 49152 u32 = 196608 B
// ---------------------------------------------------------------------------
__global__ void __launch_bounds__(512, 1)
k_tail(const unsigned* __restrict__ ybf,
       const float* __restrict__ e1b, const float* __restrict__ e2w,
       const float* __restrict__ e2b, float* __restrict__ out)
{
    extern __shared__ unsigned smu[];
    unsigned* Hh = smu + 15360;
    unsigned* Hl = smu + 32256;
    float* part = (float*)smu;

    int tid = threadIdx.x;     // 512
    int lane = tid & 31, w = tid >> 5;
    int wm = w >> 1, wn = w & 1;
    int grp = lane >> 2, t4 = lane & 3;
    int p0 = blockIdx.x * 128;
    unsigned smb = smaddr(smu);
    unsigned lr = ((lane >> 3) & 1) * 8 + (lane & 7);
    unsigned lc = (lane >> 4) * 4;
    int bm = lane >> 3, br = lane & 7;
    unsigned bl20  = ((unsigned)((bm >> 1) * 8 + br)) * 20  + (unsigned)(bm & 1) * 4;
    unsigned bl132 = ((unsigned)((bm >> 1) * 8 + br)) * 132 + (unsigned)(bm & 1) * 4;

    float d[2][8][4];
#pragma unroll
    for (int mt = 0; mt < 2; mt++)
#pragma unroll
        for (int nt = 0; nt < 8; nt++)
#pragma unroll
            for (int j = 0; j < 4; j++) d[mt][nt][j] = 0.f;

    int sp = tid >> 2, sq = (tid & 3) * 4;

    {   // prefetch kc = 0
        cp16(smb + (0 * 7680 + sp * 20 + sq) * 4,
             &ybf[(size_t)(p0 + sp) * 16 + sq]);
        for (int l = tid; l < 1024; l += 512) {
            int row = l >> 2, qg = (l & 3) * 4;
            cp16(smb + (0 * 7680 + 2560 + row * 20 + qg) * 4,
                 &g_swf[row * 16 + qg]);
        }
        CP_COMMIT();
    }
    for (int kc = 0; kc < 40; kc++) {
        CP_WAIT0();
        __syncthreads();
        if (kc < 39) {
            int nb = (kc + 1) & 1;
            cp16(smb + (nb * 7680 + sp * 20 + sq) * 4,
                 &ybf[(size_t)(kc + 1) * 16 * FINAL + (size_t)(p0 + sp) * 16 + sq]);
            for (int l = tid; l < 1024; l += 512) {
                int row = l >> 2, qg = (l & 3) * 4;
                cp16(smb + (nb * 7680 + 2560 + row * 20 + qg) * 4,
                     &g_swf[((kc + 1) * 256 + row) * 16 + qg]);
            }
            CP_COMMIT();
        }
        unsigned bcb = smb + ((kc & 1) * 7680) * 4;   // Bst base (bytes)
        unsigned wcb = bcb + 2560 * 4;                // Ws base
#pragma unroll
        for (int ck = 0; ck < 2; ck++) {
            int k2b = ck * 8;
            unsigned a0[4], a1[4];
            ldsm_x4(a0, wcb + (((unsigned)(wm * 32) + lr) * 20 + k2b + lc) * 4);
            ldsm_x4(a1, wcb + (((unsigned)(wm * 32 + 16) + lr) * 20 + k2b + lc) * 4);
#pragma unroll
            for (int ntp = 0; ntp < 4; ntp++) {
                unsigned q[4];
                ldsm_x4(q, bcb + (((unsigned)(wn * 64 + ntp * 16)) * 20 + k2b + bl20) * 4);
                unsigned b0[2] = {q[0], q[1]}, b1[2] = {q[2], q[3]};
                mma16(d[0][2 * ntp], a0, b0);
                mma16(d[1][2 * ntp], a1, b0);
                mma16(d[0][2 * ntp + 1], a0, b1);
                mma16(d[1][2 * ntp + 1], a1, b1);
            }
        }
    }

    // ---- relu + split into Hh/Hl: in-thread pair (r, r+8), STS.32 ----
    __syncthreads();
#pragma unroll
    for (int mt = 0; mt < 2; mt++) {
        int k2 = (wm * 2 + mt) * 8 + grp;
#pragma unroll
        for (int nt = 0; nt < 8; nt++) {
            int col = wn * 64 + nt * 8 + 2 * t4;
            float v0 = d[mt][nt][0]; v0 = v0 > 0.f ? v0 : 0.f;
            float v2 = d[mt][nt][2]; v2 = v2 > 0.f ? v2 : 0.f;
            float v1 = d[mt][nt][1]; v1 = v1 > 0.f ? v1 : 0.f;
            float v3 = d[mt][nt][3]; v3 = v3 > 0.f ? v3 : 0.f;
            unsigned H, L;
            split_pack(v0, v2, H, L);
            Hh[col * 132 + k2] = H;  Hl[col * 132 + k2] = L;
            split_pack(v1, v3, H, L);
            Hh[(col + 1) * 132 + k2] = H;  Hl[(col + 1) * 132 + k2] = L;
        }
    }

#pragma unroll
    for (int mt = 0; mt < 2; mt++)
#pragma unroll
        for (int nt = 0; nt < 8; nt++)
#pragma unroll
            for (int j = 0; j < 4; j++) d[mt][nt][j] = 0.f;

    // ---- phase B: e1 GEMM (256x128, K=256), 2-term, double-buffered Eh ----
    {
        __syncthreads();     // H writes complete; weight region free
        int row = tid >> 1, qg = (tid & 1) * 4;
        cp16(smb + (row * 12 + qg) * 4, &g_e1fh[row * 128 + qg]);
        CP_COMMIT();
    }
    unsigned hhB = smaddr(Hh), hlB = smaddr(Hl);
    for (int kk = 0; kk < 16; kk++) {
        CP_WAIT0();
        __syncthreads();
        if (kk < 15) {
            int nb = (kk + 1) & 1;
            int row = tid >> 1, qg = (tid & 1) * 4;
            cp16(smb + (nb * 3072 + row * 12 + qg) * 4,
                 &g_e1fh[row * 128 + (kk + 1) * 8 + qg]);
            CP_COMMIT();
        }
        unsigned ecb = smb + ((kk & 1) * 3072) * 4;
        unsigned ah0[4], ah1[4];
        ldsm_x4(ah0, ecb + (((unsigned)(wm * 32) + lr) * 12 + lc) * 4);
        ldsm_x4(ah1, ecb + (((unsigned)(wm * 32 + 16) + lr) * 12 + lc) * 4);
#pragma unroll
        for (int ntp = 0; ntp < 4; ntp++) {
            unsigned base = (((unsigned)(wn * 64 + ntp * 16)) * 132 + kk * 8 + bl132) * 4;
            unsigned qh[4], ql[4];
            ldsm_x4(qh, hhB + base);
            ldsm_x4(ql, hlB + base);
            unsigned bh0[2] = {qh[0], qh[1]}, bl0[2] = {ql[0], ql[1]};
            unsigned bh1[2] = {qh[2], qh[3]}, bl1[2] = {ql[2], ql[3]};
            mma16(d[0][2 * ntp], ah0, bh0);
            mma16(d[0][2 * ntp], ah0, bl0);
            mma16(d[1][2 * ntp], ah1, bh0);
            mma16(d[1][2 * ntp], ah1, bl0);
            mma16(d[0][2 * ntp + 1], ah0, bh1);
            mma16(d[0][2 * ntp + 1], ah0, bl1);
            mma16(d[1][2 * ntp + 1], ah1, bh1);
            mma16(d[1][2 * ntp + 1], ah1, bl1);
        }
    }

    // ---- epilogue: bias + relu + e2 dot + reduce ----
    int r0 = wm * 32 + grp;
    float eb0 = e1b[r0],      eb1 = e1b[r0 + 8];
    float eb2 = e1b[r0 + 16], eb3 = e1b[r0 + 24];
    float ew0 = e2w[r0],      ew1 = e2w[r0 + 8];
    float ew2 = e2w[r0 + 16], ew3 = e2w[r0 + 24];

    float pc[16];
#pragma unroll
    for (int nt = 0; nt < 8; nt++) {
#pragma unroll
        for (int j = 0; j < 2; j++) {
            float h0 = d[0][nt][j]     + eb0; h0 = h0 > 0.f ? h0 : 0.f;
            float h1 = d[0][nt][2 + j] + eb1; h1 = h1 > 0.f ? h1 : 0.f;
            float h2 = d[1][nt][j]     + eb2; h2 = h2 > 0.f ? h2 : 0.f;
            float h3 = d[1][nt][2 + j] + eb3; h3 = h3 > 0.f ? h3 : 0.f;
            pc[nt * 2 + j] = ew0 * h0 + ew1 * h1 + ew2 * h2 + ew3 * h3;
        }
    }
#pragma unroll
    for (int off = 16; off >= 4; off >>= 1)
#pragma unroll
        for (int t = 0; t < 16; t++)
            pc[t] += __shfl_xor_sync(0xffffffff, pc[t], off);

    if (lane < 4) {
#pragma unroll
        for (int nt = 0; nt < 8; nt++) {
            part[wm * 128 + wn * 64 + nt * 8 + 2 * lane]     = pc[nt * 2];
            part[wm * 128 + wn * 64 + nt * 8 + 2 * lane + 1] = pc[nt * 2 + 1];
        }
    }
    __syncthreads();
    if (tid < 128) {
        float s = e2b[0];
#pragma unroll
        for (int ww = 0; ww < 8; ww++) s += part[ww * 128 + tid];
        int p = p0 + tid;
        out[(p & 15) * TOUT + (p >> 4)] = s;
    }
}

// ---------------------------------------------------------------------------
extern "C" void kernel_launch(void* const* d_in, const int* in_sizes, int n_in,
                              void* d_out, int out_size)
{
    const float* input    = (const float*)d_in[0];
    const float* start_w  = (const float*)d_in[1];
    const float* filter_w = (const float*)d_in[2];
    const float* gate_w   = (const float*)d_in[3];
    const float* res_w    = (const float*)d_in[4];
    const float* skip_w   = (const float*)d_in[5];
    const float* e1w      = (const float*)d_in[6];
    const float* e1b      = (const float*)d_in[7];
    const float* e2w      = (const float*)d_in[8];
    const float* e2b      = (const float*)d_in[9];
    float* out = (float*)d_out;
    (void)in_sizes; (void)n_in; (void)out_size;

    static int attr_done = 0;
    if (!attr_done) {
        cudaFuncSetAttribute(k_layer, cudaFuncAttributeMaxDynamicSharedMemorySize, 51200);
        cudaFuncSetAttribute(k_tail,  cudaFuncAttributeMaxDynamicSharedMemorySize, 196608);
        attr_done = 1;
    }

    uint2 *xa, *xb;
    unsigned *ybf;
    cudaGetSymbolAddress((void**)&xa, g_xa);
    cudaGetSymbolAddress((void**)&xb, g_xb);
    cudaGetSymbolAddress((void**)&ybf, g_ybf);

    k_prep<<<48, 256>>>(filter_w, gate_w, res_w, skip_w, e1w);
    k_start<<<1024, 256>>>(input, start_w, xa);

    uint2 *cur = xa, *nxt = xb;
    for (int i = 0; i < 40; i++) {
        int b = i / 10, k = i % 10;
        int Mb = 262144 - 8192 * b;
        int Min, Mout, P, S;
        if (k == 0) { Min = Mb; Mout = Mb - 16; P = 0; S = 16; }
        else {
            int d = 1 << k;
            Min = Mb - 8 * d;
            Mout = Mb - 16 * d;
            P = 8 * d;
            S = 16 * d;
        }
        int ofs = Mout - FINAL;
        int grid = (Mout + 127) / 128;
        k_layer<<<grid, 256, 51200>>>(cur, nxt,
                                      ybf + (size_t)i * 16 * FINAL,
                                      i, Min, Mout, P, S, ofs);
        uint2* t = cur; cur = nxt; nxt = t;
    }

    k_tail<<<FINAL / 128, 512, 196608>>>(ybf, e1b, e2w, e2b, out);
}

// round 15
// speedup vs baseline: 5.8282x; 1.0656x over previous
#include <cuda_runtime.h>
#include <cuda_fp16.h>
#include <math.h>

#define FINAL 229376        // 16 * 14336 final flat length
#define XLD   262144        // fixed channel stride for x buffers
#define TOUT  14336

// Scratch (device globals; no allocation anywhere)
__device__ uint2    g_xa[16 * XLD];                       // x ping: {hi,lo} fp16x2 pairs
__device__ uint2    g_xb[16 * XLD];                       // x pong
__device__ unsigned g_ybf[640 * FINAL];     // y hi: per layer [FINAL pos][16 k2] (pairs (c,c+8))
__device__ unsigned g_w1h[40 * 2048];                     // [s=64][k2=32] per layer (hi only)
__device__ unsigned g_wrh[40 * 512],  g_wrl[40 * 512];    // [row=32][k2=16] (rows+k permuted)
__device__ unsigned g_swf[163840];                        // skip_w fp16 [40*256][k2=16] (pairs (c,c+8))
__device__ unsigned g_e1fh[32768];                        // e1w fp16 hi [256][k2=128] (pairs (r,r+8))
__device__ unsigned g_s0h[2048], g_s0l[2048];             // start_w split [32 rows perm][64 k2]

// ---------------------------------------------------------------------------
// helpers (fp16 limbs)
// ---------------------------------------------------------------------------
__device__ __forceinline__ void mma16(float d[4], const unsigned a[4], const unsigned b[2]) {
    asm volatile(
        "mma.sync.aligned.m16n8k16.row.col.f32.f16.f16.f32 "
        "{%0,%1,%2,%3},{%4,%5,%6,%7},{%8,%9},{%0,%1,%2,%3};"
        : "+f"(d[0]), "+f"(d[1]), "+f"(d[2]), "+f"(d[3])
        : "r"(a[0]), "r"(a[1]), "r"(a[2]), "r"(a[3]), "r"(b[0]), "r"(b[1]));
}
__device__ __forceinline__ void ldsm_x4(unsigned a[4], unsigned saddr) {
    asm volatile("ldmatrix.sync.aligned.m8n8.x4.shared.b16 {%0,%1,%2,%3}, [%4];"
        : "=r"(a[0]), "=r"(a[1]), "=r"(a[2]), "=r"(a[3]) : "r"(saddr));
}
__device__ __forceinline__ unsigned smaddr(const void* p) {
    return (unsigned)__cvta_generic_to_shared(p);
}
__device__ __forceinline__ void cp16(unsigned dst, const unsigned* src) {
    asm volatile("cp.async.ca.shared.global [%0], [%1], 16;" :: "r"(dst), "l"(src));
}
#define CP_COMMIT() asm volatile("cp.async.commit_group;")
#define CP_WAIT0()  asm volatile("cp.async.wait_group 0;")

// ---- fast activations via MUFU (ex2/rcp approx)
__device__ __forceinline__ float fast_ex2(float x) {
    float y; asm("ex2.approx.f32 %0, %1;" : "=f"(y) : "f"(x)); return y;
}
__device__ __forceinline__ float fast_rcp(float x) {
    float y; asm("rcp.approx.f32 %0, %1;" : "=f"(y) : "f"(x)); return y;
}
__device__ __forceinline__ float fast_sigmoid(float x) {
    return fast_rcp(1.f + fast_ex2(-1.4426950408889634f * x));
}
__device__ __forceinline__ float fast_tanh(float x) {
    return 2.f * fast_rcp(1.f + fast_ex2(-2.8853900817779268f * x)) - 1.f;
}

// pack two floats into fp16x2 hi and lo components
__device__ __forceinline__ void split_pack(float a, float b, unsigned& h, unsigned& l) {
    __half ah = __float2half(a), bh = __float2half(b);
    float ar = a - __half2float(ah), br = b - __half2float(bh);
    __half2 th; th.x = ah; th.y = bh; h = *(unsigned*)&th;
    __half2 tl; tl.x = __float2half(ar); tl.y = __float2half(br);
    l = *(unsigned*)&tl;
}
__device__ __forceinline__ unsigned pack1(float a, float b) {
    __half2 t; t.x = __float2half(a); t.y = __float2half(b);
    return *(unsigned*)&t;
}
__device__ __forceinline__ float fp_half(unsigned u, int hi) {
    __half2 t = *(__half2*)&u;
    return hi ? __half2float(t.y) : __half2float(t.x);
}

// ---------------------------------------------------------------------------
// prep: split weights into packed fp16 pairs (permuted for fragments)
// ---------------------------------------------------------------------------
__global__ void k_prep(const float* __restrict__ fw, const float* __restrict__ gw,
                       const float* __restrict__ rw, const float* __restrict__ sw,
                       const float* __restrict__ e1w, const float* __restrict__ s0w)
{
    int i = blockIdx.x, tid = threadIdx.x;
    if (i < 40) {
        for (int l = tid; l < 2048; l += 256) {
            int s = l >> 5, k2 = l & 31;
            int c = ((s >> 4) << 3) + (s & 7);
            int isg = (s >> 3) & 1;
            const float* src = (isg ? gw : fw) + i * 2048;
            int k0 = 2 * k2;
            float v0 = src[(c * 32 + (k0 & 31)) * 2 + (k0 >> 5)];
            float v1 = src[(c * 32 + ((k0 + 1) & 31)) * 2 + ((k0 + 1) >> 5)];
            g_w1h[i * 2048 + l] = pack1(v0, v1);
        }
        for (int l = tid; l < 512; l += 256) {
            int r = l >> 4, p = l & 15;
            int t = r >> 4, s = r & 15;
            int chan = t * 16 + (s & 7) * 2 + (s >> 3);
            int klo = ((p >> 3) << 4) + (p & 7);       // (c, c+8) pairing
            float v0 = rw[i * 1024 + chan * 32 + klo];
            float v1 = rw[i * 1024 + chan * 32 + klo + 8];
            unsigned h, lo;
            split_pack(v0, v1, h, lo);
            g_wrh[i * 512 + l] = h;
            g_wrl[i * 512 + l] = lo;
        }
    } else {
        int bi = i - 40;  // 0..7
        for (int l = bi * 256 + tid; l < 163840; l += 2048) {
            int og = l >> 4, p = l & 15;
            int klo = ((p >> 3) << 4) + (p & 7);       // (c, c+8) pairing
            g_swf[l] = pack1(sw[og * 32 + klo], sw[og * 32 + klo + 8]);
        }
        for (int l = bi * 256 + tid; l < 32768; l += 2048) {
            int o = l >> 7, p = l & 127;
            int rlo = ((p >> 3) << 4) + (p & 7);       // (r, r+8) pairing
            g_e1fh[l] = pack1(e1w[o * 256 + rlo], e1w[o * 256 + rlo + 8]);
        }
        for (int l = bi * 256 + tid; l < 2048; l += 2048) {
            int r = l >> 6, k2 = l & 63;
            int t = r >> 4, s = r & 15;
            int chan = t * 16 + (s & 7) * 2 + (s >> 3);  // row perm as res_w
            float v0 = s0w[chan * 128 + 2 * k2];
            float v1 = s0w[chan * 128 + 2 * k2 + 1];
            unsigned h, lo;
            split_pack(v0, v1, h, lo);
            g_s0h[l] = h; g_s0l[l] = lo;
        }
    }
}

// ---------------------------------------------------------------------------
// start conv (mma, 3-term fp16 split): out 32 x 256 positions per block.
// dyn smem (u32): Wh[32][68]@0, Wl@2176, Xh[256][12]@4352, Xl@7424,
//                 s_in (float)[16*272]@10496  -> 14848 u32 = 59392 B
// ---------------------------------------------------------------------------
__global__ void __launch_bounds__(256, 2)
k_start(const float* __restrict__ in, uint2* __restrict__ xo)
{
    extern __shared__ unsigned smk[];
    unsigned* Wh = smk;
    unsigned* Wl = smk + 2176;
    unsigned* Xh = smk + 4352;
    unsigned* Xl = smk + 7424;
    float* s_in  = (float*)(smk + 10496);

    int tid = threadIdx.x;               // 256
    int m0 = blockIdx.x * 256;
    int t0 = blockIdx.x * 16;
    int lane = tid & 31, w = tid >> 5;
    int wm = w >> 2, wn2 = w & 3;
    int grp = lane >> 2, t4 = lane & 3;
    unsigned lr = ((lane >> 3) & 1) * 8 + (lane & 7);
    unsigned lc = (lane >> 4) * 4;
    int bm = lane >> 3, br = lane & 7;
    unsigned bl12 = ((unsigned)((bm >> 1) * 8 + br)) * 12 + (unsigned)(bm & 1) * 4;

    // stage weights (32x64 -> pad 68)
    for (int l = tid; l < 512; l += 256) {
        int row = l >> 4, q = (l & 15) * 4;
        *(uint4*)&Wh[row * 68 + q] = *(const uint4*)&g_s0h[row * 64 + q];
        *(uint4*)&Wl[row * 68 + q] = *(const uint4*)&g_s0l[row * 64 + q];
    }

    float d[8][4];
#pragma unroll
    for (int a = 0; a < 8; a++)
#pragma unroll
        for (int b = 0; b < 4; b++) d[a][b] = 0.f;

    int tt = tid & 15, rhalf = tid >> 4;
    unsigned whA = smaddr(Wh) + ((wm * 16 + lr) * 68 + lc) * 4;
    unsigned wlA = smaddr(Wl) + ((wm * 16 + lr) * 68 + lc) * 4;
    unsigned xhB = smaddr(Xh), xlB = smaddr(Xl);

    for (int fc = 0; fc < 8; fc++) {
        __syncthreads();     // protect Xh/Xl from previous mma; s_in free
        // ---- stage s_in (coalesced, proven pattern) ----
#pragma unroll
        for (int pass = 0; pass < 16; pass++) {
            int row = pass * 16 + rhalf;
            int bb = row >> 4, ff = row & 15;
            s_in[ff * 272 + tt * 17 + bb] =
                in[(bb * 128 + fc * 16 + ff) * 16384 + t0 + tt];
        }
        __syncthreads();
        // ---- transpose + split to Xh/Xl [pos][k2] ----
        for (int l = tid; l < 2048; l += 256) {
            int pos = l & 255, k2l = l >> 8;
            int ptt = pos >> 4, pbb = pos & 15;
            float f0 = s_in[(2 * k2l) * 272 + ptt * 17 + pbb];
            float f1 = s_in[(2 * k2l + 1) * 272 + ptt * 17 + pbb];
            unsigned H, L;
            split_pack(f0, f1, H, L);
            Xh[pos * 12 + k2l] = H;
            Xl[pos * 12 + k2l] = L;
        }
        __syncthreads();
        // ---- mma: one k16 chunk, 3-term ----
        unsigned ah[4], al[4];
        ldsm_x4(ah, whA + (fc * 8) * 4);
        ldsm_x4(al, wlA + (fc * 8) * 4);
#pragma unroll
        for (int ntp = 0; ntp < 4; ntp++) {
            unsigned base = (((unsigned)(wn2 * 64 + ntp * 16)) * 12 + bl12) * 4;
            unsigned qh[4], ql[4];
            ldsm_x4(qh, xhB + base);
            ldsm_x4(ql, xlB + base);
            unsigned bh0[2] = {qh[0], qh[1]}, bl0[2] = {ql[0], ql[1]};
            unsigned bh1[2] = {qh[2], qh[3]}, bl1[2] = {ql[2], ql[3]};
            mma16(d[2 * ntp], ah, bh0);
            mma16(d[2 * ntp], ah, bl0);
            mma16(d[2 * ntp], al, bh0);
            mma16(d[2 * ntp + 1], ah, bh1);
            mma16(d[2 * ntp + 1], ah, bl1);
            mma16(d[2 * ntp + 1], al, bh1);
        }
    }

    // ---- epilogue: rows permuted -> thread holds adjacent channel pair ----
    {
        int c2 = wm * 8 + grp;
#pragma unroll
        for (int f = 0; f < 8; f++) {
            int col = wn2 * 64 + (f >> 1) * 16 + (f & 1) * 8 + 2 * t4;
            int m = m0 + col;
            unsigned H, L;
            split_pack(d[f][0], d[f][2], H, L);
            xo[(size_t)c2 * XLD + m] = make_uint2(H, L);
            split_pack(d[f][1], d[f][3], H, L);
            xo[(size_t)c2 * XLD + m + 1] = make_uint2(H, L);
        }
    }
}

// ---------------------------------------------------------------------------
// fused dilated layer (UNCHANGED from R14)
// ---------------------------------------------------------------------------
__global__ void __launch_bounds__(256, 4)
k_layer(const uint2* __restrict__ xin, uint2* __restrict__ xout,
        unsigned* __restrict__ ytf, int layer,
        int Min, int Mout, int P, int S, int ofs)
{
    extern __shared__ unsigned smu[];
    unsigned* Wh  = smu;
    unsigned* Rh  = smu + 2304;
    unsigned* Rl  = smu + 2944;
    unsigned* Xth = smu + 3584;
    unsigned* Xtl = smu + 8192;

    int tid = threadIdx.x;          // 256
    int m0 = blockIdx.x * 128;
    int lane = tid & 31, w = tid >> 5;
    int grp = lane >> 2, t4 = lane & 3;
    unsigned lr = ((lane >> 3) & 1) * 8 + (lane & 7);
    unsigned lc = (lane >> 4) * 4;
    int bm = lane >> 3, br = lane & 7;
    unsigned bloff = ((unsigned)((bm >> 1) * 8 + br)) * 36 + (unsigned)(bm & 1) * 4;

    const unsigned* wsh = g_w1h + layer * 2048;
    for (int l = tid; l < 512; l += 256) {
        int row = l >> 3, q = (l & 7) * 4;
        *(uint4*)&Wh[row * 36 + q] = *(const uint4*)&wsh[row * 32 + q];
    }
    const unsigned* rsh = g_wrh + layer * 512;
    const unsigned* rsl = g_wrl + layer * 512;
    for (int l = tid; l < 128; l += 256) {
        int row = l >> 2, q = (l & 3) * 4;
        *(uint4*)&Rh[row * 20 + q] = *(const uint4*)&rsh[row * 16 + q];
        *(uint4*)&Rl[row * 20 + q] = *(const uint4*)&rsl[row * 16 + q];
    }

    for (int v = tid; v < 1024; v += 256) {
        int g = v >> 7;
        int p = v & 127;
        int tap = g >> 2;
        int ch2b = (g & 3) * 4;
        int off = tap ? (S - P) : -P;
        int idx = m0 + p + off;
        uint4 H, L;
        if (idx >= 0 && idx < Min) {
            const uint2* px = xin + idx;
            uint2 v0 = px[(size_t)(ch2b    ) * XLD];
            uint2 v1 = px[(size_t)(ch2b + 1) * XLD];
            uint2 v2 = px[(size_t)(ch2b + 2) * XLD];
            uint2 v3 = px[(size_t)(ch2b + 3) * XLD];
            H.x = v0.x; L.x = v0.y;
            H.y = v1.x; L.y = v1.y;
            H.z = v2.x; L.z = v2.y;
            H.w = v3.x; L.w = v3.y;
        } else {
            H.x = H.y = H.z = H.w = 0u;
            L.x = L.y = L.z = L.w = 0u;
        }
        *(uint4*)&Xth[p * 36 + g * 4] = H;
        *(uint4*)&Xtl[p * 36 + g * 4] = L;
    }
    __syncthreads();

    int wr1 = w >> 2, wc1 = w & 3;
    unsigned whb = smaddr(Wh) + ((wr1 * 32 + lr) * 36 + lc) * 4;
    unsigned xhb = smaddr(Xth), xlb = smaddr(Xtl);
    float d[2][4][4];
#pragma unroll
    for (int a = 0; a < 2; a++)
#pragma unroll
        for (int b = 0; b < 4; b++)
#pragma unroll
            for (int c = 0; c < 4; c++) d[a][b][c] = 0.f;

#pragma unroll
    for (int kc = 0; kc < 4; kc++) {
        int k2b = kc * 8;
        unsigned ah[2][4];
#pragma unroll
        for (int mf = 0; mf < 2; mf++)
            ldsm_x4(ah[mf], whb + (mf * 576 + k2b) * 4);
#pragma unroll
        for (int ntp = 0; ntp < 2; ntp++) {
            unsigned bo = (((unsigned)(wc1 * 32 + ntp * 16)) * 36 + k2b + bloff) * 4;
            unsigned qh[4], ql[4];
            ldsm_x4(qh, xhb + bo);
            ldsm_x4(ql, xlb + bo);
            unsigned bh0[2] = {qh[0], qh[1]}, bl0[2] = {ql[0], ql[1]};
            unsigned bh1[2] = {qh[2], qh[3]}, bl1[2] = {ql[2], ql[3]};
#pragma unroll
            for (int mf = 0; mf < 2; mf++) {
                mma16(d[mf][2 * ntp], ah[mf], bh0);
                mma16(d[mf][2 * ntp], ah[mf], bl0);
                mma16(d[mf][2 * ntp + 1], ah[mf], bh1);
                mma16(d[mf][2 * ntp + 1], ah[mf], bl1);
            }
        }
    }

    float yv[2][4][2];
#pragma unroll
    for (int mf = 0; mf < 2; mf++)
#pragma unroll
        for (int nt = 0; nt < 4; nt++) {
            yv[mf][nt][0] = fast_tanh(d[mf][nt][0]) * fast_sigmoid(d[mf][nt][2]);
            yv[mf][nt][1] = fast_tanh(d[mf][nt][1]) * fast_sigmoid(d[mf][nt][3]);
        }
    __syncthreads();

    {
        int p_idx = wr1 * 8 + grp;
#pragma unroll
        for (int nt = 0; nt < 4; nt++) {
            int col = wc1 * 32 + nt * 8 + 2 * t4;
            unsigned H, L;
            split_pack(yv[0][nt][0], yv[1][nt][0], H, L);
            Xth[col * 36 + p_idx] = H;
            Xtl[col * 36 + p_idx] = L;
            split_pack(yv[0][nt][1], yv[1][nt][1], H, L);
            Xth[(col + 1) * 36 + p_idx] = H;
            Xtl[(col + 1) * 36 + p_idx] = L;
        }
    }
    __syncthreads();

    for (int v = tid; v < 512; v += 256) {
        int p = v >> 2, qg = v & 3;
        int m = m0 + p;
        if (m >= ofs && m < Mout)
            *(uint4*)&ytf[(size_t)(m - ofs) * 16 + qg * 4] = *(uint4*)&Xth[p * 36 + qg * 4];
    }

    int wr2 = w >> 2, wc2 = w & 3;
    unsigned rhb = smaddr(Rh) + ((wr2 * 16 + lr) * 20 + lc) * 4;
    unsigned rlb = smaddr(Rl) + ((wr2 * 16 + lr) * 20 + lc) * 4;
    float e[4][4];
#pragma unroll
    for (int a = 0; a < 4; a++)
#pragma unroll
        for (int b = 0; b < 4; b++) e[a][b] = 0.f;

#pragma unroll
    for (int kc = 0; kc < 2; kc++) {
        int k2b = kc * 8;
        unsigned ah[4], al[4];
        ldsm_x4(ah, rhb + k2b * 4);
        ldsm_x4(al, rlb + k2b * 4);
#pragma unroll
        for (int ntp = 0; ntp < 2; ntp++) {
            unsigned bo = (((unsigned)(wc2 * 32 + ntp * 16)) * 36 + k2b + bloff) * 4;
            unsigned qh[4], ql[4];
            ldsm_x4(qh, xhb + bo);
            ldsm_x4(ql, xlb + bo);
            unsigned bh0[2] = {qh[0], qh[1]}, bl0[2] = {ql[0], ql[1]};
            unsigned bh1[2] = {qh[2], qh[3]}, bl1[2] = {ql[2], ql[3]};
            mma16(e[2 * ntp], ah, bh0);
            mma16(e[2 * ntp], ah, bl0);
            mma16(e[2 * ntp], al, bh0);
            mma16(e[2 * ntp + 1], ah, bh1);
            mma16(e[2 * ntp + 1], ah, bl1);
            mma16(e[2 * ntp + 1], al, bh1);
        }
    }
    {
        int ch2 = wr2 * 8 + grp;
        int colB = 16 + ch2;
#pragma unroll
        for (int nt = 0; nt < 4; nt++) {
            int col = wc2 * 32 + nt * 8 + 2 * t4;
            int m = m0 + col;
            if (m < Mout) {
                unsigned rh0 = Xth[col * 36 + colB],       rl0 = Xtl[col * 36 + colB];
                unsigned rh1 = Xth[(col + 1) * 36 + colB], rl1 = Xtl[(col + 1) * 36 + colB];
                float v0e = e[nt][0] + fp_half(rh0, 0) + fp_half(rl0, 0);
                float v0o = e[nt][2] + fp_half(rh0, 1) + fp_half(rl0, 1);
                float v1e = e[nt][1] + fp_half(rh1, 0) + fp_half(rl1, 0);
                float v1o = e[nt][3] + fp_half(rh1, 1) + fp_half(rl1, 1);
                unsigned H, L;
                split_pack(v0e, v0o, H, L);
                xout[(size_t)ch2 * XLD + m] = make_uint2(H, L);
                split_pack(v1e, v1o, H, L);
                xout[(size_t)ch2 * XLD + m + 1] = make_uint2(H, L);
            }
        }
    }
}

// ---------------------------------------------------------------------------
// fused tail v4: phase B 1-term (e1 hi x H hi), no Hl.
// smem (u32): [2] x (Bst[128][20] + Ws[256][20]) = 15360 (phase B: 2 x Eh[256][12])
//             Hh[128][132] @15360 -> 32256 u32 = 129024 B
// ---------------------------------------------------------------------------
__global__ void __launch_bounds__(512, 1)
k_tail(const unsigned* __restrict__ ybf,
       const float* __restrict__ e1b, const float* __restrict__ e2w,
       const float* __restrict__ e2b, float* __restrict__ out)
{
    extern __shared__ unsigned smu[];
    unsigned* Hh = smu + 15360;
    float* part = (float*)smu;

    int tid = threadIdx.x;     // 512
    int lane = tid & 31, w = tid >> 5;
    int wm = w >> 1, wn = w & 1;
    int grp = lane >> 2, t4 = lane & 3;
    int p0 = blockIdx.x * 128;
    unsigned smb = smaddr(smu);
    unsigned lr = ((lane >> 3) & 1) * 8 + (lane & 7);
    unsigned lc = (lane >> 4) * 4;
    int bm = lane >> 3, br = lane & 7;
    unsigned bl20  = ((unsigned)((bm >> 1) * 8 + br)) * 20  + (unsigned)(bm & 1) * 4;
    unsigned bl132 = ((unsigned)((bm >> 1) * 8 + br)) * 132 + (unsigned)(bm & 1) * 4;

    float d[2][8][4];
#pragma unroll
    for (int mt = 0; mt < 2; mt++)
#pragma unroll
        for (int nt = 0; nt < 8; nt++)
#pragma unroll
            for (int j = 0; j < 4; j++) d[mt][nt][j] = 0.f;

    int sp = tid >> 2, sq = (tid & 3) * 4;

    {   // prefetch kc = 0
        cp16(smb + (0 * 7680 + sp * 20 + sq) * 4,
             &ybf[(size_t)(p0 + sp) * 16 + sq]);
        for (int l = tid; l < 1024; l += 512) {
            int row = l >> 2, qg = (l & 3) * 4;
            cp16(smb + (0 * 7680 + 2560 + row * 20 + qg) * 4,
                 &g_swf[row * 16 + qg]);
        }
        CP_COMMIT();
    }
    for (int kc = 0; kc < 40; kc++) {
        CP_WAIT0();
        __syncthreads();
        if (kc < 39) {
            int nb = (kc + 1) & 1;
            cp16(smb + (nb * 7680 + sp * 20 + sq) * 4,
                 &ybf[(size_t)(kc + 1) * 16 * FINAL + (size_t)(p0 + sp) * 16 + sq]);
            for (int l = tid; l < 1024; l += 512) {
                int row = l >> 2, qg = (l & 3) * 4;
                cp16(smb + (nb * 7680 + 2560 + row * 20 + qg) * 4,
                     &g_swf[((kc + 1) * 256 + row) * 16 + qg]);
            }
            CP_COMMIT();
        }
        unsigned bcb = smb + ((kc & 1) * 7680) * 4;
        unsigned wcb = bcb + 2560 * 4;
#pragma unroll
        for (int ck = 0; ck < 2; ck++) {
            int k2b = ck * 8;
            unsigned a0[4], a1[4];
            ldsm_x4(a0, wcb + (((unsigned)(wm * 32) + lr) * 20 + k2b + lc) * 4);
            ldsm_x4(a1, wcb + (((unsigned)(wm * 32 + 16) + lr) * 20 + k2b + lc) * 4);
#pragma unroll
            for (int ntp = 0; ntp < 4; ntp++) {
                unsigned q[4];
                ldsm_x4(q, bcb + (((unsigned)(wn * 64 + ntp * 16)) * 20 + k2b + bl20) * 4);
                unsigned b0[2] = {q[0], q[1]}, b1[2] = {q[2], q[3]};
                mma16(d[0][2 * ntp], a0, b0);
                mma16(d[1][2 * ntp], a1, b0);
                mma16(d[0][2 * ntp + 1], a0, b1);
                mma16(d[1][2 * ntp + 1], a1, b1);
            }
        }
    }

    // ---- relu + pack hi into Hh: in-thread pair (r, r+8), STS.32 ----
    __syncthreads();
#pragma unroll
    for (int mt = 0; mt < 2; mt++) {
        int k2 = (wm * 2 + mt) * 8 + grp;
#pragma unroll
        for (int nt = 0; nt < 8; nt++) {
            int col = wn * 64 + nt * 8 + 2 * t4;
            float v0 = d[mt][nt][0]; v0 = v0 > 0.f ? v0 : 0.f;
            float v2 = d[mt][nt][2]; v2 = v2 > 0.f ? v2 : 0.f;
            float v1 = d[mt][nt][1]; v1 = v1 > 0.f ? v1 : 0.f;
            float v3 = d[mt][nt][3]; v3 = v3 > 0.f ? v3 : 0.f;
            Hh[col * 132 + k2]       = pack1(v0, v2);
            Hh[(col + 1) * 132 + k2] = pack1(v1, v3);
        }
    }

#pragma unroll
    for (int mt = 0; mt < 2; mt++)
#pragma unroll
        for (int nt = 0; nt < 8; nt++)
#pragma unroll
            for (int j = 0; j < 4; j++) d[mt][nt][j] = 0.f;

    // ---- phase B: e1 GEMM (256x128, K=256), 1-term, double-buffered Eh ----
    {
        __syncthreads();
        int row = tid >> 1, qg = (tid & 1) * 4;
        cp16(smb + (row * 12 + qg) * 4, &g_e1fh[row * 128 + qg]);
        CP_COMMIT();
    }
    unsigned hhB = smaddr(Hh);
    for (int kk = 0; kk < 16; kk++) {
        CP_WAIT0();
        __syncthreads();
        if (kk < 15) {
            int nb = (kk + 1) & 1;
            int row = tid >> 1, qg = (tid & 1) * 4;
            cp16(smb + (nb * 3072 + row * 12 + qg) * 4,
                 &g_e1fh[row * 128 + (kk + 1) * 8 + qg]);
            CP_COMMIT();
        }
        unsigned ecb = smb + ((kk & 1) * 3072) * 4;
        unsigned ah0[4], ah1[4];
        ldsm_x4(ah0, ecb + (((unsigned)(wm * 32) + lr) * 12 + lc) * 4);
        ldsm_x4(ah1, ecb + (((unsigned)(wm * 32 + 16) + lr) * 12 + lc) * 4);
#pragma unroll
        for (int ntp = 0; ntp < 4; ntp++) {
            unsigned base = (((unsigned)(wn * 64 + ntp * 16)) * 132 + kk * 8 + bl132) * 4;
            unsigned qh[4];
            ldsm_x4(qh, hhB + base);
            unsigned bh0[2] = {qh[0], qh[1]}, bh1[2] = {qh[2], qh[3]};
            mma16(d[0][2 * ntp], ah0, bh0);
            mma16(d[1][2 * ntp], ah1, bh0);
            mma16(d[0][2 * ntp + 1], ah0, bh1);
            mma16(d[1][2 * ntp + 1], ah1, bh1);
        }
    }

    // ---- epilogue: bias + relu + e2 dot + reduce ----
    int r0 = wm * 32 + grp;
    float eb0 = e1b[r0],      eb1 = e1b[r0 + 8];
    float eb2 = e1b[r0 + 16], eb3 = e1b[r0 + 24];
    float ew0 = e2w[r0],      ew1 = e2w[r0 + 8];
    float ew2 = e2w[r0 + 16], ew3 = e2w[r0 + 24];

    float pc[16];
#pragma unroll
    for (int nt = 0; nt < 8; nt++) {
#pragma unroll
        for (int j = 0; j < 2; j++) {
            float h0 = d[0][nt][j]     + eb0; h0 = h0 > 0.f ? h0 : 0.f;
            float h1 = d[0][nt][2 + j] + eb1; h1 = h1 > 0.f ? h1 : 0.f;
            float h2 = d[1][nt][j]     + eb2; h2 = h2 > 0.f ? h2 : 0.f;
            float h3 = d[1][nt][2 + j] + eb3; h3 = h3 > 0.f ? h3 : 0.f;
            pc[nt * 2 + j] = ew0 * h0 + ew1 * h1 + ew2 * h2 + ew3 * h3;
        }
    }
#pragma unroll
    for (int off = 16; off >= 4; off >>= 1)
#pragma unroll
        for (int t = 0; t < 16; t++)
            pc[t] += __shfl_xor_sync(0xffffffff, pc[t], off);

    if (lane < 4) {
#pragma unroll
        for (int nt = 0; nt < 8; nt++) {
            part[wm * 128 + wn * 64 + nt * 8 + 2 * lane]     = pc[nt * 2];
            part[wm * 128 + wn * 64 + nt * 8 + 2 * lane + 1] = pc[nt * 2 + 1];
        }
    }
    __syncthreads();
    if (tid < 128) {
        float s = e2b[0];
#pragma unroll
        for (int ww = 0; ww < 8; ww++) s += part[ww * 128 + tid];
        int p = p0 + tid;
        out[(p & 15) * TOUT + (p >> 4)] = s;
    }
}

// ---------------------------------------------------------------------------
extern "C" void kernel_launch(void* const* d_in, const int* in_sizes, int n_in,
                              void* d_out, int out_size)
{
    const float* input    = (const float*)d_in[0];
    const float* start_w  = (const float*)d_in[1];
    const float* filter_w = (const float*)d_in[2];
    const float* gate_w   = (const float*)d_in[3];
    const float* res_w    = (const float*)d_in[4];
    const float* skip_w   = (const float*)d_in[5];
    const float* e1w      = (const float*)d_in[6];
    const float* e1b      = (const float*)d_in[7];
    const float* e2w      = (const float*)d_in[8];
    const float* e2b      = (const float*)d_in[9];
    float* out = (float*)d_out;
    (void)in_sizes; (void)n_in; (void)out_size;

    static int attr_done = 0;
    if (!attr_done) {
        cudaFuncSetAttribute(k_layer, cudaFuncAttributeMaxDynamicSharedMemorySize, 51200);
        cudaFuncSetAttribute(k_start, cudaFuncAttributeMaxDynamicSharedMemorySize, 59392);
        cudaFuncSetAttribute(k_tail,  cudaFuncAttributeMaxDynamicSharedMemorySize, 129024);
        attr_done = 1;
    }

    uint2 *xa, *xb;
    unsigned *ybf;
    cudaGetSymbolAddress((void**)&xa, g_xa);
    cudaGetSymbolAddress((void**)&xb, g_xb);
    cudaGetSymbolAddress((void**)&ybf, g_ybf);

    k_prep<<<48, 256>>>(filter_w, gate_w, res_w, skip_w, e1w, start_w);
    k_start<<<1024, 256, 59392>>>(input, xa);

    uint2 *cur = xa, *nxt = xb;
    for (int i = 0; i < 40; i++) {
        int b = i / 10, k = i % 10;
        int Mb = 262144 - 8192 * b;
        int Min, Mout, P, S;
        if (k == 0) { Min = Mb; Mout = Mb - 16; P = 0; S = 16; }
        else {
            int d = 1 << k;
            Min = Mb - 8 * d;
            Mout = Mb - 16 * d;
            P = 8 * d;
            S = 16 * d;
        }
        int ofs = Mout - FINAL;
        int grid = (Mout + 127) / 128;
        k_layer<<<grid, 256, 51200>>>(cur, nxt,
                                      ybf + (size_t)i * 16 * FINAL,
                                      i, Min, Mout, P, S, ofs);
        uint2* t = cur; cur = nxt; nxt = t;
    }

    k_tail<<<FINAL / 128, 512, 129024>>>(ybf, e1b, e2w, e2b, out);
}

// round 16
// speedup vs baseline: 6.0880x; 1.0446x over previous
#include <cuda_runtime.h>
#include <cuda_fp16.h>
#include <math.h>

#define FINAL 229376        // 16 * 14336 final flat length
#define XLD   262144        // fixed channel stride for x buffers
#define TOUT  14336

// Scratch (device globals; no allocation anywhere)
__device__ uint2    g_xa[16 * XLD];                       // x ping: {hi,lo} fp16x2 pairs
__device__ uint2    g_xb[16 * XLD];                       // x pong
__device__ unsigned g_ybf[640 * FINAL];     // y hi: per layer [FINAL pos][16 k2] (pairs (c,c+8))
__device__ unsigned g_w1h[40 * 2048];                     // [s=64][k2=32] per layer (hi only)
__device__ unsigned g_wrh[40 * 512],  g_wrl[40 * 512];    // [row=32][k2=16] (rows+k permuted)
__device__ unsigned g_swf[163840];                        // skip_w fp16 [40*256][k2=16] (pairs (c,c+8))
__device__ unsigned g_e1fh[32768];                        // e1w fp16 hi [256][k2=128] (pairs (r,r+8))
__device__ unsigned g_s0h[2048], g_s0l[2048];             // start_w split [32 rows perm][64 k2]

// ---------------------------------------------------------------------------
// helpers (fp16 limbs)
// ---------------------------------------------------------------------------
__device__ __forceinline__ void mma16(float d[4], const unsigned a[4], const unsigned b[2]) {
    asm volatile(
        "mma.sync.aligned.m16n8k16.row.col.f32.f16.f16.f32 "
        "{%0,%1,%2,%3},{%4,%5,%6,%7},{%8,%9},{%0,%1,%2,%3};"
        : "+f"(d[0]), "+f"(d[1]), "+f"(d[2]), "+f"(d[3])
        : "r"(a[0]), "r"(a[1]), "r"(a[2]), "r"(a[3]), "r"(b[0]), "r"(b[1]));
}
__device__ __forceinline__ void ldsm_x4(unsigned a[4], unsigned saddr) {
    asm volatile("ldmatrix.sync.aligned.m8n8.x4.shared.b16 {%0,%1,%2,%3}, [%4];"
        : "=r"(a[0]), "=r"(a[1]), "=r"(a[2]), "=r"(a[3]) : "r"(saddr));
}
__device__ __forceinline__ unsigned smaddr(const void* p) {
    return (unsigned)__cvta_generic_to_shared(p);
}
__device__ __forceinline__ void cp16(unsigned dst, const unsigned* src) {
    asm volatile("cp.async.ca.shared.global [%0], [%1], 16;" :: "r"(dst), "l"(src));
}
#define CP_COMMIT() asm volatile("cp.async.commit_group;")
#define CP_WAIT0()  asm volatile("cp.async.wait_group 0;")

// ---- fast activations via MUFU (ex2/rcp approx)
__device__ __forceinline__ float fast_ex2(float x) {
    float y; asm("ex2.approx.f32 %0, %1;" : "=f"(y) : "f"(x)); return y;
}
__device__ __forceinline__ float fast_rcp(float x) {
    float y; asm("rcp.approx.f32 %0, %1;" : "=f"(y) : "f"(x)); return y;
}
__device__ __forceinline__ float fast_sigmoid(float x) {
    return fast_rcp(1.f + fast_ex2(-1.4426950408889634f * x));
}
__device__ __forceinline__ float fast_tanh(float x) {
    return 2.f * fast_rcp(1.f + fast_ex2(-2.8853900817779268f * x)) - 1.f;
}

// pack two floats into fp16x2 hi and lo components
__device__ __forceinline__ void split_pack(float a, float b, unsigned& h, unsigned& l) {
    __half ah = __float2half(a), bh = __float2half(b);
    float ar = a - __half2float(ah), br = b - __half2float(bh);
    __half2 th; th.x = ah; th.y = bh; h = *(unsigned*)&th;
    __half2 tl; tl.x = __float2half(ar); tl.y = __float2half(br);
    l = *(unsigned*)&tl;
}
__device__ __forceinline__ unsigned pack1(float a, float b) {
    __half2 t; t.x = __float2half(a); t.y = __float2half(b);
    return *(unsigned*)&t;
}
__device__ __forceinline__ float fp_half(unsigned u, int hi) {
    __half2 t = *(__half2*)&u;
    return hi ? __half2float(t.y) : __half2float(t.x);
}

// ---------------------------------------------------------------------------
// prep: split weights into packed fp16 pairs (permuted for fragments)
// ---------------------------------------------------------------------------
__global__ void k_prep(const float* __restrict__ fw, const float* __restrict__ gw,
                       const float* __restrict__ rw, const float* __restrict__ sw,
                       const float* __restrict__ e1w, const float* __restrict__ s0w)
{
    int i = blockIdx.x, tid = threadIdx.x;
    if (i < 40) {
        for (int l = tid; l < 2048; l += 256) {
            int s = l >> 5, k2 = l & 31;
            int c = ((s >> 4) << 3) + (s & 7);
            int isg = (s >> 3) & 1;
            const float* src = (isg ? gw : fw) + i * 2048;
            int k0 = 2 * k2;
            float v0 = src[(c * 32 + (k0 & 31)) * 2 + (k0 >> 5)];
            float v1 = src[(c * 32 + ((k0 + 1) & 31)) * 2 + ((k0 + 1) >> 5)];
            g_w1h[i * 2048 + l] = pack1(v0, v1);
        }
        for (int l = tid; l < 512; l += 256) {
            int r = l >> 4, p = l & 15;
            int t = r >> 4, s = r & 15;
            int chan = t * 16 + (s & 7) * 2 + (s >> 3);
            int klo = ((p >> 3) << 4) + (p & 7);       // (c, c+8) pairing
            float v0 = rw[i * 1024 + chan * 32 + klo];
            float v1 = rw[i * 1024 + chan * 32 + klo + 8];
            unsigned h, lo;
            split_pack(v0, v1, h, lo);
            g_wrh[i * 512 + l] = h;
            g_wrl[i * 512 + l] = lo;
        }
    } else {
        int bi = i - 40;  // 0..7
        for (int l = bi * 256 + tid; l < 163840; l += 2048) {
            int og = l >> 4, p = l & 15;
            int klo = ((p >> 3) << 4) + (p & 7);       // (c, c+8) pairing
            g_swf[l] = pack1(sw[og * 32 + klo], sw[og * 32 + klo + 8]);
        }
        for (int l = bi * 256 + tid; l < 32768; l += 2048) {
            int o = l >> 7, p = l & 127;
            int rlo = ((p >> 3) << 4) + (p & 7);       // (r, r+8) pairing
            g_e1fh[l] = pack1(e1w[o * 256 + rlo], e1w[o * 256 + rlo + 8]);
        }
        for (int l = bi * 256 + tid; l < 2048; l += 2048) {
            int r = l >> 6, k2 = l & 63;
            int t = r >> 4, s = r & 15;
            int chan = t * 16 + (s & 7) * 2 + (s >> 3);  // row perm as res_w
            float v0 = s0w[chan * 128 + 2 * k2];
            float v1 = s0w[chan * 128 + 2 * k2 + 1];
            unsigned h, lo;
            split_pack(v0, v1, h, lo);
            g_s0h[l] = h; g_s0l[l] = lo;
        }
    }
}

// ---------------------------------------------------------------------------
// start conv (mma, 3-term fp16 split): out 32 x 256 positions per block.
// dyn smem (u32): Wh[32][68]@0, Wl@2176, Xh[256][12]@4352, Xl@7424,
//                 s_in (float)[16*272]@10496  -> 14848 u32 = 59392 B
// ---------------------------------------------------------------------------
__global__ void __launch_bounds__(256, 2)
k_start(const float* __restrict__ in, uint2* __restrict__ xo)
{
    extern __shared__ unsigned smk[];
    unsigned* Wh = smk;
    unsigned* Wl = smk + 2176;
    unsigned* Xh = smk + 4352;
    unsigned* Xl = smk + 7424;
    float* s_in  = (float*)(smk + 10496);

    int tid = threadIdx.x;               // 256
    int m0 = blockIdx.x * 256;
    int t0 = blockIdx.x * 16;
    int lane = tid & 31, w = tid >> 5;
    int wm = w >> 2, wn2 = w & 3;
    int grp = lane >> 2, t4 = lane & 3;
    unsigned lr = ((lane >> 3) & 1) * 8 + (lane & 7);
    unsigned lc = (lane >> 4) * 4;
    int bm = lane >> 3, br = lane & 7;
    unsigned bl12 = ((unsigned)((bm >> 1) * 8 + br)) * 12 + (unsigned)(bm & 1) * 4;

    for (int l = tid; l < 512; l += 256) {
        int row = l >> 4, q = (l & 15) * 4;
        *(uint4*)&Wh[row * 68 + q] = *(const uint4*)&g_s0h[row * 64 + q];
        *(uint4*)&Wl[row * 68 + q] = *(const uint4*)&g_s0l[row * 64 + q];
    }

    float d[8][4];
#pragma unroll
    for (int a = 0; a < 8; a++)
#pragma unroll
        for (int b = 0; b < 4; b++) d[a][b] = 0.f;

    int tt = tid & 15, rhalf = tid >> 4;
    unsigned whA = smaddr(Wh) + ((wm * 16 + lr) * 68 + lc) * 4;
    unsigned wlA = smaddr(Wl) + ((wm * 16 + lr) * 68 + lc) * 4;
    unsigned xhB = smaddr(Xh), xlB = smaddr(Xl);

    for (int fc = 0; fc < 8; fc++) {
        __syncthreads();
#pragma unroll
        for (int pass = 0; pass < 16; pass++) {
            int row = pass * 16 + rhalf;
            int bb = row >> 4, ff = row & 15;
            s_in[ff * 272 + tt * 17 + bb] =
                in[(bb * 128 + fc * 16 + ff) * 16384 + t0 + tt];
        }
        __syncthreads();
        for (int l = tid; l < 2048; l += 256) {
            int pos = l & 255, k2l = l >> 8;
            int ptt = pos >> 4, pbb = pos & 15;
            float f0 = s_in[(2 * k2l) * 272 + ptt * 17 + pbb];
            float f1 = s_in[(2 * k2l + 1) * 272 + ptt * 17 + pbb];
            unsigned H, L;
            split_pack(f0, f1, H, L);
            Xh[pos * 12 + k2l] = H;
            Xl[pos * 12 + k2l] = L;
        }
        __syncthreads();
        unsigned ah[4], al[4];
        ldsm_x4(ah, whA + (fc * 8) * 4);
        ldsm_x4(al, wlA + (fc * 8) * 4);
#pragma unroll
        for (int ntp = 0; ntp < 4; ntp++) {
            unsigned base = (((unsigned)(wn2 * 64 + ntp * 16)) * 12 + bl12) * 4;
            unsigned qh[4], ql[4];
            ldsm_x4(qh, xhB + base);
            ldsm_x4(ql, xlB + base);
            unsigned bh0[2] = {qh[0], qh[1]}, bl0[2] = {ql[0], ql[1]};
            unsigned bh1[2] = {qh[2], qh[3]}, bl1[2] = {ql[2], ql[3]};
            mma16(d[2 * ntp], ah, bh0);
            mma16(d[2 * ntp], ah, bl0);
            mma16(d[2 * ntp], al, bh0);
            mma16(d[2 * ntp + 1], ah, bh1);
            mma16(d[2 * ntp + 1], ah, bl1);
            mma16(d[2 * ntp + 1], al, bh1);
        }
    }

    {
        int c2 = wm * 8 + grp;
#pragma unroll
        for (int f = 0; f < 8; f++) {
            int col = wn2 * 64 + (f >> 1) * 16 + (f & 1) * 8 + 2 * t4;
            int m = m0 + col;
            unsigned H, L;
            split_pack(d[f][0], d[f][2], H, L);
            xo[(size_t)c2 * XLD + m] = make_uint2(H, L);
            split_pack(d[f][1], d[f][3], H, L);
            xo[(size_t)c2 * XLD + m + 1] = make_uint2(H, L);
        }
    }
}

// ---------------------------------------------------------------------------
// fused dilated layer: GEMM1 1-term (Wh x x_hi), GEMM2 3-term (full precision
// for the carried residual state; x still stored as hi/lo).
// smem layout unchanged from R15.
// ---------------------------------------------------------------------------
__global__ void __launch_bounds__(256, 4)
k_layer(const uint2* __restrict__ xin, uint2* __restrict__ xout,
        unsigned* __restrict__ ytf, int layer,
        int Min, int Mout, int P, int S, int ofs)
{
    extern __shared__ unsigned smu[];
    unsigned* Wh  = smu;
    unsigned* Rh  = smu + 2304;
    unsigned* Rl  = smu + 2944;
    unsigned* Xth = smu + 3584;
    unsigned* Xtl = smu + 8192;

    int tid = threadIdx.x;          // 256
    int m0 = blockIdx.x * 128;
    int lane = tid & 31, w = tid >> 5;
    int grp = lane >> 2, t4 = lane & 3;
    unsigned lr = ((lane >> 3) & 1) * 8 + (lane & 7);
    unsigned lc = (lane >> 4) * 4;
    int bm = lane >> 3, br = lane & 7;
    unsigned bloff = ((unsigned)((bm >> 1) * 8 + br)) * 36 + (unsigned)(bm & 1) * 4;

    const unsigned* wsh = g_w1h + layer * 2048;
    for (int l = tid; l < 512; l += 256) {
        int row = l >> 3, q = (l & 7) * 4;
        *(uint4*)&Wh[row * 36 + q] = *(const uint4*)&wsh[row * 32 + q];
    }
    const unsigned* rsh = g_wrh + layer * 512;
    const unsigned* rsl = g_wrl + layer * 512;
    for (int l = tid; l < 128; l += 256) {
        int row = l >> 2, q = (l & 3) * 4;
        *(uint4*)&Rh[row * 20 + q] = *(const uint4*)&rsh[row * 16 + q];
        *(uint4*)&Rl[row * 20 + q] = *(const uint4*)&rsl[row * 16 + q];
    }

    for (int v = tid; v < 1024; v += 256) {
        int g = v >> 7;
        int p = v & 127;
        int tap = g >> 2;
        int ch2b = (g & 3) * 4;
        int off = tap ? (S - P) : -P;
        int idx = m0 + p + off;
        uint4 H, L;
        if (idx >= 0 && idx < Min) {
            const uint2* px = xin + idx;
            uint2 v0 = px[(size_t)(ch2b    ) * XLD];
            uint2 v1 = px[(size_t)(ch2b + 1) * XLD];
            uint2 v2 = px[(size_t)(ch2b + 2) * XLD];
            uint2 v3 = px[(size_t)(ch2b + 3) * XLD];
            H.x = v0.x; L.x = v0.y;
            H.y = v1.x; L.y = v1.y;
            H.z = v2.x; L.z = v2.y;
            H.w = v3.x; L.w = v3.y;
        } else {
            H.x = H.y = H.z = H.w = 0u;
            L.x = L.y = L.z = L.w = 0u;
        }
        *(uint4*)&Xth[p * 36 + g * 4] = H;
        *(uint4*)&Xtl[p * 36 + g * 4] = L;
    }
    __syncthreads();

    // ---- GEMM1: 64x128, K=64; 1-term (Wh x x_hi) ----
    int wr1 = w >> 2, wc1 = w & 3;
    unsigned whb = smaddr(Wh) + ((wr1 * 32 + lr) * 36 + lc) * 4;
    unsigned xhb = smaddr(Xth), xlb = smaddr(Xtl);
    float d[2][4][4];
#pragma unroll
    for (int a = 0; a < 2; a++)
#pragma unroll
        for (int b = 0; b < 4; b++)
#pragma unroll
            for (int c = 0; c < 4; c++) d[a][b][c] = 0.f;

#pragma unroll
    for (int kc = 0; kc < 4; kc++) {
        int k2b = kc * 8;
        unsigned ah[2][4];
#pragma unroll
        for (int mf = 0; mf < 2; mf++)
            ldsm_x4(ah[mf], whb + (mf * 576 + k2b) * 4);
#pragma unroll
        for (int ntp = 0; ntp < 2; ntp++) {
            unsigned bo = (((unsigned)(wc1 * 32 + ntp * 16)) * 36 + k2b + bloff) * 4;
            unsigned qh[4];
            ldsm_x4(qh, xhb + bo);
            unsigned bh0[2] = {qh[0], qh[1]};
            unsigned bh1[2] = {qh[2], qh[3]};
#pragma unroll
            for (int mf = 0; mf < 2; mf++) {
                mma16(d[mf][2 * ntp], ah[mf], bh0);
                mma16(d[mf][2 * ntp + 1], ah[mf], bh1);
            }
        }
    }

    float yv[2][4][2];
#pragma unroll
    for (int mf = 0; mf < 2; mf++)
#pragma unroll
        for (int nt = 0; nt < 4; nt++) {
            yv[mf][nt][0] = fast_tanh(d[mf][nt][0]) * fast_sigmoid(d[mf][nt][2]);
            yv[mf][nt][1] = fast_tanh(d[mf][nt][1]) * fast_sigmoid(d[mf][nt][3]);
        }
    __syncthreads();

    {
        int p_idx = wr1 * 8 + grp;
#pragma unroll
        for (int nt = 0; nt < 4; nt++) {
            int col = wc1 * 32 + nt * 8 + 2 * t4;
            unsigned H, L;
            split_pack(yv[0][nt][0], yv[1][nt][0], H, L);
            Xth[col * 36 + p_idx] = H;
            Xtl[col * 36 + p_idx] = L;
            split_pack(yv[0][nt][1], yv[1][nt][1], H, L);
            Xth[(col + 1) * 36 + p_idx] = H;
            Xtl[(col + 1) * 36 + p_idx] = L;
        }
    }
    __syncthreads();

    for (int v = tid; v < 512; v += 256) {
        int p = v >> 2, qg = v & 3;
        int m = m0 + p;
        if (m >= ofs && m < Mout)
            *(uint4*)&ytf[(size_t)(m - ofs) * 16 + qg * 4] = *(uint4*)&Xth[p * 36 + qg * 4];
    }

    // ---- GEMM2: 32x128, K=32; 3-term split (protect residual chain) ----
    int wr2 = w >> 2, wc2 = w & 3;
    unsigned rhb = smaddr(Rh) + ((wr2 * 16 + lr) * 20 + lc) * 4;
    unsigned rlb = smaddr(Rl) + ((wr2 * 16 + lr) * 20 + lc) * 4;
    float e[4][4];
#pragma unroll
    for (int a = 0; a < 4; a++)
#pragma unroll
        for (int b = 0; b < 4; b++) e[a][b] = 0.f;

#pragma unroll
    for (int kc = 0; kc < 2; kc++) {
        int k2b = kc * 8;
        unsigned ah[4], al[4];
        ldsm_x4(ah, rhb + k2b * 4);
        ldsm_x4(al, rlb + k2b * 4);
#pragma unroll
        for (int ntp = 0; ntp < 2; ntp++) {
            unsigned bo = (((unsigned)(wc2 * 32 + ntp * 16)) * 36 + k2b + bloff) * 4;
            unsigned qh[4], ql[4];
            ldsm_x4(qh, xhb + bo);
            ldsm_x4(ql, xlb + bo);
            unsigned bh0[2] = {qh[0], qh[1]}, bl0[2] = {ql[0], ql[1]};
            unsigned bh1[2] = {qh[2], qh[3]}, bl1[2] = {ql[2], ql[3]};
            mma16(e[2 * ntp], ah, bh0);
            mma16(e[2 * ntp], ah, bl0);
            mma16(e[2 * ntp], al, bh0);
            mma16(e[2 * ntp + 1], ah, bh1);
            mma16(e[2 * ntp + 1], ah, bl1);
            mma16(e[2 * ntp + 1], al, bh1);
        }
    }
    {
        int ch2 = wr2 * 8 + grp;
        int colB = 16 + ch2;
#pragma unroll
        for (int nt = 0; nt < 4; nt++) {
            int col = wc2 * 32 + nt * 8 + 2 * t4;
            int m = m0 + col;
            if (m < Mout) {
                unsigned rh0 = Xth[col * 36 + colB],       rl0 = Xtl[col * 36 + colB];
                unsigned rh1 = Xth[(col + 1) * 36 + colB], rl1 = Xtl[(col + 1) * 36 + colB];
                float v0e = e[nt][0] + fp_half(rh0, 0) + fp_half(rl0, 0);
                float v0o = e[nt][2] + fp_half(rh0, 1) + fp_half(rl0, 1);
                float v1e = e[nt][1] + fp_half(rh1, 0) + fp_half(rl1, 0);
                float v1o = e[nt][3] + fp_half(rh1, 1) + fp_half(rl1, 1);
                unsigned H, L;
                split_pack(v0e, v0o, H, L);
                xout[(size_t)ch2 * XLD + m] = make_uint2(H, L);
                split_pack(v1e, v1o, H, L);
                xout[(size_t)ch2 * XLD + m + 1] = make_uint2(H, L);
            }
        }
    }
}

// ---------------------------------------------------------------------------
// fused tail v4 (UNCHANGED from R15): phase B 1-term.
// ---------------------------------------------------------------------------
__global__ void __launch_bounds__(512, 1)
k_tail(const unsigned* __restrict__ ybf,
       const float* __restrict__ e1b, const float* __restrict__ e2w,
       const float* __restrict__ e2b, float* __restrict__ out)
{
    extern __shared__ unsigned smu[];
    unsigned* Hh = smu + 15360;
    float* part = (float*)smu;

    int tid = threadIdx.x;     // 512
    int lane = tid & 31, w = tid >> 5;
    int wm = w >> 1, wn = w & 1;
    int grp = lane >> 2, t4 = lane & 3;
    int p0 = blockIdx.x * 128;
    unsigned smb = smaddr(smu);
    unsigned lr = ((lane >> 3) & 1) * 8 + (lane & 7);
    unsigned lc = (lane >> 4) * 4;
    int bm = lane >> 3, br = lane & 7;
    unsigned bl20  = ((unsigned)((bm >> 1) * 8 + br)) * 20  + (unsigned)(bm & 1) * 4;
    unsigned bl132 = ((unsigned)((bm >> 1) * 8 + br)) * 132 + (unsigned)(bm & 1) * 4;

    float d[2][8][4];
#pragma unroll
    for (int mt = 0; mt < 2; mt++)
#pragma unroll
        for (int nt = 0; nt < 8; nt++)
#pragma unroll
            for (int j = 0; j < 4; j++) d[mt][nt][j] = 0.f;

    int sp = tid >> 2, sq = (tid & 3) * 4;

    {   // prefetch kc = 0
        cp16(smb + (0 * 7680 + sp * 20 + sq) * 4,
             &ybf[(size_t)(p0 + sp) * 16 + sq]);
        for (int l = tid; l < 1024; l += 512) {
            int row = l >> 2, qg = (l & 3) * 4;
            cp16(smb + (0 * 7680 + 2560 + row * 20 + qg) * 4,
                 &g_swf[row * 16 + qg]);
        }
        CP_COMMIT();
    }
    for (int kc = 0; kc < 40; kc++) {
        CP_WAIT0();
        __syncthreads();
        if (kc < 39) {
            int nb = (kc + 1) & 1;
            cp16(smb + (nb * 7680 + sp * 20 + sq) * 4,
                 &ybf[(size_t)(kc + 1) * 16 * FINAL + (size_t)(p0 + sp) * 16 + sq]);
            for (int l = tid; l < 1024; l += 512) {
                int row = l >> 2, qg = (l & 3) * 4;
                cp16(smb + (nb * 7680 + 2560 + row * 20 + qg) * 4,
                     &g_swf[((kc + 1) * 256 + row) * 16 + qg]);
            }
            CP_COMMIT();
        }
        unsigned bcb = smb + ((kc & 1) * 7680) * 4;
        unsigned wcb = bcb + 2560 * 4;
#pragma unroll
        for (int ck = 0; ck < 2; ck++) {
            int k2b = ck * 8;
            unsigned a0[4], a1[4];
            ldsm_x4(a0, wcb + (((unsigned)(wm * 32) + lr) * 20 + k2b + lc) * 4);
            ldsm_x4(a1, wcb + (((unsigned)(wm * 32 + 16) + lr) * 20 + k2b + lc) * 4);
#pragma unroll
            for (int ntp = 0; ntp < 4; ntp++) {
                unsigned q[4];
                ldsm_x4(q, bcb + (((unsigned)(wn * 64 + ntp * 16)) * 20 + k2b + bl20) * 4);
                unsigned b0[2] = {q[0], q[1]}, b1[2] = {q[2], q[3]};
                mma16(d[0][2 * ntp], a0, b0);
                mma16(d[1][2 * ntp], a1, b0);
                mma16(d[0][2 * ntp + 1], a0, b1);
                mma16(d[1][2 * ntp + 1], a1, b1);
            }
        }
    }

    __syncthreads();
#pragma unroll
    for (int mt = 0; mt < 2; mt++) {
        int k2 = (wm * 2 + mt) * 8 + grp;
#pragma unroll
        for (int nt = 0; nt < 8; nt++) {
            int col = wn * 64 + nt * 8 + 2 * t4;
            float v0 = d[mt][nt][0]; v0 = v0 > 0.f ? v0 : 0.f;
            float v2 = d[mt][nt][2]; v2 = v2 > 0.f ? v2 : 0.f;
            float v1 = d[mt][nt][1]; v1 = v1 > 0.f ? v1 : 0.f;
            float v3 = d[mt][nt][3]; v3 = v3 > 0.f ? v3 : 0.f;
            Hh[col * 132 + k2]       = pack1(v0, v2);
            Hh[(col + 1) * 132 + k2] = pack1(v1, v3);
        }
    }

#pragma unroll
    for (int mt = 0; mt < 2; mt++)
#pragma unroll
        for (int nt = 0; nt < 8; nt++)
#pragma unroll
            for (int j = 0; j < 4; j++) d[mt][nt][j] = 0.f;

    {
        __syncthreads();
        int row = tid >> 1, qg = (tid & 1) * 4;
        cp16(smb + (row * 12 + qg) * 4, &g_e1fh[row * 128 + qg]);
        CP_COMMIT();
    }
    unsigned hhB = smaddr(Hh);
    for (int kk = 0; kk < 16; kk++) {
        CP_WAIT0();
        __syncthreads();
        if (kk < 15) {
            int nb = (kk + 1) & 1;
            int row = tid >> 1, qg = (tid & 1) * 4;
            cp16(smb + (nb * 3072 + row * 12 + qg) * 4,
                 &g_e1fh[row * 128 + (kk + 1) * 8 + qg]);
            CP_COMMIT();
        }
        unsigned ecb = smb + ((kk & 1) * 3072) * 4;
        unsigned ah0[4], ah1[4];
        ldsm_x4(ah0, ecb + (((unsigned)(wm * 32) + lr) * 12 + lc) * 4);
        ldsm_x4(ah1, ecb + (((unsigned)(wm * 32 + 16) + lr) * 12 + lc) * 4);
#pragma unroll
        for (int ntp = 0; ntp < 4; ntp++) {
            unsigned base = (((unsigned)(wn * 64 + ntp * 16)) * 132 + kk * 8 + bl132) * 4;
            unsigned qh[4];
            ldsm_x4(qh, hhB + base);
            unsigned bh0[2] = {qh[0], qh[1]}, bh1[2] = {qh[2], qh[3]};
            mma16(d[0][2 * ntp], ah0, bh0);
            mma16(d[1][2 * ntp], ah1, bh0);
            mma16(d[0][2 * ntp + 1], ah0, bh1);
            mma16(d[1][2 * ntp + 1], ah1, bh1);
        }
    }

    int r0 = wm * 32 + grp;
    float eb0 = e1b[r0],      eb1 = e1b[r0 + 8];
    float eb2 = e1b[r0 + 16], eb3 = e1b[r0 + 24];
    float ew0 = e2w[r0],      ew1 = e2w[r0 + 8];
    float ew2 = e2w[r0 + 16], ew3 = e2w[r0 + 24];

    float pc[16];
#pragma unroll
    for (int nt = 0; nt < 8; nt++) {
#pragma unroll
        for (int j = 0; j < 2; j++) {
            float h0 = d[0][nt][j]     + eb0; h0 = h0 > 0.f ? h0 : 0.f;
            float h1 = d[0][nt][2 + j] + eb1; h1 = h1 > 0.f ? h1 : 0.f;
            float h2 = d[1][nt][j]     + eb2; h2 = h2 > 0.f ? h2 : 0.f;
            float h3 = d[1][nt][2 + j] + eb3; h3 = h3 > 0.f ? h3 : 0.f;
            pc[nt * 2 + j] = ew0 * h0 + ew1 * h1 + ew2 * h2 + ew3 * h3;
        }
    }
#pragma unroll
    for (int off = 16; off >= 4; off >>= 1)
#pragma unroll
        for (int t = 0; t < 16; t++)
            pc[t] += __shfl_xor_sync(0xffffffff, pc[t], off);

    if (lane < 4) {
#pragma unroll
        for (int nt = 0; nt < 8; nt++) {
            part[wm * 128 + wn * 64 + nt * 8 + 2 * lane]     = pc[nt * 2];
            part[wm * 128 + wn * 64 + nt * 8 + 2 * lane + 1] = pc[nt * 2 + 1];
        }
    }
    __syncthreads();
    if (tid < 128) {
        float s = e2b[0];
#pragma unroll
        for (int ww = 0; ww < 8; ww++) s += part[ww * 128 + tid];
        int p = p0 + tid;
        out[(p & 15) * TOUT + (p >> 4)] = s;
    }
}

// ---------------------------------------------------------------------------
extern "C" void kernel_launch(void* const* d_in, const int* in_sizes, int n_in,
                              void* d_out, int out_size)
{
    const float* input    = (const float*)d_in[0];
    const float* start_w  = (const float*)d_in[1];
    const float* filter_w = (const float*)d_in[2];
    const float* gate_w   = (const float*)d_in[3];
    const float* res_w    = (const float*)d_in[4];
    const float* skip_w   = (const float*)d_in[5];
    const float* e1w      = (const float*)d_in[6];
    const float* e1b      = (const float*)d_in[7];
    const float* e2w      = (const float*)d_in[8];
    const float* e2b      = (const float*)d_in[9];
    float* out = (float*)d_out;
    (void)in_sizes; (void)n_in; (void)out_size;

    static int attr_done = 0;
    if (!attr_done) {
        cudaFuncSetAttribute(k_layer, cudaFuncAttributeMaxDynamicSharedMemorySize, 51200);
        cudaFuncSetAttribute(k_start, cudaFuncAttributeMaxDynamicSharedMemorySize, 59392);
        cudaFuncSetAttribute(k_tail,  cudaFuncAttributeMaxDynamicSharedMemorySize, 129024);
        attr_done = 1;
    }

    uint2 *xa, *xb;
    unsigned *ybf;
    cudaGetSymbolAddress((void**)&xa, g_xa);
    cudaGetSymbolAddress((void**)&xb, g_xb);
    cudaGetSymbolAddress((void**)&ybf, g_ybf);

    k_prep<<<48, 256>>>(filter_w, gate_w, res_w, skip_w, e1w, start_w);
    k_start<<<1024, 256, 59392>>>(input, xa);

    uint2 *cur = xa, *nxt = xb;
    for (int i = 0; i < 40; i++) {
        int b = i / 10, k = i % 10;
        int Mb = 262144 - 8192 * b;
        int Min, Mout, P, S;
        if (k == 0) { Min = Mb; Mout = Mb - 16; P = 0; S = 16; }
        else {
            int d = 1 << k;
            Min = Mb - 8 * d;
            Mout = Mb - 16 * d;
            P = 8 * d;
            S = 16 * d;
        }
        int ofs = Mout - FINAL;
        int grid = (Mout + 127) / 128;
        k_layer<<<grid, 256, 51200>>>(cur, nxt,
                                      ybf + (size_t)i * 16 * FINAL,
                                      i, Min, Mout, P, S, ofs);
        uint2* t = cur; cur = nxt; nxt = t;
    }

    k_tail<<<FINAL / 128, 512, 129024>>>(ybf, e1b, e2w, e2b, out);
}

// round 17
// speedup vs baseline: 6.2718x; 1.0302x over previous
#include <cuda_runtime.h>
#include <cuda_fp16.h>
#include <math.h>

#define FINAL 229376        // 16 * 14336 final flat length
#define XMAX  262144        // max flat positions
#define TOUT  14336

// Scratch (device globals; no allocation anywhere)
__device__ unsigned g_xah[16 * XMAX], g_xal[16 * XMAX];   // x ping: [pos][16 ch2] hi/lo planes
__device__ unsigned g_xbh[16 * XMAX], g_xbl[16 * XMAX];   // x pong
__device__ unsigned g_ybf[640 * FINAL];     // y hi: per layer [FINAL pos][16 k2] (pairs (c,c+8))
__device__ unsigned g_w1h[40 * 2048];                     // [s=64][k2=32] per layer (hi only)
__device__ unsigned g_wrh[40 * 512],  g_wrl[40 * 512];    // [row=32][k2=16] (rows+k permuted)
__device__ unsigned g_swf[163840];                        // skip_w fp16 [40*256][k2=16] (pairs (c,c+8))
__device__ unsigned g_e1fh[32768];                        // e1w fp16 hi [256][k2=128] (pairs (r,r+8))
__device__ unsigned g_s0h[2048], g_s0l[2048];             // start_w split [32 rows perm][64 k2]

// ---------------------------------------------------------------------------
// helpers (fp16 limbs)
// ---------------------------------------------------------------------------
__device__ __forceinline__ void mma16(float d[4], const unsigned a[4], const unsigned b[2]) {
    asm volatile(
        "mma.sync.aligned.m16n8k16.row.col.f32.f16.f16.f32 "
        "{%0,%1,%2,%3},{%4,%5,%6,%7},{%8,%9},{%0,%1,%2,%3};"
        : "+f"(d[0]), "+f"(d[1]), "+f"(d[2]), "+f"(d[3])
        : "r"(a[0]), "r"(a[1]), "r"(a[2]), "r"(a[3]), "r"(b[0]), "r"(b[1]));
}
__device__ __forceinline__ void ldsm_x4(unsigned a[4], unsigned saddr) {
    asm volatile("ldmatrix.sync.aligned.m8n8.x4.shared.b16 {%0,%1,%2,%3}, [%4];"
        : "=r"(a[0]), "=r"(a[1]), "=r"(a[2]), "=r"(a[3]) : "r"(saddr));
}
__device__ __forceinline__ unsigned smaddr(const void* p) {
    return (unsigned)__cvta_generic_to_shared(p);
}
__device__ __forceinline__ void cp16(unsigned dst, const unsigned* src) {
    asm volatile("cp.async.ca.shared.global [%0], [%1], 16;" :: "r"(dst), "l"(src));
}
#define CP_COMMIT() asm volatile("cp.async.commit_group;")
#define CP_WAIT0()  asm volatile("cp.async.wait_group 0;")

// ---- fast activations via MUFU (ex2/rcp approx)
__device__ __forceinline__ float fast_ex2(float x) {
    float y; asm("ex2.approx.f32 %0, %1;" : "=f"(y) : "f"(x)); return y;
}
__device__ __forceinline__ float fast_rcp(float x) {
    float y; asm("rcp.approx.f32 %0, %1;" : "=f"(y) : "f"(x)); return y;
}
__device__ __forceinline__ float fast_sigmoid(float x) {
    return fast_rcp(1.f + fast_ex2(-1.4426950408889634f * x));
}
__device__ __forceinline__ float fast_tanh(float x) {
    return 2.f * fast_rcp(1.f + fast_ex2(-2.8853900817779268f * x)) - 1.f;
}

// pack two floats into fp16x2 hi and lo components
__device__ __forceinline__ void split_pack(float a, float b, unsigned& h, unsigned& l) {
    __half ah = __float2half(a), bh = __float2half(b);
    float ar = a - __half2float(ah), br = b - __half2float(bh);
    __half2 th; th.x = ah; th.y = bh; h = *(unsigned*)&th;
    __half2 tl; tl.x = __float2half(ar); tl.y = __float2half(br);
    l = *(unsigned*)&tl;
}
__device__ __forceinline__ unsigned pack1(float a, float b) {
    __half2 t; t.x = __float2half(a); t.y = __float2half(b);
    return *(unsigned*)&t;
}
__device__ __forceinline__ float fp_half(unsigned u, int hi) {
    __half2 t = *(__half2*)&u;
    return hi ? __half2float(t.y) : __half2float(t.x);
}

// ---------------------------------------------------------------------------
// prep: split weights into packed fp16 pairs (permuted for fragments)
// ---------------------------------------------------------------------------
__global__ void k_prep(const float* __restrict__ fw, const float* __restrict__ gw,
                       const float* __restrict__ rw, const float* __restrict__ sw,
                       const float* __restrict__ e1w, const float* __restrict__ s0w)
{
    int i = blockIdx.x, tid = threadIdx.x;
    if (i < 40) {
        for (int l = tid; l < 2048; l += 256) {
            int s = l >> 5, k2 = l & 31;
            int c = ((s >> 4) << 3) + (s & 7);
            int isg = (s >> 3) & 1;
            const float* src = (isg ? gw : fw) + i * 2048;
            int k0 = 2 * k2;
            float v0 = src[(c * 32 + (k0 & 31)) * 2 + (k0 >> 5)];
            float v1 = src[(c * 32 + ((k0 + 1) & 31)) * 2 + ((k0 + 1) >> 5)];
            g_w1h[i * 2048 + l] = pack1(v0, v1);
        }
        for (int l = tid; l < 512; l += 256) {
            int r = l >> 4, p = l & 15;
            int t = r >> 4, s = r & 15;
            int chan = t * 16 + (s & 7) * 2 + (s >> 3);
            int klo = ((p >> 3) << 4) + (p & 7);       // (c, c+8) pairing
            float v0 = rw[i * 1024 + chan * 32 + klo];
            float v1 = rw[i * 1024 + chan * 32 + klo + 8];
            unsigned h, lo;
            split_pack(v0, v1, h, lo);
            g_wrh[i * 512 + l] = h;
            g_wrl[i * 512 + l] = lo;
        }
    } else {
        int bi = i - 40;  // 0..7
        for (int l = bi * 256 + tid; l < 163840; l += 2048) {
            int og = l >> 4, p = l & 15;
            int klo = ((p >> 3) << 4) + (p & 7);       // (c, c+8) pairing
            g_swf[l] = pack1(sw[og * 32 + klo], sw[og * 32 + klo + 8]);
        }
        for (int l = bi * 256 + tid; l < 32768; l += 2048) {
            int o = l >> 7, p = l & 127;
            int rlo = ((p >> 3) << 4) + (p & 7);       // (r, r+8) pairing
            g_e1fh[l] = pack1(e1w[o * 256 + rlo], e1w[o * 256 + rlo + 8]);
        }
        for (int l = bi * 256 + tid; l < 2048; l += 2048) {
            int r = l >> 6, k2 = l & 63;
            int t = r >> 4, s = r & 15;
            int chan = t * 16 + (s & 7) * 2 + (s >> 3);  // row perm as res_w
            float v0 = s0w[chan * 128 + 2 * k2];
            float v1 = s0w[chan * 128 + 2 * k2 + 1];
            unsigned h, lo;
            split_pack(v0, v1, h, lo);
            g_s0h[l] = h; g_s0l[l] = lo;
        }
    }
}

// ---------------------------------------------------------------------------
// start conv (mma, 3-term fp16 split): out 32 ch x 256 positions per block.
// Writes transposed planes xh/xl [pos][16 ch2].
// ---------------------------------------------------------------------------
__global__ void __launch_bounds__(256, 2)
k_start(const float* __restrict__ in, unsigned* __restrict__ xoh,
        unsigned* __restrict__ xol)
{
    extern __shared__ unsigned smk[];
    unsigned* Wh = smk;
    unsigned* Wl = smk + 2176;
    unsigned* Xh = smk + 4352;
    unsigned* Xl = smk + 7424;
    float* s_in  = (float*)(smk + 10496);

    int tid = threadIdx.x;               // 256
    int m0 = blockIdx.x * 256;
    int t0 = blockIdx.x * 16;
    int lane = tid & 31, w = tid >> 5;
    int wm = w >> 2, wn2 = w & 3;
    int grp = lane >> 2, t4 = lane & 3;
    unsigned lr = ((lane >> 3) & 1) * 8 + (lane & 7);
    unsigned lc = (lane >> 4) * 4;
    int bm = lane >> 3, br = lane & 7;
    unsigned bl12 = ((unsigned)((bm >> 1) * 8 + br)) * 12 + (unsigned)(bm & 1) * 4;

    for (int l = tid; l < 512; l += 256) {
        int row = l >> 4, q = (l & 15) * 4;
        *(uint4*)&Wh[row * 68 + q] = *(const uint4*)&g_s0h[row * 64 + q];
        *(uint4*)&Wl[row * 68 + q] = *(const uint4*)&g_s0l[row * 64 + q];
    }

    float d[8][4];
#pragma unroll
    for (int a = 0; a < 8; a++)
#pragma unroll
        for (int b = 0; b < 4; b++) d[a][b] = 0.f;

    int tt = tid & 15, rhalf = tid >> 4;
    unsigned whA = smaddr(Wh) + ((wm * 16 + lr) * 68 + lc) * 4;
    unsigned wlA = smaddr(Wl) + ((wm * 16 + lr) * 68 + lc) * 4;
    unsigned xhB = smaddr(Xh), xlB = smaddr(Xl);

    for (int fc = 0; fc < 8; fc++) {
        __syncthreads();
#pragma unroll
        for (int pass = 0; pass < 16; pass++) {
            int row = pass * 16 + rhalf;
            int bb = row >> 4, ff = row & 15;
            s_in[ff * 272 + tt * 17 + bb] =
                in[(bb * 128 + fc * 16 + ff) * 16384 + t0 + tt];
        }
        __syncthreads();
        for (int l = tid; l < 2048; l += 256) {
            int pos = l & 255, k2l = l >> 8;
            int ptt = pos >> 4, pbb = pos & 15;
            float f0 = s_in[(2 * k2l) * 272 + ptt * 17 + pbb];
            float f1 = s_in[(2 * k2l + 1) * 272 + ptt * 17 + pbb];
            unsigned H, L;
            split_pack(f0, f1, H, L);
            Xh[pos * 12 + k2l] = H;
            Xl[pos * 12 + k2l] = L;
        }
        __syncthreads();
        unsigned ah[4], al[4];
        ldsm_x4(ah, whA + (fc * 8) * 4);
        ldsm_x4(al, wlA + (fc * 8) * 4);
#pragma unroll
        for (int ntp = 0; ntp < 4; ntp++) {
            unsigned base = (((unsigned)(wn2 * 64 + ntp * 16)) * 12 + bl12) * 4;
            unsigned qh[4], ql[4];
            ldsm_x4(qh, xhB + base);
            ldsm_x4(ql, xlB + base);
            unsigned bh0[2] = {qh[0], qh[1]}, bl0[2] = {ql[0], ql[1]};
            unsigned bh1[2] = {qh[2], qh[3]}, bl1[2] = {ql[2], ql[3]};
            mma16(d[2 * ntp], ah, bh0);
            mma16(d[2 * ntp], ah, bl0);
            mma16(d[2 * ntp], al, bh0);
            mma16(d[2 * ntp + 1], ah, bh1);
            mme_dummy:
            mma16(d[2 * ntp + 1], ah, bl1);
            mma16(d[2 * ntp + 1], al, bh1);
        }
    }

    // ---- epilogue: transposed planes [pos][16 ch2] ----
    {
        int c2 = wm * 8 + grp;
#pragma unroll
        for (int f = 0; f < 8; f++) {
            int col = wn2 * 64 + (f >> 1) * 16 + (f & 1) * 8 + 2 * t4;
            int m = m0 + col;
            unsigned H, L;
            split_pack(d[f][0], d[f][2], H, L);
            xoh[(size_t)m * 16 + c2] = H;
            xol[(size_t)m * 16 + c2] = L;
            split_pack(d[f][1], d[f][3], H, L);
            xoh[(size_t)(m + 1) * 16 + c2] = H;
            xol[(size_t)(m + 1) * 16 + c2] = L;
        }
    }
}

// ---------------------------------------------------------------------------
// fused dilated layer: GEMM1 1-term, GEMM2 3-term.  x in transposed planes
// [pos][16 ch2]; ALL staging via cp.async (weights + x rows).
// smem layout unchanged: Wh@0, Rh@2304, Rl@2944, Xth@3584, Xtl@8192 (51200 B)
// ---------------------------------------------------------------------------
__global__ void __launch_bounds__(256, 4)
k_layer(const unsigned* __restrict__ xinh, const unsigned* __restrict__ xinl,
        unsigned* __restrict__ xouth, unsigned* __restrict__ xoutl,
        unsigned* __restrict__ ytf, int layer,
        int Min, int Mout, int P, int S, int ofs)
{
    extern __shared__ unsigned smu[];
    unsigned* Wh  = smu;
    unsigned* Rh  = smu + 2304;
    unsigned* Rl  = smu + 2944;
    unsigned* Xth = smu + 3584;
    unsigned* Xtl = smu + 8192;

    int tid = threadIdx.x;          // 256
    int m0 = blockIdx.x * 128;
    int lane = tid & 31, w = tid >> 5;
    int grp = lane >> 2, t4 = lane & 3;
    unsigned lr = ((lane >> 3) & 1) * 8 + (lane & 7);
    unsigned lc = (lane >> 4) * 4;
    int bm = lane >> 3, br = lane & 7;
    unsigned bloff = ((unsigned)((bm >> 1) * 8 + br)) * 36 + (unsigned)(bm & 1) * 4;
    unsigned smb = smaddr(smu);

    // ---- stage weights via cp.async ----
    const unsigned* wsh = g_w1h + layer * 2048;
    for (int l = tid; l < 512; l += 256) {                 // Wh: 64 rows x 8 chunks
        int row = l >> 3, q = (l & 7) * 4;
        cp16(smb + (row * 36 + q) * 4, &wsh[row * 32 + q]);
    }
    {                                                       // Rh/Rl: 2 x 32 rows x 4 chunks
        int arr = tid >> 7, row = (tid >> 2) & 31, q = (tid & 3) * 4;
        const unsigned* rs = (arr ? g_wrl : g_wrh) + layer * 512;
        unsigned dst = smb + ((arr ? 2944 : 2304) + row * 20 + q) * 4;
        cp16(dst, &rs[row * 16 + q]);
    }

    // ---- stage x rows via cp.async: one (pos, tap) row per thread ----
    {
        int p = tid & 127, tap = tid >> 7;
        int off = tap ? (S - P) : -P;
        int idx = m0 + p + off;
        unsigned bh = smb + (3584 + p * 36 + tap * 16) * 4;
        unsigned bl = smb + (8192 + p * 36 + tap * 16) * 4;
        if (idx >= 0 && idx < Min) {
            const unsigned* gh = xinh + (size_t)idx * 16;
            const unsigned* gl = xinl + (size_t)idx * 16;
#pragma unroll
            for (int c = 0; c < 4; c++) {
                cp16(bh + c * 16, gh + c * 4);
                cp16(bl + c * 16, gl + c * 4);
            }
        } else {
            uint4 z = make_uint4(0u, 0u, 0u, 0u);
#pragma unroll
            for (int c = 0; c < 4; c++) {
                *(uint4*)&Xth[p * 36 + tap * 16 + c * 4] = z;
                *(uint4*)&Xtl[p * 36 + tap * 16 + c * 4] = z;
            }
        }
    }
    CP_COMMIT();
    CP_WAIT0();
    __syncthreads();

    // ---- GEMM1: 64x128, K=64; 1-term (Wh x x_hi) ----
    int wr1 = w >> 2, wc1 = w & 3;
    unsigned whb = smb + ((wr1 * 32 + lr) * 36 + lc) * 4;
    unsigned xhb = smb + 3584 * 4, xlb = smb + 8192 * 4;
    float d[2][4][4];
#pragma unroll
    for (int a = 0; a < 2; a++)
#pragma unroll
        for (int b = 0; b < 4; b++)
#pragma unroll
            for (int c = 0; c < 4; c++) d[a][b][c] = 0.f;

#pragma unroll
    for (int kc = 0; kc < 4; kc++) {
        int k2b = kc * 8;
        unsigned ah[2][4];
#pragma unroll
        for (int mf = 0; mf < 2; mf++)
            ldsm_x4(ah[mf], whb + (mf * 576 + k2b) * 4);
#pragma unroll
        for (int ntp = 0; ntp < 2; ntp++) {
            unsigned bo = (((unsigned)(wc1 * 32 + ntp * 16)) * 36 + k2b + bloff) * 4;
            unsigned qh[4];
            ldsm_x4(qh, xhb + bo);
            unsigned bh0[2] = {qh[0], qh[1]};
            unsigned bh1[2] = {qh[2], qh[3]};
#pragma unroll
            for (int mf = 0; mf < 2; mf++) {
                mma16(d[mf][2 * ntp], ah[mf], bh0);
                mma16(d[mf][2 * ntp + 1], ah[mf], bh1);
            }
        }
    }

    float yv[2][4][2];
#pragma unroll
    for (int mf = 0; mf < 2; mf++)
#pragma unroll
        for (int nt = 0; nt < 4; nt++) {
            yv[mf][nt][0] = fast_tanh(d[mf][nt][0]) * fast_sigmoid(d[mf][nt][2]);
            yv[mf][nt][1] = fast_tanh(d[mf][nt][1]) * fast_sigmoid(d[mf][nt][3]);
        }
    __syncthreads();

    {
        int p_idx = wr1 * 8 + grp;
#pragma unroll
        for (int nt = 0; nt < 4; nt++) {
            int col = wc1 * 32 + nt * 8 + 2 * t4;
            unsigned H, L;
            split_pack(yv[0][nt][0], yv[1][nt][0], H, L);
            Xth[col * 36 + p_idx] = H;
            Xtl[col * 36 + p_idx] = L;
            split_pack(yv[0][nt][1], yv[1][nt][1], H, L);
            Xth[(col + 1) * 36 + p_idx] = H;
            Xtl[(col + 1) * 36 + p_idx] = L;
        }
    }
    __syncthreads();

    for (int v = tid; v < 512; v += 256) {
        int p = v >> 2, qg = v & 3;
        int m = m0 + p;
        if (m >= ofs && m < Mout)
            *(uint4*)&ytf[(size_t)(m - ofs) * 16 + qg * 4] = *(uint4*)&Xth[p * 36 + qg * 4];
    }

    // ---- GEMM2: 32x128, K=32; 3-term split (protect residual chain) ----
    int wr2 = w >> 2, wc2 = w & 3;
    unsigned rhb = smb + (2304 + (wr2 * 16 + lr) * 20 + lc) * 4;
    unsigned rlb = smb + (2944 + (wr2 * 16 + lr) * 20 + lc) * 4;
    float e[4][4];
#pragma unroll
    for (int a = 0; a < 4; a++)
#pragma unroll
        for (int b = 0; b < 4; b++) e[a][b] = 0.f;

#pragma unroll
    for (int kc = 0; kc < 2; kc++) {
        int k2b = kc * 8;
        unsigned ah[4], al[4];
        ldsm_x4(ah, rhb + k2b * 4);
        ldsm_x4(al, rlb + k2b * 4);
#pragma unroll
        for (int ntp = 0; ntp < 2; ntp++) {
            unsigned bo = (((unsigned)(wc2 * 32 + ntp * 16)) * 36 + k2b + bloff) * 4;
            unsigned qh[4], ql[4];
            ldsm_x4(qh, xhb + bo);
            ldsm_x4(ql, xlb + bo);
            unsigned bh0[2] = {qh[0], qh[1]}, bl0[2] = {ql[0], ql[1]};
            unsigned bh1[2] = {qh[2], qh[3]}, bl1[2] = {ql[2], ql[3]};
            mma16(e[2 * ntp], ah, bh0);
            mma16(e[2 * ntp], ah, bl0);
            mma16(e[2 * ntp], al, bh0);
            mma16(e[2 * ntp + 1], ah, bh1);
            mma16(e[2 * ntp + 1], ah, bl1);
            mma16(e[2 * ntp + 1], al, bh1);
        }
    }
    {
        int ch2 = wr2 * 8 + grp;
        int colB = 16 + ch2;
#pragma unroll
        for (int nt = 0; nt < 4; nt++) {
            int col = wc2 * 32 + nt * 8 + 2 * t4;
            int m = m0 + col;
            if (m < Mout) {
                unsigned rh0 = Xth[col * 36 + colB],       rl0 = Xtl[col * 36 + colB];
                unsigned rh1 = Xth[(col + 1) * 36 + colB], rl1 = Xtl[(col + 1) * 36 + colB];
                float v0e = e[nt][0] + fp_half(rh0, 0) + fp_half(rl0, 0);
                float v0o = e[nt][2] + fp_half(rh0, 1) + fp_half(rl0, 1);
                float v1e = e[nt][1] + fp_half(rh1, 0) + fp_half(rl1, 0);
                float v1o = e[nt][3] + fp_half(rh1, 1) + fp_half(rl1, 1);
                unsigned H, L;
                split_pack(v0e, v0o, H, L);
                xouth[(size_t)m * 16 + ch2] = H;
                xoutl[(size_t)m * 16 + ch2] = L;
                split_pack(v1e, v1o, H, L);
                xouth[(size_t)(m + 1) * 16 + ch2] = H;
                xoutl[(size_t)(m + 1) * 16 + ch2] = L;
            }
        }
    }
}

// ---------------------------------------------------------------------------
// fused tail v4 (UNCHANGED from R16): phase B 1-term.
// ---------------------------------------------------------------------------
__global__ void __launch_bounds__(512, 1)
k_tail(const unsigned* __restrict__ ybf,
       const float* __restrict__ e1b, const float* __restrict__ e2w,
       const float* __restrict__ e2b, float* __restrict__ out)
{
    extern __shared__ unsigned smu[];
    unsigned* Hh = smu + 15360;
    float* part = (float*)smu;

    int tid = threadIdx.x;     // 512
    int lane = tid & 31, w = tid >> 5;
    int wm = w >> 1, wn = w & 1;
    int grp = lane >> 2, t4 = lane & 3;
    int p0 = blockIdx.x * 128;
    unsigned smb = smaddr(smu);
    unsigned lr = ((lane >> 3) & 1) * 8 + (lane & 7);
    unsigned lc = (lane >> 4) * 4;
    int bm = lane >> 3, br = lane & 7;
    unsigned bl20  = ((unsigned)((bm >> 1) * 8 + br)) * 20  + (unsigned)(bm & 1) * 4;
    unsigned bl132 = ((unsigned)((bm >> 1) * 8 + br)) * 132 + (unsigned)(bm & 1) * 4;

    float d[2][8][4];
#pragma unroll
    for (int mt = 0; mt < 2; mt++)
#pragma unroll
        for (int nt = 0; nt < 8; nt++)
#pragma unroll
            for (int j = 0; j < 4; j++) d[mt][nt][j] = 0.f;

    int sp = tid >> 2, sq = (tid & 3) * 4;

    {   // prefetch kc = 0
        cp16(smb + (0 * 7680 + sp * 20 + sq) * 4,
             &ybf[(size_t)(p0 + sp) * 16 + sq]);
        for (int l = tid; l < 1024; l += 512) {
            int row = l >> 2, qg = (l & 3) * 4;
            cp16(smb + (0 * 7680 + 2560 + row * 20 + qg) * 4,
                 &g_swf[row * 16 + qg]);
        }
        CP_COMMIT();
    }
    for (int kc = 0; kc < 40; kc++) {
        CP_WAIT0();
        __syncthreads();
        if (kc < 39) {
            int nb = (kc + 1) & 1;
            cp16(smb + (nb * 7680 + sp * 20 + sq) * 4,
                 &ybf[(size_t)(kc + 1) * 16 * FINAL + (size_t)(p0 + sp) * 16 + sq]);
            for (int l = tid; l < 1024; l += 512) {
                int row = l >> 2, qg = (l & 3) * 4;
                cp16(smb + (nb * 7680 + 2560 + row * 20 + qg) * 4,
                     &g_swf[((kc + 1) * 256 + row) * 16 + qg]);
            }
            CP_COMMIT();
        }
        unsigned bcb = smb + ((kc & 1) * 7680) * 4;
        unsigned wcb = bcb + 2560 * 4;
#pragma unroll
        for (int ck = 0; ck < 2; ck++) {
            int k2b = ck * 8;
            unsigned a0[4], a1[4];
            ldsm_x4(a0, wcb + (((unsigned)(wm * 32) + lr) * 20 + k2b + lc) * 4);
            ldsm_x4(a1, wcb + (((unsigned)(wm * 32 + 16) + lr) * 20 + k2b + lc) * 4);
#pragma unroll
            for (int ntp = 0; ntp < 4; ntp++) {
                unsigned q[4];
                ldsm_x4(q, bcb + (((unsigned)(wn * 64 + ntp * 16)) * 20 + k2b + bl20) * 4);
                unsigned b0[2] = {q[0], q[1]}, b1[2] = {q[2], q[3]};
                mma16(d[0][2 * ntp], a0, b0);
                mma16(d[1][2 * ntp], a1, b0);
                mma16(d[0][2 * ntp + 1], a0, b1);
                mma16(d[1][2 * ntp + 1], a1, b1);
            }
        }
    }

    __syncthreads();
#pragma unroll
    for (int mt = 0; mt < 2; mt++) {
        int k2 = (wm * 2 + mt) * 8 + grp;
#pragma unroll
        for (int nt = 0; nt < 8; nt++) {
            int col = wn * 64 + nt * 8 + 2 * t4;
            float v0 = d[mt][nt][0]; v0 = v0 > 0.f ? v0 : 0.f;
            float v2 = d[mt][nt][2]; v2 = v2 > 0.f ? v2 : 0.f;
            float v1 = d[mt][nt][1]; v1 = v1 > 0.f ? v1 : 0.f;
            float v3 = d[mt][nt][3]; v3 = v3 > 0.f ? v3 : 0.f;
            Hh[col * 132 + k2]       = pack1(v0, v2);
            Hh[(col + 1) * 132 + k2] = pack1(v1, v3);
        }
    }

#pragma unroll
    for (int mt = 0; mt < 2; mt++)
#pragma unroll
        for (int nt = 0; nt < 8; nt++)
#pragma unroll
            for (int j = 0; j < 4; j++) d[mt][nt][j] = 0.f;

    {
        __syncthreads();
        int row = tid >> 1, qg = (tid & 1) * 4;
        cp16(smb + (row * 12 + qg) * 4, &g_e1fh[row * 128 + qg]);
        CP_COMMIT();
    }
    unsigned hhB = smaddr(Hh);
    for (int kk = 0; kk < 16; kk++) {
        CP_WAIT0();
        __syncthreads();
        if (kk < 15) {
            int nb = (kk + 1) & 1;
            int row = tid >> 1, qg = (tid & 1) * 4;
            cp16(smb + (nb * 3072 + row * 12 + qg) * 4,
                 &g_e1fh[row * 128 + (kk + 1) * 8 + qg]);
            CP_COMMIT();
        }
        unsigned ecb = smb + ((kk & 1) * 3072) * 4;
        unsigned ah0[4], ah1[4];
        ldsm_x4(ah0, ecb + (((unsigned)(wm * 32) + lr) * 12 + lc) * 4);
        ldsm_x4(ah1, ecb + (((unsigned)(wm * 32 + 16) + lr) * 12 + lc) * 4);
#pragma unroll
        for (int ntp = 0; ntp < 4; ntp++) {
            unsigned base = (((unsigned)(wn * 64 + ntp * 16)) * 132 + kk * 8 + bl132) * 4;
            unsigned qh[4];
            ldsm_x4(qh, hhB + base);
            unsigned bh0[2] = {qh[0], qh[1]}, bh1[2] = {qh[2], qh[3]};
            mma16(d[0][2 * ntp], ah0, bh0);
            mma16(d[1][2 * ntp], ah1, bh0);
            mma16(d[0][2 * ntp + 1], ah0, bh1);
            mma16(d[1][2 * ntp + 1], ah1, bh1);
        }
    }

    int r0 = wm * 32 + grp;
    float eb0 = e1b[r0],      eb1 = e1b[r0 + 8];
    float eb2 = e1b[r0 + 16], eb3 = e1b[r0 + 24];
    float ew0 = e2w[r0],      ew1 = e2w[r0 + 8];
    float ew2 = e2w[r0 + 16], ew3 = e2w[r0 + 24];

    float pc[16];
#pragma unroll
    for (int nt = 0; nt < 8; nt++) {
#pragma unroll
        for (int j = 0; j < 2; j++) {
            float h0 = d[0][nt][j]     + eb0; h0 = h0 > 0.f ? h0 : 0.f;
            float h1 = d[0][nt][2 + j] + eb1; h1 = h1 > 0.f ? h1 : 0.f;
            float h2 = d[1][nt][j]     + eb2; h2 = h2 > 0.f ? h2 : 0.f;
            float h3 = d[1][nt][2 + j] + eb3; h3 = h3 > 0.f ? h3 : 0.f;
            pc[nt * 2 + j] = ew0 * h0 + ew1 * h1 + ew2 * h2 + ew3 * h3;
        }
    }
#pragma unroll
    for (int off = 16; off >= 4; off >>= 1)
#pragma unroll
        for (int t = 0; t < 16; t++)
            pc[t] += __shfl_xor_sync(0xffffffff, pc[t], off);

    if (lane < 4) {
#pragma unroll
        for (int nt = 0; nt < 8; nt++) {
            part[wm * 128 + wn * 64 + nt * 8 + 2 * lane]     = pc[nt * 2];
            part[wm * 128 + wn * 64 + nt * 8 + 2 * lane + 1] = pc[nt * 2 + 1];
        }
    }
    __syncthreads();
    if (tid < 128) {
        float s = e2b[0];
#pragma unroll
        for (int ww = 0; ww < 8; ww++) s += part[ww * 128 + tid];
        int p = p0 + tid;
        out[(p & 15) * TOUT + (p >> 4)] = s;
    }
}

// ---------------------------------------------------------------------------
extern "C" void kernel_launch(void* const* d_in, const int* in_sizes, int n_in,
                              void* d_out, int out_size)
{
    const float* input    = (const float*)d_in[0];
    const float* start_w  = (const float*)d_in[1];
    const float* filter_w = (const float*)d_in[2];
    const float* gate_w   = (const float*)d_in[3];
    const float* res_w    = (const float*)d_in[4];
    const float* skip_w   = (const float*)d_in[5];
    const float* e1w      = (const float*)d_in[6];
    const float* e1b      = (const float*)d_in[7];
    const float* e2w      = (const float*)d_in[8];
    const float* e2b      = (const float*)d_in[9];
    float* out = (float*)d_out;
    (void)in_sizes; (void)n_in; (void)out_size;

    static int attr_done = 0;
    if (!attr_done) {
        cudaFuncSetAttribute(k_layer, cudaFuncAttributeMaxDynamicSharedMemorySize, 51200);
        cudaFuncSetAttribute(k_start, cudaFuncAttributeMaxDynamicSharedMemorySize, 59392);
        cudaFuncSetAttribute(k_tail,  cudaFuncAttributeMaxDynamicSharedMemorySize, 129024);
        attr_done = 1;
    }

    unsigned *xah, *xal, *xbh, *xbl, *ybf;
    cudaGetSymbolAddress((void**)&xah, g_xah);
    cudaGetSymbolAddress((void**)&xal, g_xal);
    cudaGetSymbolAddress((void**)&xbh, g_xbh);
    cudaGetSymbolAddress((void**)&xbl, g_xbl);
    cudaGetSymbolAddress((void**)&ybf, g_ybf);

    k_prep<<<48, 256>>>(filter_w, gate_w, res_w, skip_w, e1w, start_w);
    k_start<<<1024, 256, 59392>>>(input, xah, xal);

    unsigned *curh = xah, *curl = xal, *nxth = xbh, *nxtl = xbl;
    for (int i = 0; i < 40; i++) {
        int b = i / 10, k = i % 10;
        int Mb = 262144 - 8192 * b;
        int Min, Mout, P, S;
        if (k == 0) { Min = Mb; Mout = Mb - 16; P = 0; S = 16; }
        else {
            int d = 1 << k;
            Min = Mb - 8 * d;
            Mout = Mb - 16 * d;
            P = 8 * d;
            S = 16 * d;
        }
        int ofs = Mout - FINAL;
        int grid = (Mout + 127) / 128;
        k_layer<<<grid, 256, 51200>>>(curh, curl, nxth, nxtl,
                                      ybf + (size_t)i * 16 * FINAL,
                                      i, Min, Mout, P, S, ofs);
        unsigned* t;
        t = curh; curh = nxth; nxth = t;
        t = curl; curl = nxtl; nxtl = t;
    }

    k_tail<<<FINAL / 128, 512, 129024>>>(ybf, e1b, e2w, e2b, out);
}